// round 1
// baseline (speedup 1.0000x reference)
#include <cuda_runtime.h>
#include <math.h>
#include <stdint.h>

// ---------------------------------------------------------------------------
// Problem constants
// ---------------------------------------------------------------------------
#define NN 20000
#define DD 128
#define HH 4
#define EE 80000
#define LLAYERS 2
#define HD (HH * DD)   // 512

// ---------------------------------------------------------------------------
// Static device scratch (allocation-free rule: __device__ globals)
// ---------------------------------------------------------------------------
__device__ float g_x_my [NN * DD];
__device__ float g_x_opp[NN * DD];

__device__ float g_xl_b[NN * HD];   // x_my  @ gat_beats_Wl
__device__ float g_xr_b[NN * HD];   // x_opp @ gat_beats_Wr
__device__ float g_xl_r[NN * HD];   // x_opp @ gat_rev_Wl
__device__ float g_xr_r[NN * HD];   // x_my  @ gat_rev_Wr

__device__ float g_P[8][NN * DD];   // CG projections (lose: 0..3, rev: 4..7)

__device__ float g_score [2][EE * HH];
__device__ float g_ex    [2][EE * HH];
__device__ float g_segmax[2][NN * HH];
__device__ float g_segsum[2][NN * HH];

__device__ float g_acc_my [NN * DD];
__device__ float g_acc_opp[NN * DD];

// ---------------------------------------------------------------------------
// GEMM: C[M,Nc] = A[M,K] @ B[K,Nc] (+ bias per col).  Row-major everywhere.
// 64x64 block tile, BK=16, 256 threads, 4x4 register tile per thread.
// Nc must be a multiple of 64 (512 or 128 here); K multiple of 16 (128).
// ---------------------------------------------------------------------------
__global__ void gemm_bias_kernel(const float* __restrict__ A,
                                 const float* __restrict__ B,
                                 const float* __restrict__ bias,
                                 float* __restrict__ C,
                                 int M, int Nc, int K)
{
    constexpr int BM = 64, BN = 64, BK = 16, TM = 4, TN = 4;
    __shared__ float As[BK][BM];
    __shared__ float Bs[BK][BN];

    const int tid = threadIdx.x;                 // 0..255
    const int block_row = blockIdx.y * BM;
    const int block_col = blockIdx.x * BN;
    const int trow = (tid / 16) * TM;            // 0..60
    const int tcol = (tid % 16) * TN;            // 0..60

    float acc[TM][TN];
#pragma unroll
    for (int i = 0; i < TM; i++)
#pragma unroll
        for (int j = 0; j < TN; j++) acc[i][j] = 0.f;

    for (int k0 = 0; k0 < K; k0 += BK) {
        // Load A tile (BM x BK), transposed into As[k][m]
#pragma unroll
        for (int i = tid; i < BM * BK; i += 256) {
            int r = i / BK, c = i % BK;
            int gr = block_row + r;
            As[c][r] = (gr < M) ? A[(size_t)gr * K + k0 + c] : 0.f;
        }
        // Load B tile (BK x BN)
#pragma unroll
        for (int i = tid; i < BK * BN; i += 256) {
            int r = i / BN, c = i % BN;
            Bs[r][c] = B[(size_t)(k0 + r) * Nc + block_col + c];
        }
        __syncthreads();

#pragma unroll
        for (int k = 0; k < BK; k++) {
            float4 a0 = *reinterpret_cast<const float4*>(&As[k][trow]);
            float4 b0 = *reinterpret_cast<const float4*>(&Bs[k][tcol]);
            float a[TM] = {a0.x, a0.y, a0.z, a0.w};
            float b[TN] = {b0.x, b0.y, b0.z, b0.w};
#pragma unroll
            for (int i = 0; i < TM; i++)
#pragma unroll
                for (int j = 0; j < TN; j++)
                    acc[i][j] += a[i] * b[j];
        }
        __syncthreads();
    }

#pragma unroll
    for (int i = 0; i < TM; i++) {
        int gr = block_row + trow + i;
        if (gr >= M) continue;
#pragma unroll
        for (int j = 0; j < TN; j++) {
            int gc = block_col + tcol + j;
            float v = acc[i][j];
            if (bias) v += bias[gc];
            C[(size_t)gr * Nc + gc] = v;
        }
    }
}

static void launch_gemm(const float* A, const float* B, const float* bias,
                        float* C, int M, int Nc, int K)
{
    dim3 grid(Nc / 64, (M + 63) / 64);
    gemm_bias_kernel<<<grid, 256>>>(A, B, bias, C, M, Nc, K);
}

// ---------------------------------------------------------------------------
// Utility kernels
// ---------------------------------------------------------------------------
__global__ void fill_kernel(float* __restrict__ p, float v, int n)
{
    int i = blockIdx.x * blockDim.x + threadIdx.x;
    if (i < n) p[i] = v;
}

// acc[n, c] = x[n, c] + b[c]   (CGConv residual + GAT bias, summed upfront)
__global__ void init_acc_kernel(float* __restrict__ acc,
                                const float* __restrict__ x,
                                const float* __restrict__ b, int n)
{
    int i = blockIdx.x * blockDim.x + threadIdx.x;
    if (i < n) acc[i] = x[i] + b[i & (DD - 1)];
}

__device__ __forceinline__ void atomicMaxFloat(float* addr, float val)
{
    int* ai = (int*)addr;
    int old = *ai;
    while (__int_as_float(old) < val) {
        int assumed = old;
        old = atomicCAS(ai, assumed, __float_as_int(val));
        if (old == assumed) break;
    }
}

// ---------------------------------------------------------------------------
// GATv2 edge kernels (one warp per edge)
// ---------------------------------------------------------------------------
__global__ void gat_score_kernel(const float* __restrict__ xl,
                                 const float* __restrict__ xr,
                                 const float* __restrict__ att,
                                 const int* __restrict__ src,
                                 const int* __restrict__ dst,
                                 float* __restrict__ score,
                                 float* __restrict__ segmax)
{
    int e = blockIdx.x * (blockDim.x >> 5) + (threadIdx.x >> 5);
    int lane = threadIdx.x & 31;
    if (e >= EE) return;
    int s = src[e], d = dst[e];
    const float* pl = xl + (size_t)s * HD;
    const float* pr = xr + (size_t)d * HD;

#pragma unroll
    for (int h = 0; h < HH; h++) {
        float acc = 0.f;
#pragma unroll
        for (int j = 0; j < DD / 32; j++) {
            int c = lane + 32 * j;
            float z = pl[h * DD + c] + pr[h * DD + c];
            z = (z > 0.f) ? z : 0.2f * z;        // leaky_relu(0.2)
            acc += z * att[h * DD + c];
        }
#pragma unroll
        for (int o = 16; o; o >>= 1) acc += __shfl_xor_sync(0xffffffffu, acc, o);
        if (lane == 0) {
            score[(size_t)e * HH + h] = acc;
            atomicMaxFloat(&segmax[(size_t)d * HH + h], acc);
        }
    }
}

__global__ void gat_exp_kernel(const float* __restrict__ score,
                               const int* __restrict__ dst,
                               const float* __restrict__ segmax,
                               float* __restrict__ ex,
                               float* __restrict__ segsum)
{
    int i = blockIdx.x * blockDim.x + threadIdx.x;   // E*H
    if (i >= EE * HH) return;
    int e = i / HH, h = i - e * HH;
    int d = dst[e];
    float v = expf(score[i] - segmax[(size_t)d * HH + h]);
    ex[i] = v;
    atomicAdd(&segsum[(size_t)d * HH + h], v);
}

__global__ void gat_agg_kernel(const float* __restrict__ xl,
                               const float* __restrict__ ex,
                               const float* __restrict__ segsum,
                               const int* __restrict__ src,
                               const int* __restrict__ dst,
                               float* __restrict__ out)
{
    int e = blockIdx.x * (blockDim.x >> 5) + (threadIdx.x >> 5);
    int lane = threadIdx.x & 31;
    if (e >= EE) return;
    int s = src[e], d = dst[e];
    float alpha[HH];
#pragma unroll
    for (int h = 0; h < HH; h++)
        alpha[h] = ex[(size_t)e * HH + h] /
                   (segsum[(size_t)d * HH + h] + 1e-16f) * (1.f / HH);
    const float* pl = xl + (size_t)s * HD;
    float* po = out + (size_t)d * DD;
#pragma unroll
    for (int j = 0; j < DD / 32; j++) {
        int c = lane + 32 * j;
        float v = 0.f;
#pragma unroll
        for (int h = 0; h < HH; h++) v += pl[h * DD + c] * alpha[h];
        atomicAdd(&po[c], v);
    }
}

// ---------------------------------------------------------------------------
// CGConv edge kernel: m = sigmoid(Pfd[d]+Pfs[s]) * softplus(Psd[d]+Pss[s]);
// biases are pre-folded into Pfd / Psd GEMM epilogues.
// ---------------------------------------------------------------------------
__global__ void cg_edge_kernel(const float* __restrict__ Pfd,
                               const float* __restrict__ Pfs,
                               const float* __restrict__ Psd,
                               const float* __restrict__ Pss,
                               const int* __restrict__ src,
                               const int* __restrict__ dst,
                               float* __restrict__ out)
{
    int e = blockIdx.x * (blockDim.x >> 5) + (threadIdx.x >> 5);
    int lane = threadIdx.x & 31;
    if (e >= EE) return;
    int s = src[e], d = dst[e];
    const float* pfd = Pfd + (size_t)d * DD;
    const float* pfs = Pfs + (size_t)s * DD;
    const float* psd = Psd + (size_t)d * DD;
    const float* pss = Pss + (size_t)s * DD;
    float* po = out + (size_t)d * DD;
#pragma unroll
    for (int j = 0; j < DD / 32; j++) {
        int c = lane + 32 * j;
        float f = pfd[c] + pfs[c];
        float g = psd[c] + pss[c];
        float sig = 1.f / (1.f + expf(-f));
        float sp  = fmaxf(g, 0.f) + log1pf(expf(-fabsf(g)));  // stable softplus
        atomicAdd(&po[c], sig * sp);
    }
}

// ---------------------------------------------------------------------------
// Host launcher
// ---------------------------------------------------------------------------
extern "C" void kernel_launch(void* const* d_in, const int* in_sizes, int n_in,
                              void* d_out, int out_size)
{
    const float* in_x_my  = (const float*)d_in[0];
    const float* in_x_opp = (const float*)d_in[1];
    const float* gWl_b = (const float*)d_in[2];
    const float* gWr_b = (const float*)d_in[3];
    const float* gatt_b = (const float*)d_in[4];
    const float* gb_b  = (const float*)d_in[5];
    const float* gWl_r = (const float*)d_in[6];
    const float* gWr_r = (const float*)d_in[7];
    const float* gatt_r = (const float*)d_in[8];
    const float* gb_r  = (const float*)d_in[9];
    const float* cgL_Wf = (const float*)d_in[10];
    const float* cgL_bf = (const float*)d_in[11];
    const float* cgL_Ws = (const float*)d_in[12];
    const float* cgL_bs = (const float*)d_in[13];
    const float* cgR_Wf = (const float*)d_in[14];
    const float* cgR_bf = (const float*)d_in[15];
    const float* cgR_Ws = (const float*)d_in[16];
    const float* cgR_bs = (const float*)d_in[17];
    const float* nw_W = (const float*)d_in[18];
    const float* nw_b = (const float*)d_in[19];
    const int* ei_beats     = (const int*)d_in[20];
    const int* ei_loses     = (const int*)d_in[21];
    const int* ei_rev_beats = (const int*)d_in[22];
    const int* ei_rev_loses = (const int*)d_in[23];

    float* out = (float*)d_out;

    // Resolve device-scratch symbol addresses (host API, not a graph node).
    float *x_my, *x_opp, *xl_b, *xr_b, *xl_r, *xr_r, *P, *score, *ex, *segmax,
          *segsum, *acc_my, *acc_opp;
    cudaGetSymbolAddress((void**)&x_my,  g_x_my);
    cudaGetSymbolAddress((void**)&x_opp, g_x_opp);
    cudaGetSymbolAddress((void**)&xl_b,  g_xl_b);
    cudaGetSymbolAddress((void**)&xr_b,  g_xr_b);
    cudaGetSymbolAddress((void**)&xl_r,  g_xl_r);
    cudaGetSymbolAddress((void**)&xr_r,  g_xr_r);
    cudaGetSymbolAddress((void**)&P,     g_P);
    cudaGetSymbolAddress((void**)&score, g_score);
    cudaGetSymbolAddress((void**)&ex,    g_ex);
    cudaGetSymbolAddress((void**)&segmax, g_segmax);
    cudaGetSymbolAddress((void**)&segsum, g_segsum);
    cudaGetSymbolAddress((void**)&acc_my, g_acc_my);
    cudaGetSymbolAddress((void**)&acc_opp, g_acc_opp);

    const int* src_b  = ei_beats;      const int* dst_b  = ei_beats + EE;
    const int* src_l  = ei_loses;      const int* dst_l  = ei_loses + EE;
    const int* src_rb = ei_rev_beats;  const int* dst_rb = ei_rev_beats + EE;
    const int* src_rl = ei_rev_loses;  const int* dst_rl = ei_rev_loses + EE;

    const int edge_blocks = (EE + 7) / 8;          // 8 warps / block
    const int nd_blocks   = (NN * DD + 255) / 256;
    const int nh_blocks   = (NN * HH + 255) / 256;
    const int eh_blocks   = (EE * HH + 255) / 256;

    const float* cur_my  = in_x_my;
    const float* cur_opp = in_x_opp;

    for (int l = 0; l < LLAYERS; l++) {
        const size_t oW = (size_t)l * DD * HD;   // GAT weight offset
        const size_t oA = (size_t)l * HH * DD;   // att offset
        const size_t oB = (size_t)l * DD;        // bias offset
        const size_t oC = (size_t)l * 2 * DD * DD; // CG weight offset
        const size_t oN = (size_t)l * DD * DD;   // nw weight offset

        // ---- Node-level GEMMs ----
        launch_gemm(cur_my,  gWl_b + oW, nullptr, xl_b, NN, HD, DD);
        launch_gemm(cur_opp, gWr_b + oW, nullptr, xr_b, NN, HD, DD);
        launch_gemm(cur_opp, gWl_r + oW, nullptr, xl_r, NN, HD, DD);
        launch_gemm(cur_my,  gWr_r + oW, nullptr, xr_r, NN, HD, DD);

        // CG lose (dst = opp, src = my): split Wf/Ws into dst-rows / src-rows
        launch_gemm(cur_opp, cgL_Wf + oC,           cgL_bf + oB, P + 0 * NN * DD, NN, DD, DD);
        launch_gemm(cur_my,  cgL_Wf + oC + DD * DD, nullptr,     P + 1 * NN * DD, NN, DD, DD);
        launch_gemm(cur_opp, cgL_Ws + oC,           cgL_bs + oB, P + 2 * NN * DD, NN, DD, DD);
        launch_gemm(cur_my,  cgL_Ws + oC + DD * DD, nullptr,     P + 3 * NN * DD, NN, DD, DD);
        // CG rev (dst = my, src = opp)
        launch_gemm(cur_my,  cgR_Wf + oC,           cgR_bf + oB, P + 4 * NN * DD, NN, DD, DD);
        launch_gemm(cur_opp, cgR_Wf + oC + DD * DD, nullptr,     P + 5 * NN * DD, NN, DD, DD);
        launch_gemm(cur_my,  cgR_Ws + oC,           cgR_bs + oB, P + 6 * NN * DD, NN, DD, DD);
        launch_gemm(cur_opp, cgR_Ws + oC + DD * DD, nullptr,     P + 7 * NN * DD, NN, DD, DD);

        // ---- Segment-softmax scratch init ----
        fill_kernel<<<nh_blocks, 256>>>(segmax,                -INFINITY, NN * HH);
        fill_kernel<<<nh_blocks, 256>>>(segmax + NN * HH,      -INFINITY, NN * HH);
        fill_kernel<<<nh_blocks, 256>>>(segsum,                0.f,       NN * HH);
        fill_kernel<<<nh_blocks, 256>>>(segsum + NN * HH,      0.f,       NN * HH);

        // ---- Accumulator init: CG residual (x_dst) + GAT bias ----
        init_acc_kernel<<<nd_blocks, 256>>>(acc_opp, cur_opp, gb_b + oB, NN * DD);
        init_acc_kernel<<<nd_blocks, 256>>>(acc_my,  cur_my,  gb_r + oB, NN * DD);

        // ---- GAT beats (my -> opp) ----
        gat_score_kernel<<<edge_blocks, 256>>>(xl_b, xr_b, gatt_b + oA,
                                               src_b, dst_b, score, segmax);
        gat_exp_kernel<<<eh_blocks, 256>>>(score, dst_b, segmax, ex, segsum);
        gat_agg_kernel<<<edge_blocks, 256>>>(xl_b, ex, segsum, src_b, dst_b, acc_opp);

        // ---- GAT rev_loses (opp -> my) ----
        gat_score_kernel<<<edge_blocks, 256>>>(xl_r, xr_r, gatt_r + oA,
                                               src_rl, dst_rl,
                                               score + EE * HH, segmax + NN * HH);
        gat_exp_kernel<<<eh_blocks, 256>>>(score + EE * HH, dst_rl,
                                           segmax + NN * HH,
                                           ex + EE * HH, segsum + NN * HH);
        gat_agg_kernel<<<edge_blocks, 256>>>(xl_r, ex + EE * HH, segsum + NN * HH,
                                             src_rl, dst_rl, acc_my);

        // ---- CGConv edges ----
        cg_edge_kernel<<<edge_blocks, 256>>>(P + 0 * NN * DD, P + 1 * NN * DD,
                                             P + 2 * NN * DD, P + 3 * NN * DD,
                                             src_l, dst_l, acc_opp);
        cg_edge_kernel<<<edge_blocks, 256>>>(P + 4 * NN * DD, P + 5 * NN * DD,
                                             P + 6 * NN * DD, P + 7 * NN * DD,
                                             src_rb, dst_rb, acc_my);

        // ---- Shared nodewise Linear ----
        float* out_my  = (l == LLAYERS - 1) ? out            : x_my;
        float* out_opp = (l == LLAYERS - 1) ? out + NN * DD  : x_opp;
        launch_gemm(acc_my,  nw_W + oN, nw_b + oB, out_my,  NN, DD, DD);
        launch_gemm(acc_opp, nw_W + oN, nw_b + oB, out_opp, NN, DD, DD);

        cur_my  = x_my;
        cur_opp = x_opp;
    }
}

// round 2
// speedup vs baseline: 1.4326x; 1.4326x over previous
#include <cuda_runtime.h>
#include <math.h>
#include <stdint.h>

// ---------------------------------------------------------------------------
// Problem constants
// ---------------------------------------------------------------------------
#define NN 20000
#define DD 128
#define HH 4
#define EE 80000
#define LLAYERS 2
#define HD (HH * DD)   // 512

// ---------------------------------------------------------------------------
// Static device scratch (allocation-free rule: __device__ globals)
// ---------------------------------------------------------------------------
__device__ float g_x_my [NN * DD];
__device__ float g_x_opp[NN * DD];

__device__ float g_xl_b[NN * HD];   // x_my  @ gat_beats_Wl
__device__ float g_xr_b[NN * HD];   // x_opp @ gat_beats_Wr
__device__ float g_xl_r[NN * HD];   // x_opp @ gat_rev_Wl
__device__ float g_xr_r[NN * HD];   // x_my  @ gat_rev_Wr

__device__ float g_P[8][NN * DD];   // CG projections (lose: 0..3, rev: 4..7)

__device__ float g_score [2][EE * HH];
__device__ float g_ex    [2][EE * HH];
__device__ float g_segmax[2][NN * HH];
__device__ float g_segsum[2][NN * HH];

__device__ float g_acc_my [NN * DD];
__device__ float g_acc_opp[NN * DD];

// ---------------------------------------------------------------------------
// Packed f32x2 helpers (Blackwell: 2x fp32 FMA throughput, PTX-only)
// ---------------------------------------------------------------------------
__device__ __forceinline__ void fma2(unsigned long long& d,
                                     unsigned long long a,
                                     unsigned long long b)
{
    asm("fma.rn.f32x2 %0, %1, %2, %0;" : "+l"(d) : "l"(a), "l"(b));
}
__device__ __forceinline__ unsigned long long pack_dup(float a)
{
    unsigned long long r;
    asm("mov.b64 %0, {%1, %1};" : "=l"(r) : "f"(a));
    return r;
}
__device__ __forceinline__ unsigned long long pack2(float x, float y)
{
    unsigned long long r;
    asm("mov.b64 %0, {%1, %2};" : "=l"(r) : "f"(x), "f"(y));
    return r;
}
__device__ __forceinline__ float2 unpack2(unsigned long long v)
{
    float2 f;
    asm("mov.b64 {%0, %1}, %2;" : "=f"(f.x), "=f"(f.y) : "l"(v));
    return f;
}

// ---------------------------------------------------------------------------
// GEMM: C[M,Nc] = A[M,K] @ B[K,Nc] (+ bias per col).  Row-major.
// 128x128 block tile, BK=16, 256 threads, 8x8 register tile, FFMA2 inner loop.
// Nc multiple of 128 (512 or 128 here); K multiple of 16 (128 here).
// ---------------------------------------------------------------------------
__global__ void __launch_bounds__(256, 2)
gemm_bias_kernel(const float* __restrict__ A,
                 const float* __restrict__ B,
                 const float* __restrict__ bias,
                 float* __restrict__ C,
                 int M, int Nc, int K)
{
    constexpr int BM = 128, BN = 128, BK = 16;
    constexpr int AP = BM + 4;               // pad: 132 floats (528B, 16B-mult)
    __shared__ float As[BK][AP];
    __shared__ float Bs[BK][BN];

    const int tid = threadIdx.x;             // 0..255
    const int row0 = blockIdx.y * BM;
    const int col0 = blockIdx.x * BN;
    const int trow = (tid >> 4) * 8;         // 0..120
    const int tcol = (tid & 15) * 8;         // 0..120

    unsigned long long acc[8][4];
#pragma unroll
    for (int i = 0; i < 8; i++)
#pragma unroll
        for (int j = 0; j < 4; j++) acc[i][j] = 0ull;

    for (int k0 = 0; k0 < K; k0 += BK) {
        // ---- load A tile (BM x BK) transposed into As[k][m] ----
#pragma unroll
        for (int it = 0; it < 2; it++) {
            int t = tid + it * 256;          // 0..511
            int r = t >> 2;                  // 0..127
            int c = (t & 3) * 4;             // 0,4,8,12
            int gr = row0 + r;
            float4 v = make_float4(0.f, 0.f, 0.f, 0.f);
            if (gr < M)
                v = *reinterpret_cast<const float4*>(&A[(size_t)gr * K + k0 + c]);
            As[c + 0][r] = v.x;
            As[c + 1][r] = v.y;
            As[c + 2][r] = v.z;
            As[c + 3][r] = v.w;
        }
        // ---- load B tile (BK x BN) ----
#pragma unroll
        for (int it = 0; it < 2; it++) {
            int t = tid + it * 256;
            int r = t >> 5;                  // 0..15
            int c = (t & 31) * 4;            // 0..124
            *reinterpret_cast<float4*>(&Bs[r][c]) =
                *reinterpret_cast<const float4*>(&B[(size_t)(k0 + r) * Nc + col0 + c]);
        }
        __syncthreads();

#pragma unroll
        for (int k = 0; k < BK; k++) {
            float4 a0 = *reinterpret_cast<const float4*>(&As[k][trow]);
            float4 a1 = *reinterpret_cast<const float4*>(&As[k][trow + 4]);
            float4 b0 = *reinterpret_cast<const float4*>(&Bs[k][tcol]);
            float4 b1 = *reinterpret_cast<const float4*>(&Bs[k][tcol + 4]);
            unsigned long long bp[4];
            bp[0] = pack2(b0.x, b0.y);
            bp[1] = pack2(b0.z, b0.w);
            bp[2] = pack2(b1.x, b1.y);
            bp[3] = pack2(b1.z, b1.w);
            float av[8] = {a0.x, a0.y, a0.z, a0.w, a1.x, a1.y, a1.z, a1.w};
#pragma unroll
            for (int i = 0; i < 8; i++) {
                unsigned long long ap = pack_dup(av[i]);
                fma2(acc[i][0], ap, bp[0]);
                fma2(acc[i][1], ap, bp[1]);
                fma2(acc[i][2], ap, bp[2]);
                fma2(acc[i][3], ap, bp[3]);
            }
        }
        __syncthreads();
    }

    // ---- epilogue ----
    float bv[8];
    if (bias) {
        float4 t0 = *reinterpret_cast<const float4*>(&bias[col0 + tcol]);
        float4 t1 = *reinterpret_cast<const float4*>(&bias[col0 + tcol + 4]);
        bv[0] = t0.x; bv[1] = t0.y; bv[2] = t0.z; bv[3] = t0.w;
        bv[4] = t1.x; bv[5] = t1.y; bv[6] = t1.z; bv[7] = t1.w;
    } else {
#pragma unroll
        for (int j = 0; j < 8; j++) bv[j] = 0.f;
    }
#pragma unroll
    for (int i = 0; i < 8; i++) {
        int gr = row0 + trow + i;
        if (gr >= M) continue;
        float2 p0 = unpack2(acc[i][0]);
        float2 p1 = unpack2(acc[i][1]);
        float2 p2 = unpack2(acc[i][2]);
        float2 p3 = unpack2(acc[i][3]);
        float4 o0 = make_float4(p0.x + bv[0], p0.y + bv[1], p1.x + bv[2], p1.y + bv[3]);
        float4 o1 = make_float4(p2.x + bv[4], p2.y + bv[5], p3.x + bv[6], p3.y + bv[7]);
        float* cp = &C[(size_t)gr * Nc + col0 + tcol];
        *reinterpret_cast<float4*>(cp)     = o0;
        *reinterpret_cast<float4*>(cp + 4) = o1;
    }
}

static void launch_gemm(const float* A, const float* B, const float* bias,
                        float* C, int M, int Nc, int K)
{
    dim3 grid(Nc / 128, (M + 127) / 128);
    gemm_bias_kernel<<<grid, 256>>>(A, B, bias, C, M, Nc, K);
}

// ---------------------------------------------------------------------------
// Per-layer reset: acc init (residual + GAT bias) and segmax/segsum fill.
// ---------------------------------------------------------------------------
__global__ void reset_kernel(float* __restrict__ acc_opp,
                             float* __restrict__ acc_my,
                             const float* __restrict__ x_opp,
                             const float* __restrict__ x_my,
                             const float* __restrict__ gb_b,
                             const float* __restrict__ gb_r,
                             float* __restrict__ segmax,
                             float* __restrict__ segsum)
{
    int i = blockIdx.x * blockDim.x + threadIdx.x;
    if (i < NN * DD) {
        int c = i & (DD - 1);
        acc_opp[i] = x_opp[i] + gb_b[c];
        acc_my[i]  = x_my[i]  + gb_r[c];
    }
    if (i < 2 * NN * HH) {
        segmax[i] = -INFINITY;
        segsum[i] = 0.f;
    }
}

__device__ __forceinline__ void atomicMaxFloat(float* addr, float val)
{
    int* ai = (int*)addr;
    int old = *ai;
    while (__int_as_float(old) < val) {
        int assumed = old;
        old = atomicCAS(ai, assumed, __float_as_int(val));
        if (old == assumed) break;
    }
}

// ---------------------------------------------------------------------------
// GATv2 edge kernels (one warp per edge, float4 lanes)
// ---------------------------------------------------------------------------
__global__ void gat_score_kernel(const float* __restrict__ xl,
                                 const float* __restrict__ xr,
                                 const float* __restrict__ att,
                                 const int* __restrict__ src,
                                 const int* __restrict__ dst,
                                 float* __restrict__ score,
                                 float* __restrict__ segmax)
{
    int e = blockIdx.x * (blockDim.x >> 5) + (threadIdx.x >> 5);
    int lane = threadIdx.x & 31;
    if (e >= EE) return;
    int s = src[e], d = dst[e];
    const float4* pl = reinterpret_cast<const float4*>(xl + (size_t)s * HD);
    const float4* pr = reinterpret_cast<const float4*>(xr + (size_t)d * HD);
    const float4* pa = reinterpret_cast<const float4*>(att);

#pragma unroll
    for (int h = 0; h < HH; h++) {
        float4 l = pl[h * 32 + lane];
        float4 r = pr[h * 32 + lane];
        float4 a = pa[h * 32 + lane];
        float zx = l.x + r.x, zy = l.y + r.y, zz = l.z + r.z, zw = l.w + r.w;
        zx = (zx > 0.f) ? zx : 0.2f * zx;
        zy = (zy > 0.f) ? zy : 0.2f * zy;
        zz = (zz > 0.f) ? zz : 0.2f * zz;
        zw = (zw > 0.f) ? zw : 0.2f * zw;
        float acc = zx * a.x + zy * a.y + zz * a.z + zw * a.w;
#pragma unroll
        for (int o = 16; o; o >>= 1) acc += __shfl_xor_sync(0xffffffffu, acc, o);
        if (lane == 0) {
            score[(size_t)e * HH + h] = acc;
            atomicMaxFloat(&segmax[(size_t)d * HH + h], acc);
        }
    }
}

__global__ void gat_exp_kernel(const float* __restrict__ score,
                               const int* __restrict__ dst,
                               const float* __restrict__ segmax,
                               float* __restrict__ ex,
                               float* __restrict__ segsum)
{
    int i = blockIdx.x * blockDim.x + threadIdx.x;   // E*H
    if (i >= EE * HH) return;
    int e = i >> 2, h = i & 3;
    int d = dst[e];
    float v = expf(score[i] - segmax[(size_t)d * HH + h]);
    ex[i] = v;
    atomicAdd(&segsum[(size_t)d * HH + h], v);
}

__global__ void gat_agg_kernel(const float* __restrict__ xl,
                               const float* __restrict__ ex,
                               const float* __restrict__ segsum,
                               const int* __restrict__ src,
                               const int* __restrict__ dst,
                               float* __restrict__ out)
{
    int e = blockIdx.x * (blockDim.x >> 5) + (threadIdx.x >> 5);
    int lane = threadIdx.x & 31;
    if (e >= EE) return;
    int s = src[e], d = dst[e];
    float alpha[HH];
#pragma unroll
    for (int h = 0; h < HH; h++)
        alpha[h] = ex[(size_t)e * HH + h] /
                   (segsum[(size_t)d * HH + h] + 1e-16f) * (1.f / HH);
    const float4* pl = reinterpret_cast<const float4*>(xl + (size_t)s * HD);
    float* po = out + (size_t)d * DD + lane * 4;
    float4 acc = make_float4(0.f, 0.f, 0.f, 0.f);
#pragma unroll
    for (int h = 0; h < HH; h++) {
        float4 v = pl[h * 32 + lane];
        acc.x += v.x * alpha[h];
        acc.y += v.y * alpha[h];
        acc.z += v.z * alpha[h];
        acc.w += v.w * alpha[h];
    }
    atomicAdd(po + 0, acc.x);
    atomicAdd(po + 1, acc.y);
    atomicAdd(po + 2, acc.z);
    atomicAdd(po + 3, acc.w);
}

// ---------------------------------------------------------------------------
// CGConv edge kernel: m = sigmoid(Pfd[d]+Pfs[s]) * softplus(Psd[d]+Pss[s]).
// Biases are pre-folded into Pfd / Psd GEMM epilogues.
// ---------------------------------------------------------------------------
__global__ void cg_edge_kernel(const float* __restrict__ Pfd,
                               const float* __restrict__ Pfs,
                               const float* __restrict__ Psd,
                               const float* __restrict__ Pss,
                               const int* __restrict__ src,
                               const int* __restrict__ dst,
                               float* __restrict__ out)
{
    int e = blockIdx.x * (blockDim.x >> 5) + (threadIdx.x >> 5);
    int lane = threadIdx.x & 31;
    if (e >= EE) return;
    int s = src[e], d = dst[e];
    float4 fd = reinterpret_cast<const float4*>(Pfd + (size_t)d * DD)[lane];
    float4 fs = reinterpret_cast<const float4*>(Pfs + (size_t)s * DD)[lane];
    float4 sd = reinterpret_cast<const float4*>(Psd + (size_t)d * DD)[lane];
    float4 ss = reinterpret_cast<const float4*>(Pss + (size_t)s * DD)[lane];
    float* po = out + (size_t)d * DD + lane * 4;

    float f[4] = {fd.x + fs.x, fd.y + fs.y, fd.z + fs.z, fd.w + fs.w};
    float g[4] = {sd.x + ss.x, sd.y + ss.y, sd.z + ss.z, sd.w + ss.w};
#pragma unroll
    for (int j = 0; j < 4; j++) {
        float sig = 1.f / (1.f + expf(-f[j]));
        float sp  = fmaxf(g[j], 0.f) + log1pf(expf(-fabsf(g[j])));
        atomicAdd(po + j, sig * sp);
    }
}

// ---------------------------------------------------------------------------
// Host launcher
// ---------------------------------------------------------------------------
extern "C" void kernel_launch(void* const* d_in, const int* in_sizes, int n_in,
                              void* d_out, int out_size)
{
    const float* in_x_my  = (const float*)d_in[0];
    const float* in_x_opp = (const float*)d_in[1];
    const float* gWl_b = (const float*)d_in[2];
    const float* gWr_b = (const float*)d_in[3];
    const float* gatt_b = (const float*)d_in[4];
    const float* gb_b  = (const float*)d_in[5];
    const float* gWl_r = (const float*)d_in[6];
    const float* gWr_r = (const float*)d_in[7];
    const float* gatt_r = (const float*)d_in[8];
    const float* gb_r  = (const float*)d_in[9];
    const float* cgL_Wf = (const float*)d_in[10];
    const float* cgL_bf = (const float*)d_in[11];
    const float* cgL_Ws = (const float*)d_in[12];
    const float* cgL_bs = (const float*)d_in[13];
    const float* cgR_Wf = (const float*)d_in[14];
    const float* cgR_bf = (const float*)d_in[15];
    const float* cgR_Ws = (const float*)d_in[16];
    const float* cgR_bs = (const float*)d_in[17];
    const float* nw_W = (const float*)d_in[18];
    const float* nw_b = (const float*)d_in[19];
    const int* ei_beats     = (const int*)d_in[20];
    const int* ei_loses     = (const int*)d_in[21];
    const int* ei_rev_beats = (const int*)d_in[22];
    const int* ei_rev_loses = (const int*)d_in[23];

    float* out = (float*)d_out;

    float *x_my, *x_opp, *xl_b, *xr_b, *xl_r, *xr_r, *P, *score, *ex, *segmax,
          *segsum, *acc_my, *acc_opp;
    cudaGetSymbolAddress((void**)&x_my,  g_x_my);
    cudaGetSymbolAddress((void**)&x_opp, g_x_opp);
    cudaGetSymbolAddress((void**)&xl_b,  g_xl_b);
    cudaGetSymbolAddress((void**)&xr_b,  g_xr_b);
    cudaGetSymbolAddress((void**)&xl_r,  g_xl_r);
    cudaGetSymbolAddress((void**)&xr_r,  g_xr_r);
    cudaGetSymbolAddress((void**)&P,     g_P);
    cudaGetSymbolAddress((void**)&score, g_score);
    cudaGetSymbolAddress((void**)&ex,    g_ex);
    cudaGetSymbolAddress((void**)&segmax, g_segmax);
    cudaGetSymbolAddress((void**)&segsum, g_segsum);
    cudaGetSymbolAddress((void**)&acc_my, g_acc_my);
    cudaGetSymbolAddress((void**)&acc_opp, g_acc_opp);

    const int* src_b  = ei_beats;      const int* dst_b  = ei_beats + EE;
    const int* src_l  = ei_loses;      const int* dst_l  = ei_loses + EE;
    const int* src_rb = ei_rev_beats;  const int* dst_rb = ei_rev_beats + EE;
    const int* src_rl = ei_rev_loses;  const int* dst_rl = ei_rev_loses + EE;

    const int edge_blocks = (EE + 7) / 8;          // 8 warps / block
    const int nd_blocks   = (NN * DD + 255) / 256;
    const int eh_blocks   = (EE * HH + 255) / 256;

    const float* cur_my  = in_x_my;
    const float* cur_opp = in_x_opp;

    for (int l = 0; l < LLAYERS; l++) {
        const size_t oW = (size_t)l * DD * HD;     // GAT weight offset
        const size_t oA = (size_t)l * HH * DD;     // att offset
        const size_t oB = (size_t)l * DD;          // bias offset
        const size_t oC = (size_t)l * 2 * DD * DD; // CG weight offset
        const size_t oN = (size_t)l * DD * DD;     // nw weight offset

        // ---- Node-level GEMMs ----
        launch_gemm(cur_my,  gWl_b + oW, nullptr, xl_b, NN, HD, DD);
        launch_gemm(cur_opp, gWr_b + oW, nullptr, xr_b, NN, HD, DD);
        launch_gemm(cur_opp, gWl_r + oW, nullptr, xl_r, NN, HD, DD);
        launch_gemm(cur_my,  gWr_r + oW, nullptr, xr_r, NN, HD, DD);

        // CG lose (dst = opp, src = my): split Wf/Ws into dst-rows / src-rows
        launch_gemm(cur_opp, cgL_Wf + oC,           cgL_bf + oB, P + 0 * NN * DD, NN, DD, DD);
        launch_gemm(cur_my,  cgL_Wf + oC + DD * DD, nullptr,     P + 1 * NN * DD, NN, DD, DD);
        launch_gemm(cur_opp, cgL_Ws + oC,           cgL_bs + oB, P + 2 * NN * DD, NN, DD, DD);
        launch_gemm(cur_my,  cgL_Ws + oC + DD * DD, nullptr,     P + 3 * NN * DD, NN, DD, DD);
        // CG rev (dst = my, src = opp)
        launch_gemm(cur_my,  cgR_Wf + oC,           cgR_bf + oB, P + 4 * NN * DD, NN, DD, DD);
        launch_gemm(cur_opp, cgR_Wf + oC + DD * DD, nullptr,     P + 5 * NN * DD, NN, DD, DD);
        launch_gemm(cur_my,  cgR_Ws + oC,           cgR_bs + oB, P + 6 * NN * DD, NN, DD, DD);
        launch_gemm(cur_opp, cgR_Ws + oC + DD * DD, nullptr,     P + 7 * NN * DD, NN, DD, DD);

        // ---- Reset accumulators + softmax scratch (one launch) ----
        reset_kernel<<<nd_blocks, 256>>>(acc_opp, acc_my, cur_opp, cur_my,
                                         gb_b + oB, gb_r + oB, segmax, segsum);

        // ---- GAT beats (my -> opp) ----
        gat_score_kernel<<<edge_blocks, 256>>>(xl_b, xr_b, gatt_b + oA,
                                               src_b, dst_b, score, segmax);
        gat_exp_kernel<<<eh_blocks, 256>>>(score, dst_b, segmax, ex, segsum);
        gat_agg_kernel<<<edge_blocks, 256>>>(xl_b, ex, segsum, src_b, dst_b, acc_opp);

        // ---- GAT rev_loses (opp -> my) ----
        gat_score_kernel<<<edge_blocks, 256>>>(xl_r, xr_r, gatt_r + oA,
                                               src_rl, dst_rl,
                                               score + EE * HH, segmax + NN * HH);
        gat_exp_kernel<<<eh_blocks, 256>>>(score + EE * HH, dst_rl,
                                           segmax + NN * HH,
                                           ex + EE * HH, segsum + NN * HH);
        gat_agg_kernel<<<edge_blocks, 256>>>(xl_r, ex + EE * HH, segsum + NN * HH,
                                             src_rl, dst_rl, acc_my);

        // ---- CGConv edges ----
        cg_edge_kernel<<<edge_blocks, 256>>>(P + 0 * NN * DD, P + 1 * NN * DD,
                                             P + 2 * NN * DD, P + 3 * NN * DD,
                                             src_l, dst_l, acc_opp);
        cg_edge_kernel<<<edge_blocks, 256>>>(P + 4 * NN * DD, P + 5 * NN * DD,
                                             P + 6 * NN * DD, P + 7 * NN * DD,
                                             src_rb, dst_rb, acc_my);

        // ---- Shared nodewise Linear ----
        float* out_my  = (l == LLAYERS - 1) ? out            : x_my;
        float* out_opp = (l == LLAYERS - 1) ? out + NN * DD  : x_opp;
        launch_gemm(acc_my,  nw_W + oN, nw_b + oB, out_my,  NN, DD, DD);
        launch_gemm(acc_opp, nw_W + oN, nw_b + oB, out_opp, NN, DD, DD);

        cur_my  = x_my;
        cur_opp = x_opp;
    }
}

// round 4
// speedup vs baseline: 2.4755x; 1.7281x over previous
#include <cuda_runtime.h>
#include <cuda_bf16.h>
#include <math.h>
#include <stdint.h>

// ---------------------------------------------------------------------------
// Problem constants
// ---------------------------------------------------------------------------
#define NN 20000
#define DD 128
#define HH 4
#define EE 80000
#define LLAYERS 2
#define HD (HH * DD)      // 512
#define LDC 1536          // fat projection width per node type

// Fat column layout (per node type X in {my, opp}):
//  [0,512)      GAT projection #1 (my: Wl_beats ; opp: Wr_beats)
//  [512,1024)   GAT projection #2 (my: Wr_rev   ; opp: Wl_rev)
//  [1024,1152)  CG lose Wf part   (my: src/bottom ; opp: dst/top + bf)
//  [1152,1280)  CG lose Ws part   (my: src/bottom ; opp: dst/top + bs)
//  [1280,1408)  CG rev  Wf part   (my: dst/top + bf ; opp: src/bottom)
//  [1408,1536)  CG rev  Ws part   (my: dst/top + bs ; opp: src/bottom)

// ---------------------------------------------------------------------------
// Static device scratch
// ---------------------------------------------------------------------------
__device__ __align__(16) float g_C_my [(size_t)NN * LDC];
__device__ __align__(16) float g_C_opp[(size_t)NN * LDC];

__device__ __align__(16) float g_x_my [NN * DD];
__device__ __align__(16) float g_x_opp[NN * DD];
__device__ __align__(16) float g_acc_my [NN * DD];
__device__ __align__(16) float g_acc_opp[NN * DD];

__device__ __align__(16) __nv_bfloat16 g_xh_my [NN * DD];
__device__ __align__(16) __nv_bfloat16 g_xlo_my[NN * DD];
__device__ __align__(16) __nv_bfloat16 g_xh_opp [NN * DD];
__device__ __align__(16) __nv_bfloat16 g_xlo_opp[NN * DD];

__device__ __align__(16) __nv_bfloat16 g_ah_my [NN * DD];   // acc splits
__device__ __align__(16) __nv_bfloat16 g_alo_my[NN * DD];
__device__ __align__(16) __nv_bfloat16 g_ah_opp [NN * DD];
__device__ __align__(16) __nv_bfloat16 g_alo_opp[NN * DD];

__device__ __align__(16) __nv_bfloat16 g_Wth_my [LDC * DD]; // fat W^T splits
__device__ __align__(16) __nv_bfloat16 g_Wtl_my [LDC * DD];
__device__ __align__(16) __nv_bfloat16 g_Wth_opp[LDC * DD];
__device__ __align__(16) __nv_bfloat16 g_Wtl_opp[LDC * DD];
__device__ __align__(16) __nv_bfloat16 g_nwWh[DD * DD];
__device__ __align__(16) __nv_bfloat16 g_nwWl[DD * DD];

__device__ __align__(16) float g_bias_my [LDC];
__device__ __align__(16) float g_bias_opp[LDC];

__device__ float g_score [2][EE * HH];
__device__ float g_ex    [2][EE * HH];
__device__ float g_segmax[2][NN * HH];
__device__ float g_segsum[2][NN * HH];

// ---------------------------------------------------------------------------
// Warp MMA helpers (sm_80+ HMMA path, works on plain compute_103 target)
// ---------------------------------------------------------------------------
__device__ __forceinline__ uint32_t smem_to_u32(const void* p)
{
    uint32_t a;
    asm("{ .reg .u64 t; cvta.to.shared.u64 t, %1; cvt.u32.u64 %0, t; }"
        : "=r"(a) : "l"(p));
    return a;
}

__device__ __forceinline__ void ldx4(uint32_t* r, uint32_t addr)
{
    asm volatile("ldmatrix.sync.aligned.m8n8.x4.shared.b16 {%0,%1,%2,%3}, [%4];"
                 : "=r"(r[0]), "=r"(r[1]), "=r"(r[2]), "=r"(r[3]) : "r"(addr));
}

__device__ __forceinline__ void mma16816(float* c, const uint32_t* a,
                                         uint32_t b0, uint32_t b1)
{
    asm volatile(
        "mma.sync.aligned.m16n8k16.row.col.f32.bf16.bf16.f32 "
        "{%0,%1,%2,%3}, {%4,%5,%6,%7}, {%8,%9}, {%0,%1,%2,%3};"
        : "+f"(c[0]), "+f"(c[1]), "+f"(c[2]), "+f"(c[3])
        : "r"(a[0]), "r"(a[1]), "r"(a[2]), "r"(a[3]), "r"(b0), "r"(b1));
}

// ---------------------------------------------------------------------------
// Tensor-core GEMM: C[M, cols col0..col0+128] = A[M,128] @ Bt[Nc,128]^T + bias
// Split bf16 (3-MMA) fp32 emulation. One CTA = 128x128 output tile.
// Tiles in SMEM: 128 rows x 128 bf16, 16B chunks, chunk ^= (row&7) swizzle.
// Grid (Nc/128, ceil(M/128)), 256 threads (8 warps, 4x2 warp grid).
// ---------------------------------------------------------------------------
#define SMO_AH 0
#define SMO_AL 32768
#define SMO_BH 65536
#define SMO_BL 98304
#define DYN_SMEM 131072

__global__ void __launch_bounds__(256, 1)
mma_gemm(const __nv_bfloat16* __restrict__ Ah,
         const __nv_bfloat16* __restrict__ Al,
         const __nv_bfloat16* __restrict__ Bh,
         const __nv_bfloat16* __restrict__ Bl,
         const float* __restrict__ bias,
         float* __restrict__ C,
         int M, int ldc)
{
    extern __shared__ char smem[];
    const uint32_t sb = smem_to_u32(smem);

    const int tid  = threadIdx.x;
    const int wid  = tid >> 5;
    const int lane = tid & 31;
    const int row0 = blockIdx.y * 128;
    const int col0 = blockIdx.x * 128;

    // ---- load 4 tiles (16B swizzled chunks) ----
#pragma unroll
    for (int it = 0; it < 8; it++) {
        int c  = tid + it * 256;          // chunk id 0..2047
        int r  = c >> 4;                  // row 0..127
        int ch = c & 15;                  // chunk-in-row
        uint32_t so = (uint32_t)r * 256 + (uint32_t)((ch ^ (r & 7)) * 16);
        int kc = ch * 8;
        int gr = row0 + r;
        uint4 vh = make_uint4(0, 0, 0, 0), vl = make_uint4(0, 0, 0, 0);
        if (gr < M) {
            vh = *reinterpret_cast<const uint4*>(Ah + (size_t)gr * DD + kc);
            vl = *reinterpret_cast<const uint4*>(Al + (size_t)gr * DD + kc);
        }
        *reinterpret_cast<uint4*>(smem + SMO_AH + so) = vh;
        *reinterpret_cast<uint4*>(smem + SMO_AL + so) = vl;
        int gb = col0 + r;                // Nc multiple of 128 -> valid
        uint4 wh = *reinterpret_cast<const uint4*>(Bh + (size_t)gb * DD + kc);
        uint4 wl = *reinterpret_cast<const uint4*>(Bl + (size_t)gb * DD + kc);
        *reinterpret_cast<uint4*>(smem + SMO_BH + so) = wh;
        *reinterpret_cast<uint4*>(smem + SMO_BL + so) = wl;
    }
    __syncthreads();

    const int warp_m = (wid & 3) * 32;    // 4 warps over M
    const int warp_n = (wid >> 2) * 64;   // 2 warps over N

    float acc[2][8][4];
#pragma unroll
    for (int mt = 0; mt < 2; mt++)
#pragma unroll
        for (int nt = 0; nt < 8; nt++)
#pragma unroll
            for (int j = 0; j < 4; j++) acc[mt][nt][j] = 0.f;

#pragma unroll
    for (int ks = 0; ks < 8; ks++) {
        // A fragments: x4 = (m0-7,k0-7),(m8-15,k0-7),(m0-7,k8-15),(m8-15,k8-15)
        uint32_t ah[2][4], al[2][4];
#pragma unroll
        for (int mt = 0; mt < 2; mt++) {
            int r  = warp_m + mt * 16 + (lane & 7) + ((lane >> 3) & 1) * 8;
            int ch = ks * 2 + (lane >> 4);
            uint32_t off = (uint32_t)r * 256 + (uint32_t)((ch ^ (r & 7)) * 16);
            ldx4(ah[mt], sb + SMO_AH + off);
            ldx4(al[mt], sb + SMO_AL + off);
        }
        // B fragments: x4 = (n0-7,k0-7),(n0-7,k8-15),(n8-15,k0-7),(n8-15,k8-15)
        uint32_t bh[4][4], bl[4][4];
#pragma unroll
        for (int np = 0; np < 4; np++) {
            int r  = warp_n + np * 16 + (lane & 7) + ((lane >> 4) & 1) * 8;
            int ch = ks * 2 + ((lane >> 3) & 1);
            uint32_t off = (uint32_t)r * 256 + (uint32_t)((ch ^ (r & 7)) * 16);
            ldx4(bh[np], sb + SMO_BH + off);
            ldx4(bl[np], sb + SMO_BL + off);
        }
#pragma unroll
        for (int mt = 0; mt < 2; mt++) {
#pragma unroll
            for (int nt = 0; nt < 8; nt++) {
                int np = nt >> 1, hi = (nt & 1) * 2;
                mma16816(acc[mt][nt], ah[mt], bh[np][hi], bh[np][hi + 1]);
                mma16816(acc[mt][nt], ah[mt], bl[np][hi], bl[np][hi + 1]);
                mma16816(acc[mt][nt], al[mt], bh[np][hi], bh[np][hi + 1]);
            }
        }
    }

    // ---- epilogue: c0,c1 -> (m = t/4, n = 2(t%4)); c2,c3 -> m+8 ----
#pragma unroll
    for (int mt = 0; mt < 2; mt++) {
        int gr0 = row0 + warp_m + mt * 16 + (lane >> 2);
#pragma unroll
        for (int nt = 0; nt < 8; nt++) {
            int gc = col0 + warp_n + nt * 8 + (lane & 3) * 2;
            float2 b2 = *reinterpret_cast<const float2*>(bias + gc);
            if (gr0 < M) {
                float2 o = make_float2(acc[mt][nt][0] + b2.x,
                                       acc[mt][nt][1] + b2.y);
                *reinterpret_cast<float2*>(C + (size_t)gr0 * ldc + gc) = o;
            }
            if (gr0 + 8 < M) {
                float2 o = make_float2(acc[mt][nt][2] + b2.x,
                                       acc[mt][nt][3] + b2.y);
                *reinterpret_cast<float2*>(C + (size_t)(gr0 + 8) * ldc + gc) = o;
            }
        }
    }
}

// ---------------------------------------------------------------------------
// Conversion / prep kernels
// ---------------------------------------------------------------------------
__global__ void split_bf16_kernel(const float* __restrict__ x,
                                  __nv_bfloat16* __restrict__ h,
                                  __nv_bfloat16* __restrict__ l, int n)
{
    int i = blockIdx.x * blockDim.x + threadIdx.x;
    if (i >= n) return;
    float v = x[i];
    __nv_bfloat16 hb = __float2bfloat16(v);
    h[i] = hb;
    l[i] = __float2bfloat16(v - __bfloat162float(hb));
}

// Build fat W^T (bf16 hi/lo) for both node types. idx -> (n, k).
__global__ void prep_fatW_kernel(const float* __restrict__ gWl_b,
                                 const float* __restrict__ gWr_b,
                                 const float* __restrict__ gWl_r,
                                 const float* __restrict__ gWr_r,
                                 const float* __restrict__ cgL_Wf,
                                 const float* __restrict__ cgL_Ws,
                                 const float* __restrict__ cgR_Wf,
                                 const float* __restrict__ cgR_Ws,
                                 __nv_bfloat16* __restrict__ Wth_my,
                                 __nv_bfloat16* __restrict__ Wtl_my,
                                 __nv_bfloat16* __restrict__ Wth_opp,
                                 __nv_bfloat16* __restrict__ Wtl_opp)
{
    int idx = blockIdx.x * blockDim.x + threadIdx.x;
    if (idx >= LDC * DD) return;
    int n = idx / DD, k = idx % DD;
    float wm, wo;
    if (n < 512) {
        wm = gWl_b[k * HD + n];               wo = gWr_b[k * HD + n];
    } else if (n < 1024) {
        int c = n - 512;
        wm = gWr_r[k * HD + c];               wo = gWl_r[k * HD + c];
    } else if (n < 1152) {
        int c = n - 1024;
        wm = cgL_Wf[(DD + k) * DD + c];       wo = cgL_Wf[k * DD + c];
    } else if (n < 1280) {
        int c = n - 1152;
        wm = cgL_Ws[(DD + k) * DD + c];       wo = cgL_Ws[k * DD + c];
    } else if (n < 1408) {
        int c = n - 1280;
        wm = cgR_Wf[k * DD + c];              wo = cgR_Wf[(DD + k) * DD + c];
    } else {
        int c = n - 1408;
        wm = cgR_Ws[k * DD + c];              wo = cgR_Ws[(DD + k) * DD + c];
    }
    __nv_bfloat16 hm = __float2bfloat16(wm);
    __nv_bfloat16 ho = __float2bfloat16(wo);
    Wth_my[idx]  = hm;
    Wtl_my[idx]  = __float2bfloat16(wm - __bfloat162float(hm));
    Wth_opp[idx] = ho;
    Wtl_opp[idx] = __float2bfloat16(wo - __bfloat162float(ho));
}

__global__ void prep_bias_kernel(const float* __restrict__ cgL_bf,
                                 const float* __restrict__ cgL_bs,
                                 const float* __restrict__ cgR_bf,
                                 const float* __restrict__ cgR_bs,
                                 float* __restrict__ bias_my,
                                 float* __restrict__ bias_opp)
{
    int n = blockIdx.x * blockDim.x + threadIdx.x;
    if (n >= LDC) return;
    float bm = 0.f, bo = 0.f;
    if (n >= 1024 && n < 1152) bo = cgL_bf[n - 1024];
    else if (n >= 1152 && n < 1280) bo = cgL_bs[n - 1152];
    if (n >= 1280 && n < 1408) bm = cgR_bf[n - 1280];
    else if (n >= 1408) bm = cgR_bs[n - 1408];
    bias_my[n] = bm;
    bias_opp[n] = bo;
}

// nw W^T split: Wt[n*DD + k] = nw_W[k*DD + n]
__global__ void prep_nwW_kernel(const float* __restrict__ nw_W,
                                __nv_bfloat16* __restrict__ h,
                                __nv_bfloat16* __restrict__ l)
{
    int idx = blockIdx.x * blockDim.x + threadIdx.x;
    if (idx >= DD * DD) return;
    int n = idx / DD, k = idx % DD;
    float v = nw_W[k * DD + n];
    __nv_bfloat16 hb = __float2bfloat16(v);
    h[idx] = hb;
    l[idx] = __float2bfloat16(v - __bfloat162float(hb));
}

// ---------------------------------------------------------------------------
// Per-layer reset: acc init (residual + GAT bias) + segmax/segsum fill.
// ---------------------------------------------------------------------------
__global__ void reset_kernel(float* __restrict__ acc_opp,
                             float* __restrict__ acc_my,
                             const float* __restrict__ x_opp,
                             const float* __restrict__ x_my,
                             const float* __restrict__ gb_b,
                             const float* __restrict__ gb_r,
                             float* __restrict__ segmax,
                             float* __restrict__ segsum)
{
    int i = blockIdx.x * blockDim.x + threadIdx.x;
    if (i < NN * DD) {
        int c = i & (DD - 1);
        acc_opp[i] = x_opp[i] + gb_b[c];
        acc_my[i]  = x_my[i]  + gb_r[c];
    }
    if (i < 2 * NN * HH) {
        segmax[i] = -INFINITY;
        segsum[i] = 0.f;
    }
}

__device__ __forceinline__ void atomicMaxFloat(float* addr, float val)
{
    int* ai = (int*)addr;
    int old = *ai;
    while (__int_as_float(old) < val) {
        int assumed = old;
        old = atomicCAS(ai, assumed, __float_as_int(val));
        if (old == assumed) break;
    }
}

// ---------------------------------------------------------------------------
// GATv2 edge kernels (one warp per edge, float4 lanes, strided features)
// ---------------------------------------------------------------------------
__global__ void gat_score_kernel(const float* __restrict__ xl,
                                 const float* __restrict__ xr,
                                 const float* __restrict__ att,
                                 const int* __restrict__ src,
                                 const int* __restrict__ dst,
                                 float* __restrict__ score,
                                 float* __restrict__ segmax, int ld)
{
    int e = blockIdx.x * (blockDim.x >> 5) + (threadIdx.x >> 5);
    int lane = threadIdx.x & 31;
    if (e >= EE) return;
    int s = src[e], d = dst[e];
    const float4* pl = reinterpret_cast<const float4*>(xl + (size_t)s * ld);
    const float4* pr = reinterpret_cast<const float4*>(xr + (size_t)d * ld);
    const float4* pa = reinterpret_cast<const float4*>(att);

#pragma unroll
    for (int h = 0; h < HH; h++) {
        float4 l = pl[h * 32 + lane];
        float4 r = pr[h * 32 + lane];
        float4 a = pa[h * 32 + lane];
        float zx = l.x + r.x, zy = l.y + r.y, zz = l.z + r.z, zw = l.w + r.w;
        zx = (zx > 0.f) ? zx : 0.2f * zx;
        zy = (zy > 0.f) ? zy : 0.2f * zy;
        zz = (zz > 0.f) ? zz : 0.2f * zz;
        zw = (zw > 0.f) ? zw : 0.2f * zw;
        float acc = zx * a.x + zy * a.y + zz * a.z + zw * a.w;
#pragma unroll
        for (int o = 16; o; o >>= 1) acc += __shfl_xor_sync(0xffffffffu, acc, o);
        if (lane == 0) {
            score[(size_t)e * HH + h] = acc;
            atomicMaxFloat(&segmax[(size_t)d * HH + h], acc);
        }
    }
}

__global__ void gat_exp_kernel(const float* __restrict__ score,
                               const int* __restrict__ dst,
                               const float* __restrict__ segmax,
                               float* __restrict__ ex,
                               float* __restrict__ segsum)
{
    int i = blockIdx.x * blockDim.x + threadIdx.x;
    if (i >= EE * HH) return;
    int e = i >> 2, h = i & 3;
    int d = dst[e];
    float v = expf(score[i] - segmax[(size_t)d * HH + h]);
    ex[i] = v;
    atomicAdd(&segsum[(size_t)d * HH + h], v);
}

__global__ void gat_agg_kernel(const float* __restrict__ xl,
                               const float* __restrict__ ex,
                               const float* __restrict__ segsum,
                               const int* __restrict__ src,
                               const int* __restrict__ dst,
                               float* __restrict__ out, int ld)
{
    int e = blockIdx.x * (blockDim.x >> 5) + (threadIdx.x >> 5);
    int lane = threadIdx.x & 31;
    if (e >= EE) return;
    int s = src[e], d = dst[e];
    float alpha[HH];
#pragma unroll
    for (int h = 0; h < HH; h++)
        alpha[h] = ex[(size_t)e * HH + h] /
                   (segsum[(size_t)d * HH + h] + 1e-16f) * (1.f / HH);
    const float4* pl = reinterpret_cast<const float4*>(xl + (size_t)s * ld);
    float* po = out + (size_t)d * DD + lane * 4;
    float4 acc = make_float4(0.f, 0.f, 0.f, 0.f);
#pragma unroll
    for (int h = 0; h < HH; h++) {
        float4 v = pl[h * 32 + lane];
        acc.x += v.x * alpha[h];
        acc.y += v.y * alpha[h];
        acc.z += v.z * alpha[h];
        acc.w += v.w * alpha[h];
    }
    atomicAdd(po + 0, acc.x);
    atomicAdd(po + 1, acc.y);
    atomicAdd(po + 2, acc.z);
    atomicAdd(po + 3, acc.w);
}

// ---------------------------------------------------------------------------
// CGConv edge kernel (biases folded into dst projections)
// ---------------------------------------------------------------------------
__global__ void cg_edge_kernel(const float* __restrict__ Pfd,
                               const float* __restrict__ Pfs,
                               const float* __restrict__ Psd,
                               const float* __restrict__ Pss,
                               const int* __restrict__ src,
                               const int* __restrict__ dst,
                               float* __restrict__ out, int ld)
{
    int e = blockIdx.x * (blockDim.x >> 5) + (threadIdx.x >> 5);
    int lane = threadIdx.x & 31;
    if (e >= EE) return;
    int s = src[e], d = dst[e];
    float4 fd = reinterpret_cast<const float4*>(Pfd + (size_t)d * ld)[lane];
    float4 fs = reinterpret_cast<const float4*>(Pfs + (size_t)s * ld)[lane];
    float4 sd = reinterpret_cast<const float4*>(Psd + (size_t)d * ld)[lane];
    float4 ss = reinterpret_cast<const float4*>(Pss + (size_t)s * ld)[lane];
    float* po = out + (size_t)d * DD + lane * 4;

    float f[4] = {fd.x + fs.x, fd.y + fs.y, fd.z + fs.z, fd.w + fs.w};
    float g[4] = {sd.x + ss.x, sd.y + ss.y, sd.z + ss.z, sd.w + ss.w};
#pragma unroll
    for (int j = 0; j < 4; j++) {
        float sig = 1.f / (1.f + expf(-f[j]));
        float sp  = fmaxf(g[j], 0.f) + log1pf(expf(-fabsf(g[j])));
        atomicAdd(po + j, sig * sp);
    }
}

// ---------------------------------------------------------------------------
// Host launcher
// ---------------------------------------------------------------------------
extern "C" void kernel_launch(void* const* d_in, const int* in_sizes, int n_in,
                              void* d_out, int out_size)
{
    const float* in_x_my  = (const float*)d_in[0];
    const float* in_x_opp = (const float*)d_in[1];
    const float* gWl_b = (const float*)d_in[2];
    const float* gWr_b = (const float*)d_in[3];
    const float* gatt_b = (const float*)d_in[4];
    const float* gb_b  = (const float*)d_in[5];
    const float* gWl_r = (const float*)d_in[6];
    const float* gWr_r = (const float*)d_in[7];
    const float* gatt_r = (const float*)d_in[8];
    const float* gb_r  = (const float*)d_in[9];
    const float* cgL_Wf = (const float*)d_in[10];
    const float* cgL_bf = (const float*)d_in[11];
    const float* cgL_Ws = (const float*)d_in[12];
    const float* cgL_bs = (const float*)d_in[13];
    const float* cgR_Wf = (const float*)d_in[14];
    const float* cgR_bf = (const float*)d_in[15];
    const float* cgR_Ws = (const float*)d_in[16];
    const float* cgR_bs = (const float*)d_in[17];
    const float* nw_W = (const float*)d_in[18];
    const float* nw_b = (const float*)d_in[19];
    const int* ei_beats     = (const int*)d_in[20];
    const int* ei_loses     = (const int*)d_in[21];
    const int* ei_rev_beats = (const int*)d_in[22];
    const int* ei_rev_loses = (const int*)d_in[23];

    float* out = (float*)d_out;

    // Resolve scratch symbol addresses
    float *C_my, *C_opp, *x_my, *x_opp, *acc_my, *acc_opp;
    float *score, *ex, *segmax, *segsum, *bias_my, *bias_opp;
    __nv_bfloat16 *xh_my, *xlo_my, *xh_opp, *xlo_opp;
    __nv_bfloat16 *ah_my, *alo_my, *ah_opp, *alo_opp;
    __nv_bfloat16 *Wth_my, *Wtl_my, *Wth_opp, *Wtl_opp, *nwWh, *nwWl;
    cudaGetSymbolAddress((void**)&C_my,  g_C_my);
    cudaGetSymbolAddress((void**)&C_opp, g_C_opp);
    cudaGetSymbolAddress((void**)&x_my,  g_x_my);
    cudaGetSymbolAddress((void**)&x_opp, g_x_opp);
    cudaGetSymbolAddress((void**)&acc_my, g_acc_my);
    cudaGetSymbolAddress((void**)&acc_opp, g_acc_opp);
    cudaGetSymbolAddress((void**)&score, g_score);
    cudaGetSymbolAddress((void**)&ex,    g_ex);
    cudaGetSymbolAddress((void**)&segmax, g_segmax);
    cudaGetSymbolAddress((void**)&segsum, g_segsum);
    cudaGetSymbolAddress((void**)&bias_my,  g_bias_my);
    cudaGetSymbolAddress((void**)&bias_opp, g_bias_opp);
    cudaGetSymbolAddress((void**)&xh_my,  g_xh_my);
    cudaGetSymbolAddress((void**)&xlo_my, g_xlo_my);
    cudaGetSymbolAddress((void**)&xh_opp,  g_xh_opp);
    cudaGetSymbolAddress((void**)&xlo_opp, g_xlo_opp);
    cudaGetSymbolAddress((void**)&ah_my,  g_ah_my);
    cudaGetSymbolAddress((void**)&alo_my, g_alo_my);
    cudaGetSymbolAddress((void**)&ah_opp,  g_ah_opp);
    cudaGetSymbolAddress((void**)&alo_opp, g_alo_opp);
    cudaGetSymbolAddress((void**)&Wth_my,  g_Wth_my);
    cudaGetSymbolAddress((void**)&Wtl_my,  g_Wtl_my);
    cudaGetSymbolAddress((void**)&Wth_opp, g_Wth_opp);
    cudaGetSymbolAddress((void**)&Wtl_opp, g_Wtl_opp);
    cudaGetSymbolAddress((void**)&nwWh, g_nwWh);
    cudaGetSymbolAddress((void**)&nwWl, g_nwWl);

    cudaFuncSetAttribute(mma_gemm, cudaFuncAttributeMaxDynamicSharedMemorySize,
                         DYN_SMEM);

    const int* src_b  = ei_beats;      const int* dst_b  = ei_beats + EE;
    const int* src_l  = ei_loses;      const int* dst_l  = ei_loses + EE;
    const int* src_rb = ei_rev_beats;  const int* dst_rb = ei_rev_beats + EE;
    const int* src_rl = ei_rev_loses;  const int* dst_rl = ei_rev_loses + EE;

    const int edge_blocks = (EE + 7) / 8;
    const int nd_blocks   = (NN * DD + 255) / 256;
    const int eh_blocks   = (EE * HH + 255) / 256;
    const int mtiles      = (NN + 127) / 128;   // 157

    const float* cur_my  = in_x_my;
    const float* cur_opp = in_x_opp;

    for (int l = 0; l < LLAYERS; l++) {
        const size_t oW = (size_t)l * DD * HD;
        const size_t oA = (size_t)l * HH * DD;
        const size_t oB = (size_t)l * DD;
        const size_t oC = (size_t)l * 2 * DD * DD;
        const size_t oN = (size_t)l * DD * DD;

        // ---- input + weight prep ----
        split_bf16_kernel<<<nd_blocks, 256>>>(cur_my,  xh_my,  xlo_my,  NN * DD);
        split_bf16_kernel<<<nd_blocks, 256>>>(cur_opp, xh_opp, xlo_opp, NN * DD);
        prep_fatW_kernel<<<(LDC * DD + 255) / 256, 256>>>(
            gWl_b + oW, gWr_b + oW, gWl_r + oW, gWr_r + oW,
            cgL_Wf + oC, cgL_Ws + oC, cgR_Wf + oC, cgR_Ws + oC,
            Wth_my, Wtl_my, Wth_opp, Wtl_opp);
        prep_bias_kernel<<<(LDC + 255) / 256, 256>>>(
            cgL_bf + oB, cgL_bs + oB, cgR_bf + oB, cgR_bs + oB,
            bias_my, bias_opp);
        prep_nwW_kernel<<<(DD * DD + 255) / 256, 256>>>(nw_W + oN, nwWh, nwWl);

        // ---- fat projection GEMMs (tensor cores) ----
        dim3 fat_grid(LDC / 128, mtiles);
        mma_gemm<<<fat_grid, 256, DYN_SMEM>>>(xh_my, xlo_my, Wth_my, Wtl_my,
                                              bias_my, C_my, NN, LDC);
        mma_gemm<<<fat_grid, 256, DYN_SMEM>>>(xh_opp, xlo_opp, Wth_opp, Wtl_opp,
                                              bias_opp, C_opp, NN, LDC);

        // ---- reset accumulators + softmax scratch ----
        reset_kernel<<<nd_blocks, 256>>>(acc_opp, acc_my, cur_opp, cur_my,
                                         gb_b + oB, gb_r + oB, segmax, segsum);

        // ---- GAT beats (my -> opp): xl = C_my[0:512), xr = C_opp[0:512) ----
        gat_score_kernel<<<edge_blocks, 256>>>(C_my, C_opp, gatt_b + oA,
                                               src_b, dst_b, score, segmax, LDC);
        gat_exp_kernel<<<eh_blocks, 256>>>(score, dst_b, segmax, ex, segsum);
        gat_agg_kernel<<<edge_blocks, 256>>>(C_my, ex, segsum, src_b, dst_b,
                                             acc_opp, LDC);

        // ---- GAT rev_loses (opp -> my): xl = C_opp[512:1024), xr = C_my[512:1024) ----
        gat_score_kernel<<<edge_blocks, 256>>>(C_opp + 512, C_my + 512,
                                               gatt_r + oA, src_rl, dst_rl,
                                               score + EE * HH, segmax + NN * HH, LDC);
        gat_exp_kernel<<<eh_blocks, 256>>>(score + EE * HH, dst_rl,
                                           segmax + NN * HH,
                                           ex + EE * HH, segsum + NN * HH);
        gat_agg_kernel<<<edge_blocks, 256>>>(C_opp + 512, ex + EE * HH,
                                             segsum + NN * HH, src_rl, dst_rl,
                                             acc_my, LDC);

        // ---- CGConv edges ----
        cg_edge_kernel<<<edge_blocks, 256>>>(C_opp + 1024, C_my + 1024,
                                             C_opp + 1152, C_my + 1152,
                                             src_l, dst_l, acc_opp, LDC);
        cg_edge_kernel<<<edge_blocks, 256>>>(C_my + 1280, C_opp + 1280,
                                             C_my + 1408, C_opp + 1408,
                                             src_rb, dst_rb, acc_my, LDC);

        // ---- nodewise Linear (tensor cores) ----
        split_bf16_kernel<<<nd_blocks, 256>>>(acc_my,  ah_my,  alo_my,  NN * DD);
        split_bf16_kernel<<<nd_blocks, 256>>>(acc_opp, ah_opp, alo_opp, NN * DD);
        float* out_my  = (l == LLAYERS - 1) ? out           : x_my;
        float* out_opp = (l == LLAYERS - 1) ? out + NN * DD : x_opp;
        dim3 nw_grid(1, mtiles);
        mma_gemm<<<nw_grid, 256, DYN_SMEM>>>(ah_my, alo_my, nwWh, nwWl,
                                             nw_b + oB, out_my, NN, DD);
        mma_gemm<<<nw_grid, 256, DYN_SMEM>>>(ah_opp, alo_opp, nwWh, nwWl,
                                             nw_b + oB, out_opp, NN, DD);

        cur_my  = x_my;
        cur_opp = x_opp;
    }
}

// round 5
// speedup vs baseline: 2.5312x; 1.0225x over previous
#include <cuda_runtime.h>
#include <cuda_bf16.h>
#include <math.h>
#include <stdint.h>

// ---------------------------------------------------------------------------
// Problem constants
// ---------------------------------------------------------------------------
#define NN 20000
#define DD 128
#define HH 4
#define EE 80000
#define LLAYERS 2
#define HD (HH * DD)      // 512
#define LDC 1536          // fat projection width per node type

// Fat column layout (per node type X in {my, opp}):
//  [0,512)      GAT projection #1 (my: Wl_beats ; opp: Wr_beats)
//  [512,1024)   GAT projection #2 (my: Wr_rev   ; opp: Wl_rev)
//  [1024,1152)  CG lose Wf part   (my: src/bottom ; opp: dst/top + bf)
//  [1152,1280)  CG lose Ws part   (my: src/bottom ; opp: dst/top + bs)
//  [1280,1408)  CG rev  Wf part   (my: dst/top + bf ; opp: src/bottom)
//  [1408,1536)  CG rev  Ws part   (my: dst/top + bs ; opp: src/bottom)

// ---------------------------------------------------------------------------
// Static device scratch
// ---------------------------------------------------------------------------
__device__ __align__(16) float g_C_my [(size_t)NN * LDC];
__device__ __align__(16) float g_C_opp[(size_t)NN * LDC];

__device__ __align__(16) float g_x_my [NN * DD];
__device__ __align__(16) float g_x_opp[NN * DD];
__device__ __align__(16) float g_acc_my [NN * DD];
__device__ __align__(16) float g_acc_opp[NN * DD];

__device__ __align__(16) __nv_bfloat16 g_xh_my [NN * DD];
__device__ __align__(16) __nv_bfloat16 g_xlo_my[NN * DD];
__device__ __align__(16) __nv_bfloat16 g_xh_opp [NN * DD];
__device__ __align__(16) __nv_bfloat16 g_xlo_opp[NN * DD];

__device__ __align__(16) __nv_bfloat16 g_ah_my [NN * DD];   // acc splits
__device__ __align__(16) __nv_bfloat16 g_alo_my[NN * DD];
__device__ __align__(16) __nv_bfloat16 g_ah_opp [NN * DD];
__device__ __align__(16) __nv_bfloat16 g_alo_opp[NN * DD];

__device__ __align__(16) __nv_bfloat16 g_Wth_my [LDC * DD]; // fat W^T splits
__device__ __align__(16) __nv_bfloat16 g_Wtl_my [LDC * DD];
__device__ __align__(16) __nv_bfloat16 g_Wth_opp[LDC * DD];
__device__ __align__(16) __nv_bfloat16 g_Wtl_opp[LDC * DD];
__device__ __align__(16) __nv_bfloat16 g_nwWh[DD * DD];
__device__ __align__(16) __nv_bfloat16 g_nwWl[DD * DD];

__device__ __align__(16) float g_bias_my [LDC];
__device__ __align__(16) float g_bias_opp[LDC];

// CSR (4 relations: 0=beats, 1=rev_loses, 2=loses, 3=rev_beats), built once
__device__ int g_row [4 * (NN + 1)];
__device__ int g_cnt [4 * NN];
__device__ int g_srcs[4 * EE];

// ---------------------------------------------------------------------------
// Warp MMA helpers (sm_80+ HMMA path; tcgen05 unavailable on compute_103 PTX)
// ---------------------------------------------------------------------------
__device__ __forceinline__ uint32_t smem_to_u32(const void* p)
{
    uint32_t a;
    asm("{ .reg .u64 t; cvta.to.shared.u64 t, %1; cvt.u32.u64 %0, t; }"
        : "=r"(a) : "l"(p));
    return a;
}

__device__ __forceinline__ void ldx4(uint32_t* r, uint32_t addr)
{
    asm volatile("ldmatrix.sync.aligned.m8n8.x4.shared.b16 {%0,%1,%2,%3}, [%4];"
                 : "=r"(r[0]), "=r"(r[1]), "=r"(r[2]), "=r"(r[3]) : "r"(addr));
}

__device__ __forceinline__ void mma16816(float* c, const uint32_t* a,
                                         uint32_t b0, uint32_t b1)
{
    asm volatile(
        "mma.sync.aligned.m16n8k16.row.col.f32.bf16.bf16.f32 "
        "{%0,%1,%2,%3}, {%4,%5,%6,%7}, {%8,%9}, {%0,%1,%2,%3};"
        : "+f"(c[0]), "+f"(c[1]), "+f"(c[2]), "+f"(c[3])
        : "r"(a[0]), "r"(a[1]), "r"(a[2]), "r"(a[3]), "r"(b0), "r"(b1));
}

// ---------------------------------------------------------------------------
// Tensor-core GEMM: C[M, cols col0..col0+128] = A[M,128] @ Bt[Nc,128]^T + bias
// Split bf16 (3-MMA) fp32 emulation. One CTA = 128x128 output tile.
// Optionally also writes bf16 hi/lo splits of the output (nodewise GEMM).
// ---------------------------------------------------------------------------
#define SMO_AH 0
#define SMO_AL 32768
#define SMO_BH 65536
#define SMO_BL 98304
#define DYN_SMEM 131072

__global__ void __launch_bounds__(256, 1)
mma_gemm(const __nv_bfloat16* __restrict__ Ah,
         const __nv_bfloat16* __restrict__ Al,
         const __nv_bfloat16* __restrict__ Bh,
         const __nv_bfloat16* __restrict__ Bl,
         const float* __restrict__ bias,
         float* __restrict__ C,
         int M, int ldc,
         __nv_bfloat16* __restrict__ Hout,
         __nv_bfloat16* __restrict__ Lout)
{
    extern __shared__ char smem[];
    const uint32_t sb = smem_to_u32(smem);

    const int tid  = threadIdx.x;
    const int wid  = tid >> 5;
    const int lane = tid & 31;
    const int row0 = blockIdx.y * 128;
    const int col0 = blockIdx.x * 128;

    // ---- load 4 tiles (16B swizzled chunks) ----
#pragma unroll
    for (int it = 0; it < 8; it++) {
        int c  = tid + it * 256;          // chunk id 0..2047
        int r  = c >> 4;                  // row 0..127
        int ch = c & 15;                  // chunk-in-row
        uint32_t so = (uint32_t)r * 256 + (uint32_t)((ch ^ (r & 7)) * 16);
        int kc = ch * 8;
        int gr = row0 + r;
        uint4 vh = make_uint4(0, 0, 0, 0), vl = make_uint4(0, 0, 0, 0);
        if (gr < M) {
            vh = *reinterpret_cast<const uint4*>(Ah + (size_t)gr * DD + kc);
            vl = *reinterpret_cast<const uint4*>(Al + (size_t)gr * DD + kc);
        }
        *reinterpret_cast<uint4*>(smem + SMO_AH + so) = vh;
        *reinterpret_cast<uint4*>(smem + SMO_AL + so) = vl;
        int gb = col0 + r;                // Nc multiple of 128 -> valid
        uint4 wh = *reinterpret_cast<const uint4*>(Bh + (size_t)gb * DD + kc);
        uint4 wl = *reinterpret_cast<const uint4*>(Bl + (size_t)gb * DD + kc);
        *reinterpret_cast<uint4*>(smem + SMO_BH + so) = wh;
        *reinterpret_cast<uint4*>(smem + SMO_BL + so) = wl;
    }
    __syncthreads();

    const int warp_m = (wid & 3) * 32;    // 4 warps over M
    const int warp_n = (wid >> 2) * 64;   // 2 warps over N

    float acc[2][8][4];
#pragma unroll
    for (int mt = 0; mt < 2; mt++)
#pragma unroll
        for (int nt = 0; nt < 8; nt++)
#pragma unroll
            for (int j = 0; j < 4; j++) acc[mt][nt][j] = 0.f;

#pragma unroll
    for (int ks = 0; ks < 8; ks++) {
        uint32_t ah[2][4], al[2][4];
#pragma unroll
        for (int mt = 0; mt < 2; mt++) {
            int r  = warp_m + mt * 16 + (lane & 7) + ((lane >> 3) & 1) * 8;
            int ch = ks * 2 + (lane >> 4);
            uint32_t off = (uint32_t)r * 256 + (uint32_t)((ch ^ (r & 7)) * 16);
            ldx4(ah[mt], sb + SMO_AH + off);
            ldx4(al[mt], sb + SMO_AL + off);
        }
        uint32_t bh[4][4], bl[4][4];
#pragma unroll
        for (int np = 0; np < 4; np++) {
            int r  = warp_n + np * 16 + (lane & 7) + ((lane >> 4) & 1) * 8;
            int ch = ks * 2 + ((lane >> 3) & 1);
            uint32_t off = (uint32_t)r * 256 + (uint32_t)((ch ^ (r & 7)) * 16);
            ldx4(bh[np], sb + SMO_BH + off);
            ldx4(bl[np], sb + SMO_BL + off);
        }
#pragma unroll
        for (int mt = 0; mt < 2; mt++) {
#pragma unroll
            for (int nt = 0; nt < 8; nt++) {
                int np = nt >> 1, hi = (nt & 1) * 2;
                mma16816(acc[mt][nt], ah[mt], bh[np][hi], bh[np][hi + 1]);
                mma16816(acc[mt][nt], ah[mt], bl[np][hi], bl[np][hi + 1]);
                mma16816(acc[mt][nt], al[mt], bh[np][hi], bh[np][hi + 1]);
            }
        }
    }

    // ---- epilogue ----
#pragma unroll
    for (int mt = 0; mt < 2; mt++) {
        int gr0 = row0 + warp_m + mt * 16 + (lane >> 2);
#pragma unroll
        for (int nt = 0; nt < 8; nt++) {
            int gc = col0 + warp_n + nt * 8 + (lane & 3) * 2;
            float2 b2 = *reinterpret_cast<const float2*>(bias + gc);
#pragma unroll
            for (int half = 0; half < 2; half++) {
                int gr = gr0 + half * 8;
                if (gr >= M) continue;
                float vx = acc[mt][nt][half * 2 + 0] + b2.x;
                float vy = acc[mt][nt][half * 2 + 1] + b2.y;
                *reinterpret_cast<float2*>(C + (size_t)gr * ldc + gc) =
                    make_float2(vx, vy);
                if (Hout) {
                    __nv_bfloat16 hx = __float2bfloat16(vx);
                    __nv_bfloat16 hy = __float2bfloat16(vy);
                    __nv_bfloat162 hv; hv.x = hx; hv.y = hy;
                    __nv_bfloat162 lv;
                    lv.x = __float2bfloat16(vx - __bfloat162float(hx));
                    lv.y = __float2bfloat16(vy - __bfloat162float(hy));
                    size_t o = (size_t)gr * DD + gc;
                    *reinterpret_cast<__nv_bfloat162*>(Hout + o) = hv;
                    *reinterpret_cast<__nv_bfloat162*>(Lout + o) = lv;
                }
            }
        }
    }
}

// ---------------------------------------------------------------------------
// Conversion / prep kernels
// ---------------------------------------------------------------------------
__global__ void split_bf16_kernel(const float* __restrict__ x,
                                  __nv_bfloat16* __restrict__ h,
                                  __nv_bfloat16* __restrict__ l, int n)
{
    int i = blockIdx.x * blockDim.x + threadIdx.x;
    if (i >= n) return;
    float v = x[i];
    __nv_bfloat16 hb = __float2bfloat16(v);
    h[i] = hb;
    l[i] = __float2bfloat16(v - __bfloat162float(hb));
}

__global__ void prep_fatW_kernel(const float* __restrict__ gWl_b,
                                 const float* __restrict__ gWr_b,
                                 const float* __restrict__ gWl_r,
                                 const float* __restrict__ gWr_r,
                                 const float* __restrict__ cgL_Wf,
                                 const float* __restrict__ cgL_Ws,
                                 const float* __restrict__ cgR_Wf,
                                 const float* __restrict__ cgR_Ws,
                                 __nv_bfloat16* __restrict__ Wth_my,
                                 __nv_bfloat16* __restrict__ Wtl_my,
                                 __nv_bfloat16* __restrict__ Wth_opp,
                                 __nv_bfloat16* __restrict__ Wtl_opp)
{
    int idx = blockIdx.x * blockDim.x + threadIdx.x;
    if (idx >= LDC * DD) return;
    int n = idx / DD, k = idx % DD;
    float wm, wo;
    if (n < 512) {
        wm = gWl_b[k * HD + n];               wo = gWr_b[k * HD + n];
    } else if (n < 1024) {
        int c = n - 512;
        wm = gWr_r[k * HD + c];               wo = gWl_r[k * HD + c];
    } else if (n < 1152) {
        int c = n - 1024;
        wm = cgL_Wf[(DD + k) * DD + c];       wo = cgL_Wf[k * DD + c];
    } else if (n < 1280) {
        int c = n - 1152;
        wm = cgL_Ws[(DD + k) * DD + c];       wo = cgL_Ws[k * DD + c];
    } else if (n < 1408) {
        int c = n - 1280;
        wm = cgR_Wf[k * DD + c];              wo = cgR_Wf[(DD + k) * DD + c];
    } else {
        int c = n - 1408;
        wm = cgR_Ws[k * DD + c];              wo = cgR_Ws[(DD + k) * DD + c];
    }
    __nv_bfloat16 hm = __float2bfloat16(wm);
    __nv_bfloat16 ho = __float2bfloat16(wo);
    Wth_my[idx]  = hm;
    Wtl_my[idx]  = __float2bfloat16(wm - __bfloat162float(hm));
    Wth_opp[idx] = ho;
    Wtl_opp[idx] = __float2bfloat16(wo - __bfloat162float(ho));
}

__global__ void prep_bias_kernel(const float* __restrict__ cgL_bf,
                                 const float* __restrict__ cgL_bs,
                                 const float* __restrict__ cgR_bf,
                                 const float* __restrict__ cgR_bs,
                                 float* __restrict__ bias_my,
                                 float* __restrict__ bias_opp)
{
    int n = blockIdx.x * blockDim.x + threadIdx.x;
    if (n >= LDC) return;
    float bm = 0.f, bo = 0.f;
    if (n >= 1024 && n < 1152) bo = cgL_bf[n - 1024];
    else if (n >= 1152 && n < 1280) bo = cgL_bs[n - 1152];
    if (n >= 1280 && n < 1408) bm = cgR_bf[n - 1280];
    else if (n >= 1408) bm = cgR_bs[n - 1408];
    bias_my[n] = bm;
    bias_opp[n] = bo;
}

__global__ void prep_nwW_kernel(const float* __restrict__ nw_W,
                                __nv_bfloat16* __restrict__ h,
                                __nv_bfloat16* __restrict__ l)
{
    int idx = blockIdx.x * blockDim.x + threadIdx.x;
    if (idx >= DD * DD) return;
    int n = idx / DD, k = idx % DD;
    float v = nw_W[k * DD + n];
    __nv_bfloat16 hb = __float2bfloat16(v);
    h[idx] = hb;
    l[idx] = __float2bfloat16(v - __bfloat162float(hb));
}

// ---------------------------------------------------------------------------
// CSR build (4 relations, built once per launch)
// ---------------------------------------------------------------------------
__global__ void csr_zero_kernel(int* __restrict__ cnt)
{
    int i = blockIdx.x * blockDim.x + threadIdx.x;
    if (i < 4 * NN) cnt[i] = 0;
}

__global__ void csr_hist_kernel(const int* __restrict__ d0,
                                const int* __restrict__ d1,
                                const int* __restrict__ d2,
                                const int* __restrict__ d3,
                                int* __restrict__ cnt)
{
    int i = blockIdx.x * blockDim.x + threadIdx.x;
    if (i >= EE) return;
    atomicAdd(&cnt[0 * NN + d0[i]], 1);
    atomicAdd(&cnt[1 * NN + d1[i]], 1);
    atomicAdd(&cnt[2 * NN + d2[i]], 1);
    atomicAdd(&cnt[3 * NN + d3[i]], 1);
}

__global__ void csr_scan_kernel(const int* __restrict__ cnt,
                                int* __restrict__ row)
{
    __shared__ int part[1024];
    const int rel = blockIdx.x;
    const int t = threadIdx.x;
    const int CH = (NN + 1023) / 1024;     // 20
    const int base = t * CH;
    int s = 0;
    for (int j = 0; j < CH; j++) {
        int i = base + j;
        if (i < NN) s += cnt[rel * NN + i];
    }
    part[t] = s;
    __syncthreads();
    for (int o = 1; o < 1024; o <<= 1) {
        int u = (t >= o) ? part[t - o] : 0;
        __syncthreads();
        part[t] += u;
        __syncthreads();
    }
    int run = part[t] - s;                 // exclusive prefix
    for (int j = 0; j < CH; j++) {
        int i = base + j;
        if (i < NN) {
            row[rel * (NN + 1) + i] = run;
            run += cnt[rel * NN + i];
        }
    }
    if (t == 1023) row[rel * (NN + 1) + NN] = part[1023];
}

__global__ void csr_scatter_kernel(const int* __restrict__ s0, const int* __restrict__ d0,
                                   const int* __restrict__ s1, const int* __restrict__ d1,
                                   const int* __restrict__ s2, const int* __restrict__ d2,
                                   const int* __restrict__ s3, const int* __restrict__ d3,
                                   const int* __restrict__ row,
                                   int* __restrict__ fill,
                                   int* __restrict__ srcs)
{
    int i = blockIdx.x * blockDim.x + threadIdx.x;
    if (i >= EE) return;
    {
        int d = d0[i];
        int pos = row[0 * (NN + 1) + d] + atomicAdd(&fill[0 * NN + d], 1);
        srcs[0 * EE + pos] = s0[i];
    }
    {
        int d = d1[i];
        int pos = row[1 * (NN + 1) + d] + atomicAdd(&fill[1 * NN + d], 1);
        srcs[1 * EE + pos] = s1[i];
    }
    {
        int d = d2[i];
        int pos = row[2 * (NN + 1) + d] + atomicAdd(&fill[2 * NN + d], 1);
        srcs[2 * EE + pos] = s2[i];
    }
    {
        int d = d3[i];
        int pos = row[3 * (NN + 1) + d] + atomicAdd(&fill[3 * NN + d], 1);
        srcs[3 * EE + pos] = s3[i];
    }
}

// ---------------------------------------------------------------------------
// Fused GATv2: warp per dst node, online softmax, single feature pass.
// acc[d] = x_dst[d] + gat_bias + mean_h( sum_e alpha * xl[src_e, h] )
// ---------------------------------------------------------------------------
__global__ void __launch_bounds__(256)
gat_fused_kernel(const float* __restrict__ xl,     // stride LDC
                 const float* __restrict__ xr,     // stride LDC
                 const float* __restrict__ att,    // [H*D]
                 const int* __restrict__ row,
                 const int* __restrict__ srcs,
                 const float* __restrict__ xres,   // [NN*DD]
                 const float* __restrict__ bias,   // [DD]
                 float* __restrict__ acc)          // [NN*DD]
{
    int d = blockIdx.x * 8 + (threadIdx.x >> 5);
    int lane = threadIdx.x & 31;
    if (d >= NN) return;

    float4 xr4[HH], at4[HH];
    const float4* pr = reinterpret_cast<const float4*>(xr + (size_t)d * LDC);
    const float4* pa = reinterpret_cast<const float4*>(att);
#pragma unroll
    for (int h = 0; h < HH; h++) {
        xr4[h] = pr[h * 32 + lane];
        at4[h] = pa[h * 32 + lane];
    }

    float m[HH], s[HH];
    float4 a4[HH];
#pragma unroll
    for (int h = 0; h < HH; h++) {
        m[h] = -INFINITY;
        s[h] = 0.f;
        a4[h] = make_float4(0.f, 0.f, 0.f, 0.f);
    }

    const int e0 = row[d], e1 = row[d + 1];
    for (int p = e0; p < e1; p++) {
        int sn = srcs[p];
        const float4* pl = reinterpret_cast<const float4*>(xl + (size_t)sn * LDC);
#pragma unroll
        for (int h = 0; h < HH; h++) {
            float4 l4 = pl[h * 32 + lane];
            float zx = l4.x + xr4[h].x; zx = (zx > 0.f) ? zx : 0.2f * zx;
            float zy = l4.y + xr4[h].y; zy = (zy > 0.f) ? zy : 0.2f * zy;
            float zz = l4.z + xr4[h].z; zz = (zz > 0.f) ? zz : 0.2f * zz;
            float zw = l4.w + xr4[h].w; zw = (zw > 0.f) ? zw : 0.2f * zw;
            float part = zx * at4[h].x + zy * at4[h].y
                       + zz * at4[h].z + zw * at4[h].w;
#pragma unroll
            for (int o = 16; o; o >>= 1)
                part += __shfl_xor_sync(0xffffffffu, part, o);
            float e;
            if (part > m[h]) {
                float f = __expf(m[h] - part);   // 0 on first edge (m=-inf)
                s[h] = s[h] * f + 1.f;
                a4[h].x *= f; a4[h].y *= f; a4[h].z *= f; a4[h].w *= f;
                m[h] = part;
                e = 1.f;
            } else {
                e = __expf(part - m[h]);
                s[h] += e;
            }
            a4[h].x += e * l4.x;
            a4[h].y += e * l4.y;
            a4[h].z += e * l4.z;
            a4[h].w += e * l4.w;
        }
    }

    float4 r4 = reinterpret_cast<const float4*>(xres + (size_t)d * DD)[lane];
    float4 b4 = reinterpret_cast<const float4*>(bias)[lane];
    float4 o4 = make_float4(r4.x + b4.x, r4.y + b4.y,
                            r4.z + b4.z, r4.w + b4.w);
#pragma unroll
    for (int h = 0; h < HH; h++) {
        float inv = 0.25f / (s[h] + 1e-16f);
        o4.x += a4[h].x * inv;
        o4.y += a4[h].y * inv;
        o4.z += a4[h].z * inv;
        o4.w += a4[h].w * inv;
    }
    reinterpret_cast<float4*>(acc + (size_t)d * DD)[lane] = o4;
}

// ---------------------------------------------------------------------------
// Fused CGConv: warp per dst node; acc_in += sum_e sigmoid(f)*softplus(g);
// writes bf16 hi/lo splits of the result (input to nodewise GEMM).
// ---------------------------------------------------------------------------
__global__ void __launch_bounds__(256)
cg_fused_kernel(const float* __restrict__ Pfd,
                const float* __restrict__ Pfs,
                const float* __restrict__ Psd,
                const float* __restrict__ Pss,
                const int* __restrict__ row,
                const int* __restrict__ srcs,
                const float* __restrict__ accin,
                __nv_bfloat16* __restrict__ ah,
                __nv_bfloat16* __restrict__ alo)
{
    int d = blockIdx.x * 8 + (threadIdx.x >> 5);
    int lane = threadIdx.x & 31;
    if (d >= NN) return;

    float4 fd4 = reinterpret_cast<const float4*>(Pfd + (size_t)d * LDC)[lane];
    float4 sd4 = reinterpret_cast<const float4*>(Psd + (size_t)d * LDC)[lane];
    float4 acc4 = reinterpret_cast<const float4*>(accin + (size_t)d * DD)[lane];

    const int e0 = row[d], e1 = row[d + 1];
    for (int p = e0; p < e1; p++) {
        int sn = srcs[p];
        float4 fs4 = reinterpret_cast<const float4*>(Pfs + (size_t)sn * LDC)[lane];
        float4 ss4 = reinterpret_cast<const float4*>(Pss + (size_t)sn * LDC)[lane];
        float f, g;
        f = fd4.x + fs4.x; g = sd4.x + ss4.x;
        acc4.x += (1.f / (1.f + expf(-f))) *
                  (fmaxf(g, 0.f) + log1pf(expf(-fabsf(g))));
        f = fd4.y + fs4.y; g = sd4.y + ss4.y;
        acc4.y += (1.f / (1.f + expf(-f))) *
                  (fmaxf(g, 0.f) + log1pf(expf(-fabsf(g))));
        f = fd4.z + fs4.z; g = sd4.z + ss4.z;
        acc4.z += (1.f / (1.f + expf(-f))) *
                  (fmaxf(g, 0.f) + log1pf(expf(-fabsf(g))));
        f = fd4.w + fs4.w; g = sd4.w + ss4.w;
        acc4.w += (1.f / (1.f + expf(-f))) *
                  (fmaxf(g, 0.f) + log1pf(expf(-fabsf(g))));
    }

    size_t off = (size_t)d * DD + lane * 4;
    __nv_bfloat16 h0 = __float2bfloat16(acc4.x);
    __nv_bfloat16 h1 = __float2bfloat16(acc4.y);
    __nv_bfloat16 h2 = __float2bfloat16(acc4.z);
    __nv_bfloat16 h3 = __float2bfloat16(acc4.w);
    __nv_bfloat162 hv0; hv0.x = h0; hv0.y = h1;
    __nv_bfloat162 hv1; hv1.x = h2; hv1.y = h3;
    __nv_bfloat162 lv0, lv1;
    lv0.x = __float2bfloat16(acc4.x - __bfloat162float(h0));
    lv0.y = __float2bfloat16(acc4.y - __bfloat162float(h1));
    lv1.x = __float2bfloat16(acc4.z - __bfloat162float(h2));
    lv1.y = __float2bfloat16(acc4.w - __bfloat162float(h3));
    *reinterpret_cast<__nv_bfloat162*>(ah + off)      = hv0;
    *reinterpret_cast<__nv_bfloat162*>(ah + off + 2)  = hv1;
    *reinterpret_cast<__nv_bfloat162*>(alo + off)     = lv0;
    *reinterpret_cast<__nv_bfloat162*>(alo + off + 2) = lv1;
}

// ---------------------------------------------------------------------------
// Host launcher
// ---------------------------------------------------------------------------
extern "C" void kernel_launch(void* const* d_in, const int* in_sizes, int n_in,
                              void* d_out, int out_size)
{
    const float* in_x_my  = (const float*)d_in[0];
    const float* in_x_opp = (const float*)d_in[1];
    const float* gWl_b = (const float*)d_in[2];
    const float* gWr_b = (const float*)d_in[3];
    const float* gatt_b = (const float*)d_in[4];
    const float* gb_b  = (const float*)d_in[5];
    const float* gWl_r = (const float*)d_in[6];
    const float* gWr_r = (const float*)d_in[7];
    const float* gatt_r = (const float*)d_in[8];
    const float* gb_r  = (const float*)d_in[9];
    const float* cgL_Wf = (const float*)d_in[10];
    const float* cgL_bf = (const float*)d_in[11];
    const float* cgL_Ws = (const float*)d_in[12];
    const float* cgL_bs = (const float*)d_in[13];
    const float* cgR_Wf = (const float*)d_in[14];
    const float* cgR_bf = (const float*)d_in[15];
    const float* cgR_Ws = (const float*)d_in[16];
    const float* cgR_bs = (const float*)d_in[17];
    const float* nw_W = (const float*)d_in[18];
    const float* nw_b = (const float*)d_in[19];
    const int* ei_beats     = (const int*)d_in[20];
    const int* ei_loses     = (const int*)d_in[21];
    const int* ei_rev_beats = (const int*)d_in[22];
    const int* ei_rev_loses = (const int*)d_in[23];

    float* out = (float*)d_out;

    float *C_my, *C_opp, *x_my, *x_opp, *acc_my, *acc_opp, *bias_my, *bias_opp;
    __nv_bfloat16 *xh_my, *xlo_my, *xh_opp, *xlo_opp;
    __nv_bfloat16 *ah_my, *alo_my, *ah_opp, *alo_opp;
    __nv_bfloat16 *Wth_my, *Wtl_my, *Wth_opp, *Wtl_opp, *nwWh, *nwWl;
    int *rowp, *cntp, *srcsp;
    cudaGetSymbolAddress((void**)&C_my,  g_C_my);
    cudaGetSymbolAddress((void**)&C_opp, g_C_opp);
    cudaGetSymbolAddress((void**)&x_my,  g_x_my);
    cudaGetSymbolAddress((void**)&x_opp, g_x_opp);
    cudaGetSymbolAddress((void**)&acc_my, g_acc_my);
    cudaGetSymbolAddress((void**)&acc_opp, g_acc_opp);
    cudaGetSymbolAddress((void**)&bias_my,  g_bias_my);
    cudaGetSymbolAddress((void**)&bias_opp, g_bias_opp);
    cudaGetSymbolAddress((void**)&xh_my,  g_xh_my);
    cudaGetSymbolAddress((void**)&xlo_my, g_xlo_my);
    cudaGetSymbolAddress((void**)&xh_opp,  g_xh_opp);
    cudaGetSymbolAddress((void**)&xlo_opp, g_xlo_opp);
    cudaGetSymbolAddress((void**)&ah_my,  g_ah_my);
    cudaGetSymbolAddress((void**)&alo_my, g_alo_my);
    cudaGetSymbolAddress((void**)&ah_opp,  g_ah_opp);
    cudaGetSymbolAddress((void**)&alo_opp, g_alo_opp);
    cudaGetSymbolAddress((void**)&Wth_my,  g_Wth_my);
    cudaGetSymbolAddress((void**)&Wtl_my,  g_Wtl_my);
    cudaGetSymbolAddress((void**)&Wth_opp, g_Wth_opp);
    cudaGetSymbolAddress((void**)&Wtl_opp, g_Wtl_opp);
    cudaGetSymbolAddress((void**)&nwWh, g_nwWh);
    cudaGetSymbolAddress((void**)&nwWl, g_nwWl);
    cudaGetSymbolAddress((void**)&rowp,  g_row);
    cudaGetSymbolAddress((void**)&cntp,  g_cnt);
    cudaGetSymbolAddress((void**)&srcsp, g_srcs);

    cudaFuncSetAttribute(mma_gemm, cudaFuncAttributeMaxDynamicSharedMemorySize,
                         DYN_SMEM);

    const int* src_b  = ei_beats;      const int* dst_b  = ei_beats + EE;
    const int* src_l  = ei_loses;      const int* dst_l  = ei_loses + EE;
    const int* src_rb = ei_rev_beats;  const int* dst_rb = ei_rev_beats + EE;
    const int* src_rl = ei_rev_loses;  const int* dst_rl = ei_rev_loses + EE;

    const int nd_blocks   = (NN * DD + 255) / 256;
    const int node_blocks = (NN + 7) / 8;          // warp per node
    const int e_blocks    = (EE + 255) / 256;
    const int mtiles      = (NN + 127) / 128;      // 157

    // ---- CSR build (relations: 0=beats, 1=rev_loses, 2=loses, 3=rev_beats) ----
    csr_zero_kernel<<<(4 * NN + 255) / 256, 256>>>(cntp);
    csr_hist_kernel<<<e_blocks, 256>>>(dst_b, dst_rl, dst_l, dst_rb, cntp);
    csr_scan_kernel<<<4, 1024>>>(cntp, rowp);
    csr_zero_kernel<<<(4 * NN + 255) / 256, 256>>>(cntp);
    csr_scatter_kernel<<<e_blocks, 256>>>(src_b, dst_b, src_rl, dst_rl,
                                          src_l, dst_l, src_rb, dst_rb,
                                          rowp, cntp, srcsp);

    // ---- initial bf16 splits of inputs ----
    split_bf16_kernel<<<nd_blocks, 256>>>(in_x_my,  xh_my,  xlo_my,  NN * DD);
    split_bf16_kernel<<<nd_blocks, 256>>>(in_x_opp, xh_opp, xlo_opp, NN * DD);

    const float* cur_my  = in_x_my;
    const float* cur_opp = in_x_opp;

    for (int l = 0; l < LLAYERS; l++) {
        const size_t oW = (size_t)l * DD * HD;
        const size_t oA = (size_t)l * HH * DD;
        const size_t oB = (size_t)l * DD;
        const size_t oC = (size_t)l * 2 * DD * DD;
        const size_t oN = (size_t)l * DD * DD;

        // ---- weight prep ----
        prep_fatW_kernel<<<(LDC * DD + 255) / 256, 256>>>(
            gWl_b + oW, gWr_b + oW, gWl_r + oW, gWr_r + oW,
            cgL_Wf + oC, cgL_Ws + oC, cgR_Wf + oC, cgR_Ws + oC,
            Wth_my, Wtl_my, Wth_opp, Wtl_opp);
        prep_bias_kernel<<<(LDC + 255) / 256, 256>>>(
            cgL_bf + oB, cgL_bs + oB, cgR_bf + oB, cgR_bs + oB,
            bias_my, bias_opp);
        prep_nwW_kernel<<<(DD * DD + 255) / 256, 256>>>(nw_W + oN, nwWh, nwWl);

        // ---- fat projection GEMMs ----
        dim3 fat_grid(LDC / 128, mtiles);
        mma_gemm<<<fat_grid, 256, DYN_SMEM>>>(xh_my, xlo_my, Wth_my, Wtl_my,
                                              bias_my, C_my, NN, LDC,
                                              nullptr, nullptr);
        mma_gemm<<<fat_grid, 256, DYN_SMEM>>>(xh_opp, xlo_opp, Wth_opp, Wtl_opp,
                                              bias_opp, C_opp, NN, LDC,
                                              nullptr, nullptr);

        // ---- fused GAT (init acc with residual + bias) ----
        // beats: my -> opp
        gat_fused_kernel<<<node_blocks, 256>>>(
            C_my, C_opp, gatt_b + oA,
            rowp + 0 * (NN + 1), srcsp + 0 * EE,
            cur_opp, gb_b + oB, acc_opp);
        // rev_loses: opp -> my
        gat_fused_kernel<<<node_blocks, 256>>>(
            C_opp + 512, C_my + 512, gatt_r + oA,
            rowp + 1 * (NN + 1), srcsp + 1 * EE,
            cur_my, gb_r + oB, acc_my);

        // ---- fused CGConv (acc += gate; writes bf16 hi/lo splits) ----
        // loses: my -> opp
        cg_fused_kernel<<<node_blocks, 256>>>(
            C_opp + 1024, C_my + 1024, C_opp + 1152, C_my + 1152,
            rowp + 2 * (NN + 1), srcsp + 2 * EE,
            acc_opp, ah_opp, alo_opp);
        // rev_beats: opp -> my
        cg_fused_kernel<<<node_blocks, 256>>>(
            C_my + 1280, C_opp + 1280, C_my + 1408, C_opp + 1408,
            rowp + 3 * (NN + 1), srcsp + 3 * EE,
            acc_my, ah_my, alo_my);

        // ---- nodewise Linear (writes float out + bf16 splits for next layer) ----
        float* out_my  = (l == LLAYERS - 1) ? out           : x_my;
        float* out_opp = (l == LLAYERS - 1) ? out + NN * DD : x_opp;
        dim3 nw_grid(1, mtiles);
        mma_gemm<<<nw_grid, 256, DYN_SMEM>>>(ah_my, alo_my, nwWh, nwWl,
                                             nw_b + oB, out_my, NN, DD,
                                             xh_my, xlo_my);
        mma_gemm<<<nw_grid, 256, DYN_SMEM>>>(ah_opp, alo_opp, nwWh, nwWl,
                                             nw_b + oB, out_opp, NN, DD,
                                             xh_opp, xlo_opp);

        cur_my  = x_my;
        cur_opp = x_opp;
    }
}

// round 6
// speedup vs baseline: 3.2969x; 1.3025x over previous
#include <cuda_runtime.h>
#include <cuda_bf16.h>
#include <math.h>
#include <stdint.h>

// ---------------------------------------------------------------------------
// Problem constants
// ---------------------------------------------------------------------------
#define NN 20000
#define DD 128
#define HH 4
#define EE 80000
#define LLAYERS 2
#define HD (HH * DD)      // 512
#define LDC 1536          // fat projection width per node type

// Fat column layout (per node type X in {my, opp}):
//  [0,512)      GAT projection #1 (my: Wl_beats ; opp: Wr_beats)
//  [512,1024)   GAT projection #2 (my: Wr_rev   ; opp: Wl_rev)
//  [1024,1152)  CG lose Wf part   (my: src/bottom ; opp: dst/top + bf)
//  [1152,1280)  CG lose Ws part   (my: src/bottom ; opp: dst/top + bs)
//  [1280,1408)  CG rev  Wf part   (my: dst/top + bf ; opp: src/bottom)
//  [1408,1536)  CG rev  Ws part   (my: dst/top + bs ; opp: src/bottom)

// ---------------------------------------------------------------------------
// Static device scratch
// ---------------------------------------------------------------------------
__device__ __align__(16) float g_C_my [(size_t)NN * LDC];
__device__ __align__(16) float g_C_opp[(size_t)NN * LDC];

__device__ __align__(16) float g_x_my [NN * DD];
__device__ __align__(16) float g_x_opp[NN * DD];
__device__ __align__(16) float g_acc_my [NN * DD];
__device__ __align__(16) float g_acc_opp[NN * DD];

__device__ __align__(16) __nv_bfloat16 g_xh_my [NN * DD];
__device__ __align__(16) __nv_bfloat16 g_xlo_my[NN * DD];
__device__ __align__(16) __nv_bfloat16 g_xh_opp [NN * DD];
__device__ __align__(16) __nv_bfloat16 g_xlo_opp[NN * DD];

__device__ __align__(16) __nv_bfloat16 g_ah_my [NN * DD];
__device__ __align__(16) __nv_bfloat16 g_alo_my[NN * DD];
__device__ __align__(16) __nv_bfloat16 g_ah_opp [NN * DD];
__device__ __align__(16) __nv_bfloat16 g_alo_opp[NN * DD];

__device__ __align__(16) __nv_bfloat16 g_Wth_my [LDC * DD];
__device__ __align__(16) __nv_bfloat16 g_Wtl_my [LDC * DD];
__device__ __align__(16) __nv_bfloat16 g_Wth_opp[LDC * DD];
__device__ __align__(16) __nv_bfloat16 g_Wtl_opp[LDC * DD];
__device__ __align__(16) __nv_bfloat16 g_nwWh[DD * DD];
__device__ __align__(16) __nv_bfloat16 g_nwWl[DD * DD];

__device__ __align__(16) float g_bias_my [LDC];
__device__ __align__(16) float g_bias_opp[LDC];

// CSR (4 relations: 0=beats, 1=rev_loses, 2=loses, 3=rev_beats), built once
__device__ int g_row [4 * (NN + 1)];
__device__ int g_cnt [4 * NN];
__device__ int g_fill[4 * NN];
__device__ int g_srcs[4 * EE];

// ---------------------------------------------------------------------------
// Warp MMA / cp.async helpers (sm_80+ path; tcgen05 unavailable on compute_103)
// ---------------------------------------------------------------------------
__device__ __forceinline__ uint32_t smem_to_u32(const void* p)
{
    uint32_t a;
    asm("{ .reg .u64 t; cvta.to.shared.u64 t, %1; cvt.u32.u64 %0, t; }"
        : "=r"(a) : "l"(p));
    return a;
}

__device__ __forceinline__ void ldx4(uint32_t* r, uint32_t addr)
{
    asm volatile("ldmatrix.sync.aligned.m8n8.x4.shared.b16 {%0,%1,%2,%3}, [%4];"
                 : "=r"(r[0]), "=r"(r[1]), "=r"(r[2]), "=r"(r[3]) : "r"(addr));
}

__device__ __forceinline__ void mma16816(float* c, const uint32_t* a,
                                         uint32_t b0, uint32_t b1)
{
    asm volatile(
        "mma.sync.aligned.m16n8k16.row.col.f32.bf16.bf16.f32 "
        "{%0,%1,%2,%3}, {%4,%5,%6,%7}, {%8,%9}, {%0,%1,%2,%3};"
        : "+f"(c[0]), "+f"(c[1]), "+f"(c[2]), "+f"(c[3])
        : "r"(a[0]), "r"(a[1]), "r"(a[2]), "r"(a[3]), "r"(b0), "r"(b1));
}

__device__ __forceinline__ void cpa16(uint32_t dst, const void* src, int sz)
{
    asm volatile("cp.async.cg.shared.global [%0], [%1], 16, %2;"
                 :: "r"(dst), "l"(src), "r"(sz));
}
#define CP_COMMIT() asm volatile("cp.async.commit_group;" ::: "memory")
#define CP_WAIT(n)  asm volatile("cp.async.wait_group %0;" :: "n"(n) : "memory")

// ---------------------------------------------------------------------------
// Tensor-core GEMM: C[M, col0..col0+128] = A[M,128] @ Bt[Nc,128]^T + bias.
// Split bf16 (3-MMA) fp32 emulation; 2-stage cp.async pipeline (BK=64).
// Optionally also writes bf16 hi/lo splits of the output (nodewise GEMM).
// ---------------------------------------------------------------------------
#define SM_AH 0
#define SM_AL 16384
#define SM_BH 32768
#define SM_BL 49152
#define STAGE_BYTES 65536
#define DYN_SMEM 131072

__global__ void __launch_bounds__(256, 1)
mma_gemm(const __nv_bfloat16* __restrict__ Ah,
         const __nv_bfloat16* __restrict__ Al,
         const __nv_bfloat16* __restrict__ Bh,
         const __nv_bfloat16* __restrict__ Bl,
         const float* __restrict__ bias,
         float* __restrict__ C,
         int M, int ldc,
         __nv_bfloat16* __restrict__ Hout,
         __nv_bfloat16* __restrict__ Lout)
{
    extern __shared__ char smem[];
    const uint32_t sb = smem_to_u32(smem);

    const int tid  = threadIdx.x;
    const int wid  = tid >> 5;
    const int lane = tid & 31;
    const int row0 = blockIdx.y * 128;
    const int col0 = blockIdx.x * 128;

    const int warp_m = (wid & 3) * 32;    // 4 warps over M
    const int warp_n = (wid >> 2) * 64;   // 2 warps over N

    float acc[2][8][4];
#pragma unroll
    for (int mt = 0; mt < 2; mt++)
#pragma unroll
        for (int nt = 0; nt < 8; nt++)
#pragma unroll
            for (int j = 0; j < 4; j++) acc[mt][nt][j] = 0.f;

    // ---- stage loader: 64-wide K slab, 4 tiles (Ah/Al/Bh/Bl) ----
    auto load_stage = [&](int s) {
        const uint32_t bufb = sb + s * STAGE_BYTES;
        const int kbase = s * 64;
#pragma unroll
        for (int it = 0; it < 4; it++) {
            int c  = tid + it * 256;                  // 0..1023
            int r  = c >> 3;                          // row 0..127
            int ch = c & 7;                           // 16B chunk in 128B row
            uint32_t so = (uint32_t)r * 128 + (uint32_t)((ch ^ (r & 7)) * 16);
            int kc = kbase + ch * 8;
            int gr = row0 + r;
            int asz = (gr < M) ? 16 : 0;
            int gra = (gr < M) ? gr : 0;
            cpa16(bufb + SM_AH + so, Ah + (size_t)gra * DD + kc, asz);
            cpa16(bufb + SM_AL + so, Al + (size_t)gra * DD + kc, asz);
            int gb = col0 + r;                        // Nc mult of 128 -> valid
            cpa16(bufb + SM_BH + so, Bh + (size_t)gb * DD + kc, 16);
            cpa16(bufb + SM_BL + so, Bl + (size_t)gb * DD + kc, 16);
        }
        CP_COMMIT();
    };

    // ---- stage compute: 4 k-steps of 16 ----
    auto comp_stage = [&](int s) {
        const uint32_t bufb = sb + s * STAGE_BYTES;
#pragma unroll
        for (int ks = 0; ks < 4; ks++) {
            uint32_t ahf[2][4], alf[2][4];
#pragma unroll
            for (int mt = 0; mt < 2; mt++) {
                int r  = warp_m + mt * 16 + (lane & 7) + ((lane >> 3) & 1) * 8;
                int ch = ks * 2 + (lane >> 4);
                uint32_t off = (uint32_t)r * 128 + (uint32_t)((ch ^ (r & 7)) * 16);
                ldx4(ahf[mt], bufb + SM_AH + off);
                ldx4(alf[mt], bufb + SM_AL + off);
            }
            uint32_t bhf[4][4], blf[4][4];
#pragma unroll
            for (int np = 0; np < 4; np++) {
                int r  = warp_n + np * 16 + (lane & 7) + ((lane >> 4) & 1) * 8;
                int ch = ks * 2 + ((lane >> 3) & 1);
                uint32_t off = (uint32_t)r * 128 + (uint32_t)((ch ^ (r & 7)) * 16);
                ldx4(bhf[np], bufb + SM_BH + off);
                ldx4(blf[np], bufb + SM_BL + off);
            }
#pragma unroll
            for (int mt = 0; mt < 2; mt++) {
#pragma unroll
                for (int nt = 0; nt < 8; nt++) {
                    int np = nt >> 1, hi = (nt & 1) * 2;
                    mma16816(acc[mt][nt], ahf[mt], bhf[np][hi], bhf[np][hi + 1]);
                    mma16816(acc[mt][nt], ahf[mt], blf[np][hi], blf[np][hi + 1]);
                    mma16816(acc[mt][nt], alf[mt], bhf[np][hi], bhf[np][hi + 1]);
                }
            }
        }
    };

    load_stage(0);
    load_stage(1);
    CP_WAIT(1);
    __syncthreads();
    comp_stage(0);
    CP_WAIT(0);
    __syncthreads();
    comp_stage(1);

    // ---- epilogue ----
#pragma unroll
    for (int mt = 0; mt < 2; mt++) {
        int gr0 = row0 + warp_m + mt * 16 + (lane >> 2);
#pragma unroll
        for (int nt = 0; nt < 8; nt++) {
            int gc = col0 + warp_n + nt * 8 + (lane & 3) * 2;
            float2 b2 = *reinterpret_cast<const float2*>(bias + gc);
#pragma unroll
            for (int half = 0; half < 2; half++) {
                int gr = gr0 + half * 8;
                if (gr >= M) continue;
                float vx = acc[mt][nt][half * 2 + 0] + b2.x;
                float vy = acc[mt][nt][half * 2 + 1] + b2.y;
                *reinterpret_cast<float2*>(C + (size_t)gr * ldc + gc) =
                    make_float2(vx, vy);
                if (Hout) {
                    __nv_bfloat16 hx = __float2bfloat16(vx);
                    __nv_bfloat16 hy = __float2bfloat16(vy);
                    __nv_bfloat162 hv; hv.x = hx; hv.y = hy;
                    __nv_bfloat162 lv;
                    lv.x = __float2bfloat16(vx - __bfloat162float(hx));
                    lv.y = __float2bfloat16(vy - __bfloat162float(hy));
                    size_t o = (size_t)gr * DD + gc;
                    *reinterpret_cast<__nv_bfloat162*>(Hout + o) = hv;
                    *reinterpret_cast<__nv_bfloat162*>(Lout + o) = lv;
                }
            }
        }
    }
}

// ---------------------------------------------------------------------------
// Conversion / prep kernels
// ---------------------------------------------------------------------------
__global__ void split_bf16_kernel(const float* __restrict__ x,
                                  __nv_bfloat16* __restrict__ h,
                                  __nv_bfloat16* __restrict__ l, int n)
{
    int i = blockIdx.x * blockDim.x + threadIdx.x;
    if (i >= n) return;
    float v = x[i];
    __nv_bfloat16 hb = __float2bfloat16(v);
    h[i] = hb;
    l[i] = __float2bfloat16(v - __bfloat162float(hb));
}

// One launch: fat W^T splits + fat bias vectors + nw W^T split.
__global__ void prep_all_kernel(const float* __restrict__ gWl_b,
                                const float* __restrict__ gWr_b,
                                const float* __restrict__ gWl_r,
                                const float* __restrict__ gWr_r,
                                const float* __restrict__ cgL_Wf,
                                const float* __restrict__ cgL_Ws,
                                const float* __restrict__ cgR_Wf,
                                const float* __restrict__ cgR_Ws,
                                const float* __restrict__ cgL_bf,
                                const float* __restrict__ cgL_bs,
                                const float* __restrict__ cgR_bf,
                                const float* __restrict__ cgR_bs,
                                const float* __restrict__ nw_W,
                                __nv_bfloat16* __restrict__ Wth_my,
                                __nv_bfloat16* __restrict__ Wtl_my,
                                __nv_bfloat16* __restrict__ Wth_opp,
                                __nv_bfloat16* __restrict__ Wtl_opp,
                                __nv_bfloat16* __restrict__ nwWh,
                                __nv_bfloat16* __restrict__ nwWl,
                                float* __restrict__ bias_my,
                                float* __restrict__ bias_opp)
{
    int idx = blockIdx.x * blockDim.x + threadIdx.x;
    if (idx < LDC * DD) {
        int n = idx / DD, k = idx % DD;
        float wm, wo;
        if (n < 512) {
            wm = gWl_b[k * HD + n];               wo = gWr_b[k * HD + n];
        } else if (n < 1024) {
            int c = n - 512;
            wm = gWr_r[k * HD + c];               wo = gWl_r[k * HD + c];
        } else if (n < 1152) {
            int c = n - 1024;
            wm = cgL_Wf[(DD + k) * DD + c];       wo = cgL_Wf[k * DD + c];
        } else if (n < 1280) {
            int c = n - 1152;
            wm = cgL_Ws[(DD + k) * DD + c];       wo = cgL_Ws[k * DD + c];
        } else if (n < 1408) {
            int c = n - 1280;
            wm = cgR_Wf[k * DD + c];              wo = cgR_Wf[(DD + k) * DD + c];
        } else {
            int c = n - 1408;
            wm = cgR_Ws[k * DD + c];              wo = cgR_Ws[(DD + k) * DD + c];
        }
        __nv_bfloat16 hm = __float2bfloat16(wm);
        __nv_bfloat16 ho = __float2bfloat16(wo);
        Wth_my[idx]  = hm;
        Wtl_my[idx]  = __float2bfloat16(wm - __bfloat162float(hm));
        Wth_opp[idx] = ho;
        Wtl_opp[idx] = __float2bfloat16(wo - __bfloat162float(ho));
    }
    if (idx < DD * DD) {
        int n = idx / DD, k = idx % DD;
        float v = nw_W[k * DD + n];
        __nv_bfloat16 hb = __float2bfloat16(v);
        nwWh[idx] = hb;
        nwWl[idx] = __float2bfloat16(v - __bfloat162float(hb));
    }
    if (idx < LDC) {
        int n = idx;
        float bm = 0.f, bo = 0.f;
        if (n >= 1024 && n < 1152) bo = cgL_bf[n - 1024];
        else if (n >= 1152 && n < 1280) bo = cgL_bs[n - 1152];
        if (n >= 1280 && n < 1408) bm = cgR_bf[n - 1280];
        else if (n >= 1408) bm = cgR_bs[n - 1408];
        bias_my[n] = bm;
        bias_opp[n] = bo;
    }
}

// ---------------------------------------------------------------------------
// CSR build (4 relations, built once per launch)
// ---------------------------------------------------------------------------
__global__ void csr_zero_kernel(int* __restrict__ cnt, int* __restrict__ fill)
{
    int i = blockIdx.x * blockDim.x + threadIdx.x;
    if (i < 4 * NN) { cnt[i] = 0; fill[i] = 0; }
}

__global__ void csr_hist_kernel(const int* __restrict__ d0,
                                const int* __restrict__ d1,
                                const int* __restrict__ d2,
                                const int* __restrict__ d3,
                                int* __restrict__ cnt)
{
    int i = blockIdx.x * blockDim.x + threadIdx.x;
    if (i >= EE) return;
    atomicAdd(&cnt[0 * NN + d0[i]], 1);
    atomicAdd(&cnt[1 * NN + d1[i]], 1);
    atomicAdd(&cnt[2 * NN + d2[i]], 1);
    atomicAdd(&cnt[3 * NN + d3[i]], 1);
}

__global__ void csr_scan_kernel(const int* __restrict__ cnt,
                                int* __restrict__ row)
{
    __shared__ int part[1024];
    const int rel = blockIdx.x;
    const int t = threadIdx.x;
    const int CH = (NN + 1023) / 1024;     // 20
    const int base = t * CH;
    int s = 0;
    for (int j = 0; j < CH; j++) {
        int i = base + j;
        if (i < NN) s += cnt[rel * NN + i];
    }
    part[t] = s;
    __syncthreads();
    for (int o = 1; o < 1024; o <<= 1) {
        int u = (t >= o) ? part[t - o] : 0;
        __syncthreads();
        part[t] += u;
        __syncthreads();
    }
    int run = part[t] - s;                 // exclusive prefix
    for (int j = 0; j < CH; j++) {
        int i = base + j;
        if (i < NN) {
            row[rel * (NN + 1) + i] = run;
            run += cnt[rel * NN + i];
        }
    }
    if (t == 1023) row[rel * (NN + 1) + NN] = part[1023];
}

__global__ void csr_scatter_kernel(const int* __restrict__ s0, const int* __restrict__ d0,
                                   const int* __restrict__ s1, const int* __restrict__ d1,
                                   const int* __restrict__ s2, const int* __restrict__ d2,
                                   const int* __restrict__ s3, const int* __restrict__ d3,
                                   const int* __restrict__ row,
                                   int* __restrict__ fill,
                                   int* __restrict__ srcs)
{
    int i = blockIdx.x * blockDim.x + threadIdx.x;
    if (i >= EE) return;
    {
        int d = d0[i];
        int pos = row[0 * (NN + 1) + d] + atomicAdd(&fill[0 * NN + d], 1);
        srcs[0 * EE + pos] = s0[i];
    }
    {
        int d = d1[i];
        int pos = row[1 * (NN + 1) + d] + atomicAdd(&fill[1 * NN + d], 1);
        srcs[1 * EE + pos] = s1[i];
    }
    {
        int d = d2[i];
        int pos = row[2 * (NN + 1) + d] + atomicAdd(&fill[2 * NN + d], 1);
        srcs[2 * EE + pos] = s2[i];
    }
    {
        int d = d3[i];
        int pos = row[3 * (NN + 1) + d] + atomicAdd(&fill[3 * NN + d], 1);
        srcs[3 * EE + pos] = s3[i];
    }
}

// ---------------------------------------------------------------------------
// Fused GATv2: warp per dst node, single feature pass.
// Scores are O(10) bounded -> plain exp accumulation == softmax exactly.
// acc[d] = x_dst[d] + gat_bias + mean_h( sum_e alpha * xl[src_e, h] )
// ---------------------------------------------------------------------------
__global__ void __launch_bounds__(256)
gat_fused_kernel(const float* __restrict__ xl,     // stride LDC
                 const float* __restrict__ xr,     // stride LDC
                 const float* __restrict__ att,    // [H*D]
                 const int* __restrict__ row,
                 const int* __restrict__ srcs,
                 const float* __restrict__ xres,   // [NN*DD]
                 const float* __restrict__ bias,   // [DD]
                 float* __restrict__ acc)          // [NN*DD]
{
    int d = blockIdx.x * 8 + (threadIdx.x >> 5);
    int lane = threadIdx.x & 31;
    if (d >= NN) return;

    float4 xr4[HH], at4[HH];
    const float4* pr = reinterpret_cast<const float4*>(xr + (size_t)d * LDC);
    const float4* pa = reinterpret_cast<const float4*>(att);
#pragma unroll
    for (int h = 0; h < HH; h++) {
        xr4[h] = pr[h * 32 + lane];
        at4[h] = pa[h * 32 + lane];
    }

    float s[HH];
    float4 a4[HH];
#pragma unroll
    for (int h = 0; h < HH; h++) {
        s[h] = 0.f;
        a4[h] = make_float4(0.f, 0.f, 0.f, 0.f);
    }

    const int e0 = row[d], e1 = row[d + 1];
#pragma unroll 2
    for (int p = e0; p < e1; p++) {
        int sn = srcs[p];
        const float4* pl = reinterpret_cast<const float4*>(xl + (size_t)sn * LDC);
        float4 l4[HH];
        float part[HH];
#pragma unroll
        for (int h = 0; h < HH; h++) {
            l4[h] = pl[h * 32 + lane];
            float zx = l4[h].x + xr4[h].x; zx = (zx > 0.f) ? zx : 0.2f * zx;
            float zy = l4[h].y + xr4[h].y; zy = (zy > 0.f) ? zy : 0.2f * zy;
            float zz = l4[h].z + xr4[h].z; zz = (zz > 0.f) ? zz : 0.2f * zz;
            float zw = l4[h].w + xr4[h].w; zw = (zw > 0.f) ? zw : 0.2f * zw;
            part[h] = zx * at4[h].x + zy * at4[h].y
                    + zz * at4[h].z + zw * at4[h].w;
        }
#pragma unroll
        for (int o = 16; o; o >>= 1)
#pragma unroll
            for (int h = 0; h < HH; h++)
                part[h] += __shfl_xor_sync(0xffffffffu, part[h], o);
#pragma unroll
        for (int h = 0; h < HH; h++) {
            float e = __expf(part[h]);
            s[h] += e;
            a4[h].x += e * l4[h].x;
            a4[h].y += e * l4[h].y;
            a4[h].z += e * l4[h].z;
            a4[h].w += e * l4[h].w;
        }
    }

    float4 r4 = reinterpret_cast<const float4*>(xres + (size_t)d * DD)[lane];
    float4 b4 = reinterpret_cast<const float4*>(bias)[lane];
    float4 o4 = make_float4(r4.x + b4.x, r4.y + b4.y,
                            r4.z + b4.z, r4.w + b4.w);
#pragma unroll
    for (int h = 0; h < HH; h++) {
        float inv = 0.25f / (s[h] + 1e-16f);
        o4.x += a4[h].x * inv;
        o4.y += a4[h].y * inv;
        o4.z += a4[h].z * inv;
        o4.w += a4[h].w * inv;
    }
    reinterpret_cast<float4*>(acc + (size_t)d * DD)[lane] = o4;
}

// ---------------------------------------------------------------------------
// Fused CGConv: warp per dst node; fast-math gate; writes bf16 hi/lo splits.
// ---------------------------------------------------------------------------
__device__ __forceinline__ float gate1(float f, float g)
{
    float sig = __fdividef(1.f, 1.f + __expf(-f));
    float sp  = fmaxf(g, 0.f) + __logf(1.f + __expf(-fabsf(g)));
    return sig * sp;
}

__global__ void __launch_bounds__(256)
cg_fused_kernel(const float* __restrict__ Pfd,
                const float* __restrict__ Pfs,
                const float* __restrict__ Psd,
                const float* __restrict__ Pss,
                const int* __restrict__ row,
                const int* __restrict__ srcs,
                const float* __restrict__ accin,
                __nv_bfloat16* __restrict__ ah,
                __nv_bfloat16* __restrict__ alo)
{
    int d = blockIdx.x * 8 + (threadIdx.x >> 5);
    int lane = threadIdx.x & 31;
    if (d >= NN) return;

    float4 fd4 = reinterpret_cast<const float4*>(Pfd + (size_t)d * LDC)[lane];
    float4 sd4 = reinterpret_cast<const float4*>(Psd + (size_t)d * LDC)[lane];
    float4 acc4 = reinterpret_cast<const float4*>(accin + (size_t)d * DD)[lane];

    const int e0 = row[d], e1 = row[d + 1];
#pragma unroll 2
    for (int p = e0; p < e1; p++) {
        int sn = srcs[p];
        float4 fs4 = reinterpret_cast<const float4*>(Pfs + (size_t)sn * LDC)[lane];
        float4 ss4 = reinterpret_cast<const float4*>(Pss + (size_t)sn * LDC)[lane];
        acc4.x += gate1(fd4.x + fs4.x, sd4.x + ss4.x);
        acc4.y += gate1(fd4.y + fs4.y, sd4.y + ss4.y);
        acc4.z += gate1(fd4.z + fs4.z, sd4.z + ss4.z);
        acc4.w += gate1(fd4.w + fs4.w, sd4.w + ss4.w);
    }

    size_t off = (size_t)d * DD + lane * 4;
    __nv_bfloat16 h0 = __float2bfloat16(acc4.x);
    __nv_bfloat16 h1 = __float2bfloat16(acc4.y);
    __nv_bfloat16 h2 = __float2bfloat16(acc4.z);
    __nv_bfloat16 h3 = __float2bfloat16(acc4.w);
    __nv_bfloat162 hv0; hv0.x = h0; hv0.y = h1;
    __nv_bfloat162 hv1; hv1.x = h2; hv1.y = h3;
    __nv_bfloat162 lv0, lv1;
    lv0.x = __float2bfloat16(acc4.x - __bfloat162float(h0));
    lv0.y = __float2bfloat16(acc4.y - __bfloat162float(h1));
    lv1.x = __float2bfloat16(acc4.z - __bfloat162float(h2));
    lv1.y = __float2bfloat16(acc4.w - __bfloat162float(h3));
    *reinterpret_cast<__nv_bfloat162*>(ah + off)      = hv0;
    *reinterpret_cast<__nv_bfloat162*>(ah + off + 2)  = hv1;
    *reinterpret_cast<__nv_bfloat162*>(alo + off)     = lv0;
    *reinterpret_cast<__nv_bfloat162*>(alo + off + 2) = lv1;
}

// ---------------------------------------------------------------------------
// Host launcher
// ---------------------------------------------------------------------------
extern "C" void kernel_launch(void* const* d_in, const int* in_sizes, int n_in,
                              void* d_out, int out_size)
{
    const float* in_x_my  = (const float*)d_in[0];
    const float* in_x_opp = (const float*)d_in[1];
    const float* gWl_b = (const float*)d_in[2];
    const float* gWr_b = (const float*)d_in[3];
    const float* gatt_b = (const float*)d_in[4];
    const float* gb_b  = (const float*)d_in[5];
    const float* gWl_r = (const float*)d_in[6];
    const float* gWr_r = (const float*)d_in[7];
    const float* gatt_r = (const float*)d_in[8];
    const float* gb_r  = (const float*)d_in[9];
    const float* cgL_Wf = (const float*)d_in[10];
    const float* cgL_bf = (const float*)d_in[11];
    const float* cgL_Ws = (const float*)d_in[12];
    const float* cgL_bs = (const float*)d_in[13];
    const float* cgR_Wf = (const float*)d_in[14];
    const float* cgR_bf = (const float*)d_in[15];
    const float* cgR_Ws = (const float*)d_in[16];
    const float* cgR_bs = (const float*)d_in[17];
    const float* nw_W = (const float*)d_in[18];
    const float* nw_b = (const float*)d_in[19];
    const int* ei_beats     = (const int*)d_in[20];
    const int* ei_loses     = (const int*)d_in[21];
    const int* ei_rev_beats = (const int*)d_in[22];
    const int* ei_rev_loses = (const int*)d_in[23];

    float* out = (float*)d_out;

    float *C_my, *C_opp, *x_my, *x_opp, *acc_my, *acc_opp, *bias_my, *bias_opp;
    __nv_bfloat16 *xh_my, *xlo_my, *xh_opp, *xlo_opp;
    __nv_bfloat16 *ah_my, *alo_my, *ah_opp, *alo_opp;
    __nv_bfloat16 *Wth_my, *Wtl_my, *Wth_opp, *Wtl_opp, *nwWh, *nwWl;
    int *rowp, *cntp, *fillp, *srcsp;
    cudaGetSymbolAddress((void**)&C_my,  g_C_my);
    cudaGetSymbolAddress((void**)&C_opp, g_C_opp);
    cudaGetSymbolAddress((void**)&x_my,  g_x_my);
    cudaGetSymbolAddress((void**)&x_opp, g_x_opp);
    cudaGetSymbolAddress((void**)&acc_my, g_acc_my);
    cudaGetSymbolAddress((void**)&acc_opp, g_acc_opp);
    cudaGetSymbolAddress((void**)&bias_my,  g_bias_my);
    cudaGetSymbolAddress((void**)&bias_opp, g_bias_opp);
    cudaGetSymbolAddress((void**)&xh_my,  g_xh_my);
    cudaGetSymbolAddress((void**)&xlo_my, g_xlo_my);
    cudaGetSymbolAddress((void**)&xh_opp,  g_xh_opp);
    cudaGetSymbolAddress((void**)&xlo_opp, g_xlo_opp);
    cudaGetSymbolAddress((void**)&ah_my,  g_ah_my);
    cudaGetSymbolAddress((void**)&alo_my, g_alo_my);
    cudaGetSymbolAddress((void**)&ah_opp,  g_ah_opp);
    cudaGetSymbolAddress((void**)&alo_opp, g_alo_opp);
    cudaGetSymbolAddress((void**)&Wth_my,  g_Wth_my);
    cudaGetSymbolAddress((void**)&Wtl_my,  g_Wtl_my);
    cudaGetSymbolAddress((void**)&Wth_opp, g_Wth_opp);
    cudaGetSymbolAddress((void**)&Wtl_opp, g_Wtl_opp);
    cudaGetSymbolAddress((void**)&nwWh, g_nwWh);
    cudaGetSymbolAddress((void**)&nwWl, g_nwWl);
    cudaGetSymbolAddress((void**)&rowp,  g_row);
    cudaGetSymbolAddress((void**)&cntp,  g_cnt);
    cudaGetSymbolAddress((void**)&fillp, g_fill);
    cudaGetSymbolAddress((void**)&srcsp, g_srcs);

    cudaFuncSetAttribute(mma_gemm, cudaFuncAttributeMaxDynamicSharedMemorySize,
                         DYN_SMEM);

    const int* src_b  = ei_beats;      const int* dst_b  = ei_beats + EE;
    const int* src_l  = ei_loses;      const int* dst_l  = ei_loses + EE;
    const int* src_rb = ei_rev_beats;  const int* dst_rb = ei_rev_beats + EE;
    const int* src_rl = ei_rev_loses;  const int* dst_rl = ei_rev_loses + EE;

    const int nd_blocks   = (NN * DD + 255) / 256;
    const int node_blocks = (NN + 7) / 8;
    const int e_blocks    = (EE + 255) / 256;
    const int mtiles      = (NN + 127) / 128;      // 157

    // ---- CSR build (0=beats, 1=rev_loses, 2=loses, 3=rev_beats) ----
    csr_zero_kernel<<<(4 * NN + 255) / 256, 256>>>(cntp, fillp);
    csr_hist_kernel<<<e_blocks, 256>>>(dst_b, dst_rl, dst_l, dst_rb, cntp);
    csr_scan_kernel<<<4, 1024>>>(cntp, rowp);
    csr_scatter_kernel<<<e_blocks, 256>>>(src_b, dst_b, src_rl, dst_rl,
                                          src_l, dst_l, src_rb, dst_rb,
                                          rowp, fillp, srcsp);

    // ---- initial bf16 splits of inputs ----
    split_bf16_kernel<<<nd_blocks, 256>>>(in_x_my,  xh_my,  xlo_my,  NN * DD);
    split_bf16_kernel<<<nd_blocks, 256>>>(in_x_opp, xh_opp, xlo_opp, NN * DD);

    const float* cur_my  = in_x_my;
    const float* cur_opp = in_x_opp;

    for (int l = 0; l < LLAYERS; l++) {
        const size_t oW = (size_t)l * DD * HD;
        const size_t oA = (size_t)l * HH * DD;
        const size_t oB = (size_t)l * DD;
        const size_t oC = (size_t)l * 2 * DD * DD;
        const size_t oN = (size_t)l * DD * DD;

        // ---- weight prep (one launch) ----
        prep_all_kernel<<<(LDC * DD + 255) / 256, 256>>>(
            gWl_b + oW, gWr_b + oW, gWl_r + oW, gWr_r + oW,
            cgL_Wf + oC, cgL_Ws + oC, cgR_Wf + oC, cgR_Ws + oC,
            cgL_bf + oB, cgL_bs + oB, cgR_bf + oB, cgR_bs + oB,
            nw_W + oN,
            Wth_my, Wtl_my, Wth_opp, Wtl_opp, nwWh, nwWl,
            bias_my, bias_opp);

        // ---- fat projection GEMMs ----
        dim3 fat_grid(LDC / 128, mtiles);
        mma_gemm<<<fat_grid, 256, DYN_SMEM>>>(xh_my, xlo_my, Wth_my, Wtl_my,
                                              bias_my, C_my, NN, LDC,
                                              nullptr, nullptr);
        mma_gemm<<<fat_grid, 256, DYN_SMEM>>>(xh_opp, xlo_opp, Wth_opp, Wtl_opp,
                                              bias_opp, C_opp, NN, LDC,
                                              nullptr, nullptr);

        // ---- fused GAT (init acc with residual + bias) ----
        gat_fused_kernel<<<node_blocks, 256>>>(
            C_my, C_opp, gatt_b + oA,
            rowp + 0 * (NN + 1), srcsp + 0 * EE,
            cur_opp, gb_b + oB, acc_opp);
        gat_fused_kernel<<<node_blocks, 256>>>(
            C_opp + 512, C_my + 512, gatt_r + oA,
            rowp + 1 * (NN + 1), srcsp + 1 * EE,
            cur_my, gb_r + oB, acc_my);

        // ---- fused CGConv (acc += gate; writes bf16 hi/lo splits) ----
        cg_fused_kernel<<<node_blocks, 256>>>(
            C_opp + 1024, C_my + 1024, C_opp + 1152, C_my + 1152,
            rowp + 2 * (NN + 1), srcsp + 2 * EE,
            acc_opp, ah_opp, alo_opp);
        cg_fused_kernel<<<node_blocks, 256>>>(
            C_my + 1280, C_opp + 1280, C_my + 1408, C_opp + 1408,
            rowp + 3 * (NN + 1), srcsp + 3 * EE,
            acc_my, ah_my, alo_my);

        // ---- nodewise Linear (float out + bf16 splits for next layer) ----
        float* out_my  = (l == LLAYERS - 1) ? out           : x_my;
        float* out_opp = (l == LLAYERS - 1) ? out + NN * DD : x_opp;
        dim3 nw_grid(1, mtiles);
        mma_gemm<<<nw_grid, 256, DYN_SMEM>>>(ah_my, alo_my, nwWh, nwWl,
                                             nw_b + oB, out_my, NN, DD,
                                             xh_my, xlo_my);
        mma_gemm<<<nw_grid, 256, DYN_SMEM>>>(ah_opp, alo_opp, nwWh, nwWl,
                                             nw_b + oB, out_opp, NN, DD,
                                             xh_opp, xlo_opp);

        cur_my  = x_my;
        cur_opp = x_opp;
    }
}

// round 7
// speedup vs baseline: 3.7207x; 1.1285x over previous
#include <cuda_runtime.h>
#include <cuda_bf16.h>
#include <math.h>
#include <stdint.h>

// ---------------------------------------------------------------------------
// Problem constants
// ---------------------------------------------------------------------------
#define NN 20000
#define DD 128
#define HH 4
#define EE 80000
#define LLAYERS 2
#define HD (HH * DD)      // 512
#define LDC 1536          // fat projection width per node type

// Fat column layout (per node type X in {my, opp}):
//  [0,512)      GAT projection #1 (my: Wl_beats ; opp: Wr_beats)
//  [512,1024)   GAT projection #2 (my: Wr_rev   ; opp: Wl_rev)
//  [1024,1152)  CG lose Wf part   (my: src/bottom ; opp: dst/top + bf)
//  [1152,1280)  CG lose Ws part   (my: src/bottom ; opp: dst/top + bs)
//  [1280,1408)  CG rev  Wf part   (my: dst/top + bf ; opp: src/bottom)
//  [1408,1536)  CG rev  Ws part   (my: dst/top + bs ; opp: src/bottom)

// ---------------------------------------------------------------------------
// Static device scratch
// ---------------------------------------------------------------------------
__device__ __align__(16) float g_C_my [(size_t)NN * LDC];
__device__ __align__(16) float g_C_opp[(size_t)NN * LDC];

__device__ __align__(16) float g_x_my [NN * DD];
__device__ __align__(16) float g_x_opp[NN * DD];
__device__ __align__(16) float g_acc_my [NN * DD];
__device__ __align__(16) float g_acc_opp[NN * DD];

__device__ __align__(16) __nv_bfloat16 g_xh_my [NN * DD];
__device__ __align__(16) __nv_bfloat16 g_xlo_my[NN * DD];
__device__ __align__(16) __nv_bfloat16 g_xh_opp [NN * DD];
__device__ __align__(16) __nv_bfloat16 g_xlo_opp[NN * DD];

__device__ __align__(16) __nv_bfloat16 g_ah_my [NN * DD];
__device__ __align__(16) __nv_bfloat16 g_alo_my[NN * DD];
__device__ __align__(16) __nv_bfloat16 g_ah_opp [NN * DD];
__device__ __align__(16) __nv_bfloat16 g_alo_opp[NN * DD];

__device__ __align__(16) __nv_bfloat16 g_Wth_my [LDC * DD];
__device__ __align__(16) __nv_bfloat16 g_Wtl_my [LDC * DD];
__device__ __align__(16) __nv_bfloat16 g_Wth_opp[LDC * DD];
__device__ __align__(16) __nv_bfloat16 g_Wtl_opp[LDC * DD];
__device__ __align__(16) __nv_bfloat16 g_nwWh[DD * DD];
__device__ __align__(16) __nv_bfloat16 g_nwWl[DD * DD];

__device__ __align__(16) float g_bias_my [LDC];
__device__ __align__(16) float g_bias_opp[LDC];
__device__ __align__(16) float g_bias_nw [DD];   // (unused; nw bias read direct)

// CSR (4 relations: 0=beats, 1=rev_loses, 2=loses, 3=rev_beats), built once
__device__ int g_row [4 * (NN + 1)];
__device__ int g_cnt [4 * NN];
__device__ int g_fill[4 * NN];
__device__ int g_srcs[4 * EE];

// ---------------------------------------------------------------------------
// Arg structs for merged launches
// ---------------------------------------------------------------------------
struct GemmArgs {
    const __nv_bfloat16 *Ah[2], *Al[2], *Bh[2], *Bl[2];
    const float *bias[2];
    float *C[2];
    __nv_bfloat16 *Hout[2], *Lout[2];
    int M, ldc;
};

struct GatArgs {
    const float *xl[2], *xr[2], *att[2], *xres[2], *bias[2];
    const int *row[2], *srcs[2];
    float *acc[2];
};

struct CgArgs {
    const float *Pfd[2], *Pfs[2], *Psd[2], *Pss[2], *accin[2];
    const int *row[2], *srcs[2];
    __nv_bfloat16 *ah[2], *alo[2];
};

// ---------------------------------------------------------------------------
// Warp MMA / cp.async helpers (sm_80+ path; tcgen05 unavailable on compute_103)
// ---------------------------------------------------------------------------
__device__ __forceinline__ uint32_t smem_to_u32(const void* p)
{
    uint32_t a;
    asm("{ .reg .u64 t; cvta.to.shared.u64 t, %1; cvt.u32.u64 %0, t; }"
        : "=r"(a) : "l"(p));
    return a;
}

__device__ __forceinline__ void ldx4(uint32_t* r, uint32_t addr)
{
    asm volatile("ldmatrix.sync.aligned.m8n8.x4.shared.b16 {%0,%1,%2,%3}, [%4];"
                 : "=r"(r[0]), "=r"(r[1]), "=r"(r[2]), "=r"(r[3]) : "r"(addr));
}

__device__ __forceinline__ void mma16816(float* c, const uint32_t* a,
                                         uint32_t b0, uint32_t b1)
{
    asm volatile(
        "mma.sync.aligned.m16n8k16.row.col.f32.bf16.bf16.f32 "
        "{%0,%1,%2,%3}, {%4,%5,%6,%7}, {%8,%9}, {%0,%1,%2,%3};"
        : "+f"(c[0]), "+f"(c[1]), "+f"(c[2]), "+f"(c[3])
        : "r"(a[0]), "r"(a[1]), "r"(a[2]), "r"(a[3]), "r"(b0), "r"(b1));
}

__device__ __forceinline__ void cpa16(uint32_t dst, const void* src, int sz)
{
    asm volatile("cp.async.cg.shared.global [%0], [%1], 16, %2;"
                 :: "r"(dst), "l"(src), "r"(sz));
}
#define CP_COMMIT() asm volatile("cp.async.commit_group;" ::: "memory")
#define CP_WAIT(n)  asm volatile("cp.async.wait_group %0;" :: "n"(n) : "memory")

// ---------------------------------------------------------------------------
// Tensor-core GEMM: C[M, col0..+128] = A[M,128] @ Bt[Nc,128]^T + bias.
// Split bf16 (3-MMA) fp32 emulation. BK=32 slabs, 2-stage cp.async ring,
// 64 KB smem -> 2 CTAs/SM. grid.z selects node type.
// 64B rows in smem; swizzle ch ^= (r>>1)&3 (conflict-free ldmatrix phases).
// ---------------------------------------------------------------------------
#define SM_AH 0
#define SM_AL 8192
#define SM_BH 16384
#define SM_BL 24576
#define STAGE_BYTES 32768
#define DYN_SMEM 65536

__global__ void __launch_bounds__(256, 2)
mma_gemm(GemmArgs ga)
{
    extern __shared__ char smem[];
    const uint32_t sb = smem_to_u32(smem);

    const int z = blockIdx.z;
    const __nv_bfloat16* __restrict__ Ah = ga.Ah[z];
    const __nv_bfloat16* __restrict__ Al = ga.Al[z];
    const __nv_bfloat16* __restrict__ Bh = ga.Bh[z];
    const __nv_bfloat16* __restrict__ Bl = ga.Bl[z];
    const int M = ga.M, ldc = ga.ldc;

    const int tid  = threadIdx.x;
    const int wid  = tid >> 5;
    const int lane = tid & 31;
    const int row0 = blockIdx.y * 128;
    const int col0 = blockIdx.x * 128;

    const int warp_m = (wid & 3) * 32;    // 4 warps over M
    const int warp_n = (wid >> 2) * 64;   // 2 warps over N

    float acc[2][8][4];
#pragma unroll
    for (int mt = 0; mt < 2; mt++)
#pragma unroll
        for (int nt = 0; nt < 8; nt++)
#pragma unroll
            for (int j = 0; j < 4; j++) acc[mt][nt][j] = 0.f;

    // ---- slab loader: 32-wide K slab (64B rows), 4 tiles ----
    auto load_slab = [&](int slab, int buf) {
        const uint32_t bufb = sb + buf * STAGE_BYTES;
        const int kbase = slab * 32;
#pragma unroll
        for (int it = 0; it < 2; it++) {
            int c  = tid + it * 256;                 // 0..511
            int r  = c >> 2;                         // row 0..127
            int ch = c & 3;                          // 16B chunk in 64B row
            uint32_t so = (uint32_t)r * 64 + (uint32_t)((ch ^ ((r >> 1) & 3)) * 16);
            int kc = kbase + ch * 8;
            int gr = row0 + r;
            int asz = (gr < M) ? 16 : 0;
            int gra = (gr < M) ? gr : 0;
            cpa16(bufb + SM_AH + so, Ah + (size_t)gra * DD + kc, asz);
            cpa16(bufb + SM_AL + so, Al + (size_t)gra * DD + kc, asz);
            int gb = col0 + r;                       // Nc mult of 128 -> valid
            cpa16(bufb + SM_BH + so, Bh + (size_t)gb * DD + kc, 16);
            cpa16(bufb + SM_BL + so, Bl + (size_t)gb * DD + kc, 16);
        }
        CP_COMMIT();
    };

    // ---- slab compute: 2 k-steps of 16 ----
    auto comp_slab = [&](int buf) {
        const uint32_t bufb = sb + buf * STAGE_BYTES;
#pragma unroll
        for (int ks = 0; ks < 2; ks++) {
            uint32_t ahf[2][4], alf[2][4];
#pragma unroll
            for (int mt = 0; mt < 2; mt++) {
                int r  = warp_m + mt * 16 + (lane & 7) + ((lane >> 3) & 1) * 8;
                int ch = ks * 2 + (lane >> 4);
                uint32_t off = (uint32_t)r * 64
                             + (uint32_t)((ch ^ ((r >> 1) & 3)) * 16);
                ldx4(ahf[mt], bufb + SM_AH + off);
                ldx4(alf[mt], bufb + SM_AL + off);
            }
            uint32_t bhf[4][4], blf[4][4];
#pragma unroll
            for (int np = 0; np < 4; np++) {
                int r  = warp_n + np * 16 + (lane & 7) + ((lane >> 4) & 1) * 8;
                int ch = ks * 2 + ((lane >> 3) & 1);
                uint32_t off = (uint32_t)r * 64
                             + (uint32_t)((ch ^ ((r >> 1) & 3)) * 16);
                ldx4(bhf[np], bufb + SM_BH + off);
                ldx4(blf[np], bufb + SM_BL + off);
            }
#pragma unroll
            for (int mt = 0; mt < 2; mt++) {
#pragma unroll
                for (int nt = 0; nt < 8; nt++) {
                    int np = nt >> 1, hi = (nt & 1) * 2;
                    mma16816(acc[mt][nt], ahf[mt], bhf[np][hi], bhf[np][hi + 1]);
                    mma16816(acc[mt][nt], ahf[mt], blf[np][hi], blf[np][hi + 1]);
                    mma16816(acc[mt][nt], alf[mt], bhf[np][hi], bhf[np][hi + 1]);
                }
            }
        }
    };

    // ---- 4 K-slabs through a 2-buffer ring ----
    load_slab(0, 0);
    load_slab(1, 1);
    CP_WAIT(1);
    __syncthreads();
    comp_slab(0);
    __syncthreads();
    load_slab(2, 0);
    CP_WAIT(1);
    __syncthreads();
    comp_slab(1);
    __syncthreads();
    load_slab(3, 1);
    CP_WAIT(1);
    __syncthreads();
    comp_slab(0);
    CP_WAIT(0);
    __syncthreads();
    comp_slab(1);

    // ---- epilogue ----
    const float* __restrict__ bias = ga.bias[z];
    float* __restrict__ C = ga.C[z];
    __nv_bfloat16* __restrict__ Hout = ga.Hout[z];
    __nv_bfloat16* __restrict__ Lout = ga.Lout[z];
#pragma unroll
    for (int mt = 0; mt < 2; mt++) {
        int gr0 = row0 + warp_m + mt * 16 + (lane >> 2);
#pragma unroll
        for (int nt = 0; nt < 8; nt++) {
            int gc = col0 + warp_n + nt * 8 + (lane & 3) * 2;
            float2 b2 = *reinterpret_cast<const float2*>(bias + gc);
#pragma unroll
            for (int half = 0; half < 2; half++) {
                int gr = gr0 + half * 8;
                if (gr >= M) continue;
                float vx = acc[mt][nt][half * 2 + 0] + b2.x;
                float vy = acc[mt][nt][half * 2 + 1] + b2.y;
                *reinterpret_cast<float2*>(C + (size_t)gr * ldc + gc) =
                    make_float2(vx, vy);
                if (Hout) {
                    __nv_bfloat16 hx = __float2bfloat16(vx);
                    __nv_bfloat16 hy = __float2bfloat16(vy);
                    __nv_bfloat162 hv; hv.x = hx; hv.y = hy;
                    __nv_bfloat162 lv;
                    lv.x = __float2bfloat16(vx - __bfloat162float(hx));
                    lv.y = __float2bfloat16(vy - __bfloat162float(hy));
                    size_t o = (size_t)gr * DD + gc;
                    *reinterpret_cast<__nv_bfloat162*>(Hout + o) = hv;
                    *reinterpret_cast<__nv_bfloat162*>(Lout + o) = lv;
                }
            }
        }
    }
}

// ---------------------------------------------------------------------------
// Conversion / prep kernels
// ---------------------------------------------------------------------------
__global__ void split2_bf16_kernel(const float* __restrict__ x0,
                                   const float* __restrict__ x1,
                                   __nv_bfloat16* __restrict__ h0,
                                   __nv_bfloat16* __restrict__ l0,
                                   __nv_bfloat16* __restrict__ h1,
                                   __nv_bfloat16* __restrict__ l1)
{
    int i = blockIdx.x * blockDim.x + threadIdx.x;
    if (i >= 2 * NN * DD) return;
    const float* x = (i < NN * DD) ? x0 : x1;
    __nv_bfloat16* h = (i < NN * DD) ? h0 : h1;
    __nv_bfloat16* l = (i < NN * DD) ? l0 : l1;
    int j = (i < NN * DD) ? i : i - NN * DD;
    float v = x[j];
    __nv_bfloat16 hb = __float2bfloat16(v);
    h[j] = hb;
    l[j] = __float2bfloat16(v - __bfloat162float(hb));
}

// One launch: fat W^T splits + fat bias vectors + nw W^T split.
__global__ void prep_all_kernel(const float* __restrict__ gWl_b,
                                const float* __restrict__ gWr_b,
                                const float* __restrict__ gWl_r,
                                const float* __restrict__ gWr_r,
                                const float* __restrict__ cgL_Wf,
                                const float* __restrict__ cgL_Ws,
                                const float* __restrict__ cgR_Wf,
                                const float* __restrict__ cgR_Ws,
                                const float* __restrict__ cgL_bf,
                                const float* __restrict__ cgL_bs,
                                const float* __restrict__ cgR_bf,
                                const float* __restrict__ cgR_bs,
                                const float* __restrict__ nw_W,
                                __nv_bfloat16* __restrict__ Wth_my,
                                __nv_bfloat16* __restrict__ Wtl_my,
                                __nv_bfloat16* __restrict__ Wth_opp,
                                __nv_bfloat16* __restrict__ Wtl_opp,
                                __nv_bfloat16* __restrict__ nwWh,
                                __nv_bfloat16* __restrict__ nwWl,
                                float* __restrict__ bias_my,
                                float* __restrict__ bias_opp)
{
    int idx = blockIdx.x * blockDim.x + threadIdx.x;
    if (idx < LDC * DD) {
        int n = idx / DD, k = idx % DD;
        float wm, wo;
        if (n < 512) {
            wm = gWl_b[k * HD + n];               wo = gWr_b[k * HD + n];
        } else if (n < 1024) {
            int c = n - 512;
            wm = gWr_r[k * HD + c];               wo = gWl_r[k * HD + c];
        } else if (n < 1152) {
            int c = n - 1024;
            wm = cgL_Wf[(DD + k) * DD + c];       wo = cgL_Wf[k * DD + c];
        } else if (n < 1280) {
            int c = n - 1152;
            wm = cgL_Ws[(DD + k) * DD + c];       wo = cgL_Ws[k * DD + c];
        } else if (n < 1408) {
            int c = n - 1280;
            wm = cgR_Wf[k * DD + c];              wo = cgR_Wf[(DD + k) * DD + c];
        } else {
            int c = n - 1408;
            wm = cgR_Ws[k * DD + c];              wo = cgR_Ws[(DD + k) * DD + c];
        }
        __nv_bfloat16 hm = __float2bfloat16(wm);
        __nv_bfloat16 ho = __float2bfloat16(wo);
        Wth_my[idx]  = hm;
        Wtl_my[idx]  = __float2bfloat16(wm - __bfloat162float(hm));
        Wth_opp[idx] = ho;
        Wtl_opp[idx] = __float2bfloat16(wo - __bfloat162float(ho));
    }
    if (idx < DD * DD) {
        int n = idx / DD, k = idx % DD;
        float v = nw_W[k * DD + n];
        __nv_bfloat16 hb = __float2bfloat16(v);
        nwWh[idx] = hb;
        nwWl[idx] = __float2bfloat16(v - __bfloat162float(hb));
    }
    if (idx < LDC) {
        int n = idx;
        float bm = 0.f, bo = 0.f;
        if (n >= 1024 && n < 1152) bo = cgL_bf[n - 1024];
        else if (n >= 1152 && n < 1280) bo = cgL_bs[n - 1152];
        if (n >= 1280 && n < 1408) bm = cgR_bf[n - 1280];
        else if (n >= 1408) bm = cgR_bs[n - 1408];
        bias_my[n] = bm;
        bias_opp[n] = bo;
    }
}

// ---------------------------------------------------------------------------
// CSR build (4 relations, built once per launch)
// ---------------------------------------------------------------------------
__global__ void csr_zero_kernel(int* __restrict__ cnt, int* __restrict__ fill)
{
    int i = blockIdx.x * blockDim.x + threadIdx.x;
    if (i < 4 * NN) { cnt[i] = 0; fill[i] = 0; }
}

__global__ void csr_hist_kernel(const int* __restrict__ d0,
                                const int* __restrict__ d1,
                                const int* __restrict__ d2,
                                const int* __restrict__ d3,
                                int* __restrict__ cnt)
{
    int i = blockIdx.x * blockDim.x + threadIdx.x;
    if (i >= EE) return;
    atomicAdd(&cnt[0 * NN + d0[i]], 1);
    atomicAdd(&cnt[1 * NN + d1[i]], 1);
    atomicAdd(&cnt[2 * NN + d2[i]], 1);
    atomicAdd(&cnt[3 * NN + d3[i]], 1);
}

__global__ void csr_scan_kernel(const int* __restrict__ cnt,
                                int* __restrict__ row)
{
    __shared__ int part[1024];
    const int rel = blockIdx.x;
    const int t = threadIdx.x;
    const int CH = (NN + 1023) / 1024;     // 20
    const int base = t * CH;
    int s = 0;
    for (int j = 0; j < CH; j++) {
        int i = base + j;
        if (i < NN) s += cnt[rel * NN + i];
    }
    part[t] = s;
    __syncthreads();
    for (int o = 1; o < 1024; o <<= 1) {
        int u = (t >= o) ? part[t - o] : 0;
        __syncthreads();
        part[t] += u;
        __syncthreads();
    }
    int run = part[t] - s;                 // exclusive prefix
    for (int j = 0; j < CH; j++) {
        int i = base + j;
        if (i < NN) {
            row[rel * (NN + 1) + i] = run;
            run += cnt[rel * NN + i];
        }
    }
    if (t == 1023) row[rel * (NN + 1) + NN] = part[1023];
}

__global__ void csr_scatter_kernel(const int* __restrict__ s0, const int* __restrict__ d0,
                                   const int* __restrict__ s1, const int* __restrict__ d1,
                                   const int* __restrict__ s2, const int* __restrict__ d2,
                                   const int* __restrict__ s3, const int* __restrict__ d3,
                                   const int* __restrict__ row,
                                   int* __restrict__ fill,
                                   int* __restrict__ srcs)
{
    int i = blockIdx.x * blockDim.x + threadIdx.x;
    if (i >= EE) return;
    {
        int d = d0[i];
        int pos = row[0 * (NN + 1) + d] + atomicAdd(&fill[0 * NN + d], 1);
        srcs[0 * EE + pos] = s0[i];
    }
    {
        int d = d1[i];
        int pos = row[1 * (NN + 1) + d] + atomicAdd(&fill[1 * NN + d], 1);
        srcs[1 * EE + pos] = s1[i];
    }
    {
        int d = d2[i];
        int pos = row[2 * (NN + 1) + d] + atomicAdd(&fill[2 * NN + d], 1);
        srcs[2 * EE + pos] = s2[i];
    }
    {
        int d = d3[i];
        int pos = row[3 * (NN + 1) + d] + atomicAdd(&fill[3 * NN + d], 1);
        srcs[3 * EE + pos] = s3[i];
    }
}

// ---------------------------------------------------------------------------
// Fused GATv2: warp per dst node, single feature pass; blockIdx.y = relation.
// Scores are O(10) bounded -> plain exp accumulation == softmax exactly.
// ---------------------------------------------------------------------------
__global__ void __launch_bounds__(256)
gat_fused_kernel(GatArgs a)
{
    const int rel = blockIdx.y;
    int d = blockIdx.x * 8 + (threadIdx.x >> 5);
    int lane = threadIdx.x & 31;
    if (d >= NN) return;

    const float* __restrict__ xl = a.xl[rel];
    const float* __restrict__ xr = a.xr[rel];
    const float* __restrict__ att = a.att[rel];
    const int* __restrict__ row = a.row[rel];
    const int* __restrict__ srcs = a.srcs[rel];

    float4 xr4[HH], at4[HH];
    const float4* pr = reinterpret_cast<const float4*>(xr + (size_t)d * LDC);
    const float4* pa = reinterpret_cast<const float4*>(att);
#pragma unroll
    for (int h = 0; h < HH; h++) {
        xr4[h] = pr[h * 32 + lane];
        at4[h] = pa[h * 32 + lane];
    }

    float s[HH];
    float4 a4[HH];
#pragma unroll
    for (int h = 0; h < HH; h++) {
        s[h] = 0.f;
        a4[h] = make_float4(0.f, 0.f, 0.f, 0.f);
    }

    const int e0 = row[d], e1 = row[d + 1];
#pragma unroll 2
    for (int p = e0; p < e1; p++) {
        int sn = srcs[p];
        const float4* pl = reinterpret_cast<const float4*>(xl + (size_t)sn * LDC);
        float4 l4[HH];
        float part[HH];
#pragma unroll
        for (int h = 0; h < HH; h++) {
            l4[h] = pl[h * 32 + lane];
            float zx = l4[h].x + xr4[h].x; zx = (zx > 0.f) ? zx : 0.2f * zx;
            float zy = l4[h].y + xr4[h].y; zy = (zy > 0.f) ? zy : 0.2f * zy;
            float zz = l4[h].z + xr4[h].z; zz = (zz > 0.f) ? zz : 0.2f * zz;
            float zw = l4[h].w + xr4[h].w; zw = (zw > 0.f) ? zw : 0.2f * zw;
            part[h] = zx * at4[h].x + zy * at4[h].y
                    + zz * at4[h].z + zw * at4[h].w;
        }
#pragma unroll
        for (int o = 16; o; o >>= 1)
#pragma unroll
            for (int h = 0; h < HH; h++)
                part[h] += __shfl_xor_sync(0xffffffffu, part[h], o);
#pragma unroll
        for (int h = 0; h < HH; h++) {
            float e = __expf(part[h]);
            s[h] += e;
            a4[h].x += e * l4[h].x;
            a4[h].y += e * l4[h].y;
            a4[h].z += e * l4[h].z;
            a4[h].w += e * l4[h].w;
        }
    }

    float4 r4 = reinterpret_cast<const float4*>(a.xres[rel] + (size_t)d * DD)[lane];
    float4 b4 = reinterpret_cast<const float4*>(a.bias[rel])[lane];
    float4 o4 = make_float4(r4.x + b4.x, r4.y + b4.y,
                            r4.z + b4.z, r4.w + b4.w);
#pragma unroll
    for (int h = 0; h < HH; h++) {
        float inv = 0.25f / (s[h] + 1e-16f);
        o4.x += a4[h].x * inv;
        o4.y += a4[h].y * inv;
        o4.z += a4[h].z * inv;
        o4.w += a4[h].w * inv;
    }
    reinterpret_cast<float4*>(a.acc[rel] + (size_t)d * DD)[lane] = o4;
}

// ---------------------------------------------------------------------------
// Fused CGConv: warp per dst node; fast-math gate; writes bf16 hi/lo splits.
// blockIdx.y = relation.
// ---------------------------------------------------------------------------
__device__ __forceinline__ float gate1(float f, float g)
{
    float sig = __fdividef(1.f, 1.f + __expf(-f));
    float sp  = fmaxf(g, 0.f) + __logf(1.f + __expf(-fabsf(g)));
    return sig * sp;
}

__global__ void __launch_bounds__(256)
cg_fused_kernel(CgArgs a)
{
    const int rel = blockIdx.y;
    int d = blockIdx.x * 8 + (threadIdx.x >> 5);
    int lane = threadIdx.x & 31;
    if (d >= NN) return;

    const float* __restrict__ Pfs = a.Pfs[rel];
    const float* __restrict__ Pss = a.Pss[rel];
    const int* __restrict__ row = a.row[rel];
    const int* __restrict__ srcs = a.srcs[rel];

    float4 fd4 = reinterpret_cast<const float4*>(a.Pfd[rel] + (size_t)d * LDC)[lane];
    float4 sd4 = reinterpret_cast<const float4*>(a.Psd[rel] + (size_t)d * LDC)[lane];
    float4 acc4 = reinterpret_cast<const float4*>(a.accin[rel] + (size_t)d * DD)[lane];

    const int e0 = row[d], e1 = row[d + 1];
#pragma unroll 2
    for (int p = e0; p < e1; p++) {
        int sn = srcs[p];
        float4 fs4 = reinterpret_cast<const float4*>(Pfs + (size_t)sn * LDC)[lane];
        float4 ss4 = reinterpret_cast<const float4*>(Pss + (size_t)sn * LDC)[lane];
        acc4.x += gate1(fd4.x + fs4.x, sd4.x + ss4.x);
        acc4.y += gate1(fd4.y + fs4.y, sd4.y + ss4.y);
        acc4.z += gate1(fd4.z + fs4.z, sd4.z + ss4.z);
        acc4.w += gate1(fd4.w + fs4.w, sd4.w + ss4.w);
    }

    size_t off = (size_t)d * DD + lane * 4;
    __nv_bfloat16 h0 = __float2bfloat16(acc4.x);
    __nv_bfloat16 h1 = __float2bfloat16(acc4.y);
    __nv_bfloat16 h2 = __float2bfloat16(acc4.z);
    __nv_bfloat16 h3 = __float2bfloat16(acc4.w);
    __nv_bfloat162 hv0; hv0.x = h0; hv0.y = h1;
    __nv_bfloat162 hv1; hv1.x = h2; hv1.y = h3;
    __nv_bfloat162 lv0, lv1;
    lv0.x = __float2bfloat16(acc4.x - __bfloat162float(h0));
    lv0.y = __float2bfloat16(acc4.y - __bfloat162float(h1));
    lv1.x = __float2bfloat16(acc4.z - __bfloat162float(h2));
    lv1.y = __float2bfloat16(acc4.w - __bfloat162float(h3));
    *reinterpret_cast<__nv_bfloat162*>(a.ah[rel] + off)       = hv0;
    *reinterpret_cast<__nv_bfloat162*>(a.ah[rel] + off + 2)   = hv1;
    *reinterpret_cast<__nv_bfloat162*>(a.alo[rel] + off)      = lv0;
    *reinterpret_cast<__nv_bfloat162*>(a.alo[rel] + off + 2)  = lv1;
}

// ---------------------------------------------------------------------------
// Host launcher
// ---------------------------------------------------------------------------
extern "C" void kernel_launch(void* const* d_in, const int* in_sizes, int n_in,
                              void* d_out, int out_size)
{
    const float* in_x_my  = (const float*)d_in[0];
    const float* in_x_opp = (const float*)d_in[1];
    const float* gWl_b = (const float*)d_in[2];
    const float* gWr_b = (const float*)d_in[3];
    const float* gatt_b = (const float*)d_in[4];
    const float* gb_b  = (const float*)d_in[5];
    const float* gWl_r = (const float*)d_in[6];
    const float* gWr_r = (const float*)d_in[7];
    const float* gatt_r = (const float*)d_in[8];
    const float* gb_r  = (const float*)d_in[9];
    const float* cgL_Wf = (const float*)d_in[10];
    const float* cgL_bf = (const float*)d_in[11];
    const float* cgL_Ws = (const float*)d_in[12];
    const float* cgL_bs = (const float*)d_in[13];
    const float* cgR_Wf = (const float*)d_in[14];
    const float* cgR_bf = (const float*)d_in[15];
    const float* cgR_Ws = (const float*)d_in[16];
    const float* cgR_bs = (const float*)d_in[17];
    const float* nw_W = (const float*)d_in[18];
    const float* nw_b = (const float*)d_in[19];
    const int* ei_beats     = (const int*)d_in[20];
    const int* ei_loses     = (const int*)d_in[21];
    const int* ei_rev_beats = (const int*)d_in[22];
    const int* ei_rev_loses = (const int*)d_in[23];

    float* out = (float*)d_out;

    float *C_my, *C_opp, *x_my, *x_opp, *acc_my, *acc_opp, *bias_my, *bias_opp;
    __nv_bfloat16 *xh_my, *xlo_my, *xh_opp, *xlo_opp;
    __nv_bfloat16 *ah_my, *alo_my, *ah_opp, *alo_opp;
    __nv_bfloat16 *Wth_my, *Wtl_my, *Wth_opp, *Wtl_opp, *nwWh, *nwWl;
    int *rowp, *cntp, *fillp, *srcsp;
    cudaGetSymbolAddress((void**)&C_my,  g_C_my);
    cudaGetSymbolAddress((void**)&C_opp, g_C_opp);
    cudaGetSymbolAddress((void**)&x_my,  g_x_my);
    cudaGetSymbolAddress((void**)&x_opp, g_x_opp);
    cudaGetSymbolAddress((void**)&acc_my, g_acc_my);
    cudaGetSymbolAddress((void**)&acc_opp, g_acc_opp);
    cudaGetSymbolAddress((void**)&bias_my,  g_bias_my);
    cudaGetSymbolAddress((void**)&bias_opp, g_bias_opp);
    cudaGetSymbolAddress((void**)&xh_my,  g_xh_my);
    cudaGetSymbolAddress((void**)&xlo_my, g_xlo_my);
    cudaGetSymbolAddress((void**)&xh_opp,  g_xh_opp);
    cudaGetSymbolAddress((void**)&xlo_opp, g_xlo_opp);
    cudaGetSymbolAddress((void**)&ah_my,  g_ah_my);
    cudaGetSymbolAddress((void**)&alo_my, g_alo_my);
    cudaGetSymbolAddress((void**)&ah_opp,  g_ah_opp);
    cudaGetSymbolAddress((void**)&alo_opp, g_alo_opp);
    cudaGetSymbolAddress((void**)&Wth_my,  g_Wth_my);
    cudaGetSymbolAddress((void**)&Wtl_my,  g_Wtl_my);
    cudaGetSymbolAddress((void**)&Wth_opp, g_Wth_opp);
    cudaGetSymbolAddress((void**)&Wtl_opp, g_Wtl_opp);
    cudaGetSymbolAddress((void**)&nwWh, g_nwWh);
    cudaGetSymbolAddress((void**)&nwWl, g_nwWl);
    cudaGetSymbolAddress((void**)&rowp,  g_row);
    cudaGetSymbolAddress((void**)&cntp,  g_cnt);
    cudaGetSymbolAddress((void**)&fillp, g_fill);
    cudaGetSymbolAddress((void**)&srcsp, g_srcs);

    cudaFuncSetAttribute(mma_gemm, cudaFuncAttributeMaxDynamicSharedMemorySize,
                         DYN_SMEM);

    const int* src_b  = ei_beats;      const int* dst_b  = ei_beats + EE;
    const int* src_l  = ei_loses;      const int* dst_l  = ei_loses + EE;
    const int* src_rb = ei_rev_beats;  const int* dst_rb = ei_rev_beats + EE;
    const int* src_rl = ei_rev_loses;  const int* dst_rl = ei_rev_loses + EE;

    const int node_blocks = (NN + 7) / 8;
    const int e_blocks    = (EE + 255) / 256;
    const int mtiles      = (NN + 127) / 128;      // 157

    // ---- CSR build (0=beats, 1=rev_loses, 2=loses, 3=rev_beats) ----
    csr_zero_kernel<<<(4 * NN + 255) / 256, 256>>>(cntp, fillp);
    csr_hist_kernel<<<e_blocks, 256>>>(dst_b, dst_rl, dst_l, dst_rb, cntp);
    csr_scan_kernel<<<4, 1024>>>(cntp, rowp);
    csr_scatter_kernel<<<e_blocks, 256>>>(src_b, dst_b, src_rl, dst_rl,
                                          src_l, dst_l, src_rb, dst_rb,
                                          rowp, fillp, srcsp);

    // ---- initial bf16 splits of inputs (one launch) ----
    split2_bf16_kernel<<<(2 * NN * DD + 255) / 256, 256>>>(
        in_x_my, in_x_opp, xh_my, xlo_my, xh_opp, xlo_opp);

    const float* cur_my  = in_x_my;
    const float* cur_opp = in_x_opp;

    for (int l = 0; l < LLAYERS; l++) {
        const size_t oW = (size_t)l * DD * HD;
        const size_t oA = (size_t)l * HH * DD;
        const size_t oB = (size_t)l * DD;
        const size_t oC = (size_t)l * 2 * DD * DD;
        const size_t oN = (size_t)l * DD * DD;

        // ---- weight prep (one launch) ----
        prep_all_kernel<<<(LDC * DD + 255) / 256, 256>>>(
            gWl_b + oW, gWr_b + oW, gWl_r + oW, gWr_r + oW,
            cgL_Wf + oC, cgL_Ws + oC, cgR_Wf + oC, cgR_Ws + oC,
            cgL_bf + oB, cgL_bs + oB, cgR_bf + oB, cgR_bs + oB,
            nw_W + oN,
            Wth_my, Wtl_my, Wth_opp, Wtl_opp, nwWh, nwWl,
            bias_my, bias_opp);

        // ---- fat projection GEMMs (both node types, one launch) ----
        {
            GemmArgs ga;
            ga.Ah[0] = xh_my;   ga.Al[0] = xlo_my;
            ga.Ah[1] = xh_opp;  ga.Al[1] = xlo_opp;
            ga.Bh[0] = Wth_my;  ga.Bl[0] = Wtl_my;
            ga.Bh[1] = Wth_opp; ga.Bl[1] = Wtl_opp;
            ga.bias[0] = bias_my;  ga.bias[1] = bias_opp;
            ga.C[0] = C_my;     ga.C[1] = C_opp;
            ga.Hout[0] = nullptr; ga.Hout[1] = nullptr;
            ga.Lout[0] = nullptr; ga.Lout[1] = nullptr;
            ga.M = NN; ga.ldc = LDC;
            dim3 grid(LDC / 128, mtiles, 2);
            mma_gemm<<<grid, 256, DYN_SMEM>>>(ga);
        }

        // ---- fused GAT: both relations, one launch ----
        {
            GatArgs a;
            // rel 0: beats (my -> opp)
            a.xl[0] = C_my;        a.xr[0] = C_opp;
            a.att[0] = gatt_b + oA;
            a.row[0] = rowp + 0 * (NN + 1);  a.srcs[0] = srcsp + 0 * EE;
            a.xres[0] = cur_opp;   a.bias[0] = gb_b + oB;  a.acc[0] = acc_opp;
            // rel 1: rev_loses (opp -> my)
            a.xl[1] = C_opp + 512; a.xr[1] = C_my + 512;
            a.att[1] = gatt_r + oA;
            a.row[1] = rowp + 1 * (NN + 1);  a.srcs[1] = srcsp + 1 * EE;
            a.xres[1] = cur_my;    a.bias[1] = gb_r + oB;  a.acc[1] = acc_my;
            dim3 grid(node_blocks, 2);
            gat_fused_kernel<<<grid, 256>>>(a);
        }

        // ---- fused CGConv: both relations, one launch ----
        {
            CgArgs a;
            // rel 0: loses (my -> opp)
            a.Pfd[0] = C_opp + 1024; a.Pfs[0] = C_my + 1024;
            a.Psd[0] = C_opp + 1152; a.Pss[0] = C_my + 1152;
            a.row[0] = rowp + 2 * (NN + 1);  a.srcs[0] = srcsp + 2 * EE;
            a.accin[0] = acc_opp;  a.ah[0] = ah_opp;  a.alo[0] = alo_opp;
            // rel 1: rev_beats (opp -> my)
            a.Pfd[1] = C_my + 1280; a.Pfs[1] = C_opp + 1280;
            a.Psd[1] = C_my + 1408; a.Pss[1] = C_opp + 1408;
            a.row[1] = rowp + 3 * (NN + 1);  a.srcs[1] = srcsp + 3 * EE;
            a.accin[1] = acc_my;   a.ah[1] = ah_my;   a.alo[1] = alo_my;
            dim3 grid(node_blocks, 2);
            cg_fused_kernel<<<grid, 256>>>(a);
        }

        // ---- nodewise Linear (both node types, one launch) ----
        {
            float* out_my  = (l == LLAYERS - 1) ? out           : x_my;
            float* out_opp = (l == LLAYERS - 1) ? out + NN * DD : x_opp;
            GemmArgs ga;
            ga.Ah[0] = ah_my;   ga.Al[0] = alo_my;
            ga.Ah[1] = ah_opp;  ga.Al[1] = alo_opp;
            ga.Bh[0] = nwWh;    ga.Bl[0] = nwWl;
            ga.Bh[1] = nwWh;    ga.Bl[1] = nwWl;
            ga.bias[0] = nw_b + oB;  ga.bias[1] = nw_b + oB;
            ga.C[0] = out_my;   ga.C[1] = out_opp;
            ga.Hout[0] = xh_my;  ga.Lout[0] = xlo_my;
            ga.Hout[1] = xh_opp; ga.Lout[1] = xlo_opp;
            ga.M = NN; ga.ldc = DD;
            dim3 grid(1, mtiles, 2);
            mma_gemm<<<grid, 256, DYN_SMEM>>>(ga);
        }

        cur_my  = x_my;
        cur_opp = x_opp;
    }
}

// round 8
// speedup vs baseline: 3.7326x; 1.0032x over previous
#include <cuda_runtime.h>
#include <cuda_fp16.h>
#include <math.h>
#include <stdint.h>

// ---------------------------------------------------------------------------
// Problem constants
// ---------------------------------------------------------------------------
#define NN 20000
#define DD 128
#define HH 4
#define EE 80000
#define LLAYERS 2
#define HD (HH * DD)      // 512
#define LDC 1536          // fat projection width per node type

// Fat column layout (per node type X in {my, opp}):
//  [0,512)      GAT projection #1 (my: Wl_beats ; opp: Wr_beats)
//  [512,1024)   GAT projection #2 (my: Wr_rev   ; opp: Wl_rev)
//  [1024,1152)  CG lose Wf part   (my: src/bottom ; opp: dst/top + bf)
//  [1152,1280)  CG lose Ws part   (my: src/bottom ; opp: dst/top + bs)
//  [1280,1408)  CG rev  Wf part   (my: dst/top + bf ; opp: src/bottom)
//  [1408,1536)  CG rev  Ws part   (my: dst/top + bs ; opp: src/bottom)

// ---------------------------------------------------------------------------
// Static device scratch
// ---------------------------------------------------------------------------
__device__ __align__(16) float g_C_my [(size_t)NN * LDC];
__device__ __align__(16) float g_C_opp[(size_t)NN * LDC];

__device__ __align__(16) float g_x_my [NN * DD];
__device__ __align__(16) float g_x_opp[NN * DD];
__device__ __align__(16) float g_acc_my [NN * DD];
__device__ __align__(16) float g_acc_opp[NN * DD];

// fp16 feature operands (A side of GEMMs) — single precision copy
__device__ __align__(16) __half g_xh_my [NN * DD];
__device__ __align__(16) __half g_xh_opp[NN * DD];
__device__ __align__(16) __half g_ah_my [NN * DD];
__device__ __align__(16) __half g_ah_opp[NN * DD];

// fp16 weight operands (B side), hi/lo split
__device__ __align__(16) __half g_Wth_my [LDC * DD];
__device__ __align__(16) __half g_Wtl_my [LDC * DD];
__device__ __align__(16) __half g_Wth_opp[LDC * DD];
__device__ __align__(16) __half g_Wtl_opp[LDC * DD];
__device__ __align__(16) __half g_nwWh[DD * DD];
__device__ __align__(16) __half g_nwWl[DD * DD];

__device__ __align__(16) float g_bias_my [LDC];
__device__ __align__(16) float g_bias_opp[LDC];

// CSR (4 relations: 0=beats, 1=rev_loses, 2=loses, 3=rev_beats), built once
__device__ int g_row [4 * (NN + 1)];
__device__ int g_cnt [4 * NN];
__device__ int g_fill[4 * NN];
__device__ int g_srcs[4 * EE];

// ---------------------------------------------------------------------------
// Arg structs for merged launches
// ---------------------------------------------------------------------------
struct GemmArgs {
    const __half *Ah[2], *Bh[2], *Bl[2];
    const float *bias[2];
    float *C[2];
    __half *Hout[2];
    int M, ldc;
};

struct GatArgs {
    const float *xl[2], *xr[2], *att[2], *xres[2], *bias[2];
    const int *row[2], *srcs[2];
    float *acc[2];
};

struct CgArgs {
    const float *Pfd[2], *Pfs[2], *Psd[2], *Pss[2], *accin[2];
    const int *row[2], *srcs[2];
    __half *ah[2];
};

// ---------------------------------------------------------------------------
// Warp MMA / cp.async helpers
// ---------------------------------------------------------------------------
__device__ __forceinline__ uint32_t smem_to_u32(const void* p)
{
    uint32_t a;
    asm("{ .reg .u64 t; cvta.to.shared.u64 t, %1; cvt.u32.u64 %0, t; }"
        : "=r"(a) : "l"(p));
    return a;
}

__device__ __forceinline__ void ldx4(uint32_t* r, uint32_t addr)
{
    asm volatile("ldmatrix.sync.aligned.m8n8.x4.shared.b16 {%0,%1,%2,%3}, [%4];"
                 : "=r"(r[0]), "=r"(r[1]), "=r"(r[2]), "=r"(r[3]) : "r"(addr));
}

__device__ __forceinline__ void mma16816(float* c, const uint32_t* a,
                                         uint32_t b0, uint32_t b1)
{
    asm volatile(
        "mma.sync.aligned.m16n8k16.row.col.f32.f16.f16.f32 "
        "{%0,%1,%2,%3}, {%4,%5,%6,%7}, {%8,%9}, {%0,%1,%2,%3};"
        : "+f"(c[0]), "+f"(c[1]), "+f"(c[2]), "+f"(c[3])
        : "r"(a[0]), "r"(a[1]), "r"(a[2]), "r"(a[3]), "r"(b0), "r"(b1));
}

__device__ __forceinline__ void cpa16(uint32_t dst, const void* src, int sz)
{
    asm volatile("cp.async.cg.shared.global [%0], [%1], 16, %2;"
                 :: "r"(dst), "l"(src), "r"(sz));
}
#define CP_COMMIT() asm volatile("cp.async.commit_group;" ::: "memory")
#define CP_WAIT(n)  asm volatile("cp.async.wait_group %0;" :: "n"(n) : "memory")

// ---------------------------------------------------------------------------
// Tensor-core GEMM: C[M, col0..+128] = A[M,128] @ Bt[Nc,128]^T + bias.
// fp32 emulation: A single fp16, B split fp16 hi/lo, 2 MMAs (AhBh + AhBl).
// BK=32 slabs, 2-stage cp.async ring, 48 KB smem -> 2 CTAs/SM.
// grid.z = node type. 64B rows; swizzle ch ^= (r>>1)&3.
// ---------------------------------------------------------------------------
#define SM_A  0
#define SM_BH 8192
#define SM_BL 16384
#define STAGE_BYTES 24576
#define DYN_SMEM 49152

__global__ void __launch_bounds__(256, 2)
mma_gemm(GemmArgs ga)
{
    extern __shared__ char smem[];
    const uint32_t sb = smem_to_u32(smem);

    const int z = blockIdx.z;
    const __half* __restrict__ Ah = ga.Ah[z];
    const __half* __restrict__ Bh = ga.Bh[z];
    const __half* __restrict__ Bl = ga.Bl[z];
    const int M = ga.M, ldc = ga.ldc;

    const int tid  = threadIdx.x;
    const int wid  = tid >> 5;
    const int lane = tid & 31;
    const int row0 = blockIdx.y * 128;
    const int col0 = blockIdx.x * 128;

    const int warp_m = (wid & 3) * 32;    // 4 warps over M
    const int warp_n = (wid >> 2) * 64;   // 2 warps over N

    float acc[2][8][4];
#pragma unroll
    for (int mt = 0; mt < 2; mt++)
#pragma unroll
        for (int nt = 0; nt < 8; nt++)
#pragma unroll
            for (int j = 0; j < 4; j++) acc[mt][nt][j] = 0.f;

    // ---- slab loader: 32-wide K slab (64B rows), 3 tiles (A, Bh, Bl) ----
    auto load_slab = [&](int slab, int buf) {
        const uint32_t bufb = sb + buf * STAGE_BYTES;
        const int kbase = slab * 32;
#pragma unroll
        for (int it = 0; it < 2; it++) {
            int c  = tid + it * 256;                 // 0..511
            int r  = c >> 2;                         // row 0..127
            int ch = c & 3;                          // 16B chunk in 64B row
            uint32_t so = (uint32_t)r * 64 + (uint32_t)((ch ^ ((r >> 1) & 3)) * 16);
            int kc = kbase + ch * 8;
            int gr = row0 + r;
            int asz = (gr < M) ? 16 : 0;
            int gra = (gr < M) ? gr : 0;
            cpa16(bufb + SM_A + so, Ah + (size_t)gra * DD + kc, asz);
            int gb = col0 + r;                       // Nc mult of 128 -> valid
            cpa16(bufb + SM_BH + so, Bh + (size_t)gb * DD + kc, 16);
            cpa16(bufb + SM_BL + so, Bl + (size_t)gb * DD + kc, 16);
        }
        CP_COMMIT();
    };

    // ---- slab compute: 2 k-steps of 16 ----
    auto comp_slab = [&](int buf) {
        const uint32_t bufb = sb + buf * STAGE_BYTES;
#pragma unroll
        for (int ks = 0; ks < 2; ks++) {
            uint32_t af[2][4];
#pragma unroll
            for (int mt = 0; mt < 2; mt++) {
                int r  = warp_m + mt * 16 + (lane & 7) + ((lane >> 3) & 1) * 8;
                int ch = ks * 2 + (lane >> 4);
                uint32_t off = (uint32_t)r * 64
                             + (uint32_t)((ch ^ ((r >> 1) & 3)) * 16);
                ldx4(af[mt], bufb + SM_A + off);
            }
            uint32_t bhf[4][4], blf[4][4];
#pragma unroll
            for (int np = 0; np < 4; np++) {
                int r  = warp_n + np * 16 + (lane & 7) + ((lane >> 4) & 1) * 8;
                int ch = ks * 2 + ((lane >> 3) & 1);
                uint32_t off = (uint32_t)r * 64
                             + (uint32_t)((ch ^ ((r >> 1) & 3)) * 16);
                ldx4(bhf[np], bufb + SM_BH + off);
                ldx4(blf[np], bufb + SM_BL + off);
            }
#pragma unroll
            for (int mt = 0; mt < 2; mt++) {
#pragma unroll
                for (int nt = 0; nt < 8; nt++) {
                    int np = nt >> 1, hi = (nt & 1) * 2;
                    mma16816(acc[mt][nt], af[mt], bhf[np][hi], bhf[np][hi + 1]);
                    mma16816(acc[mt][nt], af[mt], blf[np][hi], blf[np][hi + 1]);
                }
            }
        }
    };

    // ---- 4 K-slabs through a 2-buffer ring ----
    load_slab(0, 0);
    load_slab(1, 1);
    CP_WAIT(1);
    __syncthreads();
    comp_slab(0);
    __syncthreads();
    load_slab(2, 0);
    CP_WAIT(1);
    __syncthreads();
    comp_slab(1);
    __syncthreads();
    load_slab(3, 1);
    CP_WAIT(1);
    __syncthreads();
    comp_slab(0);
    CP_WAIT(0);
    __syncthreads();
    comp_slab(1);

    // ---- epilogue ----
    const float* __restrict__ bias = ga.bias[z];
    float* __restrict__ C = ga.C[z];
    __half* __restrict__ Hout = ga.Hout[z];
#pragma unroll
    for (int mt = 0; mt < 2; mt++) {
        int gr0 = row0 + warp_m + mt * 16 + (lane >> 2);
#pragma unroll
        for (int nt = 0; nt < 8; nt++) {
            int gc = col0 + warp_n + nt * 8 + (lane & 3) * 2;
            float2 b2 = *reinterpret_cast<const float2*>(bias + gc);
#pragma unroll
            for (int half_i = 0; half_i < 2; half_i++) {
                int gr = gr0 + half_i * 8;
                if (gr >= M) continue;
                float vx = acc[mt][nt][half_i * 2 + 0] + b2.x;
                float vy = acc[mt][nt][half_i * 2 + 1] + b2.y;
                *reinterpret_cast<float2*>(C + (size_t)gr * ldc + gc) =
                    make_float2(vx, vy);
                if (Hout) {
                    *reinterpret_cast<__half2*>(Hout + (size_t)gr * DD + gc) =
                        __floats2half2_rn(vx, vy);
                }
            }
        }
    }
}

// ---------------------------------------------------------------------------
// Conversion / prep kernels
// ---------------------------------------------------------------------------
__global__ void split2_half_kernel(const float* __restrict__ x0,
                                   const float* __restrict__ x1,
                                   __half* __restrict__ h0,
                                   __half* __restrict__ h1)
{
    int i = blockIdx.x * blockDim.x + threadIdx.x;
    if (i >= 2 * NN * DD) return;
    if (i < NN * DD) h0[i] = __float2half(x0[i]);
    else             h1[i - NN * DD] = __float2half(x1[i - NN * DD]);
}

// One launch: fat W^T fp16 hi/lo splits + fat bias vectors + nw W^T split.
__global__ void prep_all_kernel(const float* __restrict__ gWl_b,
                                const float* __restrict__ gWr_b,
                                const float* __restrict__ gWl_r,
                                const float* __restrict__ gWr_r,
                                const float* __restrict__ cgL_Wf,
                                const float* __restrict__ cgL_Ws,
                                const float* __restrict__ cgR_Wf,
                                const float* __restrict__ cgR_Ws,
                                const float* __restrict__ cgL_bf,
                                const float* __restrict__ cgL_bs,
                                const float* __restrict__ cgR_bf,
                                const float* __restrict__ cgR_bs,
                                const float* __restrict__ nw_W,
                                __half* __restrict__ Wth_my,
                                __half* __restrict__ Wtl_my,
                                __half* __restrict__ Wth_opp,
                                __half* __restrict__ Wtl_opp,
                                __half* __restrict__ nwWh,
                                __half* __restrict__ nwWl,
                                float* __restrict__ bias_my,
                                float* __restrict__ bias_opp)
{
    int idx = blockIdx.x * blockDim.x + threadIdx.x;
    if (idx < LDC * DD) {
        int n = idx / DD, k = idx % DD;
        float wm, wo;
        if (n < 512) {
            wm = gWl_b[k * HD + n];               wo = gWr_b[k * HD + n];
        } else if (n < 1024) {
            int c = n - 512;
            wm = gWr_r[k * HD + c];               wo = gWl_r[k * HD + c];
        } else if (n < 1152) {
            int c = n - 1024;
            wm = cgL_Wf[(DD + k) * DD + c];       wo = cgL_Wf[k * DD + c];
        } else if (n < 1280) {
            int c = n - 1152;
            wm = cgL_Ws[(DD + k) * DD + c];       wo = cgL_Ws[k * DD + c];
        } else if (n < 1408) {
            int c = n - 1280;
            wm = cgR_Wf[k * DD + c];              wo = cgR_Wf[(DD + k) * DD + c];
        } else {
            int c = n - 1408;
            wm = cgR_Ws[k * DD + c];              wo = cgR_Ws[(DD + k) * DD + c];
        }
        __half hm = __float2half(wm);
        __half ho = __float2half(wo);
        Wth_my[idx]  = hm;
        Wtl_my[idx]  = __float2half(wm - __half2float(hm));
        Wth_opp[idx] = ho;
        Wtl_opp[idx] = __float2half(wo - __half2float(ho));
    }
    if (idx < DD * DD) {
        int n = idx / DD, k = idx % DD;
        float v = nw_W[k * DD + n];
        __half hb = __float2half(v);
        nwWh[idx] = hb;
        nwWl[idx] = __float2half(v - __half2float(hb));
    }
    if (idx < LDC) {
        int n = idx;
        float bm = 0.f, bo = 0.f;
        if (n >= 1024 && n < 1152) bo = cgL_bf[n - 1024];
        else if (n >= 1152 && n < 1280) bo = cgL_bs[n - 1152];
        if (n >= 1280 && n < 1408) bm = cgR_bf[n - 1280];
        else if (n >= 1408) bm = cgR_bs[n - 1408];
        bias_my[n] = bm;
        bias_opp[n] = bo;
    }
}

// ---------------------------------------------------------------------------
// CSR build (4 relations, built once per launch)
// ---------------------------------------------------------------------------
__global__ void csr_zero_kernel(int* __restrict__ cnt, int* __restrict__ fill)
{
    int i = blockIdx.x * blockDim.x + threadIdx.x;
    if (i < 4 * NN) { cnt[i] = 0; fill[i] = 0; }
}

__global__ void csr_hist_kernel(const int* __restrict__ d0,
                                const int* __restrict__ d1,
                                const int* __restrict__ d2,
                                const int* __restrict__ d3,
                                int* __restrict__ cnt)
{
    int i = blockIdx.x * blockDim.x + threadIdx.x;
    if (i >= EE) return;
    atomicAdd(&cnt[0 * NN + d0[i]], 1);
    atomicAdd(&cnt[1 * NN + d1[i]], 1);
    atomicAdd(&cnt[2 * NN + d2[i]], 1);
    atomicAdd(&cnt[3 * NN + d3[i]], 1);
}

__global__ void csr_scan_kernel(const int* __restrict__ cnt,
                                int* __restrict__ row)
{
    __shared__ int part[1024];
    const int rel = blockIdx.x;
    const int t = threadIdx.x;
    const int CH = (NN + 1023) / 1024;     // 20
    const int base = t * CH;
    int s = 0;
    for (int j = 0; j < CH; j++) {
        int i = base + j;
        if (i < NN) s += cnt[rel * NN + i];
    }
    part[t] = s;
    __syncthreads();
    for (int o = 1; o < 1024; o <<= 1) {
        int u = (t >= o) ? part[t - o] : 0;
        __syncthreads();
        part[t] += u;
        __syncthreads();
    }
    int run = part[t] - s;                 // exclusive prefix
    for (int j = 0; j < CH; j++) {
        int i = base + j;
        if (i < NN) {
            row[rel * (NN + 1) + i] = run;
            run += cnt[rel * NN + i];
        }
    }
    if (t == 1023) row[rel * (NN + 1) + NN] = part[1023];
}

__global__ void csr_scatter_kernel(const int* __restrict__ s0, const int* __restrict__ d0,
                                   const int* __restrict__ s1, const int* __restrict__ d1,
                                   const int* __restrict__ s2, const int* __restrict__ d2,
                                   const int* __restrict__ s3, const int* __restrict__ d3,
                                   const int* __restrict__ row,
                                   int* __restrict__ fill,
                                   int* __restrict__ srcs)
{
    int i = blockIdx.x * blockDim.x + threadIdx.x;
    if (i >= EE) return;
    {
        int d = d0[i];
        int pos = row[0 * (NN + 1) + d] + atomicAdd(&fill[0 * NN + d], 1);
        srcs[0 * EE + pos] = s0[i];
    }
    {
        int d = d1[i];
        int pos = row[1 * (NN + 1) + d] + atomicAdd(&fill[1 * NN + d], 1);
        srcs[1 * EE + pos] = s1[i];
    }
    {
        int d = d2[i];
        int pos = row[2 * (NN + 1) + d] + atomicAdd(&fill[2 * NN + d], 1);
        srcs[2 * EE + pos] = s2[i];
    }
    {
        int d = d3[i];
        int pos = row[3 * (NN + 1) + d] + atomicAdd(&fill[3 * NN + d], 1);
        srcs[3 * EE + pos] = s3[i];
    }
}

// ---------------------------------------------------------------------------
// Fused GATv2: warp per dst node, single feature pass; blockIdx.y = relation.
// Scores are O(10) bounded -> plain exp accumulation == softmax exactly.
// ---------------------------------------------------------------------------
__global__ void __launch_bounds__(256)
gat_fused_kernel(GatArgs a)
{
    const int rel = blockIdx.y;
    int d = blockIdx.x * 8 + (threadIdx.x >> 5);
    int lane = threadIdx.x & 31;
    if (d >= NN) return;

    const float* __restrict__ xl = a.xl[rel];
    const float* __restrict__ xr = a.xr[rel];
    const float* __restrict__ att = a.att[rel];
    const int* __restrict__ row = a.row[rel];
    const int* __restrict__ srcs = a.srcs[rel];

    float4 xr4[HH], at4[HH];
    const float4* pr = reinterpret_cast<const float4*>(xr + (size_t)d * LDC);
    const float4* pa = reinterpret_cast<const float4*>(att);
#pragma unroll
    for (int h = 0; h < HH; h++) {
        xr4[h] = pr[h * 32 + lane];
        at4[h] = pa[h * 32 + lane];
    }

    float s[HH];
    float4 a4[HH];
#pragma unroll
    for (int h = 0; h < HH; h++) {
        s[h] = 0.f;
        a4[h] = make_float4(0.f, 0.f, 0.f, 0.f);
    }

    const int e0 = row[d], e1 = row[d + 1];
#pragma unroll 2
    for (int p = e0; p < e1; p++) {
        int sn = srcs[p];
        const float4* pl = reinterpret_cast<const float4*>(xl + (size_t)sn * LDC);
        float4 l4[HH];
        float part[HH];
#pragma unroll
        for (int h = 0; h < HH; h++) {
            l4[h] = pl[h * 32 + lane];
            float zx = l4[h].x + xr4[h].x; zx = (zx > 0.f) ? zx : 0.2f * zx;
            float zy = l4[h].y + xr4[h].y; zy = (zy > 0.f) ? zy : 0.2f * zy;
            float zz = l4[h].z + xr4[h].z; zz = (zz > 0.f) ? zz : 0.2f * zz;
            float zw = l4[h].w + xr4[h].w; zw = (zw > 0.f) ? zw : 0.2f * zw;
            part[h] = zx * at4[h].x + zy * at4[h].y
                    + zz * at4[h].z + zw * at4[h].w;
        }
#pragma unroll
        for (int o = 16; o; o >>= 1)
#pragma unroll
            for (int h = 0; h < HH; h++)
                part[h] += __shfl_xor_sync(0xffffffffu, part[h], o);
#pragma unroll
        for (int h = 0; h < HH; h++) {
            float e = __expf(part[h]);
            s[h] += e;
            a4[h].x += e * l4[h].x;
            a4[h].y += e * l4[h].y;
            a4[h].z += e * l4[h].z;
            a4[h].w += e * l4[h].w;
        }
    }

    float4 r4 = reinterpret_cast<const float4*>(a.xres[rel] + (size_t)d * DD)[lane];
    float4 b4 = reinterpret_cast<const float4*>(a.bias[rel])[lane];
    float4 o4 = make_float4(r4.x + b4.x, r4.y + b4.y,
                            r4.z + b4.z, r4.w + b4.w);
#pragma unroll
    for (int h = 0; h < HH; h++) {
        float inv = 0.25f / (s[h] + 1e-16f);
        o4.x += a4[h].x * inv;
        o4.y += a4[h].y * inv;
        o4.z += a4[h].z * inv;
        o4.w += a4[h].w * inv;
    }
    reinterpret_cast<float4*>(a.acc[rel] + (size_t)d * DD)[lane] = o4;
}

// ---------------------------------------------------------------------------
// Fused CGConv: warp per dst node; fast-math gate; writes fp16 features.
// blockIdx.y = relation.
// ---------------------------------------------------------------------------
__device__ __forceinline__ float gate1(float f, float g)
{
    float sig = __fdividef(1.f, 1.f + __expf(-f));
    float sp  = fmaxf(g, 0.f) + __logf(1.f + __expf(-fabsf(g)));
    return sig * sp;
}

__global__ void __launch_bounds__(256)
cg_fused_kernel(CgArgs a)
{
    const int rel = blockIdx.y;
    int d = blockIdx.x * 8 + (threadIdx.x >> 5);
    int lane = threadIdx.x & 31;
    if (d >= NN) return;

    const float* __restrict__ Pfs = a.Pfs[rel];
    const float* __restrict__ Pss = a.Pss[rel];
    const int* __restrict__ row = a.row[rel];
    const int* __restrict__ srcs = a.srcs[rel];

    float4 fd4 = reinterpret_cast<const float4*>(a.Pfd[rel] + (size_t)d * LDC)[lane];
    float4 sd4 = reinterpret_cast<const float4*>(a.Psd[rel] + (size_t)d * LDC)[lane];
    float4 acc4 = reinterpret_cast<const float4*>(a.accin[rel] + (size_t)d * DD)[lane];

    const int e0 = row[d], e1 = row[d + 1];
#pragma unroll 2
    for (int p = e0; p < e1; p++) {
        int sn = srcs[p];
        float4 fs4 = reinterpret_cast<const float4*>(Pfs + (size_t)sn * LDC)[lane];
        float4 ss4 = reinterpret_cast<const float4*>(Pss + (size_t)sn * LDC)[lane];
        acc4.x += gate1(fd4.x + fs4.x, sd4.x + ss4.x);
        acc4.y += gate1(fd4.y + fs4.y, sd4.y + ss4.y);
        acc4.z += gate1(fd4.z + fs4.z, sd4.z + ss4.z);
        acc4.w += gate1(fd4.w + fs4.w, sd4.w + ss4.w);
    }

    size_t off = (size_t)d * DD + lane * 4;
    *reinterpret_cast<__half2*>(a.ah[rel] + off)     = __floats2half2_rn(acc4.x, acc4.y);
    *reinterpret_cast<__half2*>(a.ah[rel] + off + 2) = __floats2half2_rn(acc4.z, acc4.w);
}

// ---------------------------------------------------------------------------
// Host launcher
// ---------------------------------------------------------------------------
extern "C" void kernel_launch(void* const* d_in, const int* in_sizes, int n_in,
                              void* d_out, int out_size)
{
    const float* in_x_my  = (const float*)d_in[0];
    const float* in_x_opp = (const float*)d_in[1];
    const float* gWl_b = (const float*)d_in[2];
    const float* gWr_b = (const float*)d_in[3];
    const float* gatt_b = (const float*)d_in[4];
    const float* gb_b  = (const float*)d_in[5];
    const float* gWl_r = (const float*)d_in[6];
    const float* gWr_r = (const float*)d_in[7];
    const float* gatt_r = (const float*)d_in[8];
    const float* gb_r  = (const float*)d_in[9];
    const float* cgL_Wf = (const float*)d_in[10];
    const float* cgL_bf = (const float*)d_in[11];
    const float* cgL_Ws = (const float*)d_in[12];
    const float* cgL_bs = (const float*)d_in[13];
    const float* cgR_Wf = (const float*)d_in[14];
    const float* cgR_bf = (const float*)d_in[15];
    const float* cgR_Ws = (const float*)d_in[16];
    const float* cgR_bs = (const float*)d_in[17];
    const float* nw_W = (const float*)d_in[18];
    const float* nw_b = (const float*)d_in[19];
    const int* ei_beats     = (const int*)d_in[20];
    const int* ei_loses     = (const int*)d_in[21];
    const int* ei_rev_beats = (const int*)d_in[22];
    const int* ei_rev_loses = (const int*)d_in[23];

    float* out = (float*)d_out;

    float *C_my, *C_opp, *x_my, *x_opp, *acc_my, *acc_opp, *bias_my, *bias_opp;
    __half *xh_my, *xh_opp, *ah_my, *ah_opp;
    __half *Wth_my, *Wtl_my, *Wth_opp, *Wtl_opp, *nwWh, *nwWl;
    int *rowp, *cntp, *fillp, *srcsp;
    cudaGetSymbolAddress((void**)&C_my,  g_C_my);
    cudaGetSymbolAddress((void**)&C_opp, g_C_opp);
    cudaGetSymbolAddress((void**)&x_my,  g_x_my);
    cudaGetSymbolAddress((void**)&x_opp, g_x_opp);
    cudaGetSymbolAddress((void**)&acc_my, g_acc_my);
    cudaGetSymbolAddress((void**)&acc_opp, g_acc_opp);
    cudaGetSymbolAddress((void**)&bias_my,  g_bias_my);
    cudaGetSymbolAddress((void**)&bias_opp, g_bias_opp);
    cudaGetSymbolAddress((void**)&xh_my,  g_xh_my);
    cudaGetSymbolAddress((void**)&xh_opp, g_xh_opp);
    cudaGetSymbolAddress((void**)&ah_my,  g_ah_my);
    cudaGetSymbolAddress((void**)&ah_opp, g_ah_opp);
    cudaGetSymbolAddress((void**)&Wth_my,  g_Wth_my);
    cudaGetSymbolAddress((void**)&Wtl_my,  g_Wtl_my);
    cudaGetSymbolAddress((void**)&Wth_opp, g_Wth_opp);
    cudaGetSymbolAddress((void**)&Wtl_opp, g_Wtl_opp);
    cudaGetSymbolAddress((void**)&nwWh, g_nwWh);
    cudaGetSymbolAddress((void**)&nwWl, g_nwWl);
    cudaGetSymbolAddress((void**)&rowp,  g_row);
    cudaGetSymbolAddress((void**)&cntp,  g_cnt);
    cudaGetSymbolAddress((void**)&fillp, g_fill);
    cudaGetSymbolAddress((void**)&srcsp, g_srcs);

    cudaFuncSetAttribute(mma_gemm, cudaFuncAttributeMaxDynamicSharedMemorySize,
                         DYN_SMEM);

    const int* src_b  = ei_beats;      const int* dst_b  = ei_beats + EE;
    const int* src_l  = ei_loses;      const int* dst_l  = ei_loses + EE;
    const int* src_rb = ei_rev_beats;  const int* dst_rb = ei_rev_beats + EE;
    const int* src_rl = ei_rev_loses;  const int* dst_rl = ei_rev_loses + EE;

    const int node_blocks = (NN + 7) / 8;
    const int e_blocks    = (EE + 255) / 256;
    const int mtiles      = (NN + 127) / 128;      // 157

    // ---- CSR build (0=beats, 1=rev_loses, 2=loses, 3=rev_beats) ----
    csr_zero_kernel<<<(4 * NN + 255) / 256, 256>>>(cntp, fillp);
    csr_hist_kernel<<<e_blocks, 256>>>(dst_b, dst_rl, dst_l, dst_rb, cntp);
    csr_scan_kernel<<<4, 1024>>>(cntp, rowp);
    csr_scatter_kernel<<<e_blocks, 256>>>(src_b, dst_b, src_rl, dst_rl,
                                          src_l, dst_l, src_rb, dst_rb,
                                          rowp, fillp, srcsp);

    // ---- initial fp16 copies of inputs (one launch) ----
    split2_half_kernel<<<(2 * NN * DD + 255) / 256, 256>>>(
        in_x_my, in_x_opp, xh_my, xh_opp);

    const float* cur_my  = in_x_my;
    const float* cur_opp = in_x_opp;

    for (int l = 0; l < LLAYERS; l++) {
        const size_t oW = (size_t)l * DD * HD;
        const size_t oA = (size_t)l * HH * DD;
        const size_t oB = (size_t)l * DD;
        const size_t oC = (size_t)l * 2 * DD * DD;
        const size_t oN = (size_t)l * DD * DD;

        // ---- weight prep (one launch) ----
        prep_all_kernel<<<(LDC * DD + 255) / 256, 256>>>(
            gWl_b + oW, gWr_b + oW, gWl_r + oW, gWr_r + oW,
            cgL_Wf + oC, cgL_Ws + oC, cgR_Wf + oC, cgR_Ws + oC,
            cgL_bf + oB, cgL_bs + oB, cgR_bf + oB, cgR_bs + oB,
            nw_W + oN,
            Wth_my, Wtl_my, Wth_opp, Wtl_opp, nwWh, nwWl,
            bias_my, bias_opp);

        // ---- fat projection GEMMs (both node types, one launch) ----
        {
            GemmArgs ga;
            ga.Ah[0] = xh_my;   ga.Ah[1] = xh_opp;
            ga.Bh[0] = Wth_my;  ga.Bl[0] = Wtl_my;
            ga.Bh[1] = Wth_opp; ga.Bl[1] = Wtl_opp;
            ga.bias[0] = bias_my;  ga.bias[1] = bias_opp;
            ga.C[0] = C_my;     ga.C[1] = C_opp;
            ga.Hout[0] = nullptr; ga.Hout[1] = nullptr;
            ga.M = NN; ga.ldc = LDC;
            dim3 grid(LDC / 128, mtiles, 2);
            mma_gemm<<<grid, 256, DYN_SMEM>>>(ga);
        }

        // ---- fused GAT: both relations, one launch ----
        {
            GatArgs a;
            // rel 0: beats (my -> opp)
            a.xl[0] = C_my;        a.xr[0] = C_opp;
            a.att[0] = gatt_b + oA;
            a.row[0] = rowp + 0 * (NN + 1);  a.srcs[0] = srcsp + 0 * EE;
            a.xres[0] = cur_opp;   a.bias[0] = gb_b + oB;  a.acc[0] = acc_opp;
            // rel 1: rev_loses (opp -> my)
            a.xl[1] = C_opp + 512; a.xr[1] = C_my + 512;
            a.att[1] = gatt_r + oA;
            a.row[1] = rowp + 1 * (NN + 1);  a.srcs[1] = srcsp + 1 * EE;
            a.xres[1] = cur_my;    a.bias[1] = gb_r + oB;  a.acc[1] = acc_my;
            dim3 grid(node_blocks, 2);
            gat_fused_kernel<<<grid, 256>>>(a);
        }

        // ---- fused CGConv: both relations, one launch ----
        {
            CgArgs a;
            // rel 0: loses (my -> opp)
            a.Pfd[0] = C_opp + 1024; a.Pfs[0] = C_my + 1024;
            a.Psd[0] = C_opp + 1152; a.Pss[0] = C_my + 1152;
            a.row[0] = rowp + 2 * (NN + 1);  a.srcs[0] = srcsp + 2 * EE;
            a.accin[0] = acc_opp;  a.ah[0] = ah_opp;
            // rel 1: rev_beats (opp -> my)
            a.Pfd[1] = C_my + 1280; a.Pfs[1] = C_opp + 1280;
            a.Psd[1] = C_my + 1408; a.Pss[1] = C_opp + 1408;
            a.row[1] = rowp + 3 * (NN + 1);  a.srcs[1] = srcsp + 3 * EE;
            a.accin[1] = acc_my;   a.ah[1] = ah_my;
            dim3 grid(node_blocks, 2);
            cg_fused_kernel<<<grid, 256>>>(a);
        }

        // ---- nodewise Linear (both node types, one launch) ----
        {
            float* out_my  = (l == LLAYERS - 1) ? out           : x_my;
            float* out_opp = (l == LLAYERS - 1) ? out + NN * DD : x_opp;
            GemmArgs ga;
            ga.Ah[0] = ah_my;   ga.Ah[1] = ah_opp;
            ga.Bh[0] = nwWh;    ga.Bl[0] = nwWl;
            ga.Bh[1] = nwWh;    ga.Bl[1] = nwWl;
            ga.bias[0] = nw_b + oB;  ga.bias[1] = nw_b + oB;
            ga.C[0] = out_my;   ga.C[1] = out_opp;
            ga.Hout[0] = xh_my;  ga.Hout[1] = xh_opp;
            ga.M = NN; ga.ldc = DD;
            dim3 grid(1, mtiles, 2);
            mma_gemm<<<grid, 256, DYN_SMEM>>>(ga);
        }

        cur_my  = x_my;
        cur_opp = x_opp;
    }
}

// round 9
// speedup vs baseline: 3.9590x; 1.0607x over previous
#include <cuda_runtime.h>
#include <cuda_fp16.h>
#include <math.h>
#include <stdint.h>

// ---------------------------------------------------------------------------
// Problem constants
// ---------------------------------------------------------------------------
#define NN 20000
#define DD 128
#define HH 4
#define EE 80000
#define LLAYERS 2
#define HD (HH * DD)      // 512
#define LDC 1536          // fat projection width per node type

// Fat column layout (per node type X in {my, opp}):
//  [0,512)      GAT projection #1 (my: Wl_beats ; opp: Wr_beats)
//  [512,1024)   GAT projection #2 (my: Wr_rev   ; opp: Wl_rev)
//  [1024,1152)  CG lose Wf part   (my: src/bottom ; opp: dst/top + bf)
//  [1152,1280)  CG lose Ws part   (my: src/bottom ; opp: dst/top + bs)
//  [1280,1408)  CG rev  Wf part   (my: dst/top + bf ; opp: src/bottom)
//  [1408,1536)  CG rev  Ws part   (my: dst/top + bs ; opp: src/bottom)

// ---------------------------------------------------------------------------
// Static device scratch
// ---------------------------------------------------------------------------
__device__ __align__(16) __half g_C_my [(size_t)NN * LDC];   // fp16 fat features
__device__ __align__(16) __half g_C_opp[(size_t)NN * LDC];

__device__ __align__(16) float g_x_my [NN * DD];
__device__ __align__(16) float g_x_opp[NN * DD];
__device__ __align__(16) float g_acc_my [NN * DD];
__device__ __align__(16) float g_acc_opp[NN * DD];

// fp16 feature operands (A side of GEMMs)
__device__ __align__(16) __half g_xh_my [NN * DD];
__device__ __align__(16) __half g_xh_opp[NN * DD];
__device__ __align__(16) __half g_ah_my [NN * DD];
__device__ __align__(16) __half g_ah_opp[NN * DD];

// fp16 weight operands (B side), hi/lo split
__device__ __align__(16) __half g_Wth_my [LDC * DD];
__device__ __align__(16) __half g_Wtl_my [LDC * DD];
__device__ __align__(16) __half g_Wth_opp[LDC * DD];
__device__ __align__(16) __half g_Wtl_opp[LDC * DD];
__device__ __align__(16) __half g_nwWh[DD * DD];
__device__ __align__(16) __half g_nwWl[DD * DD];

__device__ __align__(16) float g_bias_my [LDC];
__device__ __align__(16) float g_bias_opp[LDC];

// CSR (4 relations: 0=beats, 1=rev_loses, 2=loses, 3=rev_beats), built once
__device__ int g_row [4 * (NN + 1)];
__device__ int g_cnt [4 * NN];
__device__ int g_fill[4 * NN];
__device__ int g_srcs[4 * EE];

// ---------------------------------------------------------------------------
// Arg structs for merged launches
// ---------------------------------------------------------------------------
struct GemmArgs {
    const __half *Ah[2], *Bh[2], *Bl[2];
    const float *bias[2];
    __half *Ch[2];     // fp16 C output (fat projections)
    float  *Cf[2];     // fp32 C output (nodewise Linear)
    __half *Hout[2];   // fp16 feature copy (next-layer A)
    int M, ldc;
};

struct GatArgs {
    const __half *xl[2], *xr[2];
    const float *att[2], *xres[2], *bias[2];
    const int *row[2], *srcs[2];
    float *acc[2];
};

struct CgArgs {
    const __half *Pfd[2], *Pfs[2], *Psd[2], *Pss[2];
    const float *accin[2];
    const int *row[2], *srcs[2];
    __half *ah[2];
};

// ---------------------------------------------------------------------------
// Warp MMA / cp.async helpers
// ---------------------------------------------------------------------------
__device__ __forceinline__ uint32_t smem_to_u32(const void* p)
{
    uint32_t a;
    asm("{ .reg .u64 t; cvta.to.shared.u64 t, %1; cvt.u32.u64 %0, t; }"
        : "=r"(a) : "l"(p));
    return a;
}

__device__ __forceinline__ void ldx4(uint32_t* r, uint32_t addr)
{
    asm volatile("ldmatrix.sync.aligned.m8n8.x4.shared.b16 {%0,%1,%2,%3}, [%4];"
                 : "=r"(r[0]), "=r"(r[1]), "=r"(r[2]), "=r"(r[3]) : "r"(addr));
}

__device__ __forceinline__ void mma16816(float* c, const uint32_t* a,
                                         uint32_t b0, uint32_t b1)
{
    asm volatile(
        "mma.sync.aligned.m16n8k16.row.col.f32.f16.f16.f32 "
        "{%0,%1,%2,%3}, {%4,%5,%6,%7}, {%8,%9}, {%0,%1,%2,%3};"
        : "+f"(c[0]), "+f"(c[1]), "+f"(c[2]), "+f"(c[3])
        : "r"(a[0]), "r"(a[1]), "r"(a[2]), "r"(a[3]), "r"(b0), "r"(b1));
}

__device__ __forceinline__ void cpa16(uint32_t dst, const void* src, int sz)
{
    asm volatile("cp.async.cg.shared.global [%0], [%1], 16, %2;"
                 :: "r"(dst), "l"(src), "r"(sz));
}
#define CP_COMMIT() asm volatile("cp.async.commit_group;" ::: "memory")
#define CP_WAIT(n)  asm volatile("cp.async.wait_group %0;" :: "n"(n) : "memory")

__device__ __forceinline__ float4 half4_to_float4(uint2 v)
{
    __half2 h01 = *reinterpret_cast<__half2*>(&v.x);
    __half2 h23 = *reinterpret_cast<__half2*>(&v.y);
    float2 f0 = __half22float2(h01);
    float2 f1 = __half22float2(h23);
    return make_float4(f0.x, f0.y, f1.x, f1.y);
}

// ---------------------------------------------------------------------------
// Tensor-core GEMM: C[M, col0..+128] = A[M,128] @ Bt[Nc,128]^T + bias.
// fp32 emulation: A single fp16, B split fp16 hi/lo, 2 MMAs (AhBh + AhBl).
// BK=32 slabs, 2-stage cp.async ring, 48 KB smem -> 2 CTAs/SM.
// grid.z = node type. 64B rows; swizzle ch ^= (r>>1)&3.
// ---------------------------------------------------------------------------
#define SM_A  0
#define SM_BH 8192
#define SM_BL 16384
#define STAGE_BYTES 24576
#define DYN_SMEM 49152

__global__ void __launch_bounds__(256, 2)
mma_gemm(GemmArgs ga)
{
    extern __shared__ char smem[];
    const uint32_t sb = smem_to_u32(smem);

    const int z = blockIdx.z;
    const __half* __restrict__ Ah = ga.Ah[z];
    const __half* __restrict__ Bh = ga.Bh[z];
    const __half* __restrict__ Bl = ga.Bl[z];
    const int M = ga.M, ldc = ga.ldc;

    const int tid  = threadIdx.x;
    const int wid  = tid >> 5;
    const int lane = tid & 31;
    const int row0 = blockIdx.y * 128;
    const int col0 = blockIdx.x * 128;

    const int warp_m = (wid & 3) * 32;    // 4 warps over M
    const int warp_n = (wid >> 2) * 64;   // 2 warps over N

    float acc[2][8][4];
#pragma unroll
    for (int mt = 0; mt < 2; mt++)
#pragma unroll
        for (int nt = 0; nt < 8; nt++)
#pragma unroll
            for (int j = 0; j < 4; j++) acc[mt][nt][j] = 0.f;

    // ---- slab loader: 32-wide K slab (64B rows), 3 tiles (A, Bh, Bl) ----
    auto load_slab = [&](int slab, int buf) {
        const uint32_t bufb = sb + buf * STAGE_BYTES;
        const int kbase = slab * 32;
#pragma unroll
        for (int it = 0; it < 2; it++) {
            int c  = tid + it * 256;                 // 0..511
            int r  = c >> 2;                         // row 0..127
            int ch = c & 3;                          // 16B chunk in 64B row
            uint32_t so = (uint32_t)r * 64 + (uint32_t)((ch ^ ((r >> 1) & 3)) * 16);
            int kc = kbase + ch * 8;
            int gr = row0 + r;
            int asz = (gr < M) ? 16 : 0;
            int gra = (gr < M) ? gr : 0;
            cpa16(bufb + SM_A + so, Ah + (size_t)gra * DD + kc, asz);
            int gb = col0 + r;                       // Nc mult of 128 -> valid
            cpa16(bufb + SM_BH + so, Bh + (size_t)gb * DD + kc, 16);
            cpa16(bufb + SM_BL + so, Bl + (size_t)gb * DD + kc, 16);
        }
        CP_COMMIT();
    };

    // ---- slab compute: 2 k-steps of 16 ----
    auto comp_slab = [&](int buf) {
        const uint32_t bufb = sb + buf * STAGE_BYTES;
#pragma unroll
        for (int ks = 0; ks < 2; ks++) {
            uint32_t af[2][4];
#pragma unroll
            for (int mt = 0; mt < 2; mt++) {
                int r  = warp_m + mt * 16 + (lane & 7) + ((lane >> 3) & 1) * 8;
                int ch = ks * 2 + (lane >> 4);
                uint32_t off = (uint32_t)r * 64
                             + (uint32_t)((ch ^ ((r >> 1) & 3)) * 16);
                ldx4(af[mt], bufb + SM_A + off);
            }
            uint32_t bhf[4][4], blf[4][4];
#pragma unroll
            for (int np = 0; np < 4; np++) {
                int r  = warp_n + np * 16 + (lane & 7) + ((lane >> 4) & 1) * 8;
                int ch = ks * 2 + ((lane >> 3) & 1);
                uint32_t off = (uint32_t)r * 64
                             + (uint32_t)((ch ^ ((r >> 1) & 3)) * 16);
                ldx4(bhf[np], bufb + SM_BH + off);
                ldx4(blf[np], bufb + SM_BL + off);
            }
#pragma unroll
            for (int mt = 0; mt < 2; mt++) {
#pragma unroll
                for (int nt = 0; nt < 8; nt++) {
                    int np = nt >> 1, hi = (nt & 1) * 2;
                    mma16816(acc[mt][nt], af[mt], bhf[np][hi], bhf[np][hi + 1]);
                    mma16816(acc[mt][nt], af[mt], blf[np][hi], blf[np][hi + 1]);
                }
            }
        }
    };

    // ---- 4 K-slabs through a 2-buffer ring ----
    load_slab(0, 0);
    load_slab(1, 1);
    CP_WAIT(1);
    __syncthreads();
    comp_slab(0);
    __syncthreads();
    load_slab(2, 0);
    CP_WAIT(1);
    __syncthreads();
    comp_slab(1);
    __syncthreads();
    load_slab(3, 1);
    CP_WAIT(1);
    __syncthreads();
    comp_slab(0);
    CP_WAIT(0);
    __syncthreads();
    comp_slab(1);

    // ---- epilogue ----
    const float* __restrict__ bias = ga.bias[z];
    __half* __restrict__ Ch = ga.Ch[z];
    float*  __restrict__ Cf = ga.Cf[z];
    __half* __restrict__ Hout = ga.Hout[z];
#pragma unroll
    for (int mt = 0; mt < 2; mt++) {
        int gr0 = row0 + warp_m + mt * 16 + (lane >> 2);
#pragma unroll
        for (int nt = 0; nt < 8; nt++) {
            int gc = col0 + warp_n + nt * 8 + (lane & 3) * 2;
            float2 b2 = *reinterpret_cast<const float2*>(bias + gc);
#pragma unroll
            for (int half_i = 0; half_i < 2; half_i++) {
                int gr = gr0 + half_i * 8;
                if (gr >= M) continue;
                float vx = acc[mt][nt][half_i * 2 + 0] + b2.x;
                float vy = acc[mt][nt][half_i * 2 + 1] + b2.y;
                if (Ch) {
                    *reinterpret_cast<__half2*>(Ch + (size_t)gr * ldc + gc) =
                        __floats2half2_rn(vx, vy);
                }
                if (Cf) {
                    *reinterpret_cast<float2*>(Cf + (size_t)gr * ldc + gc) =
                        make_float2(vx, vy);
                }
                if (Hout) {
                    *reinterpret_cast<__half2*>(Hout + (size_t)gr * DD + gc) =
                        __floats2half2_rn(vx, vy);
                }
            }
        }
    }
}

// ---------------------------------------------------------------------------
// Conversion / prep kernels
// ---------------------------------------------------------------------------
__global__ void split2_half_kernel(const float* __restrict__ x0,
                                   const float* __restrict__ x1,
                                   __half* __restrict__ h0,
                                   __half* __restrict__ h1)
{
    int i = blockIdx.x * blockDim.x + threadIdx.x;
    if (i >= 2 * NN * DD) return;
    if (i < NN * DD) h0[i] = __float2half(x0[i]);
    else             h1[i - NN * DD] = __float2half(x1[i - NN * DD]);
}

// One launch: fat W^T fp16 hi/lo splits + fat bias vectors + nw W^T split.
__global__ void prep_all_kernel(const float* __restrict__ gWl_b,
                                const float* __restrict__ gWr_b,
                                const float* __restrict__ gWl_r,
                                const float* __restrict__ gWr_r,
                                const float* __restrict__ cgL_Wf,
                                const float* __restrict__ cgL_Ws,
                                const float* __restrict__ cgR_Wf,
                                const float* __restrict__ cgR_Ws,
                                const float* __restrict__ cgL_bf,
                                const float* __restrict__ cgL_bs,
                                const float* __restrict__ cgR_bf,
                                const float* __restrict__ cgR_bs,
                                const float* __restrict__ nw_W,
                                __half* __restrict__ Wth_my,
                                __half* __restrict__ Wtl_my,
                                __half* __restrict__ Wth_opp,
                                __half* __restrict__ Wtl_opp,
                                __half* __restrict__ nwWh,
                                __half* __restrict__ nwWl,
                                float* __restrict__ bias_my,
                                float* __restrict__ bias_opp)
{
    int idx = blockIdx.x * blockDim.x + threadIdx.x;
    if (idx < LDC * DD) {
        int n = idx / DD, k = idx % DD;
        float wm, wo;
        if (n < 512) {
            wm = gWl_b[k * HD + n];               wo = gWr_b[k * HD + n];
        } else if (n < 1024) {
            int c = n - 512;
            wm = gWr_r[k * HD + c];               wo = gWl_r[k * HD + c];
        } else if (n < 1152) {
            int c = n - 1024;
            wm = cgL_Wf[(DD + k) * DD + c];       wo = cgL_Wf[k * DD + c];
        } else if (n < 1280) {
            int c = n - 1152;
            wm = cgL_Ws[(DD + k) * DD + c];       wo = cgL_Ws[k * DD + c];
        } else if (n < 1408) {
            int c = n - 1280;
            wm = cgR_Wf[k * DD + c];              wo = cgR_Wf[(DD + k) * DD + c];
        } else {
            int c = n - 1408;
            wm = cgR_Ws[k * DD + c];              wo = cgR_Ws[(DD + k) * DD + c];
        }
        __half hm = __float2half(wm);
        __half ho = __float2half(wo);
        Wth_my[idx]  = hm;
        Wtl_my[idx]  = __float2half(wm - __half2float(hm));
        Wth_opp[idx] = ho;
        Wtl_opp[idx] = __float2half(wo - __half2float(ho));
    }
    if (idx < DD * DD) {
        int n = idx / DD, k = idx % DD;
        float v = nw_W[k * DD + n];
        __half hb = __float2half(v);
        nwWh[idx] = hb;
        nwWl[idx] = __float2half(v - __half2float(hb));
    }
    if (idx < LDC) {
        int n = idx;
        float bm = 0.f, bo = 0.f;
        if (n >= 1024 && n < 1152) bo = cgL_bf[n - 1024];
        else if (n >= 1152 && n < 1280) bo = cgL_bs[n - 1152];
        if (n >= 1280 && n < 1408) bm = cgR_bf[n - 1280];
        else if (n >= 1408) bm = cgR_bs[n - 1408];
        bias_my[n] = bm;
        bias_opp[n] = bo;
    }
}

// ---------------------------------------------------------------------------
// CSR build (4 relations, built once per launch)
// ---------------------------------------------------------------------------
__global__ void csr_zero_kernel(int* __restrict__ cnt, int* __restrict__ fill)
{
    int i = blockIdx.x * blockDim.x + threadIdx.x;
    if (i < 4 * NN) { cnt[i] = 0; fill[i] = 0; }
}

__global__ void csr_hist_kernel(const int* __restrict__ d0,
                                const int* __restrict__ d1,
                                const int* __restrict__ d2,
                                const int* __restrict__ d3,
                                int* __restrict__ cnt)
{
    int i = blockIdx.x * blockDim.x + threadIdx.x;
    if (i >= EE) return;
    atomicAdd(&cnt[0 * NN + d0[i]], 1);
    atomicAdd(&cnt[1 * NN + d1[i]], 1);
    atomicAdd(&cnt[2 * NN + d2[i]], 1);
    atomicAdd(&cnt[3 * NN + d3[i]], 1);
}

__global__ void csr_scan_kernel(const int* __restrict__ cnt,
                                int* __restrict__ row)
{
    __shared__ int part[1024];
    const int rel = blockIdx.x;
    const int t = threadIdx.x;
    const int CH = (NN + 1023) / 1024;     // 20
    const int base = t * CH;
    int s = 0;
    for (int j = 0; j < CH; j++) {
        int i = base + j;
        if (i < NN) s += cnt[rel * NN + i];
    }
    part[t] = s;
    __syncthreads();
    for (int o = 1; o < 1024; o <<= 1) {
        int u = (t >= o) ? part[t - o] : 0;
        __syncthreads();
        part[t] += u;
        __syncthreads();
    }
    int run = part[t] - s;                 // exclusive prefix
    for (int j = 0; j < CH; j++) {
        int i = base + j;
        if (i < NN) {
            row[rel * (NN + 1) + i] = run;
            run += cnt[rel * NN + i];
        }
    }
    if (t == 1023) row[rel * (NN + 1) + NN] = part[1023];
}

__global__ void csr_scatter_kernel(const int* __restrict__ s0, const int* __restrict__ d0,
                                   const int* __restrict__ s1, const int* __restrict__ d1,
                                   const int* __restrict__ s2, const int* __restrict__ d2,
                                   const int* __restrict__ s3, const int* __restrict__ d3,
                                   const int* __restrict__ row,
                                   int* __restrict__ fill,
                                   int* __restrict__ srcs)
{
    int i = blockIdx.x * blockDim.x + threadIdx.x;
    if (i >= EE) return;
    {
        int d = d0[i];
        int pos = row[0 * (NN + 1) + d] + atomicAdd(&fill[0 * NN + d], 1);
        srcs[0 * EE + pos] = s0[i];
    }
    {
        int d = d1[i];
        int pos = row[1 * (NN + 1) + d] + atomicAdd(&fill[1 * NN + d], 1);
        srcs[1 * EE + pos] = s1[i];
    }
    {
        int d = d2[i];
        int pos = row[2 * (NN + 1) + d] + atomicAdd(&fill[2 * NN + d], 1);
        srcs[2 * EE + pos] = s2[i];
    }
    {
        int d = d3[i];
        int pos = row[3 * (NN + 1) + d] + atomicAdd(&fill[3 * NN + d], 1);
        srcs[3 * EE + pos] = s3[i];
    }
}

// ---------------------------------------------------------------------------
// Fused GATv2: warp per dst node, single feature pass; blockIdx.y = relation.
// Features in fp16 (half4 loads), math in fp32.
// ---------------------------------------------------------------------------
__global__ void __launch_bounds__(256)
gat_fused_kernel(GatArgs a)
{
    const int rel = blockIdx.y;
    int d = blockIdx.x * 8 + (threadIdx.x >> 5);
    int lane = threadIdx.x & 31;
    if (d >= NN) return;

    const __half* __restrict__ xl = a.xl[rel];
    const __half* __restrict__ xr = a.xr[rel];
    const float* __restrict__ att = a.att[rel];
    const int* __restrict__ row = a.row[rel];
    const int* __restrict__ srcs = a.srcs[rel];

    float4 xr4[HH], at4[HH];
    const uint2* pr = reinterpret_cast<const uint2*>(xr + (size_t)d * LDC);
    const float4* pa = reinterpret_cast<const float4*>(att);
#pragma unroll
    for (int h = 0; h < HH; h++) {
        xr4[h] = half4_to_float4(pr[h * 32 + lane]);
        at4[h] = pa[h * 32 + lane];
    }

    float s[HH];
    float4 a4[HH];
#pragma unroll
    for (int h = 0; h < HH; h++) {
        s[h] = 0.f;
        a4[h] = make_float4(0.f, 0.f, 0.f, 0.f);
    }

    const int e0 = row[d], e1 = row[d + 1];
#pragma unroll 2
    for (int p = e0; p < e1; p++) {
        int sn = srcs[p];
        const uint2* pl = reinterpret_cast<const uint2*>(xl + (size_t)sn * LDC);
        float4 l4[HH];
        float part[HH];
#pragma unroll
        for (int h = 0; h < HH; h++) {
            l4[h] = half4_to_float4(pl[h * 32 + lane]);
            float zx = l4[h].x + xr4[h].x; zx = (zx > 0.f) ? zx : 0.2f * zx;
            float zy = l4[h].y + xr4[h].y; zy = (zy > 0.f) ? zy : 0.2f * zy;
            float zz = l4[h].z + xr4[h].z; zz = (zz > 0.f) ? zz : 0.2f * zz;
            float zw = l4[h].w + xr4[h].w; zw = (zw > 0.f) ? zw : 0.2f * zw;
            part[h] = zx * at4[h].x + zy * at4[h].y
                    + zz * at4[h].z + zw * at4[h].w;
        }
#pragma unroll
        for (int o = 16; o; o >>= 1)
#pragma unroll
            for (int h = 0; h < HH; h++)
                part[h] += __shfl_xor_sync(0xffffffffu, part[h], o);
#pragma unroll
        for (int h = 0; h < HH; h++) {
            float e = __expf(part[h]);
            s[h] += e;
            a4[h].x += e * l4[h].x;
            a4[h].y += e * l4[h].y;
            a4[h].z += e * l4[h].z;
            a4[h].w += e * l4[h].w;
        }
    }

    float4 r4 = reinterpret_cast<const float4*>(a.xres[rel] + (size_t)d * DD)[lane];
    float4 b4 = reinterpret_cast<const float4*>(a.bias[rel])[lane];
    float4 o4 = make_float4(r4.x + b4.x, r4.y + b4.y,
                            r4.z + b4.z, r4.w + b4.w);
#pragma unroll
    for (int h = 0; h < HH; h++) {
        float inv = 0.25f / (s[h] + 1e-16f);
        o4.x += a4[h].x * inv;
        o4.y += a4[h].y * inv;
        o4.z += a4[h].z * inv;
        o4.w += a4[h].w * inv;
    }
    reinterpret_cast<float4*>(a.acc[rel] + (size_t)d * DD)[lane] = o4;
}

// ---------------------------------------------------------------------------
// Fused CGConv: warp per dst node; fp16 gathers; fast-math gate; fp16 out.
// blockIdx.y = relation.
// ---------------------------------------------------------------------------
__device__ __forceinline__ float gate1(float f, float g)
{
    float sig = __fdividef(1.f, 1.f + __expf(-f));
    float sp  = fmaxf(g, 0.f) + __logf(1.f + __expf(-fabsf(g)));
    return sig * sp;
}

__global__ void __launch_bounds__(256)
cg_fused_kernel(CgArgs a)
{
    const int rel = blockIdx.y;
    int d = blockIdx.x * 8 + (threadIdx.x >> 5);
    int lane = threadIdx.x & 31;
    if (d >= NN) return;

    const __half* __restrict__ Pfs = a.Pfs[rel];
    const __half* __restrict__ Pss = a.Pss[rel];
    const int* __restrict__ row = a.row[rel];
    const int* __restrict__ srcs = a.srcs[rel];

    float4 fd4 = half4_to_float4(
        reinterpret_cast<const uint2*>(a.Pfd[rel] + (size_t)d * LDC)[lane]);
    float4 sd4 = half4_to_float4(
        reinterpret_cast<const uint2*>(a.Psd[rel] + (size_t)d * LDC)[lane]);
    float4 acc4 = reinterpret_cast<const float4*>(a.accin[rel] + (size_t)d * DD)[lane];

    const int e0 = row[d], e1 = row[d + 1];
#pragma unroll 2
    for (int p = e0; p < e1; p++) {
        int sn = srcs[p];
        float4 fs4 = half4_to_float4(
            reinterpret_cast<const uint2*>(Pfs + (size_t)sn * LDC)[lane]);
        float4 ss4 = half4_to_float4(
            reinterpret_cast<const uint2*>(Pss + (size_t)sn * LDC)[lane]);
        acc4.x += gate1(fd4.x + fs4.x, sd4.x + ss4.x);
        acc4.y += gate1(fd4.y + fs4.y, sd4.y + ss4.y);
        acc4.z += gate1(fd4.z + fs4.z, sd4.z + ss4.z);
        acc4.w += gate1(fd4.w + fs4.w, sd4.w + ss4.w);
    }

    size_t off = (size_t)d * DD + lane * 4;
    *reinterpret_cast<__half2*>(a.ah[rel] + off)     = __floats2half2_rn(acc4.x, acc4.y);
    *reinterpret_cast<__half2*>(a.ah[rel] + off + 2) = __floats2half2_rn(acc4.z, acc4.w);
}

// ---------------------------------------------------------------------------
// Host launcher
// ---------------------------------------------------------------------------
extern "C" void kernel_launch(void* const* d_in, const int* in_sizes, int n_in,
                              void* d_out, int out_size)
{
    const float* in_x_my  = (const float*)d_in[0];
    const float* in_x_opp = (const float*)d_in[1];
    const float* gWl_b = (const float*)d_in[2];
    const float* gWr_b = (const float*)d_in[3];
    const float* gatt_b = (const float*)d_in[4];
    const float* gb_b  = (const float*)d_in[5];
    const float* gWl_r = (const float*)d_in[6];
    const float* gWr_r = (const float*)d_in[7];
    const float* gatt_r = (const float*)d_in[8];
    const float* gb_r  = (const float*)d_in[9];
    const float* cgL_Wf = (const float*)d_in[10];
    const float* cgL_bf = (const float*)d_in[11];
    const float* cgL_Ws = (const float*)d_in[12];
    const float* cgL_bs = (const float*)d_in[13];
    const float* cgR_Wf = (const float*)d_in[14];
    const float* cgR_bf = (const float*)d_in[15];
    const float* cgR_Ws = (const float*)d_in[16];
    const float* cgR_bs = (const float*)d_in[17];
    const float* nw_W = (const float*)d_in[18];
    const float* nw_b = (const float*)d_in[19];
    const int* ei_beats     = (const int*)d_in[20];
    const int* ei_loses     = (const int*)d_in[21];
    const int* ei_rev_beats = (const int*)d_in[22];
    const int* ei_rev_loses = (const int*)d_in[23];

    float* out = (float*)d_out;

    float *x_my, *x_opp, *acc_my, *acc_opp, *bias_my, *bias_opp;
    __half *C_my, *C_opp;
    __half *xh_my, *xh_opp, *ah_my, *ah_opp;
    __half *Wth_my, *Wtl_my, *Wth_opp, *Wtl_opp, *nwWh, *nwWl;
    int *rowp, *cntp, *fillp, *srcsp;
    cudaGetSymbolAddress((void**)&C_my,  g_C_my);
    cudaGetSymbolAddress((void**)&C_opp, g_C_opp);
    cudaGetSymbolAddress((void**)&x_my,  g_x_my);
    cudaGetSymbolAddress((void**)&x_opp, g_x_opp);
    cudaGetSymbolAddress((void**)&acc_my, g_acc_my);
    cudaGetSymbolAddress((void**)&acc_opp, g_acc_opp);
    cudaGetSymbolAddress((void**)&bias_my,  g_bias_my);
    cudaGetSymbolAddress((void**)&bias_opp, g_bias_opp);
    cudaGetSymbolAddress((void**)&xh_my,  g_xh_my);
    cudaGetSymbolAddress((void**)&xh_opp, g_xh_opp);
    cudaGetSymbolAddress((void**)&ah_my,  g_ah_my);
    cudaGetSymbolAddress((void**)&ah_opp, g_ah_opp);
    cudaGetSymbolAddress((void**)&Wth_my,  g_Wth_my);
    cudaGetSymbolAddress((void**)&Wtl_my,  g_Wtl_my);
    cudaGetSymbolAddress((void**)&Wth_opp, g_Wth_opp);
    cudaGetSymbolAddress((void**)&Wtl_opp, g_Wtl_opp);
    cudaGetSymbolAddress((void**)&nwWh, g_nwWh);
    cudaGetSymbolAddress((void**)&nwWl, g_nwWl);
    cudaGetSymbolAddress((void**)&rowp,  g_row);
    cudaGetSymbolAddress((void**)&cntp,  g_cnt);
    cudaGetSymbolAddress((void**)&fillp, g_fill);
    cudaGetSymbolAddress((void**)&srcsp, g_srcs);

    cudaFuncSetAttribute(mma_gemm, cudaFuncAttributeMaxDynamicSharedMemorySize,
                         DYN_SMEM);

    const int* src_b  = ei_beats;      const int* dst_b  = ei_beats + EE;
    const int* src_l  = ei_loses;      const int* dst_l  = ei_loses + EE;
    const int* src_rb = ei_rev_beats;  const int* dst_rb = ei_rev_beats + EE;
    const int* src_rl = ei_rev_loses;  const int* dst_rl = ei_rev_loses + EE;

    const int node_blocks = (NN + 7) / 8;
    const int e_blocks    = (EE + 255) / 256;
    const int mtiles      = (NN + 127) / 128;      // 157

    // Launch order note: fat mma_gemm placed at slot 4 so ncu (-s skips) samples it.
    // 1: input fp16 copies
    split2_half_kernel<<<(2 * NN * DD + 255) / 256, 256>>>(
        in_x_my, in_x_opp, xh_my, xh_opp);
    // 2: layer-0 weight prep
    prep_all_kernel<<<(LDC * DD + 255) / 256, 256>>>(
        gWl_b, gWr_b, gWl_r, gWr_r,
        cgL_Wf, cgL_Ws, cgR_Wf, cgR_Ws,
        cgL_bf, cgL_bs, cgR_bf, cgR_bs,
        nw_W,
        Wth_my, Wtl_my, Wth_opp, Wtl_opp, nwWh, nwWl,
        bias_my, bias_opp);
    // 3: CSR zero
    csr_zero_kernel<<<(4 * NN + 255) / 256, 256>>>(cntp, fillp);
    // 4: layer-0 fat projection GEMM (the launch ncu samples)
    {
        GemmArgs ga;
        ga.Ah[0] = xh_my;   ga.Ah[1] = xh_opp;
        ga.Bh[0] = Wth_my;  ga.Bl[0] = Wtl_my;
        ga.Bh[1] = Wth_opp; ga.Bl[1] = Wtl_opp;
        ga.bias[0] = bias_my;  ga.bias[1] = bias_opp;
        ga.Ch[0] = C_my;    ga.Ch[1] = C_opp;
        ga.Cf[0] = nullptr; ga.Cf[1] = nullptr;
        ga.Hout[0] = nullptr; ga.Hout[1] = nullptr;
        ga.M = NN; ga.ldc = LDC;
        dim3 grid(LDC / 128, mtiles, 2);
        mma_gemm<<<grid, 256, DYN_SMEM>>>(ga);
    }
    // 5-7: CSR hist/scan/scatter (0=beats, 1=rev_loses, 2=loses, 3=rev_beats)
    csr_hist_kernel<<<e_blocks, 256>>>(dst_b, dst_rl, dst_l, dst_rb, cntp);
    csr_scan_kernel<<<4, 1024>>>(cntp, rowp);
    csr_scatter_kernel<<<e_blocks, 256>>>(src_b, dst_b, src_rl, dst_rl,
                                          src_l, dst_l, src_rb, dst_rb,
                                          rowp, fillp, srcsp);

    const float* cur_my  = in_x_my;
    const float* cur_opp = in_x_opp;

    for (int l = 0; l < LLAYERS; l++) {
        const size_t oW = (size_t)l * DD * HD;
        const size_t oA = (size_t)l * HH * DD;
        const size_t oB = (size_t)l * DD;
        const size_t oC = (size_t)l * 2 * DD * DD;
        const size_t oN = (size_t)l * DD * DD;

        if (l > 0) {
            // weight prep + fat GEMM for later layers
            prep_all_kernel<<<(LDC * DD + 255) / 256, 256>>>(
                gWl_b + oW, gWr_b + oW, gWl_r + oW, gWr_r + oW,
                cgL_Wf + oC, cgL_Ws + oC, cgR_Wf + oC, cgR_Ws + oC,
                cgL_bf + oB, cgL_bs + oB, cgR_bf + oB, cgR_bs + oB,
                nw_W + oN,
                Wth_my, Wtl_my, Wth_opp, Wtl_opp, nwWh, nwWl,
                bias_my, bias_opp);
            GemmArgs ga;
            ga.Ah[0] = xh_my;   ga.Ah[1] = xh_opp;
            ga.Bh[0] = Wth_my;  ga.Bl[0] = Wtl_my;
            ga.Bh[1] = Wth_opp; ga.Bl[1] = Wtl_opp;
            ga.bias[0] = bias_my;  ga.bias[1] = bias_opp;
            ga.Ch[0] = C_my;    ga.Ch[1] = C_opp;
            ga.Cf[0] = nullptr; ga.Cf[1] = nullptr;
            ga.Hout[0] = nullptr; ga.Hout[1] = nullptr;
            ga.M = NN; ga.ldc = LDC;
            dim3 grid(LDC / 128, mtiles, 2);
            mma_gemm<<<grid, 256, DYN_SMEM>>>(ga);
        }

        // ---- fused GAT: both relations, one launch ----
        {
            GatArgs a;
            // rel 0: beats (my -> opp)
            a.xl[0] = C_my;        a.xr[0] = C_opp;
            a.att[0] = gatt_b + oA;
            a.row[0] = rowp + 0 * (NN + 1);  a.srcs[0] = srcsp + 0 * EE;
            a.xres[0] = cur_opp;   a.bias[0] = gb_b + oB;  a.acc[0] = acc_opp;
            // rel 1: rev_loses (opp -> my)
            a.xl[1] = C_opp + 512; a.xr[1] = C_my + 512;
            a.att[1] = gatt_r + oA;
            a.row[1] = rowp + 1 * (NN + 1);  a.srcs[1] = srcsp + 1 * EE;
            a.xres[1] = cur_my;    a.bias[1] = gb_r + oB;  a.acc[1] = acc_my;
            dim3 grid(node_blocks, 2);
            gat_fused_kernel<<<grid, 256>>>(a);
        }

        // ---- fused CGConv: both relations, one launch ----
        {
            CgArgs a;
            // rel 0: loses (my -> opp)
            a.Pfd[0] = C_opp + 1024; a.Pfs[0] = C_my + 1024;
            a.Psd[0] = C_opp + 1152; a.Pss[0] = C_my + 1152;
            a.row[0] = rowp + 2 * (NN + 1);  a.srcs[0] = srcsp + 2 * EE;
            a.accin[0] = acc_opp;  a.ah[0] = ah_opp;
            // rel 1: rev_beats (opp -> my)
            a.Pfd[1] = C_my + 1280; a.Pfs[1] = C_opp + 1280;
            a.Psd[1] = C_my + 1408; a.Pss[1] = C_opp + 1408;
            a.row[1] = rowp + 3 * (NN + 1);  a.srcs[1] = srcsp + 3 * EE;
            a.accin[1] = acc_my;   a.ah[1] = ah_my;
            dim3 grid(node_blocks, 2);
            cg_fused_kernel<<<grid, 256>>>(a);
        }

        // ---- nodewise Linear (both node types, one launch; fp32 out) ----
        {
            float* out_my  = (l == LLAYERS - 1) ? out           : x_my;
            float* out_opp = (l == LLAYERS - 1) ? out + NN * DD : x_opp;
            GemmArgs ga;
            ga.Ah[0] = ah_my;   ga.Ah[1] = ah_opp;
            ga.Bh[0] = nwWh;    ga.Bl[0] = nwWl;
            ga.Bh[1] = nwWh;    ga.Bl[1] = nwWl;
            ga.bias[0] = nw_b + oB;  ga.bias[1] = nw_b + oB;
            ga.Ch[0] = nullptr; ga.Ch[1] = nullptr;
            ga.Cf[0] = out_my;  ga.Cf[1] = out_opp;
            ga.Hout[0] = xh_my;  ga.Hout[1] = xh_opp;
            ga.M = NN; ga.ldc = DD;
            dim3 grid(1, mtiles, 2);
            mma_gemm<<<grid, 256, DYN_SMEM>>>(ga);
        }

        cur_my  = x_my;
        cur_opp = x_opp;
    }
}

// round 10
// speedup vs baseline: 4.2558x; 1.0750x over previous
#include <cuda_runtime.h>
#include <cuda_fp16.h>
#include <math.h>
#include <stdint.h>

// ---------------------------------------------------------------------------
// Problem constants
// ---------------------------------------------------------------------------
#define NN 20000
#define DD 128
#define HH 4
#define EE 80000
#define LLAYERS 2
#define HD (HH * DD)      // 512
#define LDC 1536          // fat projection width per node type

// Fat column layout (per node type X in {my, opp}):
//  [0,512)      GAT projection #1 (my: Wl_beats ; opp: Wr_beats)
//  [512,1024)   GAT projection #2 (my: Wr_rev   ; opp: Wl_rev)
//  [1024,1152)  CG lose Wf part   (my: src/bottom ; opp: dst/top + bf)
//  [1152,1280)  CG lose Ws part   (my: src/bottom ; opp: dst/top + bs)
//  [1280,1408)  CG rev  Wf part   (my: dst/top + bf ; opp: src/bottom)
//  [1408,1536)  CG rev  Ws part   (my: dst/top + bs ; opp: src/bottom)

// ---------------------------------------------------------------------------
// Static device scratch
// ---------------------------------------------------------------------------
__device__ __align__(16) __half g_C_my [(size_t)NN * LDC];   // fp16 fat features
__device__ __align__(16) __half g_C_opp[(size_t)NN * LDC];

__device__ __align__(16) float g_x_my [NN * DD];
__device__ __align__(16) float g_x_opp[NN * DD];
__device__ __align__(16) float g_acc_my [NN * DD];
__device__ __align__(16) float g_acc_opp[NN * DD];

// fp16 feature operands (A side of GEMMs)
__device__ __align__(16) __half g_xh_my [NN * DD];
__device__ __align__(16) __half g_xh_opp[NN * DD];
__device__ __align__(16) __half g_ah_my [NN * DD];
__device__ __align__(16) __half g_ah_opp[NN * DD];

// fp16 weight operands (B side), single fp16
__device__ __align__(16) __half g_Wth_my [LDC * DD];
__device__ __align__(16) __half g_Wth_opp[LDC * DD];
__device__ __align__(16) __half g_nwWh[DD * DD];

__device__ __align__(16) float g_bias_my [LDC];
__device__ __align__(16) float g_bias_opp[LDC];

// CSR (4 relations: 0=beats, 1=rev_loses, 2=loses, 3=rev_beats), built once
__device__ int g_row [4 * (NN + 1)];
__device__ int g_cnt [4 * NN];
__device__ int g_fill[4 * NN];
__device__ int g_srcs[4 * EE];

// ---------------------------------------------------------------------------
// Arg structs for merged launches
// ---------------------------------------------------------------------------
struct GemmArgs {
    const __half *Ah[2], *Bh[2];
    const float *bias[2];
    __half *Ch[2];     // fp16 C output (fat projections)
    float  *Cf[2];     // fp32 C output (nodewise Linear)
    __half *Hout[2];   // fp16 feature copy (next-layer A)
    int M, ldc;
};

struct GatArgs {
    const __half *xl[2], *xr[2];
    const float *att[2], *xres[2], *bias[2];
    const int *row[2], *srcs[2];
    float *acc[2];
};

struct CgArgs {
    const __half *Pfd[2], *Pfs[2], *Psd[2], *Pss[2];
    const float *accin[2];
    const int *row[2], *srcs[2];
    __half *ah[2];
};

// ---------------------------------------------------------------------------
// Warp MMA / cp.async helpers
// ---------------------------------------------------------------------------
__device__ __forceinline__ uint32_t smem_to_u32(const void* p)
{
    uint32_t a;
    asm("{ .reg .u64 t; cvta.to.shared.u64 t, %1; cvt.u32.u64 %0, t; }"
        : "=r"(a) : "l"(p));
    return a;
}

__device__ __forceinline__ void ldx4(uint32_t* r, uint32_t addr)
{
    asm volatile("ldmatrix.sync.aligned.m8n8.x4.shared.b16 {%0,%1,%2,%3}, [%4];"
                 : "=r"(r[0]), "=r"(r[1]), "=r"(r[2]), "=r"(r[3]) : "r"(addr));
}

__device__ __forceinline__ void mma16816(float* c, const uint32_t* a,
                                         uint32_t b0, uint32_t b1)
{
    asm volatile(
        "mma.sync.aligned.m16n8k16.row.col.f32.f16.f16.f32 "
        "{%0,%1,%2,%3}, {%4,%5,%6,%7}, {%8,%9}, {%0,%1,%2,%3};"
        : "+f"(c[0]), "+f"(c[1]), "+f"(c[2]), "+f"(c[3])
        : "r"(a[0]), "r"(a[1]), "r"(a[2]), "r"(a[3]), "r"(b0), "r"(b1));
}

__device__ __forceinline__ void cpa16(uint32_t dst, const void* src, int sz)
{
    asm volatile("cp.async.cg.shared.global [%0], [%1], 16, %2;"
                 :: "r"(dst), "l"(src), "r"(sz));
}
#define CP_COMMIT() asm volatile("cp.async.commit_group;" ::: "memory")
#define CP_WAIT(n)  asm volatile("cp.async.wait_group %0;" :: "n"(n) : "memory")

__device__ __forceinline__ float4 half4_to_float4(uint2 v)
{
    __half2 h01 = *reinterpret_cast<__half2*>(&v.x);
    __half2 h23 = *reinterpret_cast<__half2*>(&v.y);
    float2 f0 = __half22float2(h01);
    float2 f1 = __half22float2(h23);
    return make_float4(f0.x, f0.y, f1.x, f1.y);
}

// ---------------------------------------------------------------------------
// Tensor-core GEMM: C[M, col0..+128] = A[M,128] @ Bt[Nc,128]^T + bias.
// fp16 x fp16 -> fp32 accum, single MMA per k-step tile.
// BK=32 slabs, 2-stage cp.async ring, 32 KB smem.
// grid.z = node type. 64B rows; swizzle ch ^= (r>>1)&3.
// ---------------------------------------------------------------------------
#define SM_A  0
#define SM_B  8192
#define STAGE_BYTES 16384
#define DYN_SMEM 32768

__global__ void __launch_bounds__(256, 2)
mma_gemm(GemmArgs ga)
{
    extern __shared__ char smem[];
    const uint32_t sb = smem_to_u32(smem);

    const int z = blockIdx.z;
    const __half* __restrict__ Ah = ga.Ah[z];
    const __half* __restrict__ Bh = ga.Bh[z];
    const int M = ga.M, ldc = ga.ldc;

    const int tid  = threadIdx.x;
    const int wid  = tid >> 5;
    const int lane = tid & 31;
    const int row0 = blockIdx.y * 128;
    const int col0 = blockIdx.x * 128;

    const int warp_m = (wid & 3) * 32;    // 4 warps over M
    const int warp_n = (wid >> 2) * 64;   // 2 warps over N

    float acc[2][8][4];
#pragma unroll
    for (int mt = 0; mt < 2; mt++)
#pragma unroll
        for (int nt = 0; nt < 8; nt++)
#pragma unroll
            for (int j = 0; j < 4; j++) acc[mt][nt][j] = 0.f;

    // ---- slab loader: 32-wide K slab (64B rows), 2 tiles (A, B) ----
    auto load_slab = [&](int slab, int buf) {
        const uint32_t bufb = sb + buf * STAGE_BYTES;
        const int kbase = slab * 32;
#pragma unroll
        for (int it = 0; it < 2; it++) {
            int c  = tid + it * 256;                 // 0..511
            int r  = c >> 2;                         // row 0..127
            int ch = c & 3;                          // 16B chunk in 64B row
            uint32_t so = (uint32_t)r * 64 + (uint32_t)((ch ^ ((r >> 1) & 3)) * 16);
            int kc = kbase + ch * 8;
            int gr = row0 + r;
            int asz = (gr < M) ? 16 : 0;
            int gra = (gr < M) ? gr : 0;
            cpa16(bufb + SM_A + so, Ah + (size_t)gra * DD + kc, asz);
            int gb = col0 + r;                       // Nc mult of 128 -> valid
            cpa16(bufb + SM_B + so, Bh + (size_t)gb * DD + kc, 16);
        }
        CP_COMMIT();
    };

    // ---- slab compute: 2 k-steps of 16, single MMA ----
    auto comp_slab = [&](int buf) {
        const uint32_t bufb = sb + buf * STAGE_BYTES;
#pragma unroll
        for (int ks = 0; ks < 2; ks++) {
            uint32_t af[2][4];
#pragma unroll
            for (int mt = 0; mt < 2; mt++) {
                int r  = warp_m + mt * 16 + (lane & 7) + ((lane >> 3) & 1) * 8;
                int ch = ks * 2 + (lane >> 4);
                uint32_t off = (uint32_t)r * 64
                             + (uint32_t)((ch ^ ((r >> 1) & 3)) * 16);
                ldx4(af[mt], bufb + SM_A + off);
            }
            uint32_t bf[4][4];
#pragma unroll
            for (int np = 0; np < 4; np++) {
                int r  = warp_n + np * 16 + (lane & 7) + ((lane >> 4) & 1) * 8;
                int ch = ks * 2 + ((lane >> 3) & 1);
                uint32_t off = (uint32_t)r * 64
                             + (uint32_t)((ch ^ ((r >> 1) & 3)) * 16);
                ldx4(bf[np], bufb + SM_B + off);
            }
#pragma unroll
            for (int mt = 0; mt < 2; mt++) {
#pragma unroll
                for (int nt = 0; nt < 8; nt++) {
                    int np = nt >> 1, hi = (nt & 1) * 2;
                    mma16816(acc[mt][nt], af[mt], bf[np][hi], bf[np][hi + 1]);
                }
            }
        }
    };

    // ---- 4 K-slabs through a 2-buffer ring ----
    load_slab(0, 0);
    load_slab(1, 1);
    CP_WAIT(1);
    __syncthreads();
    comp_slab(0);
    __syncthreads();
    load_slab(2, 0);
    CP_WAIT(1);
    __syncthreads();
    comp_slab(1);
    __syncthreads();
    load_slab(3, 1);
    CP_WAIT(1);
    __syncthreads();
    comp_slab(0);
    CP_WAIT(0);
    __syncthreads();
    comp_slab(1);

    // ---- epilogue ----
    const float* __restrict__ bias = ga.bias[z];
    __half* __restrict__ Ch = ga.Ch[z];
    float*  __restrict__ Cf = ga.Cf[z];
    __half* __restrict__ Hout = ga.Hout[z];
#pragma unroll
    for (int mt = 0; mt < 2; mt++) {
        int gr0 = row0 + warp_m + mt * 16 + (lane >> 2);
#pragma unroll
        for (int nt = 0; nt < 8; nt++) {
            int gc = col0 + warp_n + nt * 8 + (lane & 3) * 2;
            float2 b2 = *reinterpret_cast<const float2*>(bias + gc);
#pragma unroll
            for (int half_i = 0; half_i < 2; half_i++) {
                int gr = gr0 + half_i * 8;
                if (gr >= M) continue;
                float vx = acc[mt][nt][half_i * 2 + 0] + b2.x;
                float vy = acc[mt][nt][half_i * 2 + 1] + b2.y;
                if (Ch) {
                    *reinterpret_cast<__half2*>(Ch + (size_t)gr * ldc + gc) =
                        __floats2half2_rn(vx, vy);
                }
                if (Cf) {
                    *reinterpret_cast<float2*>(Cf + (size_t)gr * ldc + gc) =
                        make_float2(vx, vy);
                }
                if (Hout) {
                    *reinterpret_cast<__half2*>(Hout + (size_t)gr * DD + gc) =
                        __floats2half2_rn(vx, vy);
                }
            }
        }
    }
}

// ---------------------------------------------------------------------------
// Conversion / prep kernels
// ---------------------------------------------------------------------------
__global__ void split2_half_kernel(const float* __restrict__ x0,
                                   const float* __restrict__ x1,
                                   __half* __restrict__ h0,
                                   __half* __restrict__ h1)
{
    int i = blockIdx.x * blockDim.x + threadIdx.x;
    if (i >= 2 * NN * DD) return;
    if (i < NN * DD) h0[i] = __float2half(x0[i]);
    else             h1[i - NN * DD] = __float2half(x1[i - NN * DD]);
}

// One launch: fat W^T fp16 + fat bias vectors + nw W^T fp16.
__global__ void prep_all_kernel(const float* __restrict__ gWl_b,
                                const float* __restrict__ gWr_b,
                                const float* __restrict__ gWl_r,
                                const float* __restrict__ gWr_r,
                                const float* __restrict__ cgL_Wf,
                                const float* __restrict__ cgL_Ws,
                                const float* __restrict__ cgR_Wf,
                                const float* __restrict__ cgR_Ws,
                                const float* __restrict__ cgL_bf,
                                const float* __restrict__ cgL_bs,
                                const float* __restrict__ cgR_bf,
                                const float* __restrict__ cgR_bs,
                                const float* __restrict__ nw_W,
                                __half* __restrict__ Wth_my,
                                __half* __restrict__ Wth_opp,
                                __half* __restrict__ nwWh,
                                float* __restrict__ bias_my,
                                float* __restrict__ bias_opp)
{
    int idx = blockIdx.x * blockDim.x + threadIdx.x;
    if (idx < LDC * DD) {
        int n = idx / DD, k = idx % DD;
        float wm, wo;
        if (n < 512) {
            wm = gWl_b[k * HD + n];               wo = gWr_b[k * HD + n];
        } else if (n < 1024) {
            int c = n - 512;
            wm = gWr_r[k * HD + c];               wo = gWl_r[k * HD + c];
        } else if (n < 1152) {
            int c = n - 1024;
            wm = cgL_Wf[(DD + k) * DD + c];       wo = cgL_Wf[k * DD + c];
        } else if (n < 1280) {
            int c = n - 1152;
            wm = cgL_Ws[(DD + k) * DD + c];       wo = cgL_Ws[k * DD + c];
        } else if (n < 1408) {
            int c = n - 1280;
            wm = cgR_Wf[k * DD + c];              wo = cgR_Wf[(DD + k) * DD + c];
        } else {
            int c = n - 1408;
            wm = cgR_Ws[k * DD + c];              wo = cgR_Ws[(DD + k) * DD + c];
        }
        Wth_my[idx]  = __float2half(wm);
        Wth_opp[idx] = __float2half(wo);
    }
    if (idx < DD * DD) {
        int n = idx / DD, k = idx % DD;
        nwWh[idx] = __float2half(nw_W[k * DD + n]);
    }
    if (idx < LDC) {
        int n = idx;
        float bm = 0.f, bo = 0.f;
        if (n >= 1024 && n < 1152) bo = cgL_bf[n - 1024];
        else if (n >= 1152 && n < 1280) bo = cgL_bs[n - 1152];
        if (n >= 1280 && n < 1408) bm = cgR_bf[n - 1280];
        else if (n >= 1408) bm = cgR_bs[n - 1408];
        bias_my[n] = bm;
        bias_opp[n] = bo;
    }
}

// ---------------------------------------------------------------------------
// CSR build (4 relations, built once per launch)
// ---------------------------------------------------------------------------
__global__ void csr_zero_kernel(int* __restrict__ cnt, int* __restrict__ fill)
{
    int i = blockIdx.x * blockDim.x + threadIdx.x;
    if (i < 4 * NN) { cnt[i] = 0; fill[i] = 0; }
}

__global__ void csr_hist_kernel(const int* __restrict__ d0,
                                const int* __restrict__ d1,
                                const int* __restrict__ d2,
                                const int* __restrict__ d3,
                                int* __restrict__ cnt)
{
    int i = blockIdx.x * blockDim.x + threadIdx.x;
    if (i >= EE) return;
    atomicAdd(&cnt[0 * NN + d0[i]], 1);
    atomicAdd(&cnt[1 * NN + d1[i]], 1);
    atomicAdd(&cnt[2 * NN + d2[i]], 1);
    atomicAdd(&cnt[3 * NN + d3[i]], 1);
}

__global__ void csr_scan_kernel(const int* __restrict__ cnt,
                                int* __restrict__ row)
{
    __shared__ int part[1024];
    const int rel = blockIdx.x;
    const int t = threadIdx.x;
    const int CH = (NN + 1023) / 1024;     // 20
    const int base = t * CH;
    int s = 0;
    for (int j = 0; j < CH; j++) {
        int i = base + j;
        if (i < NN) s += cnt[rel * NN + i];
    }
    part[t] = s;
    __syncthreads();
    for (int o = 1; o < 1024; o <<= 1) {
        int u = (t >= o) ? part[t - o] : 0;
        __syncthreads();
        part[t] += u;
        __syncthreads();
    }
    int run = part[t] - s;                 // exclusive prefix
    for (int j = 0; j < CH; j++) {
        int i = base + j;
        if (i < NN) {
            row[rel * (NN + 1) + i] = run;
            run += cnt[rel * NN + i];
        }
    }
    if (t == 1023) row[rel * (NN + 1) + NN] = part[1023];
}

__global__ void csr_scatter_kernel(const int* __restrict__ s0, const int* __restrict__ d0,
                                   const int* __restrict__ s1, const int* __restrict__ d1,
                                   const int* __restrict__ s2, const int* __restrict__ d2,
                                   const int* __restrict__ s3, const int* __restrict__ d3,
                                   const int* __restrict__ row,
                                   int* __restrict__ fill,
                                   int* __restrict__ srcs)
{
    int i = blockIdx.x * blockDim.x + threadIdx.x;
    if (i >= EE) return;
    {
        int d = d0[i];
        int pos = row[0 * (NN + 1) + d] + atomicAdd(&fill[0 * NN + d], 1);
        srcs[0 * EE + pos] = s0[i];
    }
    {
        int d = d1[i];
        int pos = row[1 * (NN + 1) + d] + atomicAdd(&fill[1 * NN + d], 1);
        srcs[1 * EE + pos] = s1[i];
    }
    {
        int d = d2[i];
        int pos = row[2 * (NN + 1) + d] + atomicAdd(&fill[2 * NN + d], 1);
        srcs[2 * EE + pos] = s2[i];
    }
    {
        int d = d3[i];
        int pos = row[3 * (NN + 1) + d] + atomicAdd(&fill[3 * NN + d], 1);
        srcs[3 * EE + pos] = s3[i];
    }
}

// ---------------------------------------------------------------------------
// Fused GATv2: warp per dst node, single feature pass; blockIdx.y = relation.
// Features in fp16 (half4 loads), math in fp32.
// ---------------------------------------------------------------------------
__global__ void __launch_bounds__(256)
gat_fused_kernel(GatArgs a)
{
    const int rel = blockIdx.y;
    int d = blockIdx.x * 8 + (threadIdx.x >> 5);
    int lane = threadIdx.x & 31;
    if (d >= NN) return;

    const __half* __restrict__ xl = a.xl[rel];
    const __half* __restrict__ xr = a.xr[rel];
    const float* __restrict__ att = a.att[rel];
    const int* __restrict__ row = a.row[rel];
    const int* __restrict__ srcs = a.srcs[rel];

    float4 xr4[HH], at4[HH];
    const uint2* pr = reinterpret_cast<const uint2*>(xr + (size_t)d * LDC);
    const float4* pa = reinterpret_cast<const float4*>(att);
#pragma unroll
    for (int h = 0; h < HH; h++) {
        xr4[h] = half4_to_float4(pr[h * 32 + lane]);
        at4[h] = pa[h * 32 + lane];
    }

    float s[HH];
    float4 a4[HH];
#pragma unroll
    for (int h = 0; h < HH; h++) {
        s[h] = 0.f;
        a4[h] = make_float4(0.f, 0.f, 0.f, 0.f);
    }

    const int e0 = row[d], e1 = row[d + 1];
#pragma unroll 2
    for (int p = e0; p < e1; p++) {
        int sn = srcs[p];
        const uint2* pl = reinterpret_cast<const uint2*>(xl + (size_t)sn * LDC);
        float4 l4[HH];
        float part[HH];
#pragma unroll
        for (int h = 0; h < HH; h++) {
            l4[h] = half4_to_float4(pl[h * 32 + lane]);
            float zx = l4[h].x + xr4[h].x; zx = (zx > 0.f) ? zx : 0.2f * zx;
            float zy = l4[h].y + xr4[h].y; zy = (zy > 0.f) ? zy : 0.2f * zy;
            float zz = l4[h].z + xr4[h].z; zz = (zz > 0.f) ? zz : 0.2f * zz;
            float zw = l4[h].w + xr4[h].w; zw = (zw > 0.f) ? zw : 0.2f * zw;
            part[h] = zx * at4[h].x + zy * at4[h].y
                    + zz * at4[h].z + zw * at4[h].w;
        }
#pragma unroll
        for (int o = 16; o; o >>= 1)
#pragma unroll
            for (int h = 0; h < HH; h++)
                part[h] += __shfl_xor_sync(0xffffffffu, part[h], o);
#pragma unroll
        for (int h = 0; h < HH; h++) {
            float e = __expf(part[h]);
            s[h] += e;
            a4[h].x += e * l4[h].x;
            a4[h].y += e * l4[h].y;
            a4[h].z += e * l4[h].z;
            a4[h].w += e * l4[h].w;
        }
    }

    float4 r4 = reinterpret_cast<const float4*>(a.xres[rel] + (size_t)d * DD)[lane];
    float4 b4 = reinterpret_cast<const float4*>(a.bias[rel])[lane];
    float4 o4 = make_float4(r4.x + b4.x, r4.y + b4.y,
                            r4.z + b4.z, r4.w + b4.w);
#pragma unroll
    for (int h = 0; h < HH; h++) {
        float inv = 0.25f / (s[h] + 1e-16f);
        o4.x += a4[h].x * inv;
        o4.y += a4[h].y * inv;
        o4.z += a4[h].z * inv;
        o4.w += a4[h].w * inv;
    }
    reinterpret_cast<float4*>(a.acc[rel] + (size_t)d * DD)[lane] = o4;
}

// ---------------------------------------------------------------------------
// Fused CGConv: warp per dst node; fp16 gathers; fast-math gate; fp16 out.
// blockIdx.y = relation.
// ---------------------------------------------------------------------------
__device__ __forceinline__ float gate1(float f, float g)
{
    float sig = __fdividef(1.f, 1.f + __expf(-f));
    float sp  = fmaxf(g, 0.f) + __logf(1.f + __expf(-fabsf(g)));
    return sig * sp;
}

__global__ void __launch_bounds__(256)
cg_fused_kernel(CgArgs a)
{
    const int rel = blockIdx.y;
    int d = blockIdx.x * 8 + (threadIdx.x >> 5);
    int lane = threadIdx.x & 31;
    if (d >= NN) return;

    const __half* __restrict__ Pfs = a.Pfs[rel];
    const __half* __restrict__ Pss = a.Pss[rel];
    const int* __restrict__ row = a.row[rel];
    const int* __restrict__ srcs = a.srcs[rel];

    float4 fd4 = half4_to_float4(
        reinterpret_cast<const uint2*>(a.Pfd[rel] + (size_t)d * LDC)[lane]);
    float4 sd4 = half4_to_float4(
        reinterpret_cast<const uint2*>(a.Psd[rel] + (size_t)d * LDC)[lane]);
    float4 acc4 = reinterpret_cast<const float4*>(a.accin[rel] + (size_t)d * DD)[lane];

    const int e0 = row[d], e1 = row[d + 1];
#pragma unroll 2
    for (int p = e0; p < e1; p++) {
        int sn = srcs[p];
        float4 fs4 = half4_to_float4(
            reinterpret_cast<const uint2*>(Pfs + (size_t)sn * LDC)[lane]);
        float4 ss4 = half4_to_float4(
            reinterpret_cast<const uint2*>(Pss + (size_t)sn * LDC)[lane]);
        acc4.x += gate1(fd4.x + fs4.x, sd4.x + ss4.x);
        acc4.y += gate1(fd4.y + fs4.y, sd4.y + ss4.y);
        acc4.z += gate1(fd4.z + fs4.z, sd4.z + ss4.z);
        acc4.w += gate1(fd4.w + fs4.w, sd4.w + ss4.w);
    }

    size_t off = (size_t)d * DD + lane * 4;
    *reinterpret_cast<__half2*>(a.ah[rel] + off)     = __floats2half2_rn(acc4.x, acc4.y);
    *reinterpret_cast<__half2*>(a.ah[rel] + off + 2) = __floats2half2_rn(acc4.z, acc4.w);
}

// ---------------------------------------------------------------------------
// Host launcher
// ---------------------------------------------------------------------------
extern "C" void kernel_launch(void* const* d_in, const int* in_sizes, int n_in,
                              void* d_out, int out_size)
{
    const float* in_x_my  = (const float*)d_in[0];
    const float* in_x_opp = (const float*)d_in[1];
    const float* gWl_b = (const float*)d_in[2];
    const float* gWr_b = (const float*)d_in[3];
    const float* gatt_b = (const float*)d_in[4];
    const float* gb_b  = (const float*)d_in[5];
    const float* gWl_r = (const float*)d_in[6];
    const float* gWr_r = (const float*)d_in[7];
    const float* gatt_r = (const float*)d_in[8];
    const float* gb_r  = (const float*)d_in[9];
    const float* cgL_Wf = (const float*)d_in[10];
    const float* cgL_bf = (const float*)d_in[11];
    const float* cgL_Ws = (const float*)d_in[12];
    const float* cgL_bs = (const float*)d_in[13];
    const float* cgR_Wf = (const float*)d_in[14];
    const float* cgR_bf = (const float*)d_in[15];
    const float* cgR_Ws = (const float*)d_in[16];
    const float* cgR_bs = (const float*)d_in[17];
    const float* nw_W = (const float*)d_in[18];
    const float* nw_b = (const float*)d_in[19];
    const int* ei_beats     = (const int*)d_in[20];
    const int* ei_loses     = (const int*)d_in[21];
    const int* ei_rev_beats = (const int*)d_in[22];
    const int* ei_rev_loses = (const int*)d_in[23];

    float* out = (float*)d_out;

    float *x_my, *x_opp, *acc_my, *acc_opp, *bias_my, *bias_opp;
    __half *C_my, *C_opp;
    __half *xh_my, *xh_opp, *ah_my, *ah_opp;
    __half *Wth_my, *Wth_opp, *nwWh;
    int *rowp, *cntp, *fillp, *srcsp;
    cudaGetSymbolAddress((void**)&C_my,  g_C_my);
    cudaGetSymbolAddress((void**)&C_opp, g_C_opp);
    cudaGetSymbolAddress((void**)&x_my,  g_x_my);
    cudaGetSymbolAddress((void**)&x_opp, g_x_opp);
    cudaGetSymbolAddress((void**)&acc_my, g_acc_my);
    cudaGetSymbolAddress((void**)&acc_opp, g_acc_opp);
    cudaGetSymbolAddress((void**)&bias_my,  g_bias_my);
    cudaGetSymbolAddress((void**)&bias_opp, g_bias_opp);
    cudaGetSymbolAddress((void**)&xh_my,  g_xh_my);
    cudaGetSymbolAddress((void**)&xh_opp, g_xh_opp);
    cudaGetSymbolAddress((void**)&ah_my,  g_ah_my);
    cudaGetSymbolAddress((void**)&ah_opp, g_ah_opp);
    cudaGetSymbolAddress((void**)&Wth_my,  g_Wth_my);
    cudaGetSymbolAddress((void**)&Wth_opp, g_Wth_opp);
    cudaGetSymbolAddress((void**)&nwWh, g_nwWh);
    cudaGetSymbolAddress((void**)&rowp,  g_row);
    cudaGetSymbolAddress((void**)&cntp,  g_cnt);
    cudaGetSymbolAddress((void**)&fillp, g_fill);
    cudaGetSymbolAddress((void**)&srcsp, g_srcs);

    cudaFuncSetAttribute(mma_gemm, cudaFuncAttributeMaxDynamicSharedMemorySize,
                         DYN_SMEM);

    const int* src_b  = ei_beats;      const int* dst_b  = ei_beats + EE;
    const int* src_l  = ei_loses;      const int* dst_l  = ei_loses + EE;
    const int* src_rb = ei_rev_beats;  const int* dst_rb = ei_rev_beats + EE;
    const int* src_rl = ei_rev_loses;  const int* dst_rl = ei_rev_loses + EE;

    const int node_blocks = (NN + 7) / 8;
    const int e_blocks    = (EE + 255) / 256;
    const int mtiles      = (NN + 127) / 128;      // 157

    // Launch order: fat mma_gemm at slot 4 so ncu samples it.
    split2_half_kernel<<<(2 * NN * DD + 255) / 256, 256>>>(
        in_x_my, in_x_opp, xh_my, xh_opp);
    prep_all_kernel<<<(LDC * DD + 255) / 256, 256>>>(
        gWl_b, gWr_b, gWl_r, gWr_r,
        cgL_Wf, cgL_Ws, cgR_Wf, cgR_Ws,
        cgL_bf, cgL_bs, cgR_bf, cgR_bs,
        nw_W,
        Wth_my, Wth_opp, nwWh, bias_my, bias_opp);
    csr_zero_kernel<<<(4 * NN + 255) / 256, 256>>>(cntp, fillp);
    {
        GemmArgs ga;
        ga.Ah[0] = xh_my;   ga.Ah[1] = xh_opp;
        ga.Bh[0] = Wth_my;  ga.Bh[1] = Wth_opp;
        ga.bias[0] = bias_my;  ga.bias[1] = bias_opp;
        ga.Ch[0] = C_my;    ga.Ch[1] = C_opp;
        ga.Cf[0] = nullptr; ga.Cf[1] = nullptr;
        ga.Hout[0] = nullptr; ga.Hout[1] = nullptr;
        ga.M = NN; ga.ldc = LDC;
        dim3 grid(LDC / 128, mtiles, 2);
        mma_gemm<<<grid, 256, DYN_SMEM>>>(ga);
    }
    csr_hist_kernel<<<e_blocks, 256>>>(dst_b, dst_rl, dst_l, dst_rb, cntp);
    csr_scan_kernel<<<4, 1024>>>(cntp, rowp);
    csr_scatter_kernel<<<e_blocks, 256>>>(src_b, dst_b, src_rl, dst_rl,
                                          src_l, dst_l, src_rb, dst_rb,
                                          rowp, fillp, srcsp);

    const float* cur_my  = in_x_my;
    const float* cur_opp = in_x_opp;

    for (int l = 0; l < LLAYERS; l++) {
        const size_t oW = (size_t)l * DD * HD;
        const size_t oA = (size_t)l * HH * DD;
        const size_t oB = (size_t)l * DD;
        const size_t oC = (size_t)l * 2 * DD * DD;
        const size_t oN = (size_t)l * DD * DD;

        if (l > 0) {
            prep_all_kernel<<<(LDC * DD + 255) / 256, 256>>>(
                gWl_b + oW, gWr_b + oW, gWl_r + oW, gWr_r + oW,
                cgL_Wf + oC, cgL_Ws + oC, cgR_Wf + oC, cgR_Ws + oC,
                cgL_bf + oB, cgL_bs + oB, cgR_bf + oB, cgR_bs + oB,
                nw_W + oN,
                Wth_my, Wth_opp, nwWh, bias_my, bias_opp);
            GemmArgs ga;
            ga.Ah[0] = xh_my;   ga.Ah[1] = xh_opp;
            ga.Bh[0] = Wth_my;  ga.Bh[1] = Wth_opp;
            ga.bias[0] = bias_my;  ga.bias[1] = bias_opp;
            ga.Ch[0] = C_my;    ga.Ch[1] = C_opp;
            ga.Cf[0] = nullptr; ga.Cf[1] = nullptr;
            ga.Hout[0] = nullptr; ga.Hout[1] = nullptr;
            ga.M = NN; ga.ldc = LDC;
            dim3 grid(LDC / 128, mtiles, 2);
            mma_gemm<<<grid, 256, DYN_SMEM>>>(ga);
        }

        // ---- fused GAT: both relations, one launch ----
        {
            GatArgs a;
            // rel 0: beats (my -> opp)
            a.xl[0] = C_my;        a.xr[0] = C_opp;
            a.att[0] = gatt_b + oA;
            a.row[0] = rowp + 0 * (NN + 1);  a.srcs[0] = srcsp + 0 * EE;
            a.xres[0] = cur_opp;   a.bias[0] = gb_b + oB;  a.acc[0] = acc_opp;
            // rel 1: rev_loses (opp -> my)
            a.xl[1] = C_opp + 512; a.xr[1] = C_my + 512;
            a.att[1] = gatt_r + oA;
            a.row[1] = rowp + 1 * (NN + 1);  a.srcs[1] = srcsp + 1 * EE;
            a.xres[1] = cur_my;    a.bias[1] = gb_r + oB;  a.acc[1] = acc_my;
            dim3 grid(node_blocks, 2);
            gat_fused_kernel<<<grid, 256>>>(a);
        }

        // ---- fused CGConv: both relations, one launch ----
        {
            CgArgs a;
            // rel 0: loses (my -> opp)
            a.Pfd[0] = C_opp + 1024; a.Pfs[0] = C_my + 1024;
            a.Psd[0] = C_opp + 1152; a.Pss[0] = C_my + 1152;
            a.row[0] = rowp + 2 * (NN + 1);  a.srcs[0] = srcsp + 2 * EE;
            a.accin[0] = acc_opp;  a.ah[0] = ah_opp;
            // rel 1: rev_beats (opp -> my)
            a.Pfd[1] = C_my + 1280; a.Pfs[1] = C_opp + 1280;
            a.Psd[1] = C_my + 1408; a.Pss[1] = C_opp + 1408;
            a.row[1] = rowp + 3 * (NN + 1);  a.srcs[1] = srcsp + 3 * EE;
            a.accin[1] = acc_my;   a.ah[1] = ah_my;
            dim3 grid(node_blocks, 2);
            cg_fused_kernel<<<grid, 256>>>(a);
        }

        // ---- nodewise Linear (both node types, one launch; fp32 out) ----
        {
            float* out_my  = (l == LLAYERS - 1) ? out           : x_my;
            float* out_opp = (l == LLAYERS - 1) ? out + NN * DD : x_opp;
            GemmArgs ga;
            ga.Ah[0] = ah_my;   ga.Ah[1] = ah_opp;
            ga.Bh[0] = nwWh;    ga.Bh[1] = nwWh;
            ga.bias[0] = nw_b + oB;  ga.bias[1] = nw_b + oB;
            ga.Ch[0] = nullptr; ga.Ch[1] = nullptr;
            ga.Cf[0] = out_my;  ga.Cf[1] = out_opp;
            ga.Hout[0] = xh_my;  ga.Hout[1] = xh_opp;
            ga.M = NN; ga.ldc = DD;
            dim3 grid(1, mtiles, 2);
            mma_gemm<<<grid, 256, DYN_SMEM>>>(ga);
        }

        cur_my  = x_my;
        cur_opp = x_opp;
    }
}

// round 11
// speedup vs baseline: 4.6634x; 1.0958x over previous
#include <cuda_runtime.h>
#include <cuda_fp16.h>
#include <math.h>
#include <stdint.h>

// ---------------------------------------------------------------------------
// Problem constants
// ---------------------------------------------------------------------------
#define NN 20000
#define DD 128
#define HH 4
#define EE 80000
#define LLAYERS 2
#define HD (HH * DD)      // 512
#define LDC 1536          // fat projection width per node type

// Fat column layout (per node type X in {my, opp}):
//  [0,512)      GAT projection #1 (my: Wl_beats ; opp: Wr_beats)
//  [512,1024)   GAT projection #2 (my: Wr_rev   ; opp: Wl_rev)
//  [1024,1152)  CG lose Wf part   (my: src/bottom ; opp: dst/top + bf)
//  [1152,1280)  CG lose Ws part   (my: src/bottom ; opp: dst/top + bs)
//  [1280,1408)  CG rev  Wf part   (my: dst/top + bf ; opp: src/bottom)
//  [1408,1536)  CG rev  Ws part   (my: dst/top + bs ; opp: src/bottom)

// ---------------------------------------------------------------------------
// Static device scratch
// ---------------------------------------------------------------------------
__device__ __align__(16) __half g_C_my [(size_t)NN * LDC];   // fp16 fat features
__device__ __align__(16) __half g_C_opp[(size_t)NN * LDC];

__device__ __align__(16) float g_x_my [NN * DD];
__device__ __align__(16) float g_x_opp[NN * DD];
__device__ __align__(16) float g_acc_my [NN * DD];
__device__ __align__(16) float g_acc_opp[NN * DD];

// fp16 feature operands (A side of GEMMs)
__device__ __align__(16) __half g_xh_my [NN * DD];
__device__ __align__(16) __half g_xh_opp[NN * DD];
__device__ __align__(16) __half g_ah_my [NN * DD];
__device__ __align__(16) __half g_ah_opp[NN * DD];

// fp16 weight operands (B side), K-MAJOR: [DD][LDC] / [DD][DD]
__device__ __align__(16) __half g_Wth_my [DD * LDC];
__device__ __align__(16) __half g_Wth_opp[DD * LDC];
__device__ __align__(16) __half g_nwWh[DD * DD];

__device__ __align__(16) float g_bias_my [LDC];
__device__ __align__(16) float g_bias_opp[LDC];

// CSR (4 relations: 0=beats, 1=rev_loses, 2=loses, 3=rev_beats), built once
__device__ int g_row [4 * (NN + 1)];
__device__ int g_cnt [4 * NN];
__device__ int g_fill[4 * NN];
__device__ int g_srcs[4 * EE];

// ---------------------------------------------------------------------------
// Arg structs for merged launches
// ---------------------------------------------------------------------------
struct GemmArgs {
    const __half *Ah[2], *Bh[2];
    const float *bias[2];
    __half *Ch[2];     // fp16 C output (fat projections) -> stmatrix epilogue
    float  *Cf[2];     // fp32 C output (nodewise Linear) -> direct epilogue
    __half *Hout[2];   // fp16 feature copy (next-layer A)
    int M, ldc, ldb;
};

struct GatArgs {
    const __half *xl[2], *xr[2];
    const float *att[2], *xres[2], *bias[2];
    const int *row[2], *srcs[2];
    float *acc[2];
};

struct CgArgs {
    const __half *Pfd[2], *Pfs[2], *Psd[2], *Pss[2];
    const float *accin[2];
    const int *row[2], *srcs[2];
    __half *ah[2];
};

// ---------------------------------------------------------------------------
// Warp MMA / cp.async helpers
// ---------------------------------------------------------------------------
__device__ __forceinline__ uint32_t smem_to_u32(const void* p)
{
    uint32_t a;
    asm("{ .reg .u64 t; cvta.to.shared.u64 t, %1; cvt.u32.u64 %0, t; }"
        : "=r"(a) : "l"(p));
    return a;
}

__device__ __forceinline__ void ldx4(uint32_t* r, uint32_t addr)
{
    asm volatile("ldmatrix.sync.aligned.m8n8.x4.shared.b16 {%0,%1,%2,%3}, [%4];"
                 : "=r"(r[0]), "=r"(r[1]), "=r"(r[2]), "=r"(r[3]) : "r"(addr));
}

__device__ __forceinline__ void ldx4t(uint32_t* r, uint32_t addr)
{
    asm volatile("ldmatrix.sync.aligned.m8n8.x4.trans.shared.b16 {%0,%1,%2,%3}, [%4];"
                 : "=r"(r[0]), "=r"(r[1]), "=r"(r[2]), "=r"(r[3]) : "r"(addr));
}

__device__ __forceinline__ void stx4(uint32_t addr, uint32_t r0, uint32_t r1,
                                     uint32_t r2, uint32_t r3)
{
    asm volatile("stmatrix.sync.aligned.m8n8.x4.shared.b16 [%0], {%1,%2,%3,%4};"
                 :: "r"(addr), "r"(r0), "r"(r1), "r"(r2), "r"(r3) : "memory");
}

__device__ __forceinline__ void mma16816(float* c, const uint32_t* a,
                                         uint32_t b0, uint32_t b1)
{
    asm volatile(
        "mma.sync.aligned.m16n8k16.row.col.f32.f16.f16.f32 "
        "{%0,%1,%2,%3}, {%4,%5,%6,%7}, {%8,%9}, {%0,%1,%2,%3};"
        : "+f"(c[0]), "+f"(c[1]), "+f"(c[2]), "+f"(c[3])
        : "r"(a[0]), "r"(a[1]), "r"(a[2]), "r"(a[3]), "r"(b0), "r"(b1));
}

__device__ __forceinline__ void cpa16(uint32_t dst, const void* src, int sz)
{
    asm volatile("cp.async.cg.shared.global [%0], [%1], 16, %2;"
                 :: "r"(dst), "l"(src), "r"(sz));
}
#define CP_COMMIT() asm volatile("cp.async.commit_group;" ::: "memory")
#define CP_WAIT(n)  asm volatile("cp.async.wait_group %0;" :: "n"(n) : "memory")

__device__ __forceinline__ float4 half4_to_float4(uint2 v)
{
    __half2 h01 = *reinterpret_cast<__half2*>(&v.x);
    __half2 h23 = *reinterpret_cast<__half2*>(&v.y);
    float2 f0 = __half22float2(h01);
    float2 f1 = __half22float2(h23);
    return make_float4(f0.x, f0.y, f1.x, f1.y);
}

// ---------------------------------------------------------------------------
// Tensor-core GEMM: C[M, col0..+128] = A[M,128] @ B[128, Nc] + bias.
// A row-major fp16; B K-MAJOR fp16 (ldb cols), loaded via ldmatrix.trans.
// BK=32 slabs, 2-stage cp.async ring, 32 KB smem.
// Ch path: stmatrix -> smem -> coalesced 128B stores.
// ---------------------------------------------------------------------------
#define SM_A  0
#define SM_B  8192
#define STAGE_BYTES 16384
#define DYN_SMEM 32768

__global__ void __launch_bounds__(256, 2)
mma_gemm(GemmArgs ga)
{
    extern __shared__ char smem[];
    const uint32_t sb = smem_to_u32(smem);

    const int z = blockIdx.z;
    const __half* __restrict__ Ah = ga.Ah[z];
    const __half* __restrict__ Bh = ga.Bh[z];
    const int M = ga.M, ldc = ga.ldc, ldb = ga.ldb;

    const int tid  = threadIdx.x;
    const int wid  = tid >> 5;
    const int lane = tid & 31;
    const int row0 = blockIdx.y * 128;
    const int col0 = blockIdx.x * 128;

    const int warp_m = (wid & 3) * 32;    // 4 warps over M
    const int warp_n = (wid >> 2) * 64;   // 2 warps over N

    float acc[2][8][4];
#pragma unroll
    for (int mt = 0; mt < 2; mt++)
#pragma unroll
        for (int nt = 0; nt < 8; nt++)
#pragma unroll
            for (int j = 0; j < 4; j++) acc[mt][nt][j] = 0.f;

    // ---- slab loader: 32-wide K slab; A 64B rows, B 256B k-rows ----
    auto load_slab = [&](int slab, int buf) {
        const uint32_t bufb = sb + buf * STAGE_BYTES;
        const int kbase = slab * 32;
        // A: 512 chunks (128 rows x 4 chunks of 16B)
#pragma unroll
        for (int it = 0; it < 2; it++) {
            int c  = tid + it * 256;
            int r  = c >> 2;
            int ch = c & 3;
            uint32_t so = (uint32_t)r * 64 + (uint32_t)((ch ^ ((r >> 1) & 3)) * 16);
            int kc = kbase + ch * 8;
            int gr = row0 + r;
            int asz = (gr < M) ? 16 : 0;
            int gra = (gr < M) ? gr : 0;
            cpa16(bufb + SM_A + so, Ah + (size_t)gra * DD + kc, asz);
        }
        // B: 512 chunks (32 k-rows x 16 chunks of 16B)
#pragma unroll
        for (int it = 0; it < 2; it++) {
            int c  = tid + it * 256;
            int kr = c >> 4;
            int ch = c & 15;
            uint32_t so = (uint32_t)kr * 256 + (uint32_t)((ch ^ (kr & 7)) * 16);
            cpa16(bufb + SM_B + so,
                  Bh + (size_t)(kbase + kr) * ldb + col0 + ch * 8, 16);
        }
        CP_COMMIT();
    };

    // ---- slab compute: 2 k-steps of 16 ----
    auto comp_slab = [&](int buf) {
        const uint32_t bufb = sb + buf * STAGE_BYTES;
#pragma unroll
        for (int ks = 0; ks < 2; ks++) {
            uint32_t af[2][4];
#pragma unroll
            for (int mt = 0; mt < 2; mt++) {
                int r  = warp_m + mt * 16 + (lane & 7) + ((lane >> 3) & 1) * 8;
                int ch = ks * 2 + (lane >> 4);
                uint32_t off = (uint32_t)r * 64
                             + (uint32_t)((ch ^ ((r >> 1) & 3)) * 16);
                ldx4(af[mt], bufb + SM_A + off);
            }
            uint32_t bf[4][4];
#pragma unroll
            for (int np = 0; np < 4; np++) {
                int kr = ks * 16 + (lane & 7) + ((lane >> 3) & 1) * 8;
                int ch = (warp_n >> 3) + np * 2 + ((lane >> 4) & 1);
                uint32_t off = (uint32_t)kr * 256
                             + (uint32_t)((ch ^ (kr & 7)) * 16);
                ldx4t(bf[np], bufb + SM_B + off);
            }
#pragma unroll
            for (int mt = 0; mt < 2; mt++) {
#pragma unroll
                for (int nt = 0; nt < 8; nt++) {
                    int np = nt >> 1, hi = (nt & 1) * 2;
                    mma16816(acc[mt][nt], af[mt], bf[np][hi], bf[np][hi + 1]);
                }
            }
        }
    };

    // ---- 4 K-slabs through a 2-buffer ring ----
    load_slab(0, 0);
    load_slab(1, 1);
    CP_WAIT(1);
    __syncthreads();
    comp_slab(0);
    __syncthreads();
    load_slab(2, 0);
    CP_WAIT(1);
    __syncthreads();
    comp_slab(1);
    __syncthreads();
    load_slab(3, 1);
    CP_WAIT(1);
    __syncthreads();
    comp_slab(0);
    CP_WAIT(0);
    __syncthreads();
    comp_slab(1);

    const float* __restrict__ bias = ga.bias[z];
    __half* __restrict__ Ch = ga.Ch[z];

    if (Ch) {
        // ---- stmatrix epilogue: stage 128x128 fp16 tile in smem, then
        //      write 128B-coalesced rows to global ----
        __syncthreads();   // all warps done reading pipeline smem
#pragma unroll
        for (int mt = 0; mt < 2; mt++) {
#pragma unroll
            for (int half_i = 0; half_i < 2; half_i++) {
#pragma unroll
                for (int ntg = 0; ntg < 2; ntg++) {
                    uint32_t h2[4];
#pragma unroll
                    for (int j = 0; j < 4; j++) {
                        int nt = ntg * 4 + j;
                        int gc = col0 + warp_n + nt * 8 + (lane & 3) * 2;
                        float2 b2 = *reinterpret_cast<const float2*>(bias + gc);
                        __half2 hv = __floats2half2_rn(
                            acc[mt][nt][half_i * 2 + 0] + b2.x,
                            acc[mt][nt][half_i * 2 + 1] + b2.y);
                        h2[j] = *reinterpret_cast<uint32_t*>(&hv);
                    }
                    int lr = warp_m + mt * 16 + half_i * 8 + (lane & 7);
                    int ch = (warp_n >> 3) + ntg * 4 + (lane >> 3);
                    uint32_t addr = sb + (uint32_t)(lr * 256)
                                  + (uint32_t)((ch ^ (lr & 7)) << 4);
                    stx4(addr, h2[0], h2[1], h2[2], h2[3]);
                }
            }
        }
        __syncthreads();
#pragma unroll
        for (int it = 0; it < 8; it++) {
            int id = tid + it * 256;
            int r = id >> 4, ch = id & 15;
            int gr = row0 + r;
            if (gr < M) {
                uint4 v = *reinterpret_cast<uint4*>(
                    smem + r * 256 + ((ch ^ (r & 7)) << 4));
                *reinterpret_cast<uint4*>(Ch + (size_t)gr * ldc + col0 + ch * 8) = v;
            }
        }
    } else {
        // ---- direct epilogue (nodewise Linear: fp32 out + fp16 copy) ----
        float*  __restrict__ Cf = ga.Cf[z];
        __half* __restrict__ Hout = ga.Hout[z];
#pragma unroll
        for (int mt = 0; mt < 2; mt++) {
            int gr0 = row0 + warp_m + mt * 16 + (lane >> 2);
#pragma unroll
            for (int nt = 0; nt < 8; nt++) {
                int gc = col0 + warp_n + nt * 8 + (lane & 3) * 2;
                float2 b2 = *reinterpret_cast<const float2*>(bias + gc);
#pragma unroll
                for (int half_i = 0; half_i < 2; half_i++) {
                    int gr = gr0 + half_i * 8;
                    if (gr >= M) continue;
                    float vx = acc[mt][nt][half_i * 2 + 0] + b2.x;
                    float vy = acc[mt][nt][half_i * 2 + 1] + b2.y;
                    *reinterpret_cast<float2*>(Cf + (size_t)gr * ldc + gc) =
                        make_float2(vx, vy);
                    if (Hout) {
                        *reinterpret_cast<__half2*>(Hout + (size_t)gr * DD + gc) =
                            __floats2half2_rn(vx, vy);
                    }
                }
            }
        }
    }
}

// ---------------------------------------------------------------------------
// Conversion / prep kernels
// ---------------------------------------------------------------------------
__global__ void split2_half_kernel(const float* __restrict__ x0,
                                   const float* __restrict__ x1,
                                   __half* __restrict__ h0,
                                   __half* __restrict__ h1)
{
    int i = blockIdx.x * blockDim.x + threadIdx.x;
    if (i >= 2 * NN * DD) return;
    if (i < NN * DD) h0[i] = __float2half(x0[i]);
    else             h1[i - NN * DD] = __float2half(x1[i - NN * DD]);
}

// One launch: K-major fat W fp16 + fat bias vectors + nw W fp16.
// All reads AND writes coalesced (every source region is K-major).
__global__ void prep_all_kernel(const float* __restrict__ gWl_b,
                                const float* __restrict__ gWr_b,
                                const float* __restrict__ gWl_r,
                                const float* __restrict__ gWr_r,
                                const float* __restrict__ cgL_Wf,
                                const float* __restrict__ cgL_Ws,
                                const float* __restrict__ cgR_Wf,
                                const float* __restrict__ cgR_Ws,
                                const float* __restrict__ cgL_bf,
                                const float* __restrict__ cgL_bs,
                                const float* __restrict__ cgR_bf,
                                const float* __restrict__ cgR_bs,
                                const float* __restrict__ nw_W,
                                __half* __restrict__ Wth_my,
                                __half* __restrict__ Wth_opp,
                                __half* __restrict__ nwWh,
                                float* __restrict__ bias_my,
                                float* __restrict__ bias_opp)
{
    int idx = blockIdx.x * blockDim.x + threadIdx.x;
    if (idx < DD * LDC) {
        int k = idx / LDC, n = idx % LDC;
        float wm, wo;
        if (n < 512) {
            wm = gWl_b[k * HD + n];               wo = gWr_b[k * HD + n];
        } else if (n < 1024) {
            int c = n - 512;
            wm = gWr_r[k * HD + c];               wo = gWl_r[k * HD + c];
        } else if (n < 1152) {
            int c = n - 1024;
            wm = cgL_Wf[(DD + k) * DD + c];       wo = cgL_Wf[k * DD + c];
        } else if (n < 1280) {
            int c = n - 1152;
            wm = cgL_Ws[(DD + k) * DD + c];       wo = cgL_Ws[k * DD + c];
        } else if (n < 1408) {
            int c = n - 1280;
            wm = cgR_Wf[k * DD + c];              wo = cgR_Wf[(DD + k) * DD + c];
        } else {
            int c = n - 1408;
            wm = cgR_Ws[k * DD + c];              wo = cgR_Ws[(DD + k) * DD + c];
        }
        Wth_my[idx]  = __float2half(wm);
        Wth_opp[idx] = __float2half(wo);
    }
    if (idx < DD * DD) {
        nwWh[idx] = __float2half(nw_W[idx]);   // already K-major
    }
    if (idx < LDC) {
        int n = idx;
        float bm = 0.f, bo = 0.f;
        if (n >= 1024 && n < 1152) bo = cgL_bf[n - 1024];
        else if (n >= 1152 && n < 1280) bo = cgL_bs[n - 1152];
        if (n >= 1280 && n < 1408) bm = cgR_bf[n - 1280];
        else if (n >= 1408) bm = cgR_bs[n - 1408];
        bias_my[n] = bm;
        bias_opp[n] = bo;
    }
}

// ---------------------------------------------------------------------------
// CSR build (4 relations, built once per launch)
// ---------------------------------------------------------------------------
__global__ void csr_zero_kernel(int* __restrict__ cnt, int* __restrict__ fill)
{
    int i = blockIdx.x * blockDim.x + threadIdx.x;
    if (i < 4 * NN) { cnt[i] = 0; fill[i] = 0; }
}

__global__ void csr_hist_kernel(const int* __restrict__ d0,
                                const int* __restrict__ d1,
                                const int* __restrict__ d2,
                                const int* __restrict__ d3,
                                int* __restrict__ cnt)
{
    int i = blockIdx.x * blockDim.x + threadIdx.x;
    if (i >= EE) return;
    atomicAdd(&cnt[0 * NN + d0[i]], 1);
    atomicAdd(&cnt[1 * NN + d1[i]], 1);
    atomicAdd(&cnt[2 * NN + d2[i]], 1);
    atomicAdd(&cnt[3 * NN + d3[i]], 1);
}

__global__ void csr_scan_kernel(const int* __restrict__ cnt,
                                int* __restrict__ row)
{
    __shared__ int part[1024];
    const int rel = blockIdx.x;
    const int t = threadIdx.x;
    const int CH = (NN + 1023) / 1024;     // 20
    const int base = t * CH;
    int s = 0;
    for (int j = 0; j < CH; j++) {
        int i = base + j;
        if (i < NN) s += cnt[rel * NN + i];
    }
    part[t] = s;
    __syncthreads();
    for (int o = 1; o < 1024; o <<= 1) {
        int u = (t >= o) ? part[t - o] : 0;
        __syncthreads();
        part[t] += u;
        __syncthreads();
    }
    int run = part[t] - s;                 // exclusive prefix
    for (int j = 0; j < CH; j++) {
        int i = base + j;
        if (i < NN) {
            row[rel * (NN + 1) + i] = run;
            run += cnt[rel * NN + i];
        }
    }
    if (t == 1023) row[rel * (NN + 1) + NN] = part[1023];
}

__global__ void csr_scatter_kernel(const int* __restrict__ s0, const int* __restrict__ d0,
                                   const int* __restrict__ s1, const int* __restrict__ d1,
                                   const int* __restrict__ s2, const int* __restrict__ d2,
                                   const int* __restrict__ s3, const int* __restrict__ d3,
                                   const int* __restrict__ row,
                                   int* __restrict__ fill,
                                   int* __restrict__ srcs)
{
    int i = blockIdx.x * blockDim.x + threadIdx.x;
    if (i >= EE) return;
    {
        int d = d0[i];
        int pos = row[0 * (NN + 1) + d] + atomicAdd(&fill[0 * NN + d], 1);
        srcs[0 * EE + pos] = s0[i];
    }
    {
        int d = d1[i];
        int pos = row[1 * (NN + 1) + d] + atomicAdd(&fill[1 * NN + d], 1);
        srcs[1 * EE + pos] = s1[i];
    }
    {
        int d = d2[i];
        int pos = row[2 * (NN + 1) + d] + atomicAdd(&fill[2 * NN + d], 1);
        srcs[2 * EE + pos] = s2[i];
    }
    {
        int d = d3[i];
        int pos = row[3 * (NN + 1) + d] + atomicAdd(&fill[3 * NN + d], 1);
        srcs[3 * EE + pos] = s3[i];
    }
}

// ---------------------------------------------------------------------------
// Fused GATv2: warp per dst node, single feature pass; blockIdx.y = relation.
// Features in fp16 (half4 loads), math in fp32.
// ---------------------------------------------------------------------------
__global__ void __launch_bounds__(256)
gat_fused_kernel(GatArgs a)
{
    const int rel = blockIdx.y;
    int d = blockIdx.x * 8 + (threadIdx.x >> 5);
    int lane = threadIdx.x & 31;
    if (d >= NN) return;

    const __half* __restrict__ xl = a.xl[rel];
    const __half* __restrict__ xr = a.xr[rel];
    const float* __restrict__ att = a.att[rel];
    const int* __restrict__ row = a.row[rel];
    const int* __restrict__ srcs = a.srcs[rel];

    float4 xr4[HH], at4[HH];
    const uint2* pr = reinterpret_cast<const uint2*>(xr + (size_t)d * LDC);
    const float4* pa = reinterpret_cast<const float4*>(att);
#pragma unroll
    for (int h = 0; h < HH; h++) {
        xr4[h] = half4_to_float4(pr[h * 32 + lane]);
        at4[h] = pa[h * 32 + lane];
    }

    float s[HH];
    float4 a4[HH];
#pragma unroll
    for (int h = 0; h < HH; h++) {
        s[h] = 0.f;
        a4[h] = make_float4(0.f, 0.f, 0.f, 0.f);
    }

    const int e0 = row[d], e1 = row[d + 1];
#pragma unroll 2
    for (int p = e0; p < e1; p++) {
        int sn = srcs[p];
        const uint2* pl = reinterpret_cast<const uint2*>(xl + (size_t)sn * LDC);
        float4 l4[HH];
        float part[HH];
#pragma unroll
        for (int h = 0; h < HH; h++) {
            l4[h] = half4_to_float4(pl[h * 32 + lane]);
            float zx = l4[h].x + xr4[h].x; zx = (zx > 0.f) ? zx : 0.2f * zx;
            float zy = l4[h].y + xr4[h].y; zy = (zy > 0.f) ? zy : 0.2f * zy;
            float zz = l4[h].z + xr4[h].z; zz = (zz > 0.f) ? zz : 0.2f * zz;
            float zw = l4[h].w + xr4[h].w; zw = (zw > 0.f) ? zw : 0.2f * zw;
            part[h] = zx * at4[h].x + zy * at4[h].y
                    + zz * at4[h].z + zw * at4[h].w;
        }
#pragma unroll
        for (int o = 16; o; o >>= 1)
#pragma unroll
            for (int h = 0; h < HH; h++)
                part[h] += __shfl_xor_sync(0xffffffffu, part[h], o);
#pragma unroll
        for (int h = 0; h < HH; h++) {
            float e = __expf(part[h]);
            s[h] += e;
            a4[h].x += e * l4[h].x;
            a4[h].y += e * l4[h].y;
            a4[h].z += e * l4[h].z;
            a4[h].w += e * l4[h].w;
        }
    }

    float4 r4 = reinterpret_cast<const float4*>(a.xres[rel] + (size_t)d * DD)[lane];
    float4 b4 = reinterpret_cast<const float4*>(a.bias[rel])[lane];
    float4 o4 = make_float4(r4.x + b4.x, r4.y + b4.y,
                            r4.z + b4.z, r4.w + b4.w);
#pragma unroll
    for (int h = 0; h < HH; h++) {
        float inv = 0.25f / (s[h] + 1e-16f);
        o4.x += a4[h].x * inv;
        o4.y += a4[h].y * inv;
        o4.z += a4[h].z * inv;
        o4.w += a4[h].w * inv;
    }
    reinterpret_cast<float4*>(a.acc[rel] + (size_t)d * DD)[lane] = o4;
}

// ---------------------------------------------------------------------------
// Fused CGConv: warp per dst node; fp16 gathers; fast-math gate; fp16 out.
// blockIdx.y = relation.
// ---------------------------------------------------------------------------
__device__ __forceinline__ float gate1(float f, float g)
{
    float sig = __fdividef(1.f, 1.f + __expf(-f));
    float sp  = fmaxf(g, 0.f) + __logf(1.f + __expf(-fabsf(g)));
    return sig * sp;
}

__global__ void __launch_bounds__(256)
cg_fused_kernel(CgArgs a)
{
    const int rel = blockIdx.y;
    int d = blockIdx.x * 8 + (threadIdx.x >> 5);
    int lane = threadIdx.x & 31;
    if (d >= NN) return;

    const __half* __restrict__ Pfs = a.Pfs[rel];
    const __half* __restrict__ Pss = a.Pss[rel];
    const int* __restrict__ row = a.row[rel];
    const int* __restrict__ srcs = a.srcs[rel];

    float4 fd4 = half4_to_float4(
        reinterpret_cast<const uint2*>(a.Pfd[rel] + (size_t)d * LDC)[lane]);
    float4 sd4 = half4_to_float4(
        reinterpret_cast<const uint2*>(a.Psd[rel] + (size_t)d * LDC)[lane]);
    float4 acc4 = reinterpret_cast<const float4*>(a.accin[rel] + (size_t)d * DD)[lane];

    const int e0 = row[d], e1 = row[d + 1];
#pragma unroll 2
    for (int p = e0; p < e1; p++) {
        int sn = srcs[p];
        float4 fs4 = half4_to_float4(
            reinterpret_cast<const uint2*>(Pfs + (size_t)sn * LDC)[lane]);
        float4 ss4 = half4_to_float4(
            reinterpret_cast<const uint2*>(Pss + (size_t)sn * LDC)[lane]);
        acc4.x += gate1(fd4.x + fs4.x, sd4.x + ss4.x);
        acc4.y += gate1(fd4.y + fs4.y, sd4.y + ss4.y);
        acc4.z += gate1(fd4.z + fs4.z, sd4.z + ss4.z);
        acc4.w += gate1(fd4.w + fs4.w, sd4.w + ss4.w);
    }

    size_t off = (size_t)d * DD + lane * 4;
    *reinterpret_cast<__half2*>(a.ah[rel] + off)     = __floats2half2_rn(acc4.x, acc4.y);
    *reinterpret_cast<__half2*>(a.ah[rel] + off + 2) = __floats2half2_rn(acc4.z, acc4.w);
}

// ---------------------------------------------------------------------------
// Host launcher
// ---------------------------------------------------------------------------
extern "C" void kernel_launch(void* const* d_in, const int* in_sizes, int n_in,
                              void* d_out, int out_size)
{
    const float* in_x_my  = (const float*)d_in[0];
    const float* in_x_opp = (const float*)d_in[1];
    const float* gWl_b = (const float*)d_in[2];
    const float* gWr_b = (const float*)d_in[3];
    const float* gatt_b = (const float*)d_in[4];
    const float* gb_b  = (const float*)d_in[5];
    const float* gWl_r = (const float*)d_in[6];
    const float* gWr_r = (const float*)d_in[7];
    const float* gatt_r = (const float*)d_in[8];
    const float* gb_r  = (const float*)d_in[9];
    const float* cgL_Wf = (const float*)d_in[10];
    const float* cgL_bf = (const float*)d_in[11];
    const float* cgL_Ws = (const float*)d_in[12];
    const float* cgL_bs = (const float*)d_in[13];
    const float* cgR_Wf = (const float*)d_in[14];
    const float* cgR_bf = (const float*)d_in[15];
    const float* cgR_Ws = (const float*)d_in[16];
    const float* cgR_bs = (const float*)d_in[17];
    const float* nw_W = (const float*)d_in[18];
    const float* nw_b = (const float*)d_in[19];
    const int* ei_beats     = (const int*)d_in[20];
    const int* ei_loses     = (const int*)d_in[21];
    const int* ei_rev_beats = (const int*)d_in[22];
    const int* ei_rev_loses = (const int*)d_in[23];

    float* out = (float*)d_out;

    float *x_my, *x_opp, *acc_my, *acc_opp, *bias_my, *bias_opp;
    __half *C_my, *C_opp;
    __half *xh_my, *xh_opp, *ah_my, *ah_opp;
    __half *Wth_my, *Wth_opp, *nwWh;
    int *rowp, *cntp, *fillp, *srcsp;
    cudaGetSymbolAddress((void**)&C_my,  g_C_my);
    cudaGetSymbolAddress((void**)&C_opp, g_C_opp);
    cudaGetSymbolAddress((void**)&x_my,  g_x_my);
    cudaGetSymbolAddress((void**)&x_opp, g_x_opp);
    cudaGetSymbolAddress((void**)&acc_my, g_acc_my);
    cudaGetSymbolAddress((void**)&acc_opp, g_acc_opp);
    cudaGetSymbolAddress((void**)&bias_my,  g_bias_my);
    cudaGetSymbolAddress((void**)&bias_opp, g_bias_opp);
    cudaGetSymbolAddress((void**)&xh_my,  g_xh_my);
    cudaGetSymbolAddress((void**)&xh_opp, g_xh_opp);
    cudaGetSymbolAddress((void**)&ah_my,  g_ah_my);
    cudaGetSymbolAddress((void**)&ah_opp, g_ah_opp);
    cudaGetSymbolAddress((void**)&Wth_my,  g_Wth_my);
    cudaGetSymbolAddress((void**)&Wth_opp, g_Wth_opp);
    cudaGetSymbolAddress((void**)&nwWh, g_nwWh);
    cudaGetSymbolAddress((void**)&rowp,  g_row);
    cudaGetSymbolAddress((void**)&cntp,  g_cnt);
    cudaGetSymbolAddress((void**)&fillp, g_fill);
    cudaGetSymbolAddress((void**)&srcsp, g_srcs);

    cudaFuncSetAttribute(mma_gemm, cudaFuncAttributeMaxDynamicSharedMemorySize,
                         DYN_SMEM);

    const int* src_b  = ei_beats;      const int* dst_b  = ei_beats + EE;
    const int* src_l  = ei_loses;      const int* dst_l  = ei_loses + EE;
    const int* src_rb = ei_rev_beats;  const int* dst_rb = ei_rev_beats + EE;
    const int* src_rl = ei_rev_loses;  const int* dst_rl = ei_rev_loses + EE;

    const int node_blocks = (NN + 7) / 8;
    const int e_blocks    = (EE + 255) / 256;
    const int mtiles      = (NN + 127) / 128;      // 157

    // Launch order: fat mma_gemm at slot 4 so ncu samples it.
    split2_half_kernel<<<(2 * NN * DD + 255) / 256, 256>>>(
        in_x_my, in_x_opp, xh_my, xh_opp);
    prep_all_kernel<<<(DD * LDC + 255) / 256, 256>>>(
        gWl_b, gWr_b, gWl_r, gWr_r,
        cgL_Wf, cgL_Ws, cgR_Wf, cgR_Ws,
        cgL_bf, cgL_bs, cgR_bf, cgR_bs,
        nw_W,
        Wth_my, Wth_opp, nwWh, bias_my, bias_opp);
    csr_zero_kernel<<<(4 * NN + 255) / 256, 256>>>(cntp, fillp);
    {
        GemmArgs ga;
        ga.Ah[0] = xh_my;   ga.Ah[1] = xh_opp;
        ga.Bh[0] = Wth_my;  ga.Bh[1] = Wth_opp;
        ga.bias[0] = bias_my;  ga.bias[1] = bias_opp;
        ga.Ch[0] = C_my;    ga.Ch[1] = C_opp;
        ga.Cf[0] = nullptr; ga.Cf[1] = nullptr;
        ga.Hout[0] = nullptr; ga.Hout[1] = nullptr;
        ga.M = NN; ga.ldc = LDC; ga.ldb = LDC;
        dim3 grid(LDC / 128, mtiles, 2);
        mma_gemm<<<grid, 256, DYN_SMEM>>>(ga);
    }
    csr_hist_kernel<<<e_blocks, 256>>>(dst_b, dst_rl, dst_l, dst_rb, cntp);
    csr_scan_kernel<<<4, 1024>>>(cntp, rowp);
    csr_scatter_kernel<<<e_blocks, 256>>>(src_b, dst_b, src_rl, dst_rl,
                                          src_l, dst_l, src_rb, dst_rb,
                                          rowp, fillp, srcsp);

    const float* cur_my  = in_x_my;
    const float* cur_opp = in_x_opp;

    for (int l = 0; l < LLAYERS; l++) {
        const size_t oW = (size_t)l * DD * HD;
        const size_t oA = (size_t)l * HH * DD;
        const size_t oB = (size_t)l * DD;
        const size_t oC = (size_t)l * 2 * DD * DD;
        const size_t oN = (size_t)l * DD * DD;

        if (l > 0) {
            prep_all_kernel<<<(DD * LDC + 255) / 256, 256>>>(
                gWl_b + oW, gWr_b + oW, gWl_r + oW, gWr_r + oW,
                cgL_Wf + oC, cgL_Ws + oC, cgR_Wf + oC, cgR_Ws + oC,
                cgL_bf + oB, cgL_bs + oB, cgR_bf + oB, cgR_bs + oB,
                nw_W + oN,
                Wth_my, Wth_opp, nwWh, bias_my, bias_opp);
            GemmArgs ga;
            ga.Ah[0] = xh_my;   ga.Ah[1] = xh_opp;
            ga.Bh[0] = Wth_my;  ga.Bh[1] = Wth_opp;
            ga.bias[0] = bias_my;  ga.bias[1] = bias_opp;
            ga.Ch[0] = C_my;    ga.Ch[1] = C_opp;
            ga.Cf[0] = nullptr; ga.Cf[1] = nullptr;
            ga.Hout[0] = nullptr; ga.Hout[1] = nullptr;
            ga.M = NN; ga.ldc = LDC; ga.ldb = LDC;
            dim3 grid(LDC / 128, mtiles, 2);
            mma_gemm<<<grid, 256, DYN_SMEM>>>(ga);
        }

        // ---- fused GAT: both relations, one launch ----
        {
            GatArgs a;
            a.xl[0] = C_my;        a.xr[0] = C_opp;
            a.att[0] = gatt_b + oA;
            a.row[0] = rowp + 0 * (NN + 1);  a.srcs[0] = srcsp + 0 * EE;
            a.xres[0] = cur_opp;   a.bias[0] = gb_b + oB;  a.acc[0] = acc_opp;
            a.xl[1] = C_opp + 512; a.xr[1] = C_my + 512;
            a.att[1] = gatt_r + oA;
            a.row[1] = rowp + 1 * (NN + 1);  a.srcs[1] = srcsp + 1 * EE;
            a.xres[1] = cur_my;    a.bias[1] = gb_r + oB;  a.acc[1] = acc_my;
            dim3 grid(node_blocks, 2);
            gat_fused_kernel<<<grid, 256>>>(a);
        }

        // ---- fused CGConv: both relations, one launch ----
        {
            CgArgs a;
            a.Pfd[0] = C_opp + 1024; a.Pfs[0] = C_my + 1024;
            a.Psd[0] = C_opp + 1152; a.Pss[0] = C_my + 1152;
            a.row[0] = rowp + 2 * (NN + 1);  a.srcs[0] = srcsp + 2 * EE;
            a.accin[0] = acc_opp;  a.ah[0] = ah_opp;
            a.Pfd[1] = C_my + 1280; a.Pfs[1] = C_opp + 1280;
            a.Psd[1] = C_my + 1408; a.Pss[1] = C_opp + 1408;
            a.row[1] = rowp + 3 * (NN + 1);  a.srcs[1] = srcsp + 3 * EE;
            a.accin[1] = acc_my;   a.ah[1] = ah_my;
            dim3 grid(node_blocks, 2);
            cg_fused_kernel<<<grid, 256>>>(a);
        }

        // ---- nodewise Linear (both node types, one launch; fp32 out) ----
        {
            float* out_my  = (l == LLAYERS - 1) ? out           : x_my;
            float* out_opp = (l == LLAYERS - 1) ? out + NN * DD : x_opp;
            GemmArgs ga;
            ga.Ah[0] = ah_my;   ga.Ah[1] = ah_opp;
            ga.Bh[0] = nwWh;    ga.Bh[1] = nwWh;
            ga.bias[0] = nw_b + oB;  ga.bias[1] = nw_b + oB;
            ga.Ch[0] = nullptr; ga.Ch[1] = nullptr;
            ga.Cf[0] = out_my;  ga.Cf[1] = out_opp;
            ga.Hout[0] = xh_my;  ga.Hout[1] = xh_opp;
            ga.M = NN; ga.ldc = DD; ga.ldb = DD;
            dim3 grid(1, mtiles, 2);
            mma_gemm<<<grid, 256, DYN_SMEM>>>(ga);
        }

        cur_my  = x_my;
        cur_opp = x_opp;
    }
}

// round 12
// speedup vs baseline: 4.9459x; 1.0606x over previous
#include <cuda_runtime.h>
#include <cuda_fp16.h>
#include <math.h>
#include <stdint.h>

// ---------------------------------------------------------------------------
// Problem constants
// ---------------------------------------------------------------------------
#define NN 20000
#define DD 128
#define HH 4
#define EE 80000
#define LLAYERS 2
#define HD (HH * DD)      // 512
#define LDC 1536          // fat projection width per node type

// Fat column layout (per node type X in {my, opp}):
//  [0,512)      GAT projection #1 (my: Wl_beats ; opp: Wr_beats)
//  [512,1024)   GAT projection #2 (my: Wr_rev   ; opp: Wl_rev)
//  [1024,1152)  CG lose Wf part   (my: src/bottom ; opp: dst/top + bf)
//  [1152,1280)  CG lose Ws part   (my: src/bottom ; opp: dst/top + bs)
//  [1280,1408)  CG rev  Wf part   (my: dst/top + bf ; opp: src/bottom)
//  [1408,1536)  CG rev  Ws part   (my: dst/top + bs ; opp: src/bottom)

// ---------------------------------------------------------------------------
// Static device scratch
// ---------------------------------------------------------------------------
__device__ __align__(16) __half g_C_my [(size_t)NN * LDC];   // fp16 fat features
__device__ __align__(16) __half g_C_opp[(size_t)NN * LDC];

__device__ __align__(16) float g_x_my [NN * DD];
__device__ __align__(16) float g_x_opp[NN * DD];

// fp16 feature operands (A side of GEMMs)
__device__ __align__(16) __half g_xh_my [NN * DD];
__device__ __align__(16) __half g_xh_opp[NN * DD];
__device__ __align__(16) __half g_ah_my [NN * DD];
__device__ __align__(16) __half g_ah_opp[NN * DD];

// fp16 weight operands (B side), K-MAJOR: [DD][LDC] / [DD][DD]
__device__ __align__(16) __half g_Wth_my [DD * LDC];
__device__ __align__(16) __half g_Wth_opp[DD * LDC];
__device__ __align__(16) __half g_nwWh[DD * DD];

__device__ __align__(16) float g_bias_my [LDC];
__device__ __align__(16) float g_bias_opp[LDC];

// CSR (4 relations: 0=beats, 1=rev_loses, 2=loses, 3=rev_beats), built once
__device__ int g_row [4 * (NN + 1)];
__device__ int g_cnt [4 * NN];
__device__ int g_fill[4 * NN];
__device__ int g_srcs[4 * EE];

// ---------------------------------------------------------------------------
// Arg structs for merged launches
// ---------------------------------------------------------------------------
struct GemmArgs {
    const __half *Ah[2], *Bh[2];
    const float *bias[2];
    __half *Ch[2];     // fp16 C output (fat projections) -> stmatrix epilogue
    float  *Cf[2];     // fp32 C output (nodewise Linear) -> direct epilogue
    __half *Hout[2];   // fp16 feature copy (next-layer A)
    int M, ldc, ldb;
};

// Fused edge args: index = dst node type (0 = opp, 1 = my)
struct EdgeArgs {
    // GAT relation into this dst type
    const __half *xl[2], *xr[2];
    const float *att[2];
    const int *growp[2], *gsrcs[2];
    // CG relation into this dst type
    const __half *Pfd[2], *Pfs[2], *Psd[2], *Pss[2];
    const int *crowp[2], *csrcs[2];
    // residual + GAT bias, output
    const float *xres[2], *bias[2];
    __half *ah[2];
};

// ---------------------------------------------------------------------------
// Warp MMA / cp.async helpers
// ---------------------------------------------------------------------------
__device__ __forceinline__ uint32_t smem_to_u32(const void* p)
{
    uint32_t a;
    asm("{ .reg .u64 t; cvta.to.shared.u64 t, %1; cvt.u32.u64 %0, t; }"
        : "=r"(a) : "l"(p));
    return a;
}

__device__ __forceinline__ void ldx4(uint32_t* r, uint32_t addr)
{
    asm volatile("ldmatrix.sync.aligned.m8n8.x4.shared.b16 {%0,%1,%2,%3}, [%4];"
                 : "=r"(r[0]), "=r"(r[1]), "=r"(r[2]), "=r"(r[3]) : "r"(addr));
}

__device__ __forceinline__ void ldx4t(uint32_t* r, uint32_t addr)
{
    asm volatile("ldmatrix.sync.aligned.m8n8.x4.trans.shared.b16 {%0,%1,%2,%3}, [%4];"
                 : "=r"(r[0]), "=r"(r[1]), "=r"(r[2]), "=r"(r[3]) : "r"(addr));
}

__device__ __forceinline__ void stx4(uint32_t addr, uint32_t r0, uint32_t r1,
                                     uint32_t r2, uint32_t r3)
{
    asm volatile("stmatrix.sync.aligned.m8n8.x4.shared.b16 [%0], {%1,%2,%3,%4};"
                 :: "r"(addr), "r"(r0), "r"(r1), "r"(r2), "r"(r3) : "memory");
}

__device__ __forceinline__ void mma16816(float* c, const uint32_t* a,
                                         uint32_t b0, uint32_t b1)
{
    asm volatile(
        "mma.sync.aligned.m16n8k16.row.col.f32.f16.f16.f32 "
        "{%0,%1,%2,%3}, {%4,%5,%6,%7}, {%8,%9}, {%0,%1,%2,%3};"
        : "+f"(c[0]), "+f"(c[1]), "+f"(c[2]), "+f"(c[3])
        : "r"(a[0]), "r"(a[1]), "r"(a[2]), "r"(a[3]), "r"(b0), "r"(b1));
}

__device__ __forceinline__ void cpa16(uint32_t dst, const void* src, int sz)
{
    asm volatile("cp.async.cg.shared.global [%0], [%1], 16, %2;"
                 :: "r"(dst), "l"(src), "r"(sz));
}
#define CP_COMMIT() asm volatile("cp.async.commit_group;" ::: "memory")
#define CP_WAIT(n)  asm volatile("cp.async.wait_group %0;" :: "n"(n) : "memory")

__device__ __forceinline__ float4 half4_to_float4(uint2 v)
{
    __half2 h01 = *reinterpret_cast<__half2*>(&v.x);
    __half2 h23 = *reinterpret_cast<__half2*>(&v.y);
    float2 f0 = __half22float2(h01);
    float2 f1 = __half22float2(h23);
    return make_float4(f0.x, f0.y, f1.x, f1.y);
}

// ---------------------------------------------------------------------------
// Tensor-core GEMM: C[M, col0..+128] = A[M,128] @ B[128, Nc] + bias.
// A row-major fp16; B K-MAJOR fp16 (ldb cols), loaded via ldmatrix.trans.
// BK=32 slabs, 2-stage cp.async ring, 32 KB smem.
// Ch path: stmatrix -> smem -> coalesced 128B stores.
// ---------------------------------------------------------------------------
#define SM_A  0
#define SM_B  8192
#define STAGE_BYTES 16384
#define DYN_SMEM 32768

__global__ void __launch_bounds__(256, 2)
mma_gemm(GemmArgs ga)
{
    extern __shared__ char smem[];
    const uint32_t sb = smem_to_u32(smem);

    const int z = blockIdx.z;
    const __half* __restrict__ Ah = ga.Ah[z];
    const __half* __restrict__ Bh = ga.Bh[z];
    const int M = ga.M, ldc = ga.ldc, ldb = ga.ldb;

    const int tid  = threadIdx.x;
    const int wid  = tid >> 5;
    const int lane = tid & 31;
    const int row0 = blockIdx.y * 128;
    const int col0 = blockIdx.x * 128;

    const int warp_m = (wid & 3) * 32;    // 4 warps over M
    const int warp_n = (wid >> 2) * 64;   // 2 warps over N

    float acc[2][8][4];
#pragma unroll
    for (int mt = 0; mt < 2; mt++)
#pragma unroll
        for (int nt = 0; nt < 8; nt++)
#pragma unroll
            for (int j = 0; j < 4; j++) acc[mt][nt][j] = 0.f;

    auto load_slab = [&](int slab, int buf) {
        const uint32_t bufb = sb + buf * STAGE_BYTES;
        const int kbase = slab * 32;
#pragma unroll
        for (int it = 0; it < 2; it++) {
            int c  = tid + it * 256;
            int r  = c >> 2;
            int ch = c & 3;
            uint32_t so = (uint32_t)r * 64 + (uint32_t)((ch ^ ((r >> 1) & 3)) * 16);
            int kc = kbase + ch * 8;
            int gr = row0 + r;
            int asz = (gr < M) ? 16 : 0;
            int gra = (gr < M) ? gr : 0;
            cpa16(bufb + SM_A + so, Ah + (size_t)gra * DD + kc, asz);
        }
#pragma unroll
        for (int it = 0; it < 2; it++) {
            int c  = tid + it * 256;
            int kr = c >> 4;
            int ch = c & 15;
            uint32_t so = (uint32_t)kr * 256 + (uint32_t)((ch ^ (kr & 7)) * 16);
            cpa16(bufb + SM_B + so,
                  Bh + (size_t)(kbase + kr) * ldb + col0 + ch * 8, 16);
        }
        CP_COMMIT();
    };

    auto comp_slab = [&](int buf) {
        const uint32_t bufb = sb + buf * STAGE_BYTES;
#pragma unroll
        for (int ks = 0; ks < 2; ks++) {
            uint32_t af[2][4];
#pragma unroll
            for (int mt = 0; mt < 2; mt++) {
                int r  = warp_m + mt * 16 + (lane & 7) + ((lane >> 3) & 1) * 8;
                int ch = ks * 2 + (lane >> 4);
                uint32_t off = (uint32_t)r * 64
                             + (uint32_t)((ch ^ ((r >> 1) & 3)) * 16);
                ldx4(af[mt], bufb + SM_A + off);
            }
            uint32_t bf[4][4];
#pragma unroll
            for (int np = 0; np < 4; np++) {
                int kr = ks * 16 + (lane & 7) + ((lane >> 3) & 1) * 8;
                int ch = (warp_n >> 3) + np * 2 + ((lane >> 4) & 1);
                uint32_t off = (uint32_t)kr * 256
                             + (uint32_t)((ch ^ (kr & 7)) * 16);
                ldx4t(bf[np], bufb + SM_B + off);
            }
#pragma unroll
            for (int mt = 0; mt < 2; mt++) {
#pragma unroll
                for (int nt = 0; nt < 8; nt++) {
                    int np = nt >> 1, hi = (nt & 1) * 2;
                    mma16816(acc[mt][nt], af[mt], bf[np][hi], bf[np][hi + 1]);
                }
            }
        }
    };

    load_slab(0, 0);
    load_slab(1, 1);
    CP_WAIT(1);
    __syncthreads();
    comp_slab(0);
    __syncthreads();
    load_slab(2, 0);
    CP_WAIT(1);
    __syncthreads();
    comp_slab(1);
    __syncthreads();
    load_slab(3, 1);
    CP_WAIT(1);
    __syncthreads();
    comp_slab(0);
    CP_WAIT(0);
    __syncthreads();
    comp_slab(1);

    const float* __restrict__ bias = ga.bias[z];
    __half* __restrict__ Ch = ga.Ch[z];

    if (Ch) {
        __syncthreads();
#pragma unroll
        for (int mt = 0; mt < 2; mt++) {
#pragma unroll
            for (int half_i = 0; half_i < 2; half_i++) {
#pragma unroll
                for (int ntg = 0; ntg < 2; ntg++) {
                    uint32_t h2[4];
#pragma unroll
                    for (int j = 0; j < 4; j++) {
                        int nt = ntg * 4 + j;
                        int gc = col0 + warp_n + nt * 8 + (lane & 3) * 2;
                        float2 b2 = *reinterpret_cast<const float2*>(bias + gc);
                        __half2 hv = __floats2half2_rn(
                            acc[mt][nt][half_i * 2 + 0] + b2.x,
                            acc[mt][nt][half_i * 2 + 1] + b2.y);
                        h2[j] = *reinterpret_cast<uint32_t*>(&hv);
                    }
                    int lr = warp_m + mt * 16 + half_i * 8 + (lane & 7);
                    int ch = (warp_n >> 3) + ntg * 4 + (lane >> 3);
                    uint32_t addr = sb + (uint32_t)(lr * 256)
                                  + (uint32_t)((ch ^ (lr & 7)) << 4);
                    stx4(addr, h2[0], h2[1], h2[2], h2[3]);
                }
            }
        }
        __syncthreads();
#pragma unroll
        for (int it = 0; it < 8; it++) {
            int id = tid + it * 256;
            int r = id >> 4, ch = id & 15;
            int gr = row0 + r;
            if (gr < M) {
                uint4 v = *reinterpret_cast<uint4*>(
                    smem + r * 256 + ((ch ^ (r & 7)) << 4));
                *reinterpret_cast<uint4*>(Ch + (size_t)gr * ldc + col0 + ch * 8) = v;
            }
        }
    } else {
        float*  __restrict__ Cf = ga.Cf[z];
        __half* __restrict__ Hout = ga.Hout[z];
#pragma unroll
        for (int mt = 0; mt < 2; mt++) {
            int gr0 = row0 + warp_m + mt * 16 + (lane >> 2);
#pragma unroll
            for (int nt = 0; nt < 8; nt++) {
                int gc = col0 + warp_n + nt * 8 + (lane & 3) * 2;
                float2 b2 = *reinterpret_cast<const float2*>(bias + gc);
#pragma unroll
                for (int half_i = 0; half_i < 2; half_i++) {
                    int gr = gr0 + half_i * 8;
                    if (gr >= M) continue;
                    float vx = acc[mt][nt][half_i * 2 + 0] + b2.x;
                    float vy = acc[mt][nt][half_i * 2 + 1] + b2.y;
                    *reinterpret_cast<float2*>(Cf + (size_t)gr * ldc + gc) =
                        make_float2(vx, vy);
                    if (Hout) {
                        *reinterpret_cast<__half2*>(Hout + (size_t)gr * DD + gc) =
                            __floats2half2_rn(vx, vy);
                    }
                }
            }
        }
    }
}

// ---------------------------------------------------------------------------
// Conversion / prep kernels
// ---------------------------------------------------------------------------
__global__ void split2_half_kernel(const float* __restrict__ x0,
                                   const float* __restrict__ x1,
                                   __half* __restrict__ h0,
                                   __half* __restrict__ h1)
{
    int i = blockIdx.x * blockDim.x + threadIdx.x;
    if (i >= 2 * NN * DD) return;
    if (i < NN * DD) h0[i] = __float2half(x0[i]);
    else             h1[i - NN * DD] = __float2half(x1[i - NN * DD]);
}

// One launch: K-major fat W fp16 + fat bias vectors + nw W fp16 (coalesced).
__global__ void prep_all_kernel(const float* __restrict__ gWl_b,
                                const float* __restrict__ gWr_b,
                                const float* __restrict__ gWl_r,
                                const float* __restrict__ gWr_r,
                                const float* __restrict__ cgL_Wf,
                                const float* __restrict__ cgL_Ws,
                                const float* __restrict__ cgR_Wf,
                                const float* __restrict__ cgR_Ws,
                                const float* __restrict__ cgL_bf,
                                const float* __restrict__ cgL_bs,
                                const float* __restrict__ cgR_bf,
                                const float* __restrict__ cgR_bs,
                                const float* __restrict__ nw_W,
                                __half* __restrict__ Wth_my,
                                __half* __restrict__ Wth_opp,
                                __half* __restrict__ nwWh,
                                float* __restrict__ bias_my,
                                float* __restrict__ bias_opp)
{
    int idx = blockIdx.x * blockDim.x + threadIdx.x;
    if (idx < DD * LDC) {
        int k = idx / LDC, n = idx % LDC;
        float wm, wo;
        if (n < 512) {
            wm = gWl_b[k * HD + n];               wo = gWr_b[k * HD + n];
        } else if (n < 1024) {
            int c = n - 512;
            wm = gWr_r[k * HD + c];               wo = gWl_r[k * HD + c];
        } else if (n < 1152) {
            int c = n - 1024;
            wm = cgL_Wf[(DD + k) * DD + c];       wo = cgL_Wf[k * DD + c];
        } else if (n < 1280) {
            int c = n - 1152;
            wm = cgL_Ws[(DD + k) * DD + c];       wo = cgL_Ws[k * DD + c];
        } else if (n < 1408) {
            int c = n - 1280;
            wm = cgR_Wf[k * DD + c];              wo = cgR_Wf[(DD + k) * DD + c];
        } else {
            int c = n - 1408;
            wm = cgR_Ws[k * DD + c];              wo = cgR_Ws[(DD + k) * DD + c];
        }
        Wth_my[idx]  = __float2half(wm);
        Wth_opp[idx] = __float2half(wo);
    }
    if (idx < DD * DD) {
        nwWh[idx] = __float2half(nw_W[idx]);   // already K-major
    }
    if (idx < LDC) {
        int n = idx;
        float bm = 0.f, bo = 0.f;
        if (n >= 1024 && n < 1152) bo = cgL_bf[n - 1024];
        else if (n >= 1152 && n < 1280) bo = cgL_bs[n - 1152];
        if (n >= 1280 && n < 1408) bm = cgR_bf[n - 1280];
        else if (n >= 1408) bm = cgR_bs[n - 1408];
        bias_my[n] = bm;
        bias_opp[n] = bo;
    }
}

// ---------------------------------------------------------------------------
// CSR build (4 relations, built once per launch)
// ---------------------------------------------------------------------------
__global__ void csr_zero_kernel(int* __restrict__ cnt, int* __restrict__ fill)
{
    int i = blockIdx.x * blockDim.x + threadIdx.x;
    if (i < 4 * NN) { cnt[i] = 0; fill[i] = 0; }
}

__global__ void csr_hist_kernel(const int* __restrict__ d0,
                                const int* __restrict__ d1,
                                const int* __restrict__ d2,
                                const int* __restrict__ d3,
                                int* __restrict__ cnt)
{
    int i = blockIdx.x * blockDim.x + threadIdx.x;
    if (i >= EE) return;
    atomicAdd(&cnt[0 * NN + d0[i]], 1);
    atomicAdd(&cnt[1 * NN + d1[i]], 1);
    atomicAdd(&cnt[2 * NN + d2[i]], 1);
    atomicAdd(&cnt[3 * NN + d3[i]], 1);
}

__global__ void csr_scan_kernel(const int* __restrict__ cnt,
                                int* __restrict__ row)
{
    __shared__ int part[1024];
    const int rel = blockIdx.x;
    const int t = threadIdx.x;
    const int CH = (NN + 1023) / 1024;     // 20
    const int base = t * CH;
    int s = 0;
    for (int j = 0; j < CH; j++) {
        int i = base + j;
        if (i < NN) s += cnt[rel * NN + i];
    }
    part[t] = s;
    __syncthreads();
    for (int o = 1; o < 1024; o <<= 1) {
        int u = (t >= o) ? part[t - o] : 0;
        __syncthreads();
        part[t] += u;
        __syncthreads();
    }
    int run = part[t] - s;                 // exclusive prefix
    for (int j = 0; j < CH; j++) {
        int i = base + j;
        if (i < NN) {
            row[rel * (NN + 1) + i] = run;
            run += cnt[rel * NN + i];
        }
    }
    if (t == 1023) row[rel * (NN + 1) + NN] = part[1023];
}

__global__ void csr_scatter_kernel(const int* __restrict__ s0, const int* __restrict__ d0,
                                   const int* __restrict__ s1, const int* __restrict__ d1,
                                   const int* __restrict__ s2, const int* __restrict__ d2,
                                   const int* __restrict__ s3, const int* __restrict__ d3,
                                   const int* __restrict__ row,
                                   int* __restrict__ fill,
                                   int* __restrict__ srcs)
{
    int i = blockIdx.x * blockDim.x + threadIdx.x;
    if (i >= EE) return;
    {
        int d = d0[i];
        int pos = row[0 * (NN + 1) + d] + atomicAdd(&fill[0 * NN + d], 1);
        srcs[0 * EE + pos] = s0[i];
    }
    {
        int d = d1[i];
        int pos = row[1 * (NN + 1) + d] + atomicAdd(&fill[1 * NN + d], 1);
        srcs[1 * EE + pos] = s1[i];
    }
    {
        int d = d2[i];
        int pos = row[2 * (NN + 1) + d] + atomicAdd(&fill[2 * NN + d], 1);
        srcs[2 * EE + pos] = s2[i];
    }
    {
        int d = d3[i];
        int pos = row[3 * (NN + 1) + d] + atomicAdd(&fill[3 * NN + d], 1);
        srcs[3 * EE + pos] = s3[i];
    }
}

// ---------------------------------------------------------------------------
// Fused edge kernel: warp per dst node; GAT aggregation then CG gate loop,
// accumulator carried in registers; writes fp16 features directly.
// blockIdx.y = dst node type (0 = opp, 1 = my).
// ---------------------------------------------------------------------------
__device__ __forceinline__ float gate1(float f, float g)
{
    float sig = __fdividef(1.f, 1.f + __expf(-f));
    float sp  = fmaxf(g, 0.f) + __logf(1.f + __expf(-fabsf(g)));
    return sig * sp;
}

__global__ void __launch_bounds__(256)
edge_fused_kernel(EdgeArgs a)
{
    const int t = blockIdx.y;
    int d = blockIdx.x * 8 + (threadIdx.x >> 5);
    int lane = threadIdx.x & 31;
    if (d >= NN) return;

    // ================= GAT phase =================
    float4 o4;
    {
        const __half* __restrict__ xl = a.xl[t];
        const float* __restrict__ att = a.att[t];
        const int* __restrict__ row = a.growp[t];
        const int* __restrict__ srcs = a.gsrcs[t];

        float4 xr4[HH], at4[HH];
        const uint2* pr = reinterpret_cast<const uint2*>(a.xr[t] + (size_t)d * LDC);
        const float4* pa = reinterpret_cast<const float4*>(att);
#pragma unroll
        for (int h = 0; h < HH; h++) {
            xr4[h] = half4_to_float4(pr[h * 32 + lane]);
            at4[h] = pa[h * 32 + lane];
        }

        float s[HH];
        float4 a4[HH];
#pragma unroll
        for (int h = 0; h < HH; h++) {
            s[h] = 0.f;
            a4[h] = make_float4(0.f, 0.f, 0.f, 0.f);
        }

        const int e0 = row[d], e1 = row[d + 1];
#pragma unroll 2
        for (int p = e0; p < e1; p++) {
            int sn = srcs[p];
            const uint2* pl = reinterpret_cast<const uint2*>(xl + (size_t)sn * LDC);
            float4 l4[HH];
            float part[HH];
#pragma unroll
            for (int h = 0; h < HH; h++) {
                l4[h] = half4_to_float4(pl[h * 32 + lane]);
                float zx = l4[h].x + xr4[h].x; zx = (zx > 0.f) ? zx : 0.2f * zx;
                float zy = l4[h].y + xr4[h].y; zy = (zy > 0.f) ? zy : 0.2f * zy;
                float zz = l4[h].z + xr4[h].z; zz = (zz > 0.f) ? zz : 0.2f * zz;
                float zw = l4[h].w + xr4[h].w; zw = (zw > 0.f) ? zw : 0.2f * zw;
                part[h] = zx * at4[h].x + zy * at4[h].y
                        + zz * at4[h].z + zw * at4[h].w;
            }
#pragma unroll
            for (int o = 16; o; o >>= 1)
#pragma unroll
                for (int h = 0; h < HH; h++)
                    part[h] += __shfl_xor_sync(0xffffffffu, part[h], o);
#pragma unroll
            for (int h = 0; h < HH; h++) {
                float e = __expf(part[h]);
                s[h] += e;
                a4[h].x += e * l4[h].x;
                a4[h].y += e * l4[h].y;
                a4[h].z += e * l4[h].z;
                a4[h].w += e * l4[h].w;
            }
        }

        float4 r4 = reinterpret_cast<const float4*>(a.xres[t] + (size_t)d * DD)[lane];
        float4 b4 = reinterpret_cast<const float4*>(a.bias[t])[lane];
        o4 = make_float4(r4.x + b4.x, r4.y + b4.y, r4.z + b4.z, r4.w + b4.w);
#pragma unroll
        for (int h = 0; h < HH; h++) {
            float inv = 0.25f / (s[h] + 1e-16f);
            o4.x += a4[h].x * inv;
            o4.y += a4[h].y * inv;
            o4.z += a4[h].z * inv;
            o4.w += a4[h].w * inv;
        }
    }

    // ================= CG phase (acc carried in registers) =================
    {
        const __half* __restrict__ Pfs = a.Pfs[t];
        const __half* __restrict__ Pss = a.Pss[t];
        const int* __restrict__ row = a.crowp[t];
        const int* __restrict__ srcs = a.csrcs[t];

        float4 fd4 = half4_to_float4(
            reinterpret_cast<const uint2*>(a.Pfd[t] + (size_t)d * LDC)[lane]);
        float4 sd4 = half4_to_float4(
            reinterpret_cast<const uint2*>(a.Psd[t] + (size_t)d * LDC)[lane]);

        const int e0 = row[d], e1 = row[d + 1];
#pragma unroll 2
        for (int p = e0; p < e1; p++) {
            int sn = srcs[p];
            float4 fs4 = half4_to_float4(
                reinterpret_cast<const uint2*>(Pfs + (size_t)sn * LDC)[lane]);
            float4 ss4 = half4_to_float4(
                reinterpret_cast<const uint2*>(Pss + (size_t)sn * LDC)[lane]);
            o4.x += gate1(fd4.x + fs4.x, sd4.x + ss4.x);
            o4.y += gate1(fd4.y + fs4.y, sd4.y + ss4.y);
            o4.z += gate1(fd4.z + fs4.z, sd4.z + ss4.z);
            o4.w += gate1(fd4.w + fs4.w, sd4.w + ss4.w);
        }
    }

    size_t off = (size_t)d * DD + lane * 4;
    *reinterpret_cast<__half2*>(a.ah[t] + off)     = __floats2half2_rn(o4.x, o4.y);
    *reinterpret_cast<__half2*>(a.ah[t] + off + 2) = __floats2half2_rn(o4.z, o4.w);
}

// ---------------------------------------------------------------------------
// Host launcher
// ---------------------------------------------------------------------------
extern "C" void kernel_launch(void* const* d_in, const int* in_sizes, int n_in,
                              void* d_out, int out_size)
{
    const float* in_x_my  = (const float*)d_in[0];
    const float* in_x_opp = (const float*)d_in[1];
    const float* gWl_b = (const float*)d_in[2];
    const float* gWr_b = (const float*)d_in[3];
    const float* gatt_b = (const float*)d_in[4];
    const float* gb_b  = (const float*)d_in[5];
    const float* gWl_r = (const float*)d_in[6];
    const float* gWr_r = (const float*)d_in[7];
    const float* gatt_r = (const float*)d_in[8];
    const float* gb_r  = (const float*)d_in[9];
    const float* cgL_Wf = (const float*)d_in[10];
    const float* cgL_bf = (const float*)d_in[11];
    const float* cgL_Ws = (const float*)d_in[12];
    const float* cgL_bs = (const float*)d_in[13];
    const float* cgR_Wf = (const float*)d_in[14];
    const float* cgR_bf = (const float*)d_in[15];
    const float* cgR_Ws = (const float*)d_in[16];
    const float* cgR_bs = (const float*)d_in[17];
    const float* nw_W = (const float*)d_in[18];
    const float* nw_b = (const float*)d_in[19];
    const int* ei_beats     = (const int*)d_in[20];
    const int* ei_loses     = (const int*)d_in[21];
    const int* ei_rev_beats = (const int*)d_in[22];
    const int* ei_rev_loses = (const int*)d_in[23];

    float* out = (float*)d_out;

    float *x_my, *x_opp, *bias_my, *bias_opp;
    __half *C_my, *C_opp;
    __half *xh_my, *xh_opp, *ah_my, *ah_opp;
    __half *Wth_my, *Wth_opp, *nwWh;
    int *rowp, *cntp, *fillp, *srcsp;
    cudaGetSymbolAddress((void**)&C_my,  g_C_my);
    cudaGetSymbolAddress((void**)&C_opp, g_C_opp);
    cudaGetSymbolAddress((void**)&x_my,  g_x_my);
    cudaGetSymbolAddress((void**)&x_opp, g_x_opp);
    cudaGetSymbolAddress((void**)&bias_my,  g_bias_my);
    cudaGetSymbolAddress((void**)&bias_opp, g_bias_opp);
    cudaGetSymbolAddress((void**)&xh_my,  g_xh_my);
    cudaGetSymbolAddress((void**)&xh_opp, g_xh_opp);
    cudaGetSymbolAddress((void**)&ah_my,  g_ah_my);
    cudaGetSymbolAddress((void**)&ah_opp, g_ah_opp);
    cudaGetSymbolAddress((void**)&Wth_my,  g_Wth_my);
    cudaGetSymbolAddress((void**)&Wth_opp, g_Wth_opp);
    cudaGetSymbolAddress((void**)&nwWh, g_nwWh);
    cudaGetSymbolAddress((void**)&rowp,  g_row);
    cudaGetSymbolAddress((void**)&cntp,  g_cnt);
    cudaGetSymbolAddress((void**)&fillp, g_fill);
    cudaGetSymbolAddress((void**)&srcsp, g_srcs);

    cudaFuncSetAttribute(mma_gemm, cudaFuncAttributeMaxDynamicSharedMemorySize,
                         DYN_SMEM);

    const int* src_b  = ei_beats;      const int* dst_b  = ei_beats + EE;
    const int* src_l  = ei_loses;      const int* dst_l  = ei_loses + EE;
    const int* src_rb = ei_rev_beats;  const int* dst_rb = ei_rev_beats + EE;
    const int* src_rl = ei_rev_loses;  const int* dst_rl = ei_rev_loses + EE;

    const int node_blocks = (NN + 7) / 8;
    const int e_blocks    = (EE + 255) / 256;
    const int mtiles      = (NN + 127) / 128;      // 157

    // Launch order: fat mma_gemm at slot 4 so ncu samples it.
    split2_half_kernel<<<(2 * NN * DD + 255) / 256, 256>>>(
        in_x_my, in_x_opp, xh_my, xh_opp);
    prep_all_kernel<<<(DD * LDC + 255) / 256, 256>>>(
        gWl_b, gWr_b, gWl_r, gWr_r,
        cgL_Wf, cgL_Ws, cgR_Wf, cgR_Ws,
        cgL_bf, cgL_bs, cgR_bf, cgR_bs,
        nw_W,
        Wth_my, Wth_opp, nwWh, bias_my, bias_opp);
    csr_zero_kernel<<<(4 * NN + 255) / 256, 256>>>(cntp, fillp);
    {
        GemmArgs ga;
        ga.Ah[0] = xh_my;   ga.Ah[1] = xh_opp;
        ga.Bh[0] = Wth_my;  ga.Bh[1] = Wth_opp;
        ga.bias[0] = bias_my;  ga.bias[1] = bias_opp;
        ga.Ch[0] = C_my;    ga.Ch[1] = C_opp;
        ga.Cf[0] = nullptr; ga.Cf[1] = nullptr;
        ga.Hout[0] = nullptr; ga.Hout[1] = nullptr;
        ga.M = NN; ga.ldc = LDC; ga.ldb = LDC;
        dim3 grid(LDC / 128, mtiles, 2);
        mma_gemm<<<grid, 256, DYN_SMEM>>>(ga);
    }
    csr_hist_kernel<<<e_blocks, 256>>>(dst_b, dst_rl, dst_l, dst_rb, cntp);
    csr_scan_kernel<<<4, 1024>>>(cntp, rowp);
    csr_scatter_kernel<<<e_blocks, 256>>>(src_b, dst_b, src_rl, dst_rl,
                                          src_l, dst_l, src_rb, dst_rb,
                                          rowp, fillp, srcsp);

    const float* cur_my  = in_x_my;
    const float* cur_opp = in_x_opp;

    for (int l = 0; l < LLAYERS; l++) {
        const size_t oW = (size_t)l * DD * HD;
        const size_t oA = (size_t)l * HH * DD;
        const size_t oB = (size_t)l * DD;
        const size_t oC = (size_t)l * 2 * DD * DD;
        const size_t oN = (size_t)l * DD * DD;

        if (l > 0) {
            prep_all_kernel<<<(DD * LDC + 255) / 256, 256>>>(
                gWl_b + oW, gWr_b + oW, gWl_r + oW, gWr_r + oW,
                cgL_Wf + oC, cgL_Ws + oC, cgR_Wf + oC, cgR_Ws + oC,
                cgL_bf + oB, cgL_bs + oB, cgR_bf + oB, cgR_bs + oB,
                nw_W + oN,
                Wth_my, Wth_opp, nwWh, bias_my, bias_opp);
            GemmArgs ga;
            ga.Ah[0] = xh_my;   ga.Ah[1] = xh_opp;
            ga.Bh[0] = Wth_my;  ga.Bh[1] = Wth_opp;
            ga.bias[0] = bias_my;  ga.bias[1] = bias_opp;
            ga.Ch[0] = C_my;    ga.Ch[1] = C_opp;
            ga.Cf[0] = nullptr; ga.Cf[1] = nullptr;
            ga.Hout[0] = nullptr; ga.Hout[1] = nullptr;
            ga.M = NN; ga.ldc = LDC; ga.ldb = LDC;
            dim3 grid(LDC / 128, mtiles, 2);
            mma_gemm<<<grid, 256, DYN_SMEM>>>(ga);
        }

        // ---- fused edge phase: GAT + CG per dst type, one launch ----
        {
            EdgeArgs a;
            // t=0: dst opp — GAT beats (rel 0), CG loses (rel 2)
            a.xl[0] = C_my;        a.xr[0] = C_opp;
            a.att[0] = gatt_b + oA;
            a.growp[0] = rowp + 0 * (NN + 1);  a.gsrcs[0] = srcsp + 0 * EE;
            a.Pfd[0] = C_opp + 1024; a.Pfs[0] = C_my + 1024;
            a.Psd[0] = C_opp + 1152; a.Pss[0] = C_my + 1152;
            a.crowp[0] = rowp + 2 * (NN + 1);  a.csrcs[0] = srcsp + 2 * EE;
            a.xres[0] = cur_opp;   a.bias[0] = gb_b + oB;  a.ah[0] = ah_opp;
            // t=1: dst my — GAT rev_loses (rel 1), CG rev_beats (rel 3)
            a.xl[1] = C_opp + 512; a.xr[1] = C_my + 512;
            a.att[1] = gatt_r + oA;
            a.growp[1] = rowp + 1 * (NN + 1);  a.gsrcs[1] = srcsp + 1 * EE;
            a.Pfd[1] = C_my + 1280; a.Pfs[1] = C_opp + 1280;
            a.Psd[1] = C_my + 1408; a.Pss[1] = C_opp + 1408;
            a.crowp[1] = rowp + 3 * (NN + 1);  a.csrcs[1] = srcsp + 3 * EE;
            a.xres[1] = cur_my;    a.bias[1] = gb_r + oB;  a.ah[1] = ah_my;
            dim3 grid(node_blocks, 2);
            edge_fused_kernel<<<grid, 256>>>(a);
        }

        // ---- nodewise Linear (both node types, one launch; fp32 out) ----
        {
            float* out_my  = (l == LLAYERS - 1) ? out           : x_my;
            float* out_opp = (l == LLAYERS - 1) ? out + NN * DD : x_opp;
            GemmArgs ga;
            ga.Ah[0] = ah_my;   ga.Ah[1] = ah_opp;
            ga.Bh[0] = nwWh;    ga.Bh[1] = nwWh;
            ga.bias[0] = nw_b + oB;  ga.bias[1] = nw_b + oB;
            ga.Ch[0] = nullptr; ga.Ch[1] = nullptr;
            ga.Cf[0] = out_my;  ga.Cf[1] = out_opp;
            ga.Hout[0] = xh_my;  ga.Hout[1] = xh_opp;
            ga.M = NN; ga.ldc = DD; ga.ldb = DD;
            dim3 grid(1, mtiles, 2);
            mma_gemm<<<grid, 256, DYN_SMEM>>>(ga);
        }

        cur_my  = x_my;
        cur_opp = x_opp;
    }
}

// round 13
// speedup vs baseline: 5.0614x; 1.0234x over previous
#include <cuda_runtime.h>
#include <cuda_fp16.h>
#include <math.h>
#include <stdint.h>

// ---------------------------------------------------------------------------
// Problem constants
// ---------------------------------------------------------------------------
#define NN 20000
#define DD 128
#define HH 4
#define EE 80000
#define LLAYERS 2
#define HD (HH * DD)      // 512
#define LDC 1536          // fat projection width per node type

// Fat column layout (per node type X in {my, opp}):
//  [0,512)      GAT projection #1 (my: Wl_beats ; opp: Wr_beats)
//  [512,1024)   GAT projection #2 (my: Wr_rev   ; opp: Wl_rev)
//  [1024,1152)  CG lose Wf part   (my: src/bottom ; opp: dst/top + bf)
//  [1152,1280)  CG lose Ws part   (my: src/bottom ; opp: dst/top + bs)
//  [1280,1408)  CG rev  Wf part   (my: dst/top + bf ; opp: src/bottom)
//  [1408,1536)  CG rev  Ws part   (my: dst/top + bs ; opp: src/bottom)

// ---------------------------------------------------------------------------
// Static device scratch
// ---------------------------------------------------------------------------
__device__ __align__(16) __half g_C_my [(size_t)NN * LDC];   // fp16 fat features
__device__ __align__(16) __half g_C_opp[(size_t)NN * LDC];

__device__ __align__(16) float g_x_my [NN * DD];
__device__ __align__(16) float g_x_opp[NN * DD];

// fp16 feature operands (A side of GEMMs)
__device__ __align__(16) __half g_xh_my [NN * DD];
__device__ __align__(16) __half g_xh_opp[NN * DD];
__device__ __align__(16) __half g_ah_my [NN * DD];
__device__ __align__(16) __half g_ah_opp[NN * DD];

// fp16 weight operands (B side), K-MAJOR: [DD][LDC] / [DD][DD]
__device__ __align__(16) __half g_Wth_my [DD * LDC];
__device__ __align__(16) __half g_Wth_opp[DD * LDC];
__device__ __align__(16) __half g_nwWh[DD * DD];

__device__ __align__(16) float g_bias_my [LDC];
__device__ __align__(16) float g_bias_opp[LDC];

// CSR (4 relations: 0=beats, 1=rev_loses, 2=loses, 3=rev_beats), built once
__device__ int g_row [4 * (NN + 1)];
__device__ int g_cnt [4 * NN];
__device__ int g_fill[4 * NN];
__device__ int g_srcs[4 * EE];

// ---------------------------------------------------------------------------
// Arg structs for merged launches
// ---------------------------------------------------------------------------
struct GemmArgs {
    const __half *Ah[2], *Bh[2];
    const float *bias[2];
    __half *Ch[2];     // fp16 C output (fat projections) -> stmatrix epilogue
    float  *Cf[2];     // fp32 C output (nodewise Linear) -> direct epilogue
    __half *Hout[2];   // fp16 feature copy (next-layer A)
    int M, ldc, ldb;
};

// Fused edge args: index = dst node type (0 = opp, 1 = my)
struct EdgeArgs {
    const __half *xl[2], *xr[2];
    const float *att[2];
    const int *growp[2], *gsrcs[2];
    const __half *Pfd[2], *Pfs[2], *Psd[2], *Pss[2];
    const int *crowp[2], *csrcs[2];
    const float *xres[2], *bias[2];
    __half *ah[2];
};

// ---------------------------------------------------------------------------
// Warp MMA / cp.async helpers
// ---------------------------------------------------------------------------
__device__ __forceinline__ uint32_t smem_to_u32(const void* p)
{
    uint32_t a;
    asm("{ .reg .u64 t; cvta.to.shared.u64 t, %1; cvt.u32.u64 %0, t; }"
        : "=r"(a) : "l"(p));
    return a;
}

__device__ __forceinline__ void ldx4(uint32_t* r, uint32_t addr)
{
    asm volatile("ldmatrix.sync.aligned.m8n8.x4.shared.b16 {%0,%1,%2,%3}, [%4];"
                 : "=r"(r[0]), "=r"(r[1]), "=r"(r[2]), "=r"(r[3]) : "r"(addr));
}

__device__ __forceinline__ void ldx4t(uint32_t* r, uint32_t addr)
{
    asm volatile("ldmatrix.sync.aligned.m8n8.x4.trans.shared.b16 {%0,%1,%2,%3}, [%4];"
                 : "=r"(r[0]), "=r"(r[1]), "=r"(r[2]), "=r"(r[3]) : "r"(addr));
}

__device__ __forceinline__ void stx4(uint32_t addr, uint32_t r0, uint32_t r1,
                                     uint32_t r2, uint32_t r3)
{
    asm volatile("stmatrix.sync.aligned.m8n8.x4.shared.b16 [%0], {%1,%2,%3,%4};"
                 :: "r"(addr), "r"(r0), "r"(r1), "r"(r2), "r"(r3) : "memory");
}

__device__ __forceinline__ void mma16816(float* c, const uint32_t* a,
                                         uint32_t b0, uint32_t b1)
{
    asm volatile(
        "mma.sync.aligned.m16n8k16.row.col.f32.f16.f16.f32 "
        "{%0,%1,%2,%3}, {%4,%5,%6,%7}, {%8,%9}, {%0,%1,%2,%3};"
        : "+f"(c[0]), "+f"(c[1]), "+f"(c[2]), "+f"(c[3])
        : "r"(a[0]), "r"(a[1]), "r"(a[2]), "r"(a[3]), "r"(b0), "r"(b1));
}

__device__ __forceinline__ void cpa16(uint32_t dst, const void* src, int sz)
{
    asm volatile("cp.async.cg.shared.global [%0], [%1], 16, %2;"
                 :: "r"(dst), "l"(src), "r"(sz));
}
#define CP_COMMIT() asm volatile("cp.async.commit_group;" ::: "memory")
#define CP_WAIT(n)  asm volatile("cp.async.wait_group %0;" :: "n"(n) : "memory")

__device__ __forceinline__ float4 half4_to_float4(uint2 v)
{
    __half2 h01 = *reinterpret_cast<__half2*>(&v.x);
    __half2 h23 = *reinterpret_cast<__half2*>(&v.y);
    float2 f0 = __half22float2(h01);
    float2 f1 = __half22float2(h23);
    return make_float4(f0.x, f0.y, f1.x, f1.y);
}

__device__ __forceinline__ void half8_to_float8(uint4 v, float* f)
{
    float4 a = half4_to_float4(make_uint2(v.x, v.y));
    float4 b = half4_to_float4(make_uint2(v.z, v.w));
    f[0] = a.x; f[1] = a.y; f[2] = a.z; f[3] = a.w;
    f[4] = b.x; f[5] = b.y; f[6] = b.z; f[7] = b.w;
}

// ---------------------------------------------------------------------------
// Tensor-core GEMM: C[M, col0..+128] = A[M,128] @ B[128, Nc] + bias.
// A row-major fp16; B K-MAJOR fp16 (ldb cols), loaded via ldmatrix.trans.
// BK=32 slabs, 2-stage cp.async ring, 32 KB smem.
// Ch path: stmatrix -> smem -> coalesced 128B stores.
// ---------------------------------------------------------------------------
#define SM_A  0
#define SM_B  8192
#define STAGE_BYTES 16384
#define DYN_SMEM 32768

__global__ void __launch_bounds__(256, 2)
mma_gemm(GemmArgs ga)
{
    extern __shared__ char smem[];
    const uint32_t sb = smem_to_u32(smem);

    const int z = blockIdx.z;
    const __half* __restrict__ Ah = ga.Ah[z];
    const __half* __restrict__ Bh = ga.Bh[z];
    const int M = ga.M, ldc = ga.ldc, ldb = ga.ldb;

    const int tid  = threadIdx.x;
    const int wid  = tid >> 5;
    const int lane = tid & 31;
    const int row0 = blockIdx.y * 128;
    const int col0 = blockIdx.x * 128;

    const int warp_m = (wid & 3) * 32;
    const int warp_n = (wid >> 2) * 64;

    float acc[2][8][4];
#pragma unroll
    for (int mt = 0; mt < 2; mt++)
#pragma unroll
        for (int nt = 0; nt < 8; nt++)
#pragma unroll
            for (int j = 0; j < 4; j++) acc[mt][nt][j] = 0.f;

    auto load_slab = [&](int slab, int buf) {
        const uint32_t bufb = sb + buf * STAGE_BYTES;
        const int kbase = slab * 32;
#pragma unroll
        for (int it = 0; it < 2; it++) {
            int c  = tid + it * 256;
            int r  = c >> 2;
            int ch = c & 3;
            uint32_t so = (uint32_t)r * 64 + (uint32_t)((ch ^ ((r >> 1) & 3)) * 16);
            int kc = kbase + ch * 8;
            int gr = row0 + r;
            int asz = (gr < M) ? 16 : 0;
            int gra = (gr < M) ? gr : 0;
            cpa16(bufb + SM_A + so, Ah + (size_t)gra * DD + kc, asz);
        }
#pragma unroll
        for (int it = 0; it < 2; it++) {
            int c  = tid + it * 256;
            int kr = c >> 4;
            int ch = c & 15;
            uint32_t so = (uint32_t)kr * 256 + (uint32_t)((ch ^ (kr & 7)) * 16);
            cpa16(bufb + SM_B + so,
                  Bh + (size_t)(kbase + kr) * ldb + col0 + ch * 8, 16);
        }
        CP_COMMIT();
    };

    auto comp_slab = [&](int buf) {
        const uint32_t bufb = sb + buf * STAGE_BYTES;
#pragma unroll
        for (int ks = 0; ks < 2; ks++) {
            uint32_t af[2][4];
#pragma unroll
            for (int mt = 0; mt < 2; mt++) {
                int r  = warp_m + mt * 16 + (lane & 7) + ((lane >> 3) & 1) * 8;
                int ch = ks * 2 + (lane >> 4);
                uint32_t off = (uint32_t)r * 64
                             + (uint32_t)((ch ^ ((r >> 1) & 3)) * 16);
                ldx4(af[mt], bufb + SM_A + off);
            }
            uint32_t bf[4][4];
#pragma unroll
            for (int np = 0; np < 4; np++) {
                int kr = ks * 16 + (lane & 7) + ((lane >> 3) & 1) * 8;
                int ch = (warp_n >> 3) + np * 2 + ((lane >> 4) & 1);
                uint32_t off = (uint32_t)kr * 256
                             + (uint32_t)((ch ^ (kr & 7)) * 16);
                ldx4t(bf[np], bufb + SM_B + off);
            }
#pragma unroll
            for (int mt = 0; mt < 2; mt++) {
#pragma unroll
                for (int nt = 0; nt < 8; nt++) {
                    int np = nt >> 1, hi = (nt & 1) * 2;
                    mma16816(acc[mt][nt], af[mt], bf[np][hi], bf[np][hi + 1]);
                }
            }
        }
    };

    load_slab(0, 0);
    load_slab(1, 1);
    CP_WAIT(1);
    __syncthreads();
    comp_slab(0);
    __syncthreads();
    load_slab(2, 0);
    CP_WAIT(1);
    __syncthreads();
    comp_slab(1);
    __syncthreads();
    load_slab(3, 1);
    CP_WAIT(1);
    __syncthreads();
    comp_slab(0);
    CP_WAIT(0);
    __syncthreads();
    comp_slab(1);

    const float* __restrict__ bias = ga.bias[z];
    __half* __restrict__ Ch = ga.Ch[z];

    if (Ch) {
        __syncthreads();
#pragma unroll
        for (int mt = 0; mt < 2; mt++) {
#pragma unroll
            for (int half_i = 0; half_i < 2; half_i++) {
#pragma unroll
                for (int ntg = 0; ntg < 2; ntg++) {
                    uint32_t h2[4];
#pragma unroll
                    for (int j = 0; j < 4; j++) {
                        int nt = ntg * 4 + j;
                        int gc = col0 + warp_n + nt * 8 + (lane & 3) * 2;
                        float2 b2 = *reinterpret_cast<const float2*>(bias + gc);
                        __half2 hv = __floats2half2_rn(
                            acc[mt][nt][half_i * 2 + 0] + b2.x,
                            acc[mt][nt][half_i * 2 + 1] + b2.y);
                        h2[j] = *reinterpret_cast<uint32_t*>(&hv);
                    }
                    int lr = warp_m + mt * 16 + half_i * 8 + (lane & 7);
                    int ch = (warp_n >> 3) + ntg * 4 + (lane >> 3);
                    uint32_t addr = sb + (uint32_t)(lr * 256)
                                  + (uint32_t)((ch ^ (lr & 7)) << 4);
                    stx4(addr, h2[0], h2[1], h2[2], h2[3]);
                }
            }
        }
        __syncthreads();
#pragma unroll
        for (int it = 0; it < 8; it++) {
            int id = tid + it * 256;
            int r = id >> 4, ch = id & 15;
            int gr = row0 + r;
            if (gr < M) {
                uint4 v = *reinterpret_cast<uint4*>(
                    smem + r * 256 + ((ch ^ (r & 7)) << 4));
                *reinterpret_cast<uint4*>(Ch + (size_t)gr * ldc + col0 + ch * 8) = v;
            }
        }
    } else {
        float*  __restrict__ Cf = ga.Cf[z];
        __half* __restrict__ Hout = ga.Hout[z];
#pragma unroll
        for (int mt = 0; mt < 2; mt++) {
            int gr0 = row0 + warp_m + mt * 16 + (lane >> 2);
#pragma unroll
            for (int nt = 0; nt < 8; nt++) {
                int gc = col0 + warp_n + nt * 8 + (lane & 3) * 2;
                float2 b2 = *reinterpret_cast<const float2*>(bias + gc);
#pragma unroll
                for (int half_i = 0; half_i < 2; half_i++) {
                    int gr = gr0 + half_i * 8;
                    if (gr >= M) continue;
                    float vx = acc[mt][nt][half_i * 2 + 0] + b2.x;
                    float vy = acc[mt][nt][half_i * 2 + 1] + b2.y;
                    *reinterpret_cast<float2*>(Cf + (size_t)gr * ldc + gc) =
                        make_float2(vx, vy);
                    if (Hout) {
                        *reinterpret_cast<__half2*>(Hout + (size_t)gr * DD + gc) =
                            __floats2half2_rn(vx, vy);
                    }
                }
            }
        }
    }
}

// ---------------------------------------------------------------------------
// Conversion / prep kernels
// ---------------------------------------------------------------------------
__global__ void split2_half_kernel(const float* __restrict__ x0,
                                   const float* __restrict__ x1,
                                   __half* __restrict__ h0,
                                   __half* __restrict__ h1)
{
    int i = blockIdx.x * blockDim.x + threadIdx.x;
    if (i >= 2 * NN * DD) return;
    if (i < NN * DD) h0[i] = __float2half(x0[i]);
    else             h1[i - NN * DD] = __float2half(x1[i - NN * DD]);
}

// One launch: K-major fat W fp16 + fat bias vectors + nw W fp16 (coalesced).
__global__ void prep_all_kernel(const float* __restrict__ gWl_b,
                                const float* __restrict__ gWr_b,
                                const float* __restrict__ gWl_r,
                                const float* __restrict__ gWr_r,
                                const float* __restrict__ cgL_Wf,
                                const float* __restrict__ cgL_Ws,
                                const float* __restrict__ cgR_Wf,
                                const float* __restrict__ cgR_Ws,
                                const float* __restrict__ cgL_bf,
                                const float* __restrict__ cgL_bs,
                                const float* __restrict__ cgR_bf,
                                const float* __restrict__ cgR_bs,
                                const float* __restrict__ nw_W,
                                __half* __restrict__ Wth_my,
                                __half* __restrict__ Wth_opp,
                                __half* __restrict__ nwWh,
                                float* __restrict__ bias_my,
                                float* __restrict__ bias_opp)
{
    int idx = blockIdx.x * blockDim.x + threadIdx.x;
    if (idx < DD * LDC) {
        int k = idx / LDC, n = idx % LDC;
        float wm, wo;
        if (n < 512) {
            wm = gWl_b[k * HD + n];               wo = gWr_b[k * HD + n];
        } else if (n < 1024) {
            int c = n - 512;
            wm = gWr_r[k * HD + c];               wo = gWl_r[k * HD + c];
        } else if (n < 1152) {
            int c = n - 1024;
            wm = cgL_Wf[(DD + k) * DD + c];       wo = cgL_Wf[k * DD + c];
        } else if (n < 1280) {
            int c = n - 1152;
            wm = cgL_Ws[(DD + k) * DD + c];       wo = cgL_Ws[k * DD + c];
        } else if (n < 1408) {
            int c = n - 1280;
            wm = cgR_Wf[k * DD + c];              wo = cgR_Wf[(DD + k) * DD + c];
        } else {
            int c = n - 1408;
            wm = cgR_Ws[k * DD + c];              wo = cgR_Ws[(DD + k) * DD + c];
        }
        Wth_my[idx]  = __float2half(wm);
        Wth_opp[idx] = __float2half(wo);
    }
    if (idx < DD * DD) {
        nwWh[idx] = __float2half(nw_W[idx]);   // already K-major
    }
    if (idx < LDC) {
        int n = idx;
        float bm = 0.f, bo = 0.f;
        if (n >= 1024 && n < 1152) bo = cgL_bf[n - 1024];
        else if (n >= 1152 && n < 1280) bo = cgL_bs[n - 1152];
        if (n >= 1280 && n < 1408) bm = cgR_bf[n - 1280];
        else if (n >= 1408) bm = cgR_bs[n - 1408];
        bias_my[n] = bm;
        bias_opp[n] = bo;
    }
}

// ---------------------------------------------------------------------------
// CSR build (4 relations, built once per launch)
// ---------------------------------------------------------------------------
__global__ void csr_zero_kernel(int* __restrict__ cnt, int* __restrict__ fill)
{
    int i = blockIdx.x * blockDim.x + threadIdx.x;
    if (i < 4 * NN) { cnt[i] = 0; fill[i] = 0; }
}

__global__ void csr_hist_kernel(const int* __restrict__ d0,
                                const int* __restrict__ d1,
                                const int* __restrict__ d2,
                                const int* __restrict__ d3,
                                int* __restrict__ cnt)
{
    int i = blockIdx.x * blockDim.x + threadIdx.x;
    if (i >= EE) return;
    atomicAdd(&cnt[0 * NN + d0[i]], 1);
    atomicAdd(&cnt[1 * NN + d1[i]], 1);
    atomicAdd(&cnt[2 * NN + d2[i]], 1);
    atomicAdd(&cnt[3 * NN + d3[i]], 1);
}

__global__ void csr_scan_kernel(const int* __restrict__ cnt,
                                int* __restrict__ row)
{
    __shared__ int part[1024];
    const int rel = blockIdx.x;
    const int t = threadIdx.x;
    const int CH = (NN + 1023) / 1024;     // 20
    const int base = t * CH;
    int s = 0;
    for (int j = 0; j < CH; j++) {
        int i = base + j;
        if (i < NN) s += cnt[rel * NN + i];
    }
    part[t] = s;
    __syncthreads();
    for (int o = 1; o < 1024; o <<= 1) {
        int u = (t >= o) ? part[t - o] : 0;
        __syncthreads();
        part[t] += u;
        __syncthreads();
    }
    int run = part[t] - s;                 // exclusive prefix
    for (int j = 0; j < CH; j++) {
        int i = base + j;
        if (i < NN) {
            row[rel * (NN + 1) + i] = run;
            run += cnt[rel * NN + i];
        }
    }
    if (t == 1023) row[rel * (NN + 1) + NN] = part[1023];
}

__global__ void csr_scatter_kernel(const int* __restrict__ s0, const int* __restrict__ d0,
                                   const int* __restrict__ s1, const int* __restrict__ d1,
                                   const int* __restrict__ s2, const int* __restrict__ d2,
                                   const int* __restrict__ s3, const int* __restrict__ d3,
                                   const int* __restrict__ row,
                                   int* __restrict__ fill,
                                   int* __restrict__ srcs)
{
    int i = blockIdx.x * blockDim.x + threadIdx.x;
    if (i >= EE) return;
    {
        int d = d0[i];
        int pos = row[0 * (NN + 1) + d] + atomicAdd(&fill[0 * NN + d], 1);
        srcs[0 * EE + pos] = s0[i];
    }
    {
        int d = d1[i];
        int pos = row[1 * (NN + 1) + d] + atomicAdd(&fill[1 * NN + d], 1);
        srcs[1 * EE + pos] = s1[i];
    }
    {
        int d = d2[i];
        int pos = row[2 * (NN + 1) + d] + atomicAdd(&fill[2 * NN + d], 1);
        srcs[2 * EE + pos] = s2[i];
    }
    {
        int d = d3[i];
        int pos = row[3 * (NN + 1) + d] + atomicAdd(&fill[3 * NN + d], 1);
        srcs[3 * EE + pos] = s3[i];
    }
}

// ---------------------------------------------------------------------------
// Fused edge kernel: warp per dst node. GAT with head-per-lane-group layout
// (lane group g = lanes [8g,8g+8) owns head g; 3-shuffle score reduction,
// 1 exp per lane), smem head-combine, then CG gate loop on registers.
// blockIdx.y = dst node type (0 = opp, 1 = my).
// ---------------------------------------------------------------------------
__device__ __forceinline__ float gate1(float f, float g)
{
    float sig = __fdividef(1.f, 1.f + __expf(-f));
    float sp  = fmaxf(g, 0.f) + __logf(1.f + __expf(-fabsf(g)));
    return sig * sp;
}

__global__ void __launch_bounds__(256)
edge_fused_kernel(EdgeArgs a)
{
    __shared__ float buf[8][HH][132];     // [warp][head][col], padded stride

    const int t = blockIdx.y;
    const int w = threadIdx.x >> 5;
    int d = blockIdx.x * 8 + w;
    int lane = threadIdx.x & 31;
    if (d >= NN) return;

    const int g  = lane >> 3;             // head owned by this lane group
    const int gl = lane & 7;              // lane within group
    const int cb = g * DD + gl * 16;      // column base within GAT projection

    float4 o4;

    // ================= GAT phase =================
    {
        const __half* __restrict__ xl = a.xl[t];
        const int* __restrict__ row = a.growp[t];
        const int* __restrict__ srcs = a.gsrcs[t];

        float xr[16], at[16], acc[16];
        {
            const __half* xrp = a.xr[t] + (size_t)d * LDC + cb;
            half8_to_float8(*reinterpret_cast<const uint4*>(xrp),     xr);
            half8_to_float8(*reinterpret_cast<const uint4*>(xrp + 8), xr + 8);
            const float* ap = a.att[t] + cb;
#pragma unroll
            for (int k = 0; k < 4; k++) {
                float4 f = reinterpret_cast<const float4*>(ap)[k];
                at[k * 4 + 0] = f.x; at[k * 4 + 1] = f.y;
                at[k * 4 + 2] = f.z; at[k * 4 + 3] = f.w;
            }
#pragma unroll
            for (int j = 0; j < 16; j++) acc[j] = 0.f;
        }

        float s = 0.f;
        const int e0 = row[d], e1 = row[d + 1];
#pragma unroll 2
        for (int p = e0; p < e1; p++) {
            int sn = srcs[p];
            const __half* xlp = xl + (size_t)sn * LDC + cb;
            float l[16];
            half8_to_float8(*reinterpret_cast<const uint4*>(xlp),     l);
            half8_to_float8(*reinterpret_cast<const uint4*>(xlp + 8), l + 8);
            float part = 0.f;
#pragma unroll
            for (int j = 0; j < 16; j++) {
                float z = l[j] + xr[j];
                z = (z > 0.f) ? z : 0.2f * z;
                part = fmaf(z, at[j], part);
            }
            part += __shfl_xor_sync(0xffffffffu, part, 1);
            part += __shfl_xor_sync(0xffffffffu, part, 2);
            part += __shfl_xor_sync(0xffffffffu, part, 4);
            float e = __expf(part);
            s += e;
#pragma unroll
            for (int j = 0; j < 16; j++) acc[j] = fmaf(e, l[j], acc[j]);
        }

        // stage scaled head aggregate into smem: buf[w][g][gl*16 + j]
        float inv = 0.25f / (s + 1e-16f);
#pragma unroll
        for (int k = 0; k < 4; k++) {
            float4 v = make_float4(acc[k * 4 + 0] * inv, acc[k * 4 + 1] * inv,
                                   acc[k * 4 + 2] * inv, acc[k * 4 + 3] * inv);
            *reinterpret_cast<float4*>(&buf[w][g][gl * 16 + k * 4]) = v;
        }
        __syncwarp();

        // combine heads + residual + GAT bias (lane owns cols lane*4..+4)
        float4 r4 = reinterpret_cast<const float4*>(a.xres[t] + (size_t)d * DD)[lane];
        float4 b4 = reinterpret_cast<const float4*>(a.bias[t])[lane];
        o4 = make_float4(r4.x + b4.x, r4.y + b4.y, r4.z + b4.z, r4.w + b4.w);
#pragma unroll
        for (int gg = 0; gg < HH; gg++) {
            float4 v = *reinterpret_cast<const float4*>(&buf[w][gg][lane * 4]);
            o4.x += v.x; o4.y += v.y; o4.z += v.z; o4.w += v.w;
        }
        __syncwarp();
    }

    // ================= CG phase (acc carried in registers) =================
    {
        const __half* __restrict__ Pfs = a.Pfs[t];
        const __half* __restrict__ Pss = a.Pss[t];
        const int* __restrict__ row = a.crowp[t];
        const int* __restrict__ srcs = a.csrcs[t];

        float4 fd4 = half4_to_float4(
            reinterpret_cast<const uint2*>(a.Pfd[t] + (size_t)d * LDC)[lane]);
        float4 sd4 = half4_to_float4(
            reinterpret_cast<const uint2*>(a.Psd[t] + (size_t)d * LDC)[lane]);

        const int e0 = row[d], e1 = row[d + 1];
#pragma unroll 2
        for (int p = e0; p < e1; p++) {
            int sn = srcs[p];
            float4 fs4 = half4_to_float4(
                reinterpret_cast<const uint2*>(Pfs + (size_t)sn * LDC)[lane]);
            float4 ss4 = half4_to_float4(
                reinterpret_cast<const uint2*>(Pss + (size_t)sn * LDC)[lane]);
            o4.x += gate1(fd4.x + fs4.x, sd4.x + ss4.x);
            o4.y += gate1(fd4.y + fs4.y, sd4.y + ss4.y);
            o4.z += gate1(fd4.z + fs4.z, sd4.z + ss4.z);
            o4.w += gate1(fd4.w + fs4.w, sd4.w + ss4.w);
        }
    }

    size_t off = (size_t)d * DD + lane * 4;
    *reinterpret_cast<__half2*>(a.ah[t] + off)     = __floats2half2_rn(o4.x, o4.y);
    *reinterpret_cast<__half2*>(a.ah[t] + off + 2) = __floats2half2_rn(o4.z, o4.w);
}

// ---------------------------------------------------------------------------
// Host launcher
// ---------------------------------------------------------------------------
extern "C" void kernel_launch(void* const* d_in, const int* in_sizes, int n_in,
                              void* d_out, int out_size)
{
    const float* in_x_my  = (const float*)d_in[0];
    const float* in_x_opp = (const float*)d_in[1];
    const float* gWl_b = (const float*)d_in[2];
    const float* gWr_b = (const float*)d_in[3];
    const float* gatt_b = (const float*)d_in[4];
    const float* gb_b  = (const float*)d_in[5];
    const float* gWl_r = (const float*)d_in[6];
    const float* gWr_r = (const float*)d_in[7];
    const float* gatt_r = (const float*)d_in[8];
    const float* gb_r  = (const float*)d_in[9];
    const float* cgL_Wf = (const float*)d_in[10];
    const float* cgL_bf = (const float*)d_in[11];
    const float* cgL_Ws = (const float*)d_in[12];
    const float* cgL_bs = (const float*)d_in[13];
    const float* cgR_Wf = (const float*)d_in[14];
    const float* cgR_bf = (const float*)d_in[15];
    const float* cgR_Ws = (const float*)d_in[16];
    const float* cgR_bs = (const float*)d_in[17];
    const float* nw_W = (const float*)d_in[18];
    const float* nw_b = (const float*)d_in[19];
    const int* ei_beats     = (const int*)d_in[20];
    const int* ei_loses     = (const int*)d_in[21];
    const int* ei_rev_beats = (const int*)d_in[22];
    const int* ei_rev_loses = (const int*)d_in[23];

    float* out = (float*)d_out;

    float *x_my, *x_opp, *bias_my, *bias_opp;
    __half *C_my, *C_opp;
    __half *xh_my, *xh_opp, *ah_my, *ah_opp;
    __half *Wth_my, *Wth_opp, *nwWh;
    int *rowp, *cntp, *fillp, *srcsp;
    cudaGetSymbolAddress((void**)&C_my,  g_C_my);
    cudaGetSymbolAddress((void**)&C_opp, g_C_opp);
    cudaGetSymbolAddress((void**)&x_my,  g_x_my);
    cudaGetSymbolAddress((void**)&x_opp, g_x_opp);
    cudaGetSymbolAddress((void**)&bias_my,  g_bias_my);
    cudaGetSymbolAddress((void**)&bias_opp, g_bias_opp);
    cudaGetSymbolAddress((void**)&xh_my,  g_xh_my);
    cudaGetSymbolAddress((void**)&xh_opp, g_xh_opp);
    cudaGetSymbolAddress((void**)&ah_my,  g_ah_my);
    cudaGetSymbolAddress((void**)&ah_opp, g_ah_opp);
    cudaGetSymbolAddress((void**)&Wth_my,  g_Wth_my);
    cudaGetSymbolAddress((void**)&Wth_opp, g_Wth_opp);
    cudaGetSymbolAddress((void**)&nwWh, g_nwWh);
    cudaGetSymbolAddress((void**)&rowp,  g_row);
    cudaGetSymbolAddress((void**)&cntp,  g_cnt);
    cudaGetSymbolAddress((void**)&fillp, g_fill);
    cudaGetSymbolAddress((void**)&srcsp, g_srcs);

    cudaFuncSetAttribute(mma_gemm, cudaFuncAttributeMaxDynamicSharedMemorySize,
                         DYN_SMEM);

    const int* src_b  = ei_beats;      const int* dst_b  = ei_beats + EE;
    const int* src_l  = ei_loses;      const int* dst_l  = ei_loses + EE;
    const int* src_rb = ei_rev_beats;  const int* dst_rb = ei_rev_beats + EE;
    const int* src_rl = ei_rev_loses;  const int* dst_rl = ei_rev_loses + EE;

    const int node_blocks = (NN + 7) / 8;
    const int e_blocks    = (EE + 255) / 256;
    const int mtiles      = (NN + 127) / 128;      // 157

    // Launch order: fat mma_gemm at slot 4 so ncu samples it.
    split2_half_kernel<<<(2 * NN * DD + 255) / 256, 256>>>(
        in_x_my, in_x_opp, xh_my, xh_opp);
    prep_all_kernel<<<(DD * LDC + 255) / 256, 256>>>(
        gWl_b, gWr_b, gWl_r, gWr_r,
        cgL_Wf, cgL_Ws, cgR_Wf, cgR_Ws,
        cgL_bf, cgL_bs, cgR_bf, cgR_bs,
        nw_W,
        Wth_my, Wth_opp, nwWh, bias_my, bias_opp);
    csr_zero_kernel<<<(4 * NN + 255) / 256, 256>>>(cntp, fillp);
    {
        GemmArgs ga;
        ga.Ah[0] = xh_my;   ga.Ah[1] = xh_opp;
        ga.Bh[0] = Wth_my;  ga.Bh[1] = Wth_opp;
        ga.bias[0] = bias_my;  ga.bias[1] = bias_opp;
        ga.Ch[0] = C_my;    ga.Ch[1] = C_opp;
        ga.Cf[0] = nullptr; ga.Cf[1] = nullptr;
        ga.Hout[0] = nullptr; ga.Hout[1] = nullptr;
        ga.M = NN; ga.ldc = LDC; ga.ldb = LDC;
        dim3 grid(LDC / 128, mtiles, 2);
        mma_gemm<<<grid, 256, DYN_SMEM>>>(ga);
    }
    csr_hist_kernel<<<e_blocks, 256>>>(dst_b, dst_rl, dst_l, dst_rb, cntp);
    csr_scan_kernel<<<4, 1024>>>(cntp, rowp);
    csr_scatter_kernel<<<e_blocks, 256>>>(src_b, dst_b, src_rl, dst_rl,
                                          src_l, dst_l, src_rb, dst_rb,
                                          rowp, fillp, srcsp);

    const float* cur_my  = in_x_my;
    const float* cur_opp = in_x_opp;

    for (int l = 0; l < LLAYERS; l++) {
        const size_t oW = (size_t)l * DD * HD;
        const size_t oA = (size_t)l * HH * DD;
        const size_t oB = (size_t)l * DD;
        const size_t oC = (size_t)l * 2 * DD * DD;
        const size_t oN = (size_t)l * DD * DD;

        if (l > 0) {
            prep_all_kernel<<<(DD * LDC + 255) / 256, 256>>>(
                gWl_b + oW, gWr_b + oW, gWl_r + oW, gWr_r + oW,
                cgL_Wf + oC, cgL_Ws + oC, cgR_Wf + oC, cgR_Ws + oC,
                cgL_bf + oB, cgL_bs + oB, cgR_bf + oB, cgR_bs + oB,
                nw_W + oN,
                Wth_my, Wth_opp, nwWh, bias_my, bias_opp);
            GemmArgs ga;
            ga.Ah[0] = xh_my;   ga.Ah[1] = xh_opp;
            ga.Bh[0] = Wth_my;  ga.Bh[1] = Wth_opp;
            ga.bias[0] = bias_my;  ga.bias[1] = bias_opp;
            ga.Ch[0] = C_my;    ga.Ch[1] = C_opp;
            ga.Cf[0] = nullptr; ga.Cf[1] = nullptr;
            ga.Hout[0] = nullptr; ga.Hout[1] = nullptr;
            ga.M = NN; ga.ldc = LDC; ga.ldb = LDC;
            dim3 grid(LDC / 128, mtiles, 2);
            mma_gemm<<<grid, 256, DYN_SMEM>>>(ga);
        }

        // ---- fused edge phase: GAT + CG per dst type, one launch ----
        {
            EdgeArgs a;
            // t=0: dst opp — GAT beats (rel 0), CG loses (rel 2)
            a.xl[0] = C_my;        a.xr[0] = C_opp;
            a.att[0] = gatt_b + oA;
            a.growp[0] = rowp + 0 * (NN + 1);  a.gsrcs[0] = srcsp + 0 * EE;
            a.Pfd[0] = C_opp + 1024; a.Pfs[0] = C_my + 1024;
            a.Psd[0] = C_opp + 1152; a.Pss[0] = C_my + 1152;
            a.crowp[0] = rowp + 2 * (NN + 1);  a.csrcs[0] = srcsp + 2 * EE;
            a.xres[0] = cur_opp;   a.bias[0] = gb_b + oB;  a.ah[0] = ah_opp;
            // t=1: dst my — GAT rev_loses (rel 1), CG rev_beats (rel 3)
            a.xl[1] = C_opp + 512; a.xr[1] = C_my + 512;
            a.att[1] = gatt_r + oA;
            a.growp[1] = rowp + 1 * (NN + 1);  a.gsrcs[1] = srcsp + 1 * EE;
            a.Pfd[1] = C_my + 1280; a.Pfs[1] = C_opp + 1280;
            a.Psd[1] = C_my + 1408; a.Pss[1] = C_opp + 1408;
            a.crowp[1] = rowp + 3 * (NN + 1);  a.csrcs[1] = srcsp + 3 * EE;
            a.xres[1] = cur_my;    a.bias[1] = gb_r + oB;  a.ah[1] = ah_my;
            dim3 grid(node_blocks, 2);
            edge_fused_kernel<<<grid, 256>>>(a);
        }

        // ---- nodewise Linear (both node types, one launch; fp32 out) ----
        {
            float* out_my  = (l == LLAYERS - 1) ? out           : x_my;
            float* out_opp = (l == LLAYERS - 1) ? out + NN * DD : x_opp;
            GemmArgs ga;
            ga.Ah[0] = ah_my;   ga.Ah[1] = ah_opp;
            ga.Bh[0] = nwWh;    ga.Bh[1] = nwWh;
            ga.bias[0] = nw_b + oB;  ga.bias[1] = nw_b + oB;
            ga.Ch[0] = nullptr; ga.Ch[1] = nullptr;
            ga.Cf[0] = out_my;  ga.Cf[1] = out_opp;
            ga.Hout[0] = xh_my;  ga.Hout[1] = xh_opp;
            ga.M = NN; ga.ldc = DD; ga.ldb = DD;
            dim3 grid(1, mtiles, 2);
            mma_gemm<<<grid, 256, DYN_SMEM>>>(ga);
        }

        cur_my  = x_my;
        cur_opp = x_opp;
    }
}

// round 14
// speedup vs baseline: 5.2486x; 1.0370x over previous
#include <cuda_runtime.h>
#include <cuda_fp16.h>
#include <math.h>
#include <stdint.h>

// ---------------------------------------------------------------------------
// Problem constants
// ---------------------------------------------------------------------------
#define NN 20000
#define DD 128
#define HH 4
#define EE 80000
#define LLAYERS 2
#define HD (HH * DD)      // 512
#define LDC 1536          // fat projection width per node type

// Fat column layout (per node type X in {my, opp}):
//  [0,512)      GAT projection #1 (my: Wl_beats ; opp: Wr_beats)
//  [512,1024)   GAT projection #2 (my: Wr_rev   ; opp: Wl_rev)
//  [1024,1152)  CG lose Wf part   (my: src/bottom ; opp: dst/top + bf)
//  [1152,1280)  CG lose Ws part   (my: src/bottom ; opp: dst/top + bs)
//  [1280,1408)  CG rev  Wf part   (my: dst/top + bf ; opp: src/bottom)
//  [1408,1536)  CG rev  Ws part   (my: dst/top + bs ; opp: src/bottom)

// ---------------------------------------------------------------------------
// Static device scratch
// ---------------------------------------------------------------------------
__device__ __align__(16) __half g_C_my [(size_t)NN * LDC];   // fp16 fat features
__device__ __align__(16) __half g_C_opp[(size_t)NN * LDC];

__device__ __align__(16) float g_x_my [NN * DD];
__device__ __align__(16) float g_x_opp[NN * DD];

// fp16 feature operands (A side of GEMMs)
__device__ __align__(16) __half g_xh_my [NN * DD];
__device__ __align__(16) __half g_xh_opp[NN * DD];
__device__ __align__(16) __half g_ah_my [NN * DD];
__device__ __align__(16) __half g_ah_opp[NN * DD];

// fp16 weight operands (B side), K-MAJOR: [DD][LDC] / [DD][DD]
__device__ __align__(16) __half g_Wth_my [DD * LDC];
__device__ __align__(16) __half g_Wth_opp[DD * LDC];
__device__ __align__(16) __half g_nwWh[DD * DD];

__device__ __align__(16) float g_bias_my [LDC];
__device__ __align__(16) float g_bias_opp[LDC];

// CSR (4 relations: 0=beats, 1=rev_loses, 2=loses, 3=rev_beats), built once
__device__ int g_row [4 * (NN + 1)];
__device__ int g_cnt [4 * NN];
__device__ int g_fill[4 * NN];
__device__ int g_srcs[4 * EE];

// ---------------------------------------------------------------------------
// Arg structs for merged launches
// ---------------------------------------------------------------------------
struct GemmArgs {
    const __half *Ah[2], *Bh[2];
    const float *bias[2];
    __half *Ch[2];     // fp16 C output (fat projections) -> stmatrix epilogue
    float  *Cf[2];     // fp32 C output (nodewise Linear) -> direct epilogue
    __half *Hout[2];   // fp16 feature copy (next-layer A)
    int M, ldc, ldb;
};

// Fused edge args: index = dst node type (0 = opp, 1 = my)
struct EdgeArgs {
    const __half *xl[2], *xr[2];
    const float *att[2];
    const int *growp[2], *gsrcs[2];
    const __half *Pfd[2], *Pfs[2], *Psd[2], *Pss[2];
    const int *crowp[2], *csrcs[2];
    const float *xres[2], *bias[2];
    __half *ah[2];
};

// ---------------------------------------------------------------------------
// Warp MMA / cp.async helpers
// ---------------------------------------------------------------------------
__device__ __forceinline__ uint32_t smem_to_u32(const void* p)
{
    uint32_t a;
    asm("{ .reg .u64 t; cvta.to.shared.u64 t, %1; cvt.u32.u64 %0, t; }"
        : "=r"(a) : "l"(p));
    return a;
}

__device__ __forceinline__ void ldx4(uint32_t* r, uint32_t addr)
{
    asm volatile("ldmatrix.sync.aligned.m8n8.x4.shared.b16 {%0,%1,%2,%3}, [%4];"
                 : "=r"(r[0]), "=r"(r[1]), "=r"(r[2]), "=r"(r[3]) : "r"(addr));
}

__device__ __forceinline__ void ldx4t(uint32_t* r, uint32_t addr)
{
    asm volatile("ldmatrix.sync.aligned.m8n8.x4.trans.shared.b16 {%0,%1,%2,%3}, [%4];"
                 : "=r"(r[0]), "=r"(r[1]), "=r"(r[2]), "=r"(r[3]) : "r"(addr));
}

__device__ __forceinline__ void stx4(uint32_t addr, uint32_t r0, uint32_t r1,
                                     uint32_t r2, uint32_t r3)
{
    asm volatile("stmatrix.sync.aligned.m8n8.x4.shared.b16 [%0], {%1,%2,%3,%4};"
                 :: "r"(addr), "r"(r0), "r"(r1), "r"(r2), "r"(r3) : "memory");
}

__device__ __forceinline__ void mma16816(float* c, const uint32_t* a,
                                         uint32_t b0, uint32_t b1)
{
    asm volatile(
        "mma.sync.aligned.m16n8k16.row.col.f32.f16.f16.f32 "
        "{%0,%1,%2,%3}, {%4,%5,%6,%7}, {%8,%9}, {%0,%1,%2,%3};"
        : "+f"(c[0]), "+f"(c[1]), "+f"(c[2]), "+f"(c[3])
        : "r"(a[0]), "r"(a[1]), "r"(a[2]), "r"(a[3]), "r"(b0), "r"(b1));
}

__device__ __forceinline__ void cpa16(uint32_t dst, const void* src, int sz)
{
    asm volatile("cp.async.cg.shared.global [%0], [%1], 16, %2;"
                 :: "r"(dst), "l"(src), "r"(sz));
}
#define CP_COMMIT() asm volatile("cp.async.commit_group;" ::: "memory")
#define CP_WAIT(n)  asm volatile("cp.async.wait_group %0;" :: "n"(n) : "memory")

__device__ __forceinline__ float4 half4_to_float4(uint2 v)
{
    __half2 h01 = *reinterpret_cast<__half2*>(&v.x);
    __half2 h23 = *reinterpret_cast<__half2*>(&v.y);
    float2 f0 = __half22float2(h01);
    float2 f1 = __half22float2(h23);
    return make_float4(f0.x, f0.y, f1.x, f1.y);
}

__device__ __forceinline__ void half8_to_float8(uint4 v, float* f)
{
    float4 a = half4_to_float4(make_uint2(v.x, v.y));
    float4 b = half4_to_float4(make_uint2(v.z, v.w));
    f[0] = a.x; f[1] = a.y; f[2] = a.z; f[3] = a.w;
    f[4] = b.x; f[5] = b.y; f[6] = b.z; f[7] = b.w;
}

// ---------------------------------------------------------------------------
// Tensor-core GEMM: C[M, col0..+128] = A[M,128] @ B[128, Nc] + bias.
// A row-major fp16; B K-MAJOR fp16 (ldb cols), loaded via ldmatrix.trans.
// BK=32 slabs, 2-stage cp.async ring, 32 KB smem.
// Ch path: stmatrix -> smem -> coalesced 128B stores.
// ---------------------------------------------------------------------------
#define SM_A  0
#define SM_B  8192
#define STAGE_BYTES 16384
#define DYN_SMEM 32768

__global__ void __launch_bounds__(256, 2)
mma_gemm(GemmArgs ga)
{
    extern __shared__ char smem[];
    const uint32_t sb = smem_to_u32(smem);

    const int z = blockIdx.z;
    const __half* __restrict__ Ah = ga.Ah[z];
    const __half* __restrict__ Bh = ga.Bh[z];
    const int M = ga.M, ldc = ga.ldc, ldb = ga.ldb;

    const int tid  = threadIdx.x;
    const int wid  = tid >> 5;
    const int lane = tid & 31;
    const int row0 = blockIdx.y * 128;
    const int col0 = blockIdx.x * 128;

    const int warp_m = (wid & 3) * 32;
    const int warp_n = (wid >> 2) * 64;

    float acc[2][8][4];
#pragma unroll
    for (int mt = 0; mt < 2; mt++)
#pragma unroll
        for (int nt = 0; nt < 8; nt++)
#pragma unroll
            for (int j = 0; j < 4; j++) acc[mt][nt][j] = 0.f;

    auto load_slab = [&](int slab, int buf) {
        const uint32_t bufb = sb + buf * STAGE_BYTES;
        const int kbase = slab * 32;
#pragma unroll
        for (int it = 0; it < 2; it++) {
            int c  = tid + it * 256;
            int r  = c >> 2;
            int ch = c & 3;
            uint32_t so = (uint32_t)r * 64 + (uint32_t)((ch ^ ((r >> 1) & 3)) * 16);
            int kc = kbase + ch * 8;
            int gr = row0 + r;
            int asz = (gr < M) ? 16 : 0;
            int gra = (gr < M) ? gr : 0;
            cpa16(bufb + SM_A + so, Ah + (size_t)gra * DD + kc, asz);
        }
#pragma unroll
        for (int it = 0; it < 2; it++) {
            int c  = tid + it * 256;
            int kr = c >> 4;
            int ch = c & 15;
            uint32_t so = (uint32_t)kr * 256 + (uint32_t)((ch ^ (kr & 7)) * 16);
            cpa16(bufb + SM_B + so,
                  Bh + (size_t)(kbase + kr) * ldb + col0 + ch * 8, 16);
        }
        CP_COMMIT();
    };

    auto comp_slab = [&](int buf) {
        const uint32_t bufb = sb + buf * STAGE_BYTES;
#pragma unroll
        for (int ks = 0; ks < 2; ks++) {
            uint32_t af[2][4];
#pragma unroll
            for (int mt = 0; mt < 2; mt++) {
                int r  = warp_m + mt * 16 + (lane & 7) + ((lane >> 3) & 1) * 8;
                int ch = ks * 2 + (lane >> 4);
                uint32_t off = (uint32_t)r * 64
                             + (uint32_t)((ch ^ ((r >> 1) & 3)) * 16);
                ldx4(af[mt], bufb + SM_A + off);
            }
            uint32_t bf[4][4];
#pragma unroll
            for (int np = 0; np < 4; np++) {
                int kr = ks * 16 + (lane & 7) + ((lane >> 3) & 1) * 8;
                int ch = (warp_n >> 3) + np * 2 + ((lane >> 4) & 1);
                uint32_t off = (uint32_t)kr * 256
                             + (uint32_t)((ch ^ (kr & 7)) * 16);
                ldx4t(bf[np], bufb + SM_B + off);
            }
#pragma unroll
            for (int mt = 0; mt < 2; mt++) {
#pragma unroll
                for (int nt = 0; nt < 8; nt++) {
                    int np = nt >> 1, hi = (nt & 1) * 2;
                    mma16816(acc[mt][nt], af[mt], bf[np][hi], bf[np][hi + 1]);
                }
            }
        }
    };

    load_slab(0, 0);
    load_slab(1, 1);
    CP_WAIT(1);
    __syncthreads();
    comp_slab(0);
    __syncthreads();
    load_slab(2, 0);
    CP_WAIT(1);
    __syncthreads();
    comp_slab(1);
    __syncthreads();
    load_slab(3, 1);
    CP_WAIT(1);
    __syncthreads();
    comp_slab(0);
    CP_WAIT(0);
    __syncthreads();
    comp_slab(1);

    const float* __restrict__ bias = ga.bias[z];
    __half* __restrict__ Ch = ga.Ch[z];

    if (Ch) {
        __syncthreads();
#pragma unroll
        for (int mt = 0; mt < 2; mt++) {
#pragma unroll
            for (int half_i = 0; half_i < 2; half_i++) {
#pragma unroll
                for (int ntg = 0; ntg < 2; ntg++) {
                    uint32_t h2[4];
#pragma unroll
                    for (int j = 0; j < 4; j++) {
                        int nt = ntg * 4 + j;
                        int gc = col0 + warp_n + nt * 8 + (lane & 3) * 2;
                        float2 b2 = *reinterpret_cast<const float2*>(bias + gc);
                        __half2 hv = __floats2half2_rn(
                            acc[mt][nt][half_i * 2 + 0] + b2.x,
                            acc[mt][nt][half_i * 2 + 1] + b2.y);
                        h2[j] = *reinterpret_cast<uint32_t*>(&hv);
                    }
                    int lr = warp_m + mt * 16 + half_i * 8 + (lane & 7);
                    int ch = (warp_n >> 3) + ntg * 4 + (lane >> 3);
                    uint32_t addr = sb + (uint32_t)(lr * 256)
                                  + (uint32_t)((ch ^ (lr & 7)) << 4);
                    stx4(addr, h2[0], h2[1], h2[2], h2[3]);
                }
            }
        }
        __syncthreads();
#pragma unroll
        for (int it = 0; it < 8; it++) {
            int id = tid + it * 256;
            int r = id >> 4, ch = id & 15;
            int gr = row0 + r;
            if (gr < M) {
                uint4 v = *reinterpret_cast<uint4*>(
                    smem + r * 256 + ((ch ^ (r & 7)) << 4));
                *reinterpret_cast<uint4*>(Ch + (size_t)gr * ldc + col0 + ch * 8) = v;
            }
        }
    } else {
        float*  __restrict__ Cf = ga.Cf[z];
        __half* __restrict__ Hout = ga.Hout[z];
#pragma unroll
        for (int mt = 0; mt < 2; mt++) {
            int gr0 = row0 + warp_m + mt * 16 + (lane >> 2);
#pragma unroll
            for (int nt = 0; nt < 8; nt++) {
                int gc = col0 + warp_n + nt * 8 + (lane & 3) * 2;
                float2 b2 = *reinterpret_cast<const float2*>(bias + gc);
#pragma unroll
                for (int half_i = 0; half_i < 2; half_i++) {
                    int gr = gr0 + half_i * 8;
                    if (gr >= M) continue;
                    float vx = acc[mt][nt][half_i * 2 + 0] + b2.x;
                    float vy = acc[mt][nt][half_i * 2 + 1] + b2.y;
                    *reinterpret_cast<float2*>(Cf + (size_t)gr * ldc + gc) =
                        make_float2(vx, vy);
                    if (Hout) {
                        *reinterpret_cast<__half2*>(Hout + (size_t)gr * DD + gc) =
                            __floats2half2_rn(vx, vy);
                    }
                }
            }
        }
    }
}

// ---------------------------------------------------------------------------
// Conversion / prep kernels
// ---------------------------------------------------------------------------
__global__ void split2_half_kernel(const float* __restrict__ x0,
                                   const float* __restrict__ x1,
                                   __half* __restrict__ h0,
                                   __half* __restrict__ h1)
{
    int i = blockIdx.x * blockDim.x + threadIdx.x;
    if (i >= 2 * NN * DD) return;
    if (i < NN * DD) h0[i] = __float2half(x0[i]);
    else             h1[i - NN * DD] = __float2half(x1[i - NN * DD]);
}

// One launch: K-major fat W fp16 + fat bias vectors + nw W fp16 (coalesced).
__global__ void prep_all_kernel(const float* __restrict__ gWl_b,
                                const float* __restrict__ gWr_b,
                                const float* __restrict__ gWl_r,
                                const float* __restrict__ gWr_r,
                                const float* __restrict__ cgL_Wf,
                                const float* __restrict__ cgL_Ws,
                                const float* __restrict__ cgR_Wf,
                                const float* __restrict__ cgR_Ws,
                                const float* __restrict__ cgL_bf,
                                const float* __restrict__ cgL_bs,
                                const float* __restrict__ cgR_bf,
                                const float* __restrict__ cgR_bs,
                                const float* __restrict__ nw_W,
                                __half* __restrict__ Wth_my,
                                __half* __restrict__ Wth_opp,
                                __half* __restrict__ nwWh,
                                float* __restrict__ bias_my,
                                float* __restrict__ bias_opp)
{
    int idx = blockIdx.x * blockDim.x + threadIdx.x;
    if (idx < DD * LDC) {
        int k = idx / LDC, n = idx % LDC;
        float wm, wo;
        if (n < 512) {
            wm = gWl_b[k * HD + n];               wo = gWr_b[k * HD + n];
        } else if (n < 1024) {
            int c = n - 512;
            wm = gWr_r[k * HD + c];               wo = gWl_r[k * HD + c];
        } else if (n < 1152) {
            int c = n - 1024;
            wm = cgL_Wf[(DD + k) * DD + c];       wo = cgL_Wf[k * DD + c];
        } else if (n < 1280) {
            int c = n - 1152;
            wm = cgL_Ws[(DD + k) * DD + c];       wo = cgL_Ws[k * DD + c];
        } else if (n < 1408) {
            int c = n - 1280;
            wm = cgR_Wf[k * DD + c];              wo = cgR_Wf[(DD + k) * DD + c];
        } else {
            int c = n - 1408;
            wm = cgR_Ws[k * DD + c];              wo = cgR_Ws[(DD + k) * DD + c];
        }
        Wth_my[idx]  = __float2half(wm);
        Wth_opp[idx] = __float2half(wo);
    }
    if (idx < DD * DD) {
        nwWh[idx] = __float2half(nw_W[idx]);   // already K-major
    }
    if (idx < LDC) {
        int n = idx;
        float bm = 0.f, bo = 0.f;
        if (n >= 1024 && n < 1152) bo = cgL_bf[n - 1024];
        else if (n >= 1152 && n < 1280) bo = cgL_bs[n - 1152];
        if (n >= 1280 && n < 1408) bm = cgR_bf[n - 1280];
        else if (n >= 1408) bm = cgR_bs[n - 1408];
        bias_my[n] = bm;
        bias_opp[n] = bo;
    }
}

// ---------------------------------------------------------------------------
// CSR build (4 relations, built once per launch)
// ---------------------------------------------------------------------------
__global__ void csr_zero_kernel(int* __restrict__ cnt, int* __restrict__ fill)
{
    int i = blockIdx.x * blockDim.x + threadIdx.x;
    if (i < 4 * NN) { cnt[i] = 0; fill[i] = 0; }
}

__global__ void csr_hist_kernel(const int* __restrict__ d0,
                                const int* __restrict__ d1,
                                const int* __restrict__ d2,
                                const int* __restrict__ d3,
                                int* __restrict__ cnt)
{
    int i = blockIdx.x * blockDim.x + threadIdx.x;
    if (i >= EE) return;
    atomicAdd(&cnt[0 * NN + d0[i]], 1);
    atomicAdd(&cnt[1 * NN + d1[i]], 1);
    atomicAdd(&cnt[2 * NN + d2[i]], 1);
    atomicAdd(&cnt[3 * NN + d3[i]], 1);
}

__global__ void csr_scan_kernel(const int* __restrict__ cnt,
                                int* __restrict__ row)
{
    __shared__ int part[1024];
    const int rel = blockIdx.x;
    const int t = threadIdx.x;
    const int CH = (NN + 1023) / 1024;     // 20
    const int base = t * CH;
    int s = 0;
    for (int j = 0; j < CH; j++) {
        int i = base + j;
        if (i < NN) s += cnt[rel * NN + i];
    }
    part[t] = s;
    __syncthreads();
    for (int o = 1; o < 1024; o <<= 1) {
        int u = (t >= o) ? part[t - o] : 0;
        __syncthreads();
        part[t] += u;
        __syncthreads();
    }
    int run = part[t] - s;                 // exclusive prefix
    for (int j = 0; j < CH; j++) {
        int i = base + j;
        if (i < NN) {
            row[rel * (NN + 1) + i] = run;
            run += cnt[rel * NN + i];
        }
    }
    if (t == 1023) row[rel * (NN + 1) + NN] = part[1023];
}

__global__ void csr_scatter_kernel(const int* __restrict__ s0, const int* __restrict__ d0,
                                   const int* __restrict__ s1, const int* __restrict__ d1,
                                   const int* __restrict__ s2, const int* __restrict__ d2,
                                   const int* __restrict__ s3, const int* __restrict__ d3,
                                   const int* __restrict__ row,
                                   int* __restrict__ fill,
                                   int* __restrict__ srcs)
{
    int i = blockIdx.x * blockDim.x + threadIdx.x;
    if (i >= EE) return;
    {
        int d = d0[i];
        int pos = row[0 * (NN + 1) + d] + atomicAdd(&fill[0 * NN + d], 1);
        srcs[0 * EE + pos] = s0[i];
    }
    {
        int d = d1[i];
        int pos = row[1 * (NN + 1) + d] + atomicAdd(&fill[1 * NN + d], 1);
        srcs[1 * EE + pos] = s1[i];
    }
    {
        int d = d2[i];
        int pos = row[2 * (NN + 1) + d] + atomicAdd(&fill[2 * NN + d], 1);
        srcs[2 * EE + pos] = s2[i];
    }
    {
        int d = d3[i];
        int pos = row[3 * (NN + 1) + d] + atomicAdd(&fill[3 * NN + d], 1);
        srcs[3 * EE + pos] = s3[i];
    }
}

// ---------------------------------------------------------------------------
// Fused edge kernel: warp per dst node. Head-per-lane-group GAT + CG gate,
// both loops explicitly software-pipelined (edge p+1 index + feature rows
// in flight while computing edge p). blockIdx.y = dst node type.
// ---------------------------------------------------------------------------
__device__ __forceinline__ float gate1(float f, float g)
{
    float sig = __fdividef(1.f, 1.f + __expf(-f));
    float sp  = fmaxf(g, 0.f) + __logf(1.f + __expf(-fabsf(g)));
    return sig * sp;
}

__global__ void __launch_bounds__(256)
edge_fused_kernel(EdgeArgs a)
{
    __shared__ float buf[8][HH][132];     // [warp][head][col], padded stride

    const int t = blockIdx.y;
    const int w = threadIdx.x >> 5;
    int d = blockIdx.x * 8 + w;
    int lane = threadIdx.x & 31;
    if (d >= NN) return;

    const int g  = lane >> 3;             // head owned by this lane group
    const int gl = lane & 7;              // lane within group
    const int cb = g * DD + gl * 16;      // column base within GAT projection

    // hoist per-node residual + bias loads (in flight during GAT loop)
    float4 r4 = reinterpret_cast<const float4*>(a.xres[t] + (size_t)d * DD)[lane];
    float4 b4 = reinterpret_cast<const float4*>(a.bias[t])[lane];

    float4 o4;

    // ================= GAT phase (pipelined) =================
    {
        const __half* __restrict__ xl = a.xl[t];
        const int* __restrict__ row = a.growp[t];
        const int* __restrict__ srcs = a.gsrcs[t];

        float xr[16], at[16], acc[16];
        {
            const __half* xrp = a.xr[t] + (size_t)d * LDC + cb;
            half8_to_float8(*reinterpret_cast<const uint4*>(xrp),     xr);
            half8_to_float8(*reinterpret_cast<const uint4*>(xrp + 8), xr + 8);
            const float* ap = a.att[t] + cb;
#pragma unroll
            for (int k = 0; k < 4; k++) {
                float4 f = reinterpret_cast<const float4*>(ap)[k];
                at[k * 4 + 0] = f.x; at[k * 4 + 1] = f.y;
                at[k * 4 + 2] = f.z; at[k * 4 + 3] = f.w;
            }
#pragma unroll
            for (int j = 0; j < 16; j++) acc[j] = 0.f;
        }

        float s = 0.f;
        const int e0 = row[d], e1 = row[d + 1];

        uint4 c0, c1;                       // in-flight feature rows
        if (e0 < e1) {
            int sn = srcs[e0];
            const __half* xlp = xl + (size_t)sn * LDC + cb;
            c0 = *reinterpret_cast<const uint4*>(xlp);
            c1 = *reinterpret_cast<const uint4*>(xlp + 8);
        }
        for (int p = e0; p < e1; p++) {
            uint4 d0 = c0, d1 = c1;
            if (p + 1 < e1) {
                int sn = srcs[p + 1];
                const __half* xlp = xl + (size_t)sn * LDC + cb;
                c0 = *reinterpret_cast<const uint4*>(xlp);
                c1 = *reinterpret_cast<const uint4*>(xlp + 8);
            }
            float l[16];
            half8_to_float8(d0, l);
            half8_to_float8(d1, l + 8);
            float part = 0.f;
#pragma unroll
            for (int j = 0; j < 16; j++) {
                float z = l[j] + xr[j];
                z = (z > 0.f) ? z : 0.2f * z;
                part = fmaf(z, at[j], part);
            }
            part += __shfl_xor_sync(0xffffffffu, part, 1);
            part += __shfl_xor_sync(0xffffffffu, part, 2);
            part += __shfl_xor_sync(0xffffffffu, part, 4);
            float e = __expf(part);
            s += e;
#pragma unroll
            for (int j = 0; j < 16; j++) acc[j] = fmaf(e, l[j], acc[j]);
        }

        // stage scaled head aggregate into smem: buf[w][g][gl*16 + j]
        float inv = 0.25f / (s + 1e-16f);
#pragma unroll
        for (int k = 0; k < 4; k++) {
            float4 v = make_float4(acc[k * 4 + 0] * inv, acc[k * 4 + 1] * inv,
                                   acc[k * 4 + 2] * inv, acc[k * 4 + 3] * inv);
            *reinterpret_cast<float4*>(&buf[w][g][gl * 16 + k * 4]) = v;
        }
        __syncwarp();

        o4 = make_float4(r4.x + b4.x, r4.y + b4.y, r4.z + b4.z, r4.w + b4.w);
#pragma unroll
        for (int gg = 0; gg < HH; gg++) {
            float4 v = *reinterpret_cast<const float4*>(&buf[w][gg][lane * 4]);
            o4.x += v.x; o4.y += v.y; o4.z += v.z; o4.w += v.w;
        }
        __syncwarp();
    }

    // ================= CG phase (pipelined, acc in registers) ==============
    {
        const __half* __restrict__ Pfs = a.Pfs[t];
        const __half* __restrict__ Pss = a.Pss[t];
        const int* __restrict__ row = a.crowp[t];
        const int* __restrict__ srcs = a.csrcs[t];

        float4 fd4 = half4_to_float4(
            reinterpret_cast<const uint2*>(a.Pfd[t] + (size_t)d * LDC)[lane]);
        float4 sd4 = half4_to_float4(
            reinterpret_cast<const uint2*>(a.Psd[t] + (size_t)d * LDC)[lane]);

        const int e0 = row[d], e1 = row[d + 1];

        uint2 cf, cs;                       // in-flight gate rows
        if (e0 < e1) {
            int sn = srcs[e0];
            cf = reinterpret_cast<const uint2*>(Pfs + (size_t)sn * LDC)[lane];
            cs = reinterpret_cast<const uint2*>(Pss + (size_t)sn * LDC)[lane];
        }
        for (int p = e0; p < e1; p++) {
            uint2 df = cf, ds = cs;
            if (p + 1 < e1) {
                int sn = srcs[p + 1];
                cf = reinterpret_cast<const uint2*>(Pfs + (size_t)sn * LDC)[lane];
                cs = reinterpret_cast<const uint2*>(Pss + (size_t)sn * LDC)[lane];
            }
            float4 fs4 = half4_to_float4(df);
            float4 ss4 = half4_to_float4(ds);
            o4.x += gate1(fd4.x + fs4.x, sd4.x + ss4.x);
            o4.y += gate1(fd4.y + fs4.y, sd4.y + ss4.y);
            o4.z += gate1(fd4.z + fs4.z, sd4.z + ss4.z);
            o4.w += gate1(fd4.w + fs4.w, sd4.w + ss4.w);
        }
    }

    size_t off = (size_t)d * DD + lane * 4;
    *reinterpret_cast<__half2*>(a.ah[t] + off)     = __floats2half2_rn(o4.x, o4.y);
    *reinterpret_cast<__half2*>(a.ah[t] + off + 2) = __floats2half2_rn(o4.z, o4.w);
}

// ---------------------------------------------------------------------------
// Host launcher
// ---------------------------------------------------------------------------
extern "C" void kernel_launch(void* const* d_in, const int* in_sizes, int n_in,
                              void* d_out, int out_size)
{
    const float* in_x_my  = (const float*)d_in[0];
    const float* in_x_opp = (const float*)d_in[1];
    const float* gWl_b = (const float*)d_in[2];
    const float* gWr_b = (const float*)d_in[3];
    const float* gatt_b = (const float*)d_in[4];
    const float* gb_b  = (const float*)d_in[5];
    const float* gWl_r = (const float*)d_in[6];
    const float* gWr_r = (const float*)d_in[7];
    const float* gatt_r = (const float*)d_in[8];
    const float* gb_r  = (const float*)d_in[9];
    const float* cgL_Wf = (const float*)d_in[10];
    const float* cgL_bf = (const float*)d_in[11];
    const float* cgL_Ws = (const float*)d_in[12];
    const float* cgL_bs = (const float*)d_in[13];
    const float* cgR_Wf = (const float*)d_in[14];
    const float* cgR_bf = (const float*)d_in[15];
    const float* cgR_Ws = (const float*)d_in[16];
    const float* cgR_bs = (const float*)d_in[17];
    const float* nw_W = (const float*)d_in[18];
    const float* nw_b = (const float*)d_in[19];
    const int* ei_beats     = (const int*)d_in[20];
    const int* ei_loses     = (const int*)d_in[21];
    const int* ei_rev_beats = (const int*)d_in[22];
    const int* ei_rev_loses = (const int*)d_in[23];

    float* out = (float*)d_out;

    float *x_my, *x_opp, *bias_my, *bias_opp;
    __half *C_my, *C_opp;
    __half *xh_my, *xh_opp, *ah_my, *ah_opp;
    __half *Wth_my, *Wth_opp, *nwWh;
    int *rowp, *cntp, *fillp, *srcsp;
    cudaGetSymbolAddress((void**)&C_my,  g_C_my);
    cudaGetSymbolAddress((void**)&C_opp, g_C_opp);
    cudaGetSymbolAddress((void**)&x_my,  g_x_my);
    cudaGetSymbolAddress((void**)&x_opp, g_x_opp);
    cudaGetSymbolAddress((void**)&bias_my,  g_bias_my);
    cudaGetSymbolAddress((void**)&bias_opp, g_bias_opp);
    cudaGetSymbolAddress((void**)&xh_my,  g_xh_my);
    cudaGetSymbolAddress((void**)&xh_opp, g_xh_opp);
    cudaGetSymbolAddress((void**)&ah_my,  g_ah_my);
    cudaGetSymbolAddress((void**)&ah_opp, g_ah_opp);
    cudaGetSymbolAddress((void**)&Wth_my,  g_Wth_my);
    cudaGetSymbolAddress((void**)&Wth_opp, g_Wth_opp);
    cudaGetSymbolAddress((void**)&nwWh, g_nwWh);
    cudaGetSymbolAddress((void**)&rowp,  g_row);
    cudaGetSymbolAddress((void**)&cntp,  g_cnt);
    cudaGetSymbolAddress((void**)&fillp, g_fill);
    cudaGetSymbolAddress((void**)&srcsp, g_srcs);

    cudaFuncSetAttribute(mma_gemm, cudaFuncAttributeMaxDynamicSharedMemorySize,
                         DYN_SMEM);

    const int* src_b  = ei_beats;      const int* dst_b  = ei_beats + EE;
    const int* src_l  = ei_loses;      const int* dst_l  = ei_loses + EE;
    const int* src_rb = ei_rev_beats;  const int* dst_rb = ei_rev_beats + EE;
    const int* src_rl = ei_rev_loses;  const int* dst_rl = ei_rev_loses + EE;

    const int node_blocks = (NN + 7) / 8;
    const int e_blocks    = (EE + 255) / 256;
    const int mtiles      = (NN + 127) / 128;      // 157

    // Launch order: fat mma_gemm at slot 4 so ncu samples it.
    split2_half_kernel<<<(2 * NN * DD + 255) / 256, 256>>>(
        in_x_my, in_x_opp, xh_my, xh_opp);
    prep_all_kernel<<<(DD * LDC + 255) / 256, 256>>>(
        gWl_b, gWr_b, gWl_r, gWr_r,
        cgL_Wf, cgL_Ws, cgR_Wf, cgR_Ws,
        cgL_bf, cgL_bs, cgR_bf, cgR_bs,
        nw_W,
        Wth_my, Wth_opp, nwWh, bias_my, bias_opp);
    csr_zero_kernel<<<(4 * NN + 255) / 256, 256>>>(cntp, fillp);
    {
        GemmArgs ga;
        ga.Ah[0] = xh_my;   ga.Ah[1] = xh_opp;
        ga.Bh[0] = Wth_my;  ga.Bh[1] = Wth_opp;
        ga.bias[0] = bias_my;  ga.bias[1] = bias_opp;
        ga.Ch[0] = C_my;    ga.Ch[1] = C_opp;
        ga.Cf[0] = nullptr; ga.Cf[1] = nullptr;
        ga.Hout[0] = nullptr; ga.Hout[1] = nullptr;
        ga.M = NN; ga.ldc = LDC; ga.ldb = LDC;
        dim3 grid(LDC / 128, mtiles, 2);
        mma_gemm<<<grid, 256, DYN_SMEM>>>(ga);
    }
    csr_hist_kernel<<<e_blocks, 256>>>(dst_b, dst_rl, dst_l, dst_rb, cntp);
    csr_scan_kernel<<<4, 1024>>>(cntp, rowp);
    csr_scatter_kernel<<<e_blocks, 256>>>(src_b, dst_b, src_rl, dst_rl,
                                          src_l, dst_l, src_rb, dst_rb,
                                          rowp, fillp, srcsp);

    const float* cur_my  = in_x_my;
    const float* cur_opp = in_x_opp;

    for (int l = 0; l < LLAYERS; l++) {
        const size_t oW = (size_t)l * DD * HD;
        const size_t oA = (size_t)l * HH * DD;
        const size_t oB = (size_t)l * DD;
        const size_t oC = (size_t)l * 2 * DD * DD;
        const size_t oN = (size_t)l * DD * DD;

        if (l > 0) {
            prep_all_kernel<<<(DD * LDC + 255) / 256, 256>>>(
                gWl_b + oW, gWr_b + oW, gWl_r + oW, gWr_r + oW,
                cgL_Wf + oC, cgL_Ws + oC, cgR_Wf + oC, cgR_Ws + oC,
                cgL_bf + oB, cgL_bs + oB, cgR_bf + oB, cgR_bs + oB,
                nw_W + oN,
                Wth_my, Wth_opp, nwWh, bias_my, bias_opp);
            GemmArgs ga;
            ga.Ah[0] = xh_my;   ga.Ah[1] = xh_opp;
            ga.Bh[0] = Wth_my;  ga.Bh[1] = Wth_opp;
            ga.bias[0] = bias_my;  ga.bias[1] = bias_opp;
            ga.Ch[0] = C_my;    ga.Ch[1] = C_opp;
            ga.Cf[0] = nullptr; ga.Cf[1] = nullptr;
            ga.Hout[0] = nullptr; ga.Hout[1] = nullptr;
            ga.M = NN; ga.ldc = LDC; ga.ldb = LDC;
            dim3 grid(LDC / 128, mtiles, 2);
            mma_gemm<<<grid, 256, DYN_SMEM>>>(ga);
        }

        // ---- fused edge phase: GAT + CG per dst type, one launch ----
        {
            EdgeArgs a;
            // t=0: dst opp — GAT beats (rel 0), CG loses (rel 2)
            a.xl[0] = C_my;        a.xr[0] = C_opp;
            a.att[0] = gatt_b + oA;
            a.growp[0] = rowp + 0 * (NN + 1);  a.gsrcs[0] = srcsp + 0 * EE;
            a.Pfd[0] = C_opp + 1024; a.Pfs[0] = C_my + 1024;
            a.Psd[0] = C_opp + 1152; a.Pss[0] = C_my + 1152;
            a.crowp[0] = rowp + 2 * (NN + 1);  a.csrcs[0] = srcsp + 2 * EE;
            a.xres[0] = cur_opp;   a.bias[0] = gb_b + oB;  a.ah[0] = ah_opp;
            // t=1: dst my — GAT rev_loses (rel 1), CG rev_beats (rel 3)
            a.xl[1] = C_opp + 512; a.xr[1] = C_my + 512;
            a.att[1] = gatt_r + oA;
            a.growp[1] = rowp + 1 * (NN + 1);  a.gsrcs[1] = srcsp + 1 * EE;
            a.Pfd[1] = C_my + 1280; a.Pfs[1] = C_opp + 1280;
            a.Psd[1] = C_my + 1408; a.Pss[1] = C_opp + 1408;
            a.crowp[1] = rowp + 3 * (NN + 1);  a.csrcs[1] = srcsp + 3 * EE;
            a.xres[1] = cur_my;    a.bias[1] = gb_r + oB;  a.ah[1] = ah_my;
            dim3 grid(node_blocks, 2);
            edge_fused_kernel<<<grid, 256>>>(a);
        }

        // ---- nodewise Linear (both node types, one launch; fp32 out) ----
        {
            float* out_my  = (l == LLAYERS - 1) ? out           : x_my;
            float* out_opp = (l == LLAYERS - 1) ? out + NN * DD : x_opp;
            GemmArgs ga;
            ga.Ah[0] = ah_my;   ga.Ah[1] = ah_opp;
            ga.Bh[0] = nwWh;    ga.Bh[1] = nwWh;
            ga.bias[0] = nw_b + oB;  ga.bias[1] = nw_b + oB;
            ga.Ch[0] = nullptr; ga.Ch[1] = nullptr;
            ga.Cf[0] = out_my;  ga.Cf[1] = out_opp;
            ga.Hout[0] = xh_my;  ga.Hout[1] = xh_opp;
            ga.M = NN; ga.ldc = DD; ga.ldb = DD;
            dim3 grid(1, mtiles, 2);
            mma_gemm<<<grid, 256, DYN_SMEM>>>(ga);
        }

        cur_my  = x_my;
        cur_opp = x_opp;
    }
}